// round 3
// baseline (speedup 1.0000x reference)
#include <cuda_runtime.h>
#include <cuda_bf16.h>
#include <math.h>

#define BB 4
#define SS 1024
#define DD 1024
#define II 2048
#define BS 4096
#define DHM 512
#define DHS 256
#define UU 1344

constexpr long SZ_X   = (long)BS * DD;
constexpr long SZ_UP  = (long)BS * 2 * II;
constexpr long SZ_I   = (long)BS * II;
constexpr long SZ_SC  = 16L * SS * SS;
constexpr long SZ_HB  = 16L * SS * DHM;
constexpr long SZ_PRE = 16L * BS * DHS;
constexpr long SZ_YS  = 16L * SS * DHS;
constexpr long SZ_FFN = (long)BS * 2 * UU;
constexpr long SZ_ACT = (long)BS * UU;
constexpr long SZ_V16 = 16L * SS;
constexpr long SZ_RKT = 4L * 4 * 256 * 256;

constexpr long O_X   = 0;
constexpr long O_XN  = O_X   + SZ_X;
constexpr long O_XC  = O_XN  + SZ_X;
constexpr long O_UP  = O_XC  + SZ_X;
constexpr long O_XA  = O_UP  + SZ_UP;
constexpr long O_Q   = O_XA  + SZ_I;
constexpr long O_K   = O_Q   + SZ_I;
constexpr long O_V   = O_K   + SZ_I;
constexpr long O_SC  = O_V   + SZ_I;
constexpr long O_HB  = O_SC  + SZ_SC;
constexpr long O_HM  = O_HB  + SZ_HB;
constexpr long O_PRE = O_HM  + SZ_I;
constexpr long O_YS  = O_PRE + SZ_PRE;
constexpr long O_FFN = O_YS  + SZ_YS;
constexpr long O_ACT = O_FFN + SZ_FFN;
constexpr long O_IG  = O_ACT + SZ_ACT;
constexpr long O_FG  = O_IG  + SZ_V16;
constexpr long O_A   = O_FG  + SZ_V16;
constexpr long O_RM  = O_A   + SZ_V16;
constexpr long O_EN  = O_RM  + SZ_V16;
constexpr long O_RN  = O_EN  + SZ_V16;
constexpr long O_RKT = O_RN  + SZ_V16;
constexpr long POOL_SZ = O_RKT + SZ_RKT;

__device__ float g_pool[POOL_SZ];

__device__ __forceinline__ float warpSum(float v) {
    #pragma unroll
    for (int o = 16; o > 0; o >>= 1) v += __shfl_down_sync(0xffffffffu, v, o);
    return v;
}

// ---------------- embedding gather ----------------
__global__ void embed_k(const int* __restrict__ ids, const float* __restrict__ emb,
                        float* __restrict__ x)
{
    int bs = blockIdx.x;
    long id = ids[bs];
    ((float4*)(x + (long)bs * DD))[threadIdx.x] =
        ((const float4*)(emb + id * DD))[threadIdx.x];
}

// ---------------- LayerNorm width 1024, 256 thr/row ----------------
__global__ void layernorm_k(const float* __restrict__ x, const float* __restrict__ w,
                            float* __restrict__ y)
{
    long row = blockIdx.x;
    int tid = threadIdx.x;
    float4 v = ((const float4*)(x + row * DD))[tid];
    float s = v.x + v.y + v.z + v.w;
    float ss = v.x*v.x + v.y*v.y + v.z*v.z + v.w*v.w;
    __shared__ float sb[8], sb2[8];
    __shared__ float mu_s, rs_s;
    s = warpSum(s); ss = warpSum(ss);
    if ((tid & 31) == 0) { sb[tid >> 5] = s; sb2[tid >> 5] = ss; }
    __syncthreads();
    if (tid == 0) {
        float t = 0.f, t2 = 0.f;
        #pragma unroll
        for (int i = 0; i < 8; i++) { t += sb[i]; t2 += sb2[i]; }
        float mu = t * (1.f / DD);
        mu_s = mu;
        rs_s = rsqrtf(t2 * (1.f / DD) - mu * mu + 1e-5f);
    }
    __syncthreads();
    float mu = mu_s, rs = rs_s;
    float4 wv = ((const float4*)w)[tid];
    float4 o;
    o.x = (v.x - mu) * rs * wv.x;  o.y = (v.y - mu) * rs * wv.y;
    o.z = (v.z - mu) * rs * wv.z;  o.w = (v.w - mu) * rs * wv.w;
    ((float4*)(y + row * DD))[tid] = o;
}

// ---------------- SGEMM NT: C = alpha*A(MxK)@B(NxK)^T [+bias][+=C] ----------------
__global__ void __launch_bounds__(256, 2) sgemm_nt(
    const float* __restrict__ A, const float* __restrict__ B, float* __restrict__ C,
    int M, int N, int K, int lda, int ldb, int ldc,
    float alpha, const float* __restrict__ bias, int acc)
{
    __shared__ float As[8][128];
    __shared__ float Bs[8][128];
    const int tid = threadIdx.x;
    const int lrow = tid >> 1;
    const int lcol = (tid & 1) << 2;
    const float* Ag = A + (long)(blockIdx.y * 128 + lrow) * lda + lcol;
    const float* Bg = B + (long)(blockIdx.x * 128 + lrow) * ldb + lcol;
    const int ty = tid >> 4, tx = tid & 15;
    float accv[8][8];
    #pragma unroll
    for (int i = 0; i < 8; i++)
        #pragma unroll
        for (int j = 0; j < 8; j++) accv[i][j] = 0.f;
    for (int k0 = 0; k0 < K; k0 += 8) {
        float4 av = *(const float4*)(Ag + k0);
        float4 bv = *(const float4*)(Bg + k0);
        __syncthreads();
        As[lcol+0][lrow] = av.x; As[lcol+1][lrow] = av.y;
        As[lcol+2][lrow] = av.z; As[lcol+3][lrow] = av.w;
        Bs[lcol+0][lrow] = bv.x; Bs[lcol+1][lrow] = bv.y;
        Bs[lcol+2][lrow] = bv.z; Bs[lcol+3][lrow] = bv.w;
        __syncthreads();
        #pragma unroll
        for (int kk = 0; kk < 8; kk++) {
            float ar[8], br[8];
            #pragma unroll
            for (int i = 0; i < 8; i++) ar[i] = As[kk][ty*8 + i];
            #pragma unroll
            for (int j = 0; j < 8; j++) br[j] = Bs[kk][tx*8 + j];
            #pragma unroll
            for (int i = 0; i < 8; i++)
                #pragma unroll
                for (int j = 0; j < 8; j++)
                    accv[i][j] += ar[i] * br[j];
        }
    }
    #pragma unroll
    for (int i = 0; i < 8; i++) {
        long row = blockIdx.y * 128 + ty*8 + i;
        float* Cr = C + row * (long)ldc + blockIdx.x * 128 + tx*8;
        #pragma unroll
        for (int j = 0; j < 8; j++) {
            float v = accv[i][j] * alpha;
            if (bias) v += bias[blockIdx.x * 128 + tx*8 + j];
            if (acc)  v += Cr[j];
            Cr[j] = v;
        }
    }
}

// ---------------- causal depthwise conv (K=4) + SiLU ----------------
__global__ void conv_silu(const float* __restrict__ in, const float* __restrict__ w,
                          const float* __restrict__ bias, float* __restrict__ out,
                          int C, int ldin)
{
    long idx = (long)blockIdx.x * 256 + threadIdx.x;
    if (idx >= (long)BS * C) return;
    int c = (int)(idx % C);
    long bs = idx / C;
    int s = (int)(bs & (SS - 1));
    float acc = bias[c];
    #pragma unroll
    for (int kk = 0; kk < 4; kk++) {
        int sp = s + kk - 3;
        if (sp >= 0) acc += in[(bs + kk - 3) * ldin + c] * w[c*4 + kk];
    }
    out[bs * (long)C + c] = acc / (1.f + __expf(-acc));
}

// ---------------- headwise 4x4 q,k from xa; v from xm(strided) ----------------
__global__ void headwise_qkv(const float* __restrict__ xa, const float* __restrict__ xm,
                             const float* __restrict__ qw, const float* __restrict__ kw,
                             const float* __restrict__ vw,
                             float* __restrict__ q, float* __restrict__ k,
                             float* __restrict__ v)
{
    long idx = (long)blockIdx.x * 256 + threadIdx.x;
    if (idx >= (long)BS * 512) return;
    int nb = (int)(idx & 511);
    long bs = idx >> 9;
    float4 xav = *(const float4*)(xa + bs * II + nb*4);
    float4 xmv = *(const float4*)(xm + bs * (2L*II) + nb*4);
    float xi[4] = {xav.x, xav.y, xav.z, xav.w};
    float xmi[4] = {xmv.x, xmv.y, xmv.z, xmv.w};
    float qo[4], ko[4], vo[4];
    #pragma unroll
    for (int o = 0; o < 4; o++) {
        float aq = 0.f, ak = 0.f, av = 0.f;
        #pragma unroll
        for (int i = 0; i < 4; i++) {
            aq += xi[i]  * qw[nb*16 + o*4 + i];
            ak += xi[i]  * kw[nb*16 + o*4 + i];
            av += xmi[i] * vw[nb*16 + o*4 + i];
        }
        qo[o] = aq; ko[o] = ak; vo[o] = av;
    }
    *(float4*)(q + bs * II + nb*4) = make_float4(qo[0], qo[1], qo[2], qo[3]);
    *(float4*)(k + bs * II + nb*4) = make_float4(ko[0], ko[1], ko[2], ko[3]);
    *(float4*)(v + bs * II + nb*4) = make_float4(vo[0], vo[1], vo[2], vo[3]);
}

// ---------------- ig/fg gate projections ----------------
__global__ void igfg_k(const float* __restrict__ q, const float* __restrict__ k,
                       const float* __restrict__ v,
                       const float* __restrict__ igw, const float* __restrict__ igb,
                       const float* __restrict__ fgw, const float* __restrict__ fgb,
                       float* __restrict__ ig, float* __restrict__ fg)
{
    long bs = blockIdx.x;
    int b = (int)(bs >> 10);
    int s = (int)(bs & (SS - 1));
    __shared__ float sx[3 * II];
    __shared__ float rbuf[2][8];
    int tid = threadIdx.x;
    for (int i = tid; i < II; i += 256) {
        sx[i]        = q[bs * II + i];
        sx[II + i]   = k[bs * II + i];
        sx[2*II + i] = v[bs * II + i];
    }
    __syncthreads();
    for (int h = 0; h < 4; h++) {
        float pi = 0.f, pf = 0.f;
        for (int j = tid; j < 3*II; j += 256) {
            float xv = sx[j];
            pi += xv * igw[h*(3*II) + j];
            pf += xv * fgw[h*(3*II) + j];
        }
        pi = warpSum(pi); pf = warpSum(pf);
        if ((tid & 31) == 0) { rbuf[0][tid >> 5] = pi; rbuf[1][tid >> 5] = pf; }
        __syncthreads();
        if (tid == 0) {
            float a = 0.f, bb = 0.f;
            #pragma unroll
            for (int w8 = 0; w8 < 8; w8++) { a += rbuf[0][w8]; bb += rbuf[1][w8]; }
            ig[(long)(b*4 + h) * SS + s] = a + igb[h];
            fg[(long)(b*4 + h) * SS + s] = bb + fgb[h];
        }
        __syncthreads();
    }
}

// ---------------- mLSTM decay prep (serial per (b,h)) ----------------
__global__ void mlstm_prep(const float* __restrict__ ig, const float* __restrict__ fg,
                           float* __restrict__ a, float* __restrict__ rm,
                           float* __restrict__ en)
{
    int z = blockIdx.x;
    if (threadIdx.x != 0) return;
    float cs = 0.f, run = -1e30f;
    for (int s = 0; s < SS; s++) {
        float fv = fg[(long)z * SS + s];
        cs += fminf(fv, 0.f) - log1pf(expf(-fabsf(fv)));
        float av = ig[(long)z * SS + s] - cs;
        run = fmaxf(run, av);
        a[(long)z * SS + s]  = av;
        rm[(long)z * SS + s] = run;
        en[(long)z * SS + s] = expf(-(cs + run));
    }
}

// ---------------- attention scores: SC = (q.k/sqrt(dh))*exp(a[t]-rm[s]) causal ----------------
__global__ void __launch_bounds__(256, 2) attn_qk(
    const float* __restrict__ Qb, const float* __restrict__ Kb,
    float* __restrict__ SC, const float* __restrict__ a_,
    const float* __restrict__ rm_)
{
    int z = blockIdx.z;
    int b = z >> 2, h = z & 3;
    const int bx = blockIdx.x, by = blockIdx.y;
    float* C = SC + (long)z * SS * SS;
    if (bx > by) {
        for (int i = threadIdx.x; i < 4096; i += 256) {
            int rr = i >> 5, cc = (i & 31) << 2;
            *(float4*)(C + (long)(by*128 + rr) * SS + bx*128 + cc) =
                make_float4(0.f, 0.f, 0.f, 0.f);
        }
        return;
    }
    const float* A = Qb + (long)b * SS * II + h * DHM;
    const float* B = Kb + (long)b * SS * II + h * DHM;
    __shared__ float As[8][128];
    __shared__ float Bs[8][128];
    const int tid = threadIdx.x;
    const int lrow = tid >> 1;
    const int lcol = (tid & 1) << 2;
    const float* Ag = A + (long)(by*128 + lrow) * II + lcol;
    const float* Bg = B + (long)(bx*128 + lrow) * II + lcol;
    const int ty = tid >> 4, tx = tid & 15;
    float accv[8][8];
    #pragma unroll
    for (int i = 0; i < 8; i++)
        #pragma unroll
        for (int j = 0; j < 8; j++) accv[i][j] = 0.f;
    for (int k0 = 0; k0 < DHM; k0 += 8) {
        float4 av = *(const float4*)(Ag + k0);
        float4 bv = *(const float4*)(Bg + k0);
        __syncthreads();
        As[lcol+0][lrow] = av.x; As[lcol+1][lrow] = av.y;
        As[lcol+2][lrow] = av.z; As[lcol+3][lrow] = av.w;
        Bs[lcol+0][lrow] = bv.x; Bs[lcol+1][lrow] = bv.y;
        Bs[lcol+2][lrow] = bv.z; Bs[lcol+3][lrow] = bv.w;
        __syncthreads();
        #pragma unroll
        for (int kk = 0; kk < 8; kk++) {
            float ar[8], br[8];
            #pragma unroll
            for (int i = 0; i < 8; i++) ar[i] = As[kk][ty*8 + i];
            #pragma unroll
            for (int j = 0; j < 8; j++) br[j] = Bs[kk][tx*8 + j];
            #pragma unroll
            for (int i = 0; i < 8; i++)
                #pragma unroll
                for (int j = 0; j < 8; j++)
                    accv[i][j] += ar[i] * br[j];
        }
    }
    const float* az = a_ + (long)z * SS;
    const float* rz = rm_ + (long)z * SS;
    float avv[8], rmv[8];
    #pragma unroll
    for (int j = 0; j < 8; j++) avv[j] = az[bx*128 + tx*8 + j];
    #pragma unroll
    for (int i = 0; i < 8; i++) rmv[i] = rz[by*128 + ty*8 + i];
    const float alpha = 0.04419417382415922f;  // 1/sqrt(512)
    #pragma unroll
    for (int i = 0; i < 8; i++) {
        int row = by*128 + ty*8 + i;
        float* Cr = C + (long)row * SS + bx*128 + tx*8;
        #pragma unroll
        for (int j = 0; j < 8; j++) {
            int col = bx*128 + tx*8 + j;
            Cr[j] = (col <= row) ? accv[i][j] * alpha * __expf(avv[j] - rmv[i]) : 0.f;
        }
    }
}

// ---------------- row normalizer ----------------
__global__ void attn_rowsum(const float* __restrict__ sc, const float* __restrict__ en,
                            float* __restrict__ rn)
{
    int s = blockIdx.x, z = blockIdx.y;
    const float4* row = (const float4*)(sc + ((long)z * SS + s) * SS);
    int tid = threadIdx.x;
    float4 v = row[tid];
    float sm = v.x + v.y + v.z + v.w;
    __shared__ float sb[8];
    sm = warpSum(sm);
    if ((tid & 31) == 0) sb[tid >> 5] = sm;
    __syncthreads();
    if (tid == 0) {
        float t = 0.f;
        #pragma unroll
        for (int i = 0; i < 8; i++) t += sb[i];
        rn[(long)z * SS + s] = 1.f / (fmaxf(fabsf(t), en[(long)z * SS + s]) + 1e-6f);
    }
}

// ---------------- attention value GEMM (NN), K capped at diagonal ----------------
__global__ void __launch_bounds__(256, 2) attn_av(
    const float* __restrict__ SC, const float* __restrict__ Vb,
    const float* __restrict__ Rn, float* __restrict__ H)
{
    int z = blockIdx.z;
    int b = z >> 2, h = z & 3;
    const int bx = blockIdx.x, by = blockIdx.y;
    const float* A = SC + (long)z * SS * SS;
    const float* B = Vb + (long)b * SS * II + h * DHM;
    float* C = H + (long)z * SS * DHM;
    int kend = (by + 1) * 128;
    __shared__ float As[8][128];
    __shared__ float Bs[8][128];
    const int tid = threadIdx.x;
    const int lrow = tid >> 1;
    const int lcol = (tid & 1) << 2;
    const float* Ag = A + (long)(by*128 + lrow) * SS + lcol;
    const int bkrow = tid >> 5;
    const int bncol = (tid & 31) << 2;
    const float* Bg = B + (long)bkrow * II + bx*128 + bncol;
    const int ty = tid >> 4, tx = tid & 15;
    float accv[8][8];
    #pragma unroll
    for (int i = 0; i < 8; i++)
        #pragma unroll
        for (int j = 0; j < 8; j++) accv[i][j] = 0.f;
    for (int k0 = 0; k0 < kend; k0 += 8) {
        float4 av = *(const float4*)(Ag + k0);
        float4 bv = *(const float4*)(Bg + (long)k0 * II);
        __syncthreads();
        As[lcol+0][lrow] = av.x; As[lcol+1][lrow] = av.y;
        As[lcol+2][lrow] = av.z; As[lcol+3][lrow] = av.w;
        *(float4*)&Bs[bkrow][bncol] = bv;
        __syncthreads();
        #pragma unroll
        for (int kk = 0; kk < 8; kk++) {
            float ar[8], br[8];
            #pragma unroll
            for (int i = 0; i < 8; i++) ar[i] = As[kk][ty*8 + i];
            #pragma unroll
            for (int j = 0; j < 8; j++) br[j] = Bs[kk][tx*8 + j];
            #pragma unroll
            for (int i = 0; i < 8; i++)
                #pragma unroll
                for (int j = 0; j < 8; j++)
                    accv[i][j] += ar[i] * br[j];
        }
    }
    const float* rz = Rn + (long)z * SS;
    #pragma unroll
    for (int i = 0; i < 8; i++) {
        int row = by*128 + ty*8 + i;
        float rnv = rz[row];
        float* Cr = C + (long)row * DHM + bx*128 + tx*8;
        #pragma unroll
        for (int j = 0; j < 8; j++)
            Cr[j] = accv[i][j] * rnv;
    }
}

// ---------------- mh_norm(dh=512) + (h+skip*xa)*silu(z) ----------------
__global__ void mh_mix(const float* __restrict__ H, const float* __restrict__ onw,
                       const float* __restrict__ skip, const float* __restrict__ xa,
                       const float* __restrict__ up, float* __restrict__ hmix)
{
    int bs = blockIdx.x, h = blockIdx.y;
    int b = bs >> 10;
    int s = bs & (SS - 1);
    const float* hp = H + ((long)(b*4 + h) * SS + s) * DHM;
    int tid = threadIdx.x;  // 128
    float4 v = ((const float4*)hp)[tid];
    float sm = v.x + v.y + v.z + v.w;
    float sq = v.x*v.x + v.y*v.y + v.z*v.z + v.w*v.w;
    __shared__ float s1[4], s2[4];
    sm = warpSum(sm); sq = warpSum(sq);
    if ((tid & 31) == 0) { s1[tid >> 5] = sm; s2[tid >> 5] = sq; }
    __syncthreads();
    float tot  = s1[0] + s1[1] + s1[2] + s1[3];
    float tot2 = s2[0] + s2[1] + s2[2] + s2[3];
    float mu = tot * (1.f / DHM);
    float rs = rsqrtf(tot2 * (1.f / DHM) - mu * mu + 1e-5f);
    float4 wv  = ((const float4*)onw)[h*128 + tid];
    float4 sk  = ((const float4*)skip)[h*128 + tid];
    float4 xav = ((const float4*)(xa + (long)bs * II))[h*128 + tid];
    float4 zv  = ((const float4*)(up + (long)bs * (2L*II) + II))[h*128 + tid];
    float4 o;
    o.x = ((v.x - mu)*rs*wv.x + sk.x*xav.x) * (zv.x / (1.f + __expf(-zv.x)));
    o.y = ((v.y - mu)*rs*wv.y + sk.y*xav.y) * (zv.y / (1.f + __expf(-zv.y)));
    o.z = ((v.z - mu)*rs*wv.z + sk.z*xav.z) * (zv.z / (1.f + __expf(-zv.z)));
    o.w = ((v.w - mu)*rs*wv.w + sk.w*xav.w) * (zv.w / (1.f + __expf(-zv.w)));
    ((float4*)(hmix + (long)bs * II))[h*128 + tid] = o;
}

// ---------------- rk transpose: rkT[h][g][e][d] = rk[h][d][g][e] ----------------
__global__ void rk_transpose(const float* __restrict__ rk, float* __restrict__ rkT)
{
    long idx = (long)blockIdx.x * 256 + threadIdx.x;
    if (idx >= SZ_RKT) return;
    int d = (int)(idx & 255);
    int e = (int)((idx >> 8) & 255);
    int g = (int)((idx >> 16) & 3);
    int h = (int)(idx >> 18);
    rkT[idx] = rk[(((long)h*256 + d)*4 + g)*256 + e];
}

// ---------------- sLSTM sequential scan: one block per (b,h) ----------------
__global__ void __launch_bounds__(1024) slstm_scan(
    const float* __restrict__ pre, const float* __restrict__ rkT,
    const float* __restrict__ rb, float* __restrict__ ys)
{
    int z = blockIdx.x;
    int b = z >> 2, h = z & 3;
    __shared__ float sh[DHS];
    __shared__ float sraw[1024];
    int tid = threadIdx.x;
    int g = tid >> 8, e = tid & 255;
    float c = 0.f, n = 0.f, m = 0.f;
    if (tid < DHS) sh[tid] = 0.f;
    const float4* rp4 = (const float4*)(rkT + (((long)h*4 + g)*256 + e)*256);
    float rbv = rb[(h*4 + g) * DHS + e];
    const float* pb = pre + ((long)(g*4 + h) * BS + (long)b * SS) * DHS + e;
    float* yo = ys + (long)z * SS * DHS + e;
    __syncthreads();
    for (int s = 0; s < SS; s++) {
        float acc = pb[(long)s * DHS] + rbv;
        #pragma unroll 8
        for (int d4 = 0; d4 < 64; d4++) {
            float4 rv = rp4[d4];
            float4 hv = ((const float4*)sh)[d4];
            acc += rv.x*hv.x + rv.y*hv.y + rv.z*hv.z + rv.w*hv.w;
        }
        sraw[tid] = acc;
        __syncthreads();
        if (tid < DHS) {
            float iraw = sraw[tid], fraw = sraw[256 + tid];
            float zraw = sraw[512 + tid], oraw = sraw[768 + tid];
            float lf = m + fminf(fraw, 0.f) - log1pf(__expf(-fabsf(fraw)));
            float mn = fmaxf(iraw, lf);
            float ig_ = __expf(iraw - mn);
            float fg_ = __expf(lf - mn);
            c = fg_ * c + ig_ * tanhf(zraw);
            n = fg_ * n + ig_;
            m = mn;
            float hv = c / (n * (1.f + __expf(-oraw)));
            sh[tid] = hv;
            yo[(long)s * DHS] = hv;
        }
        __syncthreads();
    }
}

// ---------------- sLSTM group norm (256) + residual add ----------------
__global__ void slstm_gnorm(const float* __restrict__ ys, const float* __restrict__ gnw,
                            float* __restrict__ x)
{
    int bs = blockIdx.x, h = blockIdx.y;
    int b = bs >> 10, s = bs & (SS - 1);
    const float* yp = ys + ((long)(b*4 + h) * SS + s) * DHS;
    int tid = threadIdx.x;  // 64
    float4 v = ((const float4*)yp)[tid];
    float sm = v.x + v.y + v.z + v.w;
    float sq = v.x*v.x + v.y*v.y + v.z*v.z + v.w*v.w;
    __shared__ float s1[2], s2[2];
    sm = warpSum(sm); sq = warpSum(sq);
    if ((tid & 31) == 0) { s1[tid >> 5] = sm; s2[tid >> 5] = sq; }
    __syncthreads();
    float tot  = s1[0] + s1[1];
    float tot2 = s2[0] + s2[1];
    float mu = tot * (1.f / DHS);
    float rs = rsqrtf(tot2 * (1.f / DHS) - mu * mu + 1e-5f);
    float4 wv = ((const float4*)gnw)[h*64 + tid];
    float* xp = x + (long)bs * DD + h * DHS + tid * 4;
    float4 xv = *(float4*)xp;
    xv.x += (v.x - mu) * rs * wv.x;
    xv.y += (v.y - mu) * rs * wv.y;
    xv.z += (v.z - mu) * rs * wv.z;
    xv.w += (v.w - mu) * rs * wv.w;
    *(float4*)xp = xv;
}

// ---------------- FFN: act = gelu_exact(gate) * up ----------------
__global__ void gelu_mul(const float* __restrict__ f, float* __restrict__ a)
{
    long idx = (long)blockIdx.x * 256 + threadIdx.x;
    if (idx >= (long)BS * UU) return;
    long bs = idx / UU;
    int u = (int)(idx % UU);
    float g = f[bs * (2L*UU) + u];
    float p = f[bs * (2L*UU) + UU + u];
    a[idx] = 0.5f * g * (1.f + erff(g * 0.70710678118654752f)) * p;
}

// ---------------- host ----------------
static inline void gemm(const float* A, const float* B, float* C,
                        int M, int N, int K, int lda, int ldb, int ldc,
                        float alpha, const float* bias, int acc)
{
    dim3 grid(N / 128, M / 128);
    sgemm_nt<<<grid, 256>>>(A, B, C, M, N, K, lda, ldb, ldc, alpha, bias, acc);
}

extern "C" void kernel_launch(void* const* d_in, const int* in_sizes, int n_in,
                              void* d_out, int out_size)
{
    const int*   ids       = (const int*)  d_in[0];
    const float* emb       = (const float*)d_in[1];
    const float* m_ln_w    = (const float*)d_in[2];
    const float* m_up_w    = (const float*)d_in[3];
    const float* m_conv_w  = (const float*)d_in[4];
    const float* m_conv_b  = (const float*)d_in[5];
    const float* m_q_w     = (const float*)d_in[6];
    const float* m_k_w     = (const float*)d_in[7];
    const float* m_v_w     = (const float*)d_in[8];
    const float* m_ig_w    = (const float*)d_in[9];
    const float* m_ig_b    = (const float*)d_in[10];
    const float* m_fg_w    = (const float*)d_in[11];
    const float* m_fg_b    = (const float*)d_in[12];
    const float* m_skip    = (const float*)d_in[13];
    const float* m_on_w    = (const float*)d_in[14];
    const float* m_down_w  = (const float*)d_in[15];
    const float* s_ln_w    = (const float*)d_in[16];
    const float* s_conv_w  = (const float*)d_in[17];
    const float* s_conv_b  = (const float*)d_in[18];
    const float* s_iw      = (const float*)d_in[19];
    const float* s_fw      = (const float*)d_in[20];
    const float* s_zw      = (const float*)d_in[21];
    const float* s_ow      = (const float*)d_in[22];
    const float* s_rk      = (const float*)d_in[23];
    const float* s_rb      = (const float*)d_in[24];
    const float* s_gn_w    = (const float*)d_in[25];
    const float* s_ln2_w   = (const float*)d_in[26];
    const float* s_ffn_up  = (const float*)d_in[27];
    const float* s_ffn_dn  = (const float*)d_in[28];
    const float* post_ln_w = (const float*)d_in[29];
    const float* head_w    = (const float*)d_in[30];
    const float* head_b    = (const float*)d_in[31];
    float* out = (float*)d_out;

    float* pool = nullptr;
    cudaGetSymbolAddress((void**)&pool, g_pool);
    float* X   = pool + O_X;   float* XN  = pool + O_XN;  float* XC  = pool + O_XC;
    float* UP  = pool + O_UP;  float* XA  = pool + O_XA;
    float* Q_  = pool + O_Q;   float* K_  = pool + O_K;   float* V_  = pool + O_V;
    float* SC  = pool + O_SC;  float* HB  = pool + O_HB;  float* HM  = pool + O_HM;
    float* PRE = pool + O_PRE; float* YS  = pool + O_YS;
    float* FFN = pool + O_FFN; float* ACT = pool + O_ACT;
    float* IG  = pool + O_IG;  float* FG  = pool + O_FG;
    float* Aa  = pool + O_A;   float* RM  = pool + O_RM;
    float* EN  = pool + O_EN;  float* RN  = pool + O_RN;
    float* RKT = pool + O_RKT;

    embed_k<<<BS, 256>>>(ids, emb, X);
    rk_transpose<<<(int)(SZ_RKT / 256), 256>>>(s_rk, RKT);

    int mi = 0;
    for (int blk = 0; blk < 4; blk++) {
        if (blk == 1) {
            // ---------------- sLSTM block ----------------
            layernorm_k<<<BS, 256>>>(X, s_ln_w, XN);
            conv_silu<<<(BS * DD) / 256, 256>>>(XN, s_conv_w, s_conv_b, XC, DD, DD);
            const float* gw[4] = { s_iw, s_fw, s_zw, s_ow };
            for (int g = 0; g < 4; g++) {
                const float* src = (g < 2) ? XC : XN;
                for (int h = 0; h < 4; h++)
                    gemm(src + h*256, gw[g] + (long)h*65536,
                         PRE + (long)(g*4 + h) * BS * DHS,
                         BS, 256, 256, DD, 256, 256, 1.f, nullptr, 0);
            }
            slstm_scan<<<16, 1024>>>(PRE, RKT, s_rb, YS);
            slstm_gnorm<<<dim3(BS, 4), 64>>>(YS, s_gn_w, X);
            layernorm_k<<<BS, 256>>>(X, s_ln2_w, XN);
            gemm(XN, s_ffn_up, FFN, BS, 2*UU, DD, DD, DD, 2*UU, 1.f, nullptr, 0);
            gelu_mul<<<(int)(((long)BS*UU + 255) / 256), 256>>>(FFN, ACT);
            gemm(ACT, s_ffn_dn, X, BS, DD, UU, UU, UU, DD, 1.f, nullptr, 1);
        } else {
            // ---------------- mLSTM block ----------------
            layernorm_k<<<BS, 256>>>(X, m_ln_w + (long)mi*DD, XN);
            gemm(XN, m_up_w + (long)mi*4096*DD, UP, BS, 4096, DD, DD, DD, 4096,
                 1.f, nullptr, 0);
            conv_silu<<<(int)(((long)BS*II) / 256), 256>>>(
                UP, m_conv_w + (long)mi*II*4, m_conv_b + (long)mi*II, XA, II, 4096);
            headwise_qkv<<<(int)(((long)BS*512) / 256), 256>>>(
                XA, UP, m_q_w + (long)mi*512*16, m_k_w + (long)mi*512*16,
                m_v_w + (long)mi*512*16, Q_, K_, V_);
            igfg_k<<<BS, 256>>>(Q_, K_, V_,
                m_ig_w + (long)mi*4*6144, m_ig_b + (long)mi*4,
                m_fg_w + (long)mi*4*6144, m_fg_b + (long)mi*4, IG, FG);
            mlstm_prep<<<16, 32>>>(IG, FG, Aa, RM, EN);
            attn_qk<<<dim3(8, 8, 16), 256>>>(Q_, K_, SC, Aa, RM);
            attn_rowsum<<<dim3(SS, 16), 256>>>(SC, EN, RN);
            attn_av<<<dim3(4, 8, 16), 256>>>(SC, V_, RN, HB);
            mh_mix<<<dim3(BS, 4), 128>>>(HB, m_on_w + (long)mi*II,
                m_skip + (long)mi*II, XA, UP, HM);
            gemm(HM, m_down_w + (long)mi*DD*II, X, BS, DD, II, II, II, DD,
                 1.f, nullptr, 1);
            mi++;
        }
    }

    layernorm_k<<<BS, 256>>>(X, post_ln_w, XN);
    gemm(XN, head_w, out, BS, 256, DD, DD, DD, 256, 1.f, head_b, 0);
}

// round 4
// speedup vs baseline: 1.7207x; 1.7207x over previous
#include <cuda_runtime.h>
#include <cuda_bf16.h>
#include <math.h>

#define BB 4
#define SS 1024
#define DD 1024
#define II 2048
#define BS 4096
#define DHM 512
#define DHS 256
#define UU 1344

constexpr long SZ_X   = (long)BS * DD;
constexpr long SZ_UP  = (long)BS * 2 * II;
constexpr long SZ_I   = (long)BS * II;
constexpr long SZ_SC  = 16L * SS * SS;
constexpr long SZ_HB  = 16L * SS * DHM;
constexpr long SZ_PRE = 16L * BS * DHS;
constexpr long SZ_YS  = 16L * SS * DHS;
constexpr long SZ_FFN = (long)BS * 2 * UU;
constexpr long SZ_ACT = (long)BS * UU;
constexpr long SZ_V16 = 16L * SS;

constexpr long O_X   = 0;
constexpr long O_XN  = O_X   + SZ_X;
constexpr long O_XC  = O_XN  + SZ_X;
constexpr long O_UP  = O_XC  + SZ_X;
constexpr long O_XA  = O_UP  + SZ_UP;
constexpr long O_Q   = O_XA  + SZ_I;
constexpr long O_K   = O_Q   + SZ_I;
constexpr long O_V   = O_K   + SZ_I;
constexpr long O_SC  = O_V   + SZ_I;
constexpr long O_HB  = O_SC  + SZ_SC;
constexpr long O_HM  = O_HB  + SZ_HB;
constexpr long O_PRE = O_HM  + SZ_I;
constexpr long O_YS  = O_PRE + SZ_PRE;
constexpr long O_FFN = O_YS  + SZ_YS;
constexpr long O_ACT = O_FFN + SZ_FFN;
constexpr long O_IG  = O_ACT + SZ_ACT;
constexpr long O_FG  = O_IG  + SZ_V16;
constexpr long O_A   = O_FG  + SZ_V16;
constexpr long O_RM  = O_A   + SZ_V16;
constexpr long O_EN  = O_RM  + SZ_V16;
constexpr long O_RN  = O_EN  + SZ_V16;
constexpr long POOL_SZ = O_RN + SZ_V16;

__device__ float g_pool[POOL_SZ];

__device__ __forceinline__ float warpSum(float v) {
    #pragma unroll
    for (int o = 16; o > 0; o >>= 1) v += __shfl_down_sync(0xffffffffu, v, o);
    return v;
}

// ---------------- embedding gather ----------------
__global__ void embed_k(const int* __restrict__ ids, const float* __restrict__ emb,
                        float* __restrict__ x)
{
    int bs = blockIdx.x;
    long id = ids[bs];
    ((float4*)(x + (long)bs * DD))[threadIdx.x] =
        ((const float4*)(emb + id * DD))[threadIdx.x];
}

// ---------------- LayerNorm width 1024, 256 thr/row ----------------
__global__ void layernorm_k(const float* __restrict__ x, const float* __restrict__ w,
                            float* __restrict__ y)
{
    long row = blockIdx.x;
    int tid = threadIdx.x;
    float4 v = ((const float4*)(x + row * DD))[tid];
    float s = v.x + v.y + v.z + v.w;
    float ss = v.x*v.x + v.y*v.y + v.z*v.z + v.w*v.w;
    __shared__ float sb[8], sb2[8];
    __shared__ float mu_s, rs_s;
    s = warpSum(s); ss = warpSum(ss);
    if ((tid & 31) == 0) { sb[tid >> 5] = s; sb2[tid >> 5] = ss; }
    __syncthreads();
    if (tid == 0) {
        float t = 0.f, t2 = 0.f;
        #pragma unroll
        for (int i = 0; i < 8; i++) { t += sb[i]; t2 += sb2[i]; }
        float mu = t * (1.f / DD);
        mu_s = mu;
        rs_s = rsqrtf(t2 * (1.f / DD) - mu * mu + 1e-5f);
    }
    __syncthreads();
    float mu = mu_s, rs = rs_s;
    float4 wv = ((const float4*)w)[tid];
    float4 o;
    o.x = (v.x - mu) * rs * wv.x;  o.y = (v.y - mu) * rs * wv.y;
    o.z = (v.z - mu) * rs * wv.z;  o.w = (v.w - mu) * rs * wv.w;
    ((float4*)(y + row * DD))[tid] = o;
}

// ---------------- SGEMM NT: C = alpha*A(MxK)@B(NxK)^T [+bias][+=C] ----------------
__global__ void __launch_bounds__(256, 2) sgemm_nt(
    const float* __restrict__ A, const float* __restrict__ B, float* __restrict__ C,
    int M, int N, int K, int lda, int ldb, int ldc,
    float alpha, const float* __restrict__ bias, int acc)
{
    __shared__ float As[8][128];
    __shared__ float Bs[8][128];
    const int tid = threadIdx.x;
    const int lrow = tid >> 1;
    const int lcol = (tid & 1) << 2;
    const float* Ag = A + (long)(blockIdx.y * 128 + lrow) * lda + lcol;
    const float* Bg = B + (long)(blockIdx.x * 128 + lrow) * ldb + lcol;
    const int ty = tid >> 4, tx = tid & 15;
    float accv[8][8];
    #pragma unroll
    for (int i = 0; i < 8; i++)
        #pragma unroll
        for (int j = 0; j < 8; j++) accv[i][j] = 0.f;
    for (int k0 = 0; k0 < K; k0 += 8) {
        float4 av = *(const float4*)(Ag + k0);
        float4 bv = *(const float4*)(Bg + k0);
        __syncthreads();
        As[lcol+0][lrow] = av.x; As[lcol+1][lrow] = av.y;
        As[lcol+2][lrow] = av.z; As[lcol+3][lrow] = av.w;
        Bs[lcol+0][lrow] = bv.x; Bs[lcol+1][lrow] = bv.y;
        Bs[lcol+2][lrow] = bv.z; Bs[lcol+3][lrow] = bv.w;
        __syncthreads();
        #pragma unroll
        for (int kk = 0; kk < 8; kk++) {
            float ar[8], br[8];
            #pragma unroll
            for (int i = 0; i < 8; i++) ar[i] = As[kk][ty*8 + i];
            #pragma unroll
            for (int j = 0; j < 8; j++) br[j] = Bs[kk][tx*8 + j];
            #pragma unroll
            for (int i = 0; i < 8; i++)
                #pragma unroll
                for (int j = 0; j < 8; j++)
                    accv[i][j] += ar[i] * br[j];
        }
    }
    #pragma unroll
    for (int i = 0; i < 8; i++) {
        long row = blockIdx.y * 128 + ty*8 + i;
        float* Cr = C + row * (long)ldc + blockIdx.x * 128 + tx*8;
        #pragma unroll
        for (int j = 0; j < 8; j++) {
            float v = accv[i][j] * alpha;
            if (bias) v += bias[blockIdx.x * 128 + tx*8 + j];
            if (acc)  v += Cr[j];
            Cr[j] = v;
        }
    }
}

// ---------------- batched sLSTM gate GEMMs: 16 (g,h) pairs in one launch ----------------
__global__ void __launch_bounds__(256, 2) sgemm_gates(
    const float* __restrict__ XC, const float* __restrict__ XN,
    const float* __restrict__ iw, const float* __restrict__ fw,
    const float* __restrict__ zw, const float* __restrict__ ow,
    float* __restrict__ PRE)
{
    const int zz = blockIdx.z;
    const int g = zz >> 2, h = zz & 3;
    const float* A = ((g < 2) ? XC : XN) + h * 256;       // lda = DD
    const float* W = (g == 0) ? iw : (g == 1) ? fw : (g == 2) ? zw : ow;
    const float* B = W + (long)h * 65536;                  // ldb = 256
    float* C = PRE + (long)zz * BS * DHS;                  // ldc = 256
    __shared__ float As[8][128];
    __shared__ float Bs[8][128];
    const int tid = threadIdx.x;
    const int lrow = tid >> 1;
    const int lcol = (tid & 1) << 2;
    const float* Ag = A + (long)(blockIdx.y * 128 + lrow) * DD + lcol;
    const float* Bg = B + (long)(blockIdx.x * 128 + lrow) * 256 + lcol;
    const int ty = tid >> 4, tx = tid & 15;
    float accv[8][8];
    #pragma unroll
    for (int i = 0; i < 8; i++)
        #pragma unroll
        for (int j = 0; j < 8; j++) accv[i][j] = 0.f;
    for (int k0 = 0; k0 < 256; k0 += 8) {
        float4 av = *(const float4*)(Ag + k0);
        float4 bv = *(const float4*)(Bg + k0);
        __syncthreads();
        As[lcol+0][lrow] = av.x; As[lcol+1][lrow] = av.y;
        As[lcol+2][lrow] = av.z; As[lcol+3][lrow] = av.w;
        Bs[lcol+0][lrow] = bv.x; Bs[lcol+1][lrow] = bv.y;
        Bs[lcol+2][lrow] = bv.z; Bs[lcol+3][lrow] = bv.w;
        __syncthreads();
        #pragma unroll
        for (int kk = 0; kk < 8; kk++) {
            float ar[8], br[8];
            #pragma unroll
            for (int i = 0; i < 8; i++) ar[i] = As[kk][ty*8 + i];
            #pragma unroll
            for (int j = 0; j < 8; j++) br[j] = Bs[kk][tx*8 + j];
            #pragma unroll
            for (int i = 0; i < 8; i++)
                #pragma unroll
                for (int j = 0; j < 8; j++)
                    accv[i][j] += ar[i] * br[j];
        }
    }
    #pragma unroll
    for (int i = 0; i < 8; i++) {
        long row = blockIdx.y * 128 + ty*8 + i;
        float* Cr = C + row * 256L + blockIdx.x * 128 + tx*8;
        #pragma unroll
        for (int j = 0; j < 8; j++)
            Cr[j] = accv[i][j];
    }
}

// ---------------- causal depthwise conv (K=4) + SiLU ----------------
__global__ void conv_silu(const float* __restrict__ in, const float* __restrict__ w,
                          const float* __restrict__ bias, float* __restrict__ out,
                          int C, int ldin)
{
    long idx = (long)blockIdx.x * 256 + threadIdx.x;
    if (idx >= (long)BS * C) return;
    int c = (int)(idx % C);
    long bs = idx / C;
    int s = (int)(bs & (SS - 1));
    float acc = bias[c];
    #pragma unroll
    for (int kk = 0; kk < 4; kk++) {
        int sp = s + kk - 3;
        if (sp >= 0) acc += in[(bs + kk - 3) * ldin + c] * w[c*4 + kk];
    }
    out[bs * (long)C + c] = acc / (1.f + __expf(-acc));
}

// ---------------- headwise 4x4 q,k from xa; v from xm(strided) ----------------
__global__ void headwise_qkv(const float* __restrict__ xa, const float* __restrict__ xm,
                             const float* __restrict__ qw, const float* __restrict__ kw,
                             const float* __restrict__ vw,
                             float* __restrict__ q, float* __restrict__ k,
                             float* __restrict__ v)
{
    long idx = (long)blockIdx.x * 256 + threadIdx.x;
    if (idx >= (long)BS * 512) return;
    int nb = (int)(idx & 511);
    long bs = idx >> 9;
    float4 xav = *(const float4*)(xa + bs * II + nb*4);
    float4 xmv = *(const float4*)(xm + bs * (2L*II) + nb*4);
    float xi[4] = {xav.x, xav.y, xav.z, xav.w};
    float xmi[4] = {xmv.x, xmv.y, xmv.z, xmv.w};
    float qo[4], ko[4], vo[4];
    #pragma unroll
    for (int o = 0; o < 4; o++) {
        float aq = 0.f, ak = 0.f, av = 0.f;
        #pragma unroll
        for (int i = 0; i < 4; i++) {
            aq += xi[i]  * qw[nb*16 + o*4 + i];
            ak += xi[i]  * kw[nb*16 + o*4 + i];
            av += xmi[i] * vw[nb*16 + o*4 + i];
        }
        qo[o] = aq; ko[o] = ak; vo[o] = av;
    }
    *(float4*)(q + bs * II + nb*4) = make_float4(qo[0], qo[1], qo[2], qo[3]);
    *(float4*)(k + bs * II + nb*4) = make_float4(ko[0], ko[1], ko[2], ko[3]);
    *(float4*)(v + bs * II + nb*4) = make_float4(vo[0], vo[1], vo[2], vo[3]);
}

// ---------------- ig/fg gate projections ----------------
__global__ void igfg_k(const float* __restrict__ q, const float* __restrict__ k,
                       const float* __restrict__ v,
                       const float* __restrict__ igw, const float* __restrict__ igb,
                       const float* __restrict__ fgw, const float* __restrict__ fgb,
                       float* __restrict__ ig, float* __restrict__ fg)
{
    long bs = blockIdx.x;
    int b = (int)(bs >> 10);
    int s = (int)(bs & (SS - 1));
    __shared__ float sx[3 * II];
    __shared__ float rbuf[2][8];
    int tid = threadIdx.x;
    for (int i = tid; i < II; i += 256) {
        sx[i]        = q[bs * II + i];
        sx[II + i]   = k[bs * II + i];
        sx[2*II + i] = v[bs * II + i];
    }
    __syncthreads();
    for (int h = 0; h < 4; h++) {
        float pi = 0.f, pf = 0.f;
        for (int j = tid; j < 3*II; j += 256) {
            float xv = sx[j];
            pi += xv * igw[h*(3*II) + j];
            pf += xv * fgw[h*(3*II) + j];
        }
        pi = warpSum(pi); pf = warpSum(pf);
        if ((tid & 31) == 0) { rbuf[0][tid >> 5] = pi; rbuf[1][tid >> 5] = pf; }
        __syncthreads();
        if (tid == 0) {
            float a = 0.f, bb = 0.f;
            #pragma unroll
            for (int w8 = 0; w8 < 8; w8++) { a += rbuf[0][w8]; bb += rbuf[1][w8]; }
            ig[(long)(b*4 + h) * SS + s] = a + igb[h];
            fg[(long)(b*4 + h) * SS + s] = bb + fgb[h];
        }
        __syncthreads();
    }
}

// ---------------- mLSTM decay prep: parallel transcendentals, serial scan ----------------
__global__ void mlstm_prep(const float* __restrict__ ig, const float* __restrict__ fg,
                           float* __restrict__ a, float* __restrict__ rm,
                           float* __restrict__ en)
{
    int z = blockIdx.x;
    int tid = threadIdx.x;  // 256
    __shared__ float slsig[SS], sig_s[SS];
    for (int i = tid; i < SS; i += 256) {
        float fv = fg[(long)z * SS + i];
        slsig[i] = fminf(fv, 0.f) - log1pf(__expf(-fabsf(fv)));
        sig_s[i] = ig[(long)z * SS + i];
    }
    __syncthreads();
    if (tid == 0) {
        float cs = 0.f, run = -1e30f;
        for (int s = 0; s < SS; s++) {
            cs += slsig[s];
            float av = sig_s[s] - cs;
            run = fmaxf(run, av);
            a[(long)z * SS + s]  = av;
            rm[(long)z * SS + s] = run;
            en[(long)z * SS + s] = __expf(-(cs + run));
        }
    }
}

// ---------------- attention scores: SC = (q.k/sqrt(dh))*exp(a[t]-rm[s]) causal ----------------
__global__ void __launch_bounds__(256, 2) attn_qk(
    const float* __restrict__ Qb, const float* __restrict__ Kb,
    float* __restrict__ SC, const float* __restrict__ a_,
    const float* __restrict__ rm_)
{
    int z = blockIdx.z;
    int b = z >> 2, h = z & 3;
    const int bx = blockIdx.x, by = blockIdx.y;
    float* C = SC + (long)z * SS * SS;
    if (bx > by) {
        for (int i = threadIdx.x; i < 4096; i += 256) {
            int rr = i >> 5, cc = (i & 31) << 2;
            *(float4*)(C + (long)(by*128 + rr) * SS + bx*128 + cc) =
                make_float4(0.f, 0.f, 0.f, 0.f);
        }
        return;
    }
    const float* A = Qb + (long)b * SS * II + h * DHM;
    const float* B = Kb + (long)b * SS * II + h * DHM;
    __shared__ float As[8][128];
    __shared__ float Bs[8][128];
    const int tid = threadIdx.x;
    const int lrow = tid >> 1;
    const int lcol = (tid & 1) << 2;
    const float* Ag = A + (long)(by*128 + lrow) * II + lcol;
    const float* Bg = B + (long)(bx*128 + lrow) * II + lcol;
    const int ty = tid >> 4, tx = tid & 15;
    float accv[8][8];
    #pragma unroll
    for (int i = 0; i < 8; i++)
        #pragma unroll
        for (int j = 0; j < 8; j++) accv[i][j] = 0.f;
    for (int k0 = 0; k0 < DHM; k0 += 8) {
        float4 av = *(const float4*)(Ag + k0);
        float4 bv = *(const float4*)(Bg + k0);
        __syncthreads();
        As[lcol+0][lrow] = av.x; As[lcol+1][lrow] = av.y;
        As[lcol+2][lrow] = av.z; As[lcol+3][lrow] = av.w;
        Bs[lcol+0][lrow] = bv.x; Bs[lcol+1][lrow] = bv.y;
        Bs[lcol+2][lrow] = bv.z; Bs[lcol+3][lrow] = bv.w;
        __syncthreads();
        #pragma unroll
        for (int kk = 0; kk < 8; kk++) {
            float ar[8], br[8];
            #pragma unroll
            for (int i = 0; i < 8; i++) ar[i] = As[kk][ty*8 + i];
            #pragma unroll
            for (int j = 0; j < 8; j++) br[j] = Bs[kk][tx*8 + j];
            #pragma unroll
            for (int i = 0; i < 8; i++)
                #pragma unroll
                for (int j = 0; j < 8; j++)
                    accv[i][j] += ar[i] * br[j];
        }
    }
    const float* az = a_ + (long)z * SS;
    const float* rz = rm_ + (long)z * SS;
    float avv[8], rmv[8];
    #pragma unroll
    for (int j = 0; j < 8; j++) avv[j] = az[bx*128 + tx*8 + j];
    #pragma unroll
    for (int i = 0; i < 8; i++) rmv[i] = rz[by*128 + ty*8 + i];
    const float alpha = 0.04419417382415922f;  // 1/sqrt(512)
    #pragma unroll
    for (int i = 0; i < 8; i++) {
        int row = by*128 + ty*8 + i;
        float* Cr = C + (long)row * SS + bx*128 + tx*8;
        #pragma unroll
        for (int j = 0; j < 8; j++) {
            int col = bx*128 + tx*8 + j;
            Cr[j] = (col <= row) ? accv[i][j] * alpha * __expf(avv[j] - rmv[i]) : 0.f;
        }
    }
}

// ---------------- row normalizer ----------------
__global__ void attn_rowsum(const float* __restrict__ sc, const float* __restrict__ en,
                            float* __restrict__ rn)
{
    int s = blockIdx.x, z = blockIdx.y;
    const float4* row = (const float4*)(sc + ((long)z * SS + s) * SS);
    int tid = threadIdx.x;
    float4 v = row[tid];
    float sm = v.x + v.y + v.z + v.w;
    __shared__ float sb[8];
    sm = warpSum(sm);
    if ((tid & 31) == 0) sb[tid >> 5] = sm;
    __syncthreads();
    if (tid == 0) {
        float t = 0.f;
        #pragma unroll
        for (int i = 0; i < 8; i++) t += sb[i];
        rn[(long)z * SS + s] = 1.f / (fmaxf(fabsf(t), en[(long)z * SS + s]) + 1e-6f);
    }
}

// ---------------- attention value GEMM (NN), K capped at diagonal ----------------
__global__ void __launch_bounds__(256, 2) attn_av(
    const float* __restrict__ SC, const float* __restrict__ Vb,
    const float* __restrict__ Rn, float* __restrict__ H)
{
    int z = blockIdx.z;
    int b = z >> 2, h = z & 3;
    const int bx = blockIdx.x, by = blockIdx.y;
    const float* A = SC + (long)z * SS * SS;
    const float* B = Vb + (long)b * SS * II + h * DHM;
    float* C = H + (long)z * SS * DHM;
    int kend = (by + 1) * 128;
    __shared__ float As[8][128];
    __shared__ float Bs[8][128];
    const int tid = threadIdx.x;
    const int lrow = tid >> 1;
    const int lcol = (tid & 1) << 2;
    const float* Ag = A + (long)(by*128 + lrow) * SS + lcol;
    const int bkrow = tid >> 5;
    const int bncol = (tid & 31) << 2;
    const float* Bg = B + (long)bkrow * II + bx*128 + bncol;
    const int ty = tid >> 4, tx = tid & 15;
    float accv[8][8];
    #pragma unroll
    for (int i = 0; i < 8; i++)
        #pragma unroll
        for (int j = 0; j < 8; j++) accv[i][j] = 0.f;
    for (int k0 = 0; k0 < kend; k0 += 8) {
        float4 av = *(const float4*)(Ag + k0);
        float4 bv = *(const float4*)(Bg + (long)k0 * II);
        __syncthreads();
        As[lcol+0][lrow] = av.x; As[lcol+1][lrow] = av.y;
        As[lcol+2][lrow] = av.z; As[lcol+3][lrow] = av.w;
        *(float4*)&Bs[bkrow][bncol] = bv;
        __syncthreads();
        #pragma unroll
        for (int kk = 0; kk < 8; kk++) {
            float ar[8], br[8];
            #pragma unroll
            for (int i = 0; i < 8; i++) ar[i] = As[kk][ty*8 + i];
            #pragma unroll
            for (int j = 0; j < 8; j++) br[j] = Bs[kk][tx*8 + j];
            #pragma unroll
            for (int i = 0; i < 8; i++)
                #pragma unroll
                for (int j = 0; j < 8; j++)
                    accv[i][j] += ar[i] * br[j];
        }
    }
    const float* rz = Rn + (long)z * SS;
    #pragma unroll
    for (int i = 0; i < 8; i++) {
        int row = by*128 + ty*8 + i;
        float rnv = rz[row];
        float* Cr = C + (long)row * DHM + bx*128 + tx*8;
        #pragma unroll
        for (int j = 0; j < 8; j++)
            Cr[j] = accv[i][j] * rnv;
    }
}

// ---------------- mh_norm(dh=512) + (h+skip*xa)*silu(z) ----------------
__global__ void mh_mix(const float* __restrict__ H, const float* __restrict__ onw,
                       const float* __restrict__ skip, const float* __restrict__ xa,
                       const float* __restrict__ up, float* __restrict__ hmix)
{
    int bs = blockIdx.x, h = blockIdx.y;
    int b = bs >> 10;
    int s = bs & (SS - 1);
    const float* hp = H + ((long)(b*4 + h) * SS + s) * DHM;
    int tid = threadIdx.x;  // 128
    float4 v = ((const float4*)hp)[tid];
    float sm = v.x + v.y + v.z + v.w;
    float sq = v.x*v.x + v.y*v.y + v.z*v.z + v.w*v.w;
    __shared__ float s1[4], s2[4];
    sm = warpSum(sm); sq = warpSum(sq);
    if ((tid & 31) == 0) { s1[tid >> 5] = sm; s2[tid >> 5] = sq; }
    __syncthreads();
    float tot  = s1[0] + s1[1] + s1[2] + s1[3];
    float tot2 = s2[0] + s2[1] + s2[2] + s2[3];
    float mu = tot * (1.f / DHM);
    float rs = rsqrtf(tot2 * (1.f / DHM) - mu * mu + 1e-5f);
    float4 wv  = ((const float4*)onw)[h*128 + tid];
    float4 sk  = ((const float4*)skip)[h*128 + tid];
    float4 xav = ((const float4*)(xa + (long)bs * II))[h*128 + tid];
    float4 zv  = ((const float4*)(up + (long)bs * (2L*II) + II))[h*128 + tid];
    float4 o;
    o.x = ((v.x - mu)*rs*wv.x + sk.x*xav.x) * (zv.x / (1.f + __expf(-zv.x)));
    o.y = ((v.y - mu)*rs*wv.y + sk.y*xav.y) * (zv.y / (1.f + __expf(-zv.y)));
    o.z = ((v.z - mu)*rs*wv.z + sk.z*xav.z) * (zv.z / (1.f + __expf(-zv.z)));
    o.w = ((v.w - mu)*rs*wv.w + sk.w*xav.w) * (zv.w / (1.f + __expf(-zv.w)));
    ((float4*)(hmix + (long)bs * II))[h*128 + tid] = o;
}

// ---------------- sLSTM scan: block per (b,h), 256 threads ----------------
// thread (g = tid>>6, e4 = tid&63) computes raws for e = 4*e4..4*e4+3 of gate g
// using rk[h][d][g][e] directly (e contiguous -> coalesced float4 loads).
__global__ void __launch_bounds__(256) slstm_scan(
    const float* __restrict__ pre, const float* __restrict__ rk,
    const float* __restrict__ rb, float* __restrict__ ys)
{
    int z = blockIdx.x;
    int b = z >> 2, h = z & 3;
    __shared__ float sh[DHS];
    __shared__ float sraw[1024];
    int tid = threadIdx.x;
    int g = tid >> 6, e4 = tid & 63;
    float c = 0.f, n = 0.f, m = 0.f;
    if (tid < DHS) sh[tid] = 0.f;
    // rk layout [h][d][g][e]: stride per d = 4*256 floats = 256 float4
    const float4* rp = (const float4*)(rk + (long)h * 256 * 1024 + g * 256) + e4;
    float4 rbv = ((const float4*)(rb + (h*4 + g) * DHS))[e4];
    const float* pb = pre + ((long)(g*4 + h) * BS + (long)b * SS) * DHS;
    float* yo = ys + (long)z * SS * DHS;
    __syncthreads();
    for (int s = 0; s < SS; s++) {
        float4 acc = ((const float4*)(pb + (long)s * DHS))[e4];
        acc.x += rbv.x; acc.y += rbv.y; acc.z += rbv.z; acc.w += rbv.w;
        #pragma unroll 8
        for (int d = 0; d < 256; d++) {
            float hv = sh[d];
            float4 rv = rp[d * 256];
            acc.x += hv * rv.x; acc.y += hv * rv.y;
            acc.z += hv * rv.z; acc.w += hv * rv.w;
        }
        ((float4*)(sraw + g * 256))[e4] = acc;
        __syncthreads();
        {
            int e = tid;
            float iraw = sraw[e],       fraw = sraw[256 + e];
            float zraw = sraw[512 + e], oraw = sraw[768 + e];
            float lf = m + fminf(fraw, 0.f) - log1pf(__expf(-fabsf(fraw)));
            float mn = fmaxf(iraw, lf);
            float ig_ = __expf(iraw - mn);
            float fg_ = __expf(lf - mn);
            c = fg_ * c + ig_ * tanhf(zraw);
            n = fg_ * n + ig_;
            m = mn;
            float hv = c / (n * (1.f + __expf(-oraw)));
            sh[e] = hv;
            yo[(long)s * DHS + e] = hv;
        }
        __syncthreads();
    }
}

// ---------------- sLSTM group norm (256) + residual add ----------------
__global__ void slstm_gnorm(const float* __restrict__ ys, const float* __restrict__ gnw,
                            float* __restrict__ x)
{
    int bs = blockIdx.x, h = blockIdx.y;
    int b = bs >> 10, s = bs & (SS - 1);
    const float* yp = ys + ((long)(b*4 + h) * SS + s) * DHS;
    int tid = threadIdx.x;  // 64
    float4 v = ((const float4*)yp)[tid];
    float sm = v.x + v.y + v.z + v.w;
    float sq = v.x*v.x + v.y*v.y + v.z*v.z + v.w*v.w;
    __shared__ float s1[2], s2[2];
    sm = warpSum(sm); sq = warpSum(sq);
    if ((tid & 31) == 0) { s1[tid >> 5] = sm; s2[tid >> 5] = sq; }
    __syncthreads();
    float tot  = s1[0] + s1[1];
    float tot2 = s2[0] + s2[1];
    float mu = tot * (1.f / DHS);
    float rs = rsqrtf(tot2 * (1.f / DHS) - mu * mu + 1e-5f);
    float4 wv = ((const float4*)gnw)[h*64 + tid];
    float* xp = x + (long)bs * DD + h * DHS + tid * 4;
    float4 xv = *(float4*)xp;
    xv.x += (v.x - mu) * rs * wv.x;
    xv.y += (v.y - mu) * rs * wv.y;
    xv.z += (v.z - mu) * rs * wv.z;
    xv.w += (v.w - mu) * rs * wv.w;
    *(float4*)xp = xv;
}

// ---------------- FFN: act = gelu_exact(gate) * up ----------------
__global__ void gelu_mul(const float* __restrict__ f, float* __restrict__ a)
{
    long idx = (long)blockIdx.x * 256 + threadIdx.x;
    if (idx >= (long)BS * UU) return;
    long bs = idx / UU;
    int u = (int)(idx % UU);
    float g = f[bs * (2L*UU) + u];
    float p = f[bs * (2L*UU) + UU + u];
    a[idx] = 0.5f * g * (1.f + erff(g * 0.70710678118654752f)) * p;
}

// ---------------- host ----------------
static inline void gemm(const float* A, const float* B, float* C,
                        int M, int N, int K, int lda, int ldb, int ldc,
                        float alpha, const float* bias, int acc)
{
    dim3 grid(N / 128, M / 128);
    sgemm_nt<<<grid, 256>>>(A, B, C, M, N, K, lda, ldb, ldc, alpha, bias, acc);
}

extern "C" void kernel_launch(void* const* d_in, const int* in_sizes, int n_in,
                              void* d_out, int out_size)
{
    const int*   ids       = (const int*)  d_in[0];
    const float* emb       = (const float*)d_in[1];
    const float* m_ln_w    = (const float*)d_in[2];
    const float* m_up_w    = (const float*)d_in[3];
    const float* m_conv_w  = (const float*)d_in[4];
    const float* m_conv_b  = (const float*)d_in[5];
    const float* m_q_w     = (const float*)d_in[6];
    const float* m_k_w     = (const float*)d_in[7];
    const float* m_v_w     = (const float*)d_in[8];
    const float* m_ig_w    = (const float*)d_in[9];
    const float* m_ig_b    = (const float*)d_in[10];
    const float* m_fg_w    = (const float*)d_in[11];
    const float* m_fg_b    = (const float*)d_in[12];
    const float* m_skip    = (const float*)d_in[13];
    const float* m_on_w    = (const float*)d_in[14];
    const float* m_down_w  = (const float*)d_in[15];
    const float* s_ln_w    = (const float*)d_in[16];
    const float* s_conv_w  = (const float*)d_in[17];
    const float* s_conv_b  = (const float*)d_in[18];
    const float* s_iw      = (const float*)d_in[19];
    const float* s_fw      = (const float*)d_in[20];
    const float* s_zw      = (const float*)d_in[21];
    const float* s_ow      = (const float*)d_in[22];
    const float* s_rk      = (const float*)d_in[23];
    const float* s_rb      = (const float*)d_in[24];
    const float* s_gn_w    = (const float*)d_in[25];
    const float* s_ln2_w   = (const float*)d_in[26];
    const float* s_ffn_up  = (const float*)d_in[27];
    const float* s_ffn_dn  = (const float*)d_in[28];
    const float* post_ln_w = (const float*)d_in[29];
    const float* head_w    = (const float*)d_in[30];
    const float* head_b    = (const float*)d_in[31];
    float* out = (float*)d_out;

    float* pool = nullptr;
    cudaGetSymbolAddress((void**)&pool, g_pool);
    float* X   = pool + O_X;   float* XN  = pool + O_XN;  float* XC  = pool + O_XC;
    float* UP  = pool + O_UP;  float* XA  = pool + O_XA;
    float* Q_  = pool + O_Q;   float* K_  = pool + O_K;   float* V_  = pool + O_V;
    float* SC  = pool + O_SC;  float* HB  = pool + O_HB;  float* HM  = pool + O_HM;
    float* PRE = pool + O_PRE; float* YS  = pool + O_YS;
    float* FFN = pool + O_FFN; float* ACT = pool + O_ACT;
    float* IG  = pool + O_IG;  float* FG  = pool + O_FG;
    float* Aa  = pool + O_A;   float* RM  = pool + O_RM;
    float* EN  = pool + O_EN;  float* RN  = pool + O_RN;

    embed_k<<<BS, 256>>>(ids, emb, X);

    int mi = 0;
    for (int blk = 0; blk < 4; blk++) {
        if (blk == 1) {
            // ---------------- sLSTM block ----------------
            layernorm_k<<<BS, 256>>>(X, s_ln_w, XN);
            conv_silu<<<(BS * DD) / 256, 256>>>(XN, s_conv_w, s_conv_b, XC, DD, DD);
            sgemm_gates<<<dim3(2, 32, 16), 256>>>(XC, XN, s_iw, s_fw, s_zw, s_ow, PRE);
            slstm_scan<<<16, 256>>>(PRE, s_rk, s_rb, YS);
            slstm_gnorm<<<dim3(BS, 4), 64>>>(YS, s_gn_w, X);
            layernorm_k<<<BS, 256>>>(X, s_ln2_w, XN);
            gemm(XN, s_ffn_up, FFN, BS, 2*UU, DD, DD, DD, 2*UU, 1.f, nullptr, 0);
            gelu_mul<<<(int)(((long)BS*UU + 255) / 256), 256>>>(FFN, ACT);
            gemm(ACT, s_ffn_dn, X, BS, DD, UU, UU, UU, DD, 1.f, nullptr, 1);
        } else {
            // ---------------- mLSTM block ----------------
            layernorm_k<<<BS, 256>>>(X, m_ln_w + (long)mi*DD, XN);
            gemm(XN, m_up_w + (long)mi*4096*DD, UP, BS, 4096, DD, DD, DD, 4096,
                 1.f, nullptr, 0);
            conv_silu<<<(int)(((long)BS*II) / 256), 256>>>(
                UP, m_conv_w + (long)mi*II*4, m_conv_b + (long)mi*II, XA, II, 4096);
            headwise_qkv<<<(int)(((long)BS*512) / 256), 256>>>(
                XA, UP, m_q_w + (long)mi*512*16, m_k_w + (long)mi*512*16,
                m_v_w + (long)mi*512*16, Q_, K_, V_);
            igfg_k<<<BS, 256>>>(Q_, K_, V_,
                m_ig_w + (long)mi*4*6144, m_ig_b + (long)mi*4,
                m_fg_w + (long)mi*4*6144, m_fg_b + (long)mi*4, IG, FG);
            mlstm_prep<<<16, 256>>>(IG, FG, Aa, RM, EN);
            attn_qk<<<dim3(8, 8, 16), 256>>>(Q_, K_, SC, Aa, RM);
            attn_rowsum<<<dim3(SS, 16), 256>>>(SC, EN, RN);
            attn_av<<<dim3(4, 8, 16), 256>>>(SC, V_, RN, HB);
            mh_mix<<<dim3(BS, 4), 128>>>(HB, m_on_w + (long)mi*II,
                m_skip + (long)mi*II, XA, UP, HM);
            gemm(HM, m_down_w + (long)mi*DD*II, X, BS, DD, II, II, II, DD,
                 1.f, nullptr, 1);
            mi++;
        }
    }

    layernorm_k<<<BS, 256>>>(X, post_ln_w, XN);
    gemm(XN, head_w, out, BS, 256, DD, DD, DD, 256, 1.f, head_b, 0);
}

// round 5
// speedup vs baseline: 3.4670x; 2.0148x over previous
#include <cuda_runtime.h>
#include <cuda_bf16.h>
#include <math.h>
#include <stdint.h>

#define BB 4
#define SS 1024
#define DD 1024
#define II 2048
#define BS 4096
#define DHM 512
#define DHS 256
#define UU 1344

constexpr long SZ_X   = (long)BS * DD;
constexpr long SZ_UP  = (long)BS * 2 * II;
constexpr long SZ_I   = (long)BS * II;
constexpr long SZ_SC  = 16L * SS * SS;
constexpr long SZ_HB  = 16L * SS * DHM;
constexpr long SZ_PRE = 16L * BS * DHS;
constexpr long SZ_YS  = 16L * SS * DHS;
constexpr long SZ_FFN = (long)BS * 2 * UU;
constexpr long SZ_ACT = (long)BS * UU;
constexpr long SZ_V16 = 16L * SS;

constexpr long O_X   = 0;
constexpr long O_XN  = O_X   + SZ_X;
constexpr long O_XC  = O_XN  + SZ_X;
constexpr long O_UP  = O_XC  + SZ_X;
constexpr long O_XA  = O_UP  + SZ_UP;
constexpr long O_Q   = O_XA  + SZ_I;
constexpr long O_K   = O_Q   + SZ_I;
constexpr long O_V   = O_K   + SZ_I;
constexpr long O_SC  = O_V   + SZ_I;
constexpr long O_HB  = O_SC  + SZ_SC;
constexpr long O_HM  = O_HB  + SZ_HB;
constexpr long O_PRE = O_HM  + SZ_I;
constexpr long O_YS  = O_PRE + SZ_PRE;
constexpr long O_FFN = O_YS  + SZ_YS;
constexpr long O_ACT = O_FFN + SZ_FFN;
constexpr long O_IG  = O_ACT + SZ_ACT;
constexpr long O_FG  = O_IG  + SZ_V16;
constexpr long O_A   = O_FG  + SZ_V16;
constexpr long O_RM  = O_A   + SZ_V16;
constexpr long O_EN  = O_RM  + SZ_V16;
constexpr long O_RN  = O_EN  + SZ_V16;
constexpr long POOL_SZ = O_RN + SZ_V16;

__device__ float g_pool[POOL_SZ];

__device__ __forceinline__ float warpSum(float v) {
    #pragma unroll
    for (int o = 16; o > 0; o >>= 1) v += __shfl_down_sync(0xffffffffu, v, o);
    return v;
}

// ---------------- embedding gather ----------------
__global__ void embed_k(const int* __restrict__ ids, const float* __restrict__ emb,
                        float* __restrict__ x)
{
    int bs = blockIdx.x;
    long id = ids[bs];
    ((float4*)(x + (long)bs * DD))[threadIdx.x] =
        ((const float4*)(emb + id * DD))[threadIdx.x];
}

// ---------------- LayerNorm width 1024, 256 thr/row ----------------
__global__ void layernorm_k(const float* __restrict__ x, const float* __restrict__ w,
                            float* __restrict__ y)
{
    long row = blockIdx.x;
    int tid = threadIdx.x;
    float4 v = ((const float4*)(x + row * DD))[tid];
    float s = v.x + v.y + v.z + v.w;
    float ss = v.x*v.x + v.y*v.y + v.z*v.z + v.w*v.w;
    __shared__ float sb[8], sb2[8];
    __shared__ float mu_s, rs_s;
    s = warpSum(s); ss = warpSum(ss);
    if ((tid & 31) == 0) { sb[tid >> 5] = s; sb2[tid >> 5] = ss; }
    __syncthreads();
    if (tid == 0) {
        float t = 0.f, t2 = 0.f;
        #pragma unroll
        for (int i = 0; i < 8; i++) { t += sb[i]; t2 += sb2[i]; }
        float mu = t * (1.f / DD);
        mu_s = mu;
        rs_s = rsqrtf(t2 * (1.f / DD) - mu * mu + 1e-5f);
    }
    __syncthreads();
    float mu = mu_s, rs = rs_s;
    float4 wv = ((const float4*)w)[tid];
    float4 o;
    o.x = (v.x - mu) * rs * wv.x;  o.y = (v.y - mu) * rs * wv.y;
    o.z = (v.z - mu) * rs * wv.z;  o.w = (v.w - mu) * rs * wv.w;
    ((float4*)(y + row * DD))[tid] = o;
}

// ---------------- SGEMM NT: C = alpha*A(MxK)@B(NxK)^T [+bias][+=C] ----------------
__global__ void __launch_bounds__(256, 2) sgemm_nt(
    const float* __restrict__ A, const float* __restrict__ B, float* __restrict__ C,
    int M, int N, int K, int lda, int ldb, int ldc,
    float alpha, const float* __restrict__ bias, int acc)
{
    __shared__ float As[8][128];
    __shared__ float Bs[8][128];
    const int tid = threadIdx.x;
    const int lrow = tid >> 1;
    const int lcol = (tid & 1) << 2;
    const float* Ag = A + (long)(blockIdx.y * 128 + lrow) * lda + lcol;
    const float* Bg = B + (long)(blockIdx.x * 128 + lrow) * ldb + lcol;
    const int ty = tid >> 4, tx = tid & 15;
    float accv[8][8];
    #pragma unroll
    for (int i = 0; i < 8; i++)
        #pragma unroll
        for (int j = 0; j < 8; j++) accv[i][j] = 0.f;
    for (int k0 = 0; k0 < K; k0 += 8) {
        float4 av = *(const float4*)(Ag + k0);
        float4 bv = *(const float4*)(Bg + k0);
        __syncthreads();
        As[lcol+0][lrow] = av.x; As[lcol+1][lrow] = av.y;
        As[lcol+2][lrow] = av.z; As[lcol+3][lrow] = av.w;
        Bs[lcol+0][lrow] = bv.x; Bs[lcol+1][lrow] = bv.y;
        Bs[lcol+2][lrow] = bv.z; Bs[lcol+3][lrow] = bv.w;
        __syncthreads();
        #pragma unroll
        for (int kk = 0; kk < 8; kk++) {
            float ar[8], br[8];
            #pragma unroll
            for (int i = 0; i < 8; i++) ar[i] = As[kk][ty*8 + i];
            #pragma unroll
            for (int j = 0; j < 8; j++) br[j] = Bs[kk][tx*8 + j];
            #pragma unroll
            for (int i = 0; i < 8; i++)
                #pragma unroll
                for (int j = 0; j < 8; j++)
                    accv[i][j] += ar[i] * br[j];
        }
    }
    #pragma unroll
    for (int i = 0; i < 8; i++) {
        long row = blockIdx.y * 128 + ty*8 + i;
        float* Cr = C + row * (long)ldc + blockIdx.x * 128 + tx*8;
        #pragma unroll
        for (int j = 0; j < 8; j++) {
            float v = accv[i][j] * alpha;
            if (bias) v += bias[blockIdx.x * 128 + tx*8 + j];
            if (acc)  v += Cr[j];
            Cr[j] = v;
        }
    }
}

// ---------------- batched sLSTM gate GEMMs ----------------
__global__ void __launch_bounds__(256, 2) sgemm_gates(
    const float* __restrict__ XC, const float* __restrict__ XN,
    const float* __restrict__ iw, const float* __restrict__ fw,
    const float* __restrict__ zw, const float* __restrict__ ow,
    float* __restrict__ PRE)
{
    const int zz = blockIdx.z;
    const int g = zz >> 2, h = zz & 3;
    const float* A = ((g < 2) ? XC : XN) + h * 256;
    const float* W = (g == 0) ? iw : (g == 1) ? fw : (g == 2) ? zw : ow;
    const float* B = W + (long)h * 65536;
    float* C = PRE + (long)zz * BS * DHS;
    __shared__ float As[8][128];
    __shared__ float Bs[8][128];
    const int tid = threadIdx.x;
    const int lrow = tid >> 1;
    const int lcol = (tid & 1) << 2;
    const float* Ag = A + (long)(blockIdx.y * 128 + lrow) * DD + lcol;
    const float* Bg = B + (long)(blockIdx.x * 128 + lrow) * 256 + lcol;
    const int ty = tid >> 4, tx = tid & 15;
    float accv[8][8];
    #pragma unroll
    for (int i = 0; i < 8; i++)
        #pragma unroll
        for (int j = 0; j < 8; j++) accv[i][j] = 0.f;
    for (int k0 = 0; k0 < 256; k0 += 8) {
        float4 av = *(const float4*)(Ag + k0);
        float4 bv = *(const float4*)(Bg + k0);
        __syncthreads();
        As[lcol+0][lrow] = av.x; As[lcol+1][lrow] = av.y;
        As[lcol+2][lrow] = av.z; As[lcol+3][lrow] = av.w;
        Bs[lcol+0][lrow] = bv.x; Bs[lcol+1][lrow] = bv.y;
        Bs[lcol+2][lrow] = bv.z; Bs[lcol+3][lrow] = bv.w;
        __syncthreads();
        #pragma unroll
        for (int kk = 0; kk < 8; kk++) {
            float ar[8], br[8];
            #pragma unroll
            for (int i = 0; i < 8; i++) ar[i] = As[kk][ty*8 + i];
            #pragma unroll
            for (int j = 0; j < 8; j++) br[j] = Bs[kk][tx*8 + j];
            #pragma unroll
            for (int i = 0; i < 8; i++)
                #pragma unroll
                for (int j = 0; j < 8; j++)
                    accv[i][j] += ar[i] * br[j];
        }
    }
    #pragma unroll
    for (int i = 0; i < 8; i++) {
        long row = blockIdx.y * 128 + ty*8 + i;
        float* Cr = C + row * 256L + blockIdx.x * 128 + tx*8;
        #pragma unroll
        for (int j = 0; j < 8; j++)
            Cr[j] = accv[i][j];
    }
}

// ---------------- causal depthwise conv (K=4) + SiLU ----------------
__global__ void conv_silu(const float* __restrict__ in, const float* __restrict__ w,
                          const float* __restrict__ bias, float* __restrict__ out,
                          int C, int ldin)
{
    long idx = (long)blockIdx.x * 256 + threadIdx.x;
    if (idx >= (long)BS * C) return;
    int c = (int)(idx % C);
    long bs = idx / C;
    int s = (int)(bs & (SS - 1));
    float acc = bias[c];
    #pragma unroll
    for (int kk = 0; kk < 4; kk++) {
        int sp = s + kk - 3;
        if (sp >= 0) acc += in[(bs + kk - 3) * ldin + c] * w[c*4 + kk];
    }
    out[bs * (long)C + c] = acc / (1.f + __expf(-acc));
}

// ---------------- headwise 4x4 q,k from xa; v from xm(strided) ----------------
__global__ void headwise_qkv(const float* __restrict__ xa, const float* __restrict__ xm,
                             const float* __restrict__ qw, const float* __restrict__ kw,
                             const float* __restrict__ vw,
                             float* __restrict__ q, float* __restrict__ k,
                             float* __restrict__ v)
{
    long idx = (long)blockIdx.x * 256 + threadIdx.x;
    if (idx >= (long)BS * 512) return;
    int nb = (int)(idx & 511);
    long bs = idx >> 9;
    float4 xav = *(const float4*)(xa + bs * II + nb*4);
    float4 xmv = *(const float4*)(xm + bs * (2L*II) + nb*4);
    float xi[4] = {xav.x, xav.y, xav.z, xav.w};
    float xmi[4] = {xmv.x, xmv.y, xmv.z, xmv.w};
    float qo[4], ko[4], vo[4];
    #pragma unroll
    for (int o = 0; o < 4; o++) {
        float aq = 0.f, ak = 0.f, av = 0.f;
        #pragma unroll
        for (int i = 0; i < 4; i++) {
            aq += xi[i]  * qw[nb*16 + o*4 + i];
            ak += xi[i]  * kw[nb*16 + o*4 + i];
            av += xmi[i] * vw[nb*16 + o*4 + i];
        }
        qo[o] = aq; ko[o] = ak; vo[o] = av;
    }
    *(float4*)(q + bs * II + nb*4) = make_float4(qo[0], qo[1], qo[2], qo[3]);
    *(float4*)(k + bs * II + nb*4) = make_float4(ko[0], ko[1], ko[2], ko[3]);
    *(float4*)(v + bs * II + nb*4) = make_float4(vo[0], vo[1], vo[2], vo[3]);
}

// ---------------- ig/fg gate projections ----------------
__global__ void igfg_k(const float* __restrict__ q, const float* __restrict__ k,
                       const float* __restrict__ v,
                       const float* __restrict__ igw, const float* __restrict__ igb,
                       const float* __restrict__ fgw, const float* __restrict__ fgb,
                       float* __restrict__ ig, float* __restrict__ fg)
{
    long bs = blockIdx.x;
    int b = (int)(bs >> 10);
    int s = (int)(bs & (SS - 1));
    __shared__ float sx[3 * II];
    __shared__ float rbuf[2][8];
    int tid = threadIdx.x;
    for (int i = tid; i < II; i += 256) {
        sx[i]        = q[bs * II + i];
        sx[II + i]   = k[bs * II + i];
        sx[2*II + i] = v[bs * II + i];
    }
    __syncthreads();
    for (int h = 0; h < 4; h++) {
        float pi = 0.f, pf = 0.f;
        for (int j = tid; j < 3*II; j += 256) {
            float xv = sx[j];
            pi += xv * igw[h*(3*II) + j];
            pf += xv * fgw[h*(3*II) + j];
        }
        pi = warpSum(pi); pf = warpSum(pf);
        if ((tid & 31) == 0) { rbuf[0][tid >> 5] = pi; rbuf[1][tid >> 5] = pf; }
        __syncthreads();
        if (tid == 0) {
            float a = 0.f, bb = 0.f;
            #pragma unroll
            for (int w8 = 0; w8 < 8; w8++) { a += rbuf[0][w8]; bb += rbuf[1][w8]; }
            ig[(long)(b*4 + h) * SS + s] = a + igb[h];
            fg[(long)(b*4 + h) * SS + s] = bb + fgb[h];
        }
        __syncthreads();
    }
}

// ---------------- mLSTM decay prep ----------------
__global__ void mlstm_prep(const float* __restrict__ ig, const float* __restrict__ fg,
                           float* __restrict__ a, float* __restrict__ rm,
                           float* __restrict__ en)
{
    int z = blockIdx.x;
    int tid = threadIdx.x;  // 256
    __shared__ float slsig[SS], sig_s[SS];
    for (int i = tid; i < SS; i += 256) {
        float fv = fg[(long)z * SS + i];
        slsig[i] = fminf(fv, 0.f) - log1pf(__expf(-fabsf(fv)));
        sig_s[i] = ig[(long)z * SS + i];
    }
    __syncthreads();
    if (tid == 0) {
        float cs = 0.f, run = -1e30f;
        for (int s = 0; s < SS; s++) {
            cs += slsig[s];
            float av = sig_s[s] - cs;
            run = fmaxf(run, av);
            a[(long)z * SS + s]  = av;
            rm[(long)z * SS + s] = run;
            en[(long)z * SS + s] = __expf(-(cs + run));
        }
    }
}

// ---------------- attention scores ----------------
__global__ void __launch_bounds__(256, 2) attn_qk(
    const float* __restrict__ Qb, const float* __restrict__ Kb,
    float* __restrict__ SC, const float* __restrict__ a_,
    const float* __restrict__ rm_)
{
    int z = blockIdx.z;
    int b = z >> 2, h = z & 3;
    const int bx = blockIdx.x, by = blockIdx.y;
    float* C = SC + (long)z * SS * SS;
    if (bx > by) {
        for (int i = threadIdx.x; i < 4096; i += 256) {
            int rr = i >> 5, cc = (i & 31) << 2;
            *(float4*)(C + (long)(by*128 + rr) * SS + bx*128 + cc) =
                make_float4(0.f, 0.f, 0.f, 0.f);
        }
        return;
    }
    const float* A = Qb + (long)b * SS * II + h * DHM;
    const float* B = Kb + (long)b * SS * II + h * DHM;
    __shared__ float As[8][128];
    __shared__ float Bs[8][128];
    const int tid = threadIdx.x;
    const int lrow = tid >> 1;
    const int lcol = (tid & 1) << 2;
    const float* Ag = A + (long)(by*128 + lrow) * II + lcol;
    const float* Bg = B + (long)(bx*128 + lrow) * II + lcol;
    const int ty = tid >> 4, tx = tid & 15;
    float accv[8][8];
    #pragma unroll
    for (int i = 0; i < 8; i++)
        #pragma unroll
        for (int j = 0; j < 8; j++) accv[i][j] = 0.f;
    for (int k0 = 0; k0 < DHM; k0 += 8) {
        float4 av = *(const float4*)(Ag + k0);
        float4 bv = *(const float4*)(Bg + k0);
        __syncthreads();
        As[lcol+0][lrow] = av.x; As[lcol+1][lrow] = av.y;
        As[lcol+2][lrow] = av.z; As[lcol+3][lrow] = av.w;
        Bs[lcol+0][lrow] = bv.x; Bs[lcol+1][lrow] = bv.y;
        Bs[lcol+2][lrow] = bv.z; Bs[lcol+3][lrow] = bv.w;
        __syncthreads();
        #pragma unroll
        for (int kk = 0; kk < 8; kk++) {
            float ar[8], br[8];
            #pragma unroll
            for (int i = 0; i < 8; i++) ar[i] = As[kk][ty*8 + i];
            #pragma unroll
            for (int j = 0; j < 8; j++) br[j] = Bs[kk][tx*8 + j];
            #pragma unroll
            for (int i = 0; i < 8; i++)
                #pragma unroll
                for (int j = 0; j < 8; j++)
                    accv[i][j] += ar[i] * br[j];
        }
    }
    const float* az = a_ + (long)z * SS;
    const float* rz = rm_ + (long)z * SS;
    float avv[8], rmv[8];
    #pragma unroll
    for (int j = 0; j < 8; j++) avv[j] = az[bx*128 + tx*8 + j];
    #pragma unroll
    for (int i = 0; i < 8; i++) rmv[i] = rz[by*128 + ty*8 + i];
    const float alpha = 0.04419417382415922f;  // 1/sqrt(512)
    #pragma unroll
    for (int i = 0; i < 8; i++) {
        int row = by*128 + ty*8 + i;
        float* Cr = C + (long)row * SS + bx*128 + tx*8;
        #pragma unroll
        for (int j = 0; j < 8; j++) {
            int col = bx*128 + tx*8 + j;
            Cr[j] = (col <= row) ? accv[i][j] * alpha * __expf(avv[j] - rmv[i]) : 0.f;
        }
    }
}

// ---------------- row normalizer ----------------
__global__ void attn_rowsum(const float* __restrict__ sc, const float* __restrict__ en,
                            float* __restrict__ rn)
{
    int s = blockIdx.x, z = blockIdx.y;
    const float4* row = (const float4*)(sc + ((long)z * SS + s) * SS);
    int tid = threadIdx.x;
    float4 v = row[tid];
    float sm = v.x + v.y + v.z + v.w;
    __shared__ float sb[8];
    sm = warpSum(sm);
    if ((tid & 31) == 0) sb[tid >> 5] = sm;
    __syncthreads();
    if (tid == 0) {
        float t = 0.f;
        #pragma unroll
        for (int i = 0; i < 8; i++) t += sb[i];
        rn[(long)z * SS + s] = 1.f / (fmaxf(fabsf(t), en[(long)z * SS + s]) + 1e-6f);
    }
}

// ---------------- attention value GEMM (NN), K capped at diagonal ----------------
__global__ void __launch_bounds__(256, 2) attn_av(
    const float* __restrict__ SC, const float* __restrict__ Vb,
    const float* __restrict__ Rn, float* __restrict__ H)
{
    int z = blockIdx.z;
    int b = z >> 2, h = z & 3;
    const int bx = blockIdx.x, by = blockIdx.y;
    const float* A = SC + (long)z * SS * SS;
    const float* B = Vb + (long)b * SS * II + h * DHM;
    float* C = H + (long)z * SS * DHM;
    int kend = (by + 1) * 128;
    __shared__ float As[8][128];
    __shared__ float Bs[8][128];
    const int tid = threadIdx.x;
    const int lrow = tid >> 1;
    const int lcol = (tid & 1) << 2;
    const float* Ag = A + (long)(by*128 + lrow) * SS + lcol;
    const int bkrow = tid >> 5;
    const int bncol = (tid & 31) << 2;
    const float* Bg = B + (long)bkrow * II + bx*128 + bncol;
    const int ty = tid >> 4, tx = tid & 15;
    float accv[8][8];
    #pragma unroll
    for (int i = 0; i < 8; i++)
        #pragma unroll
        for (int j = 0; j < 8; j++) accv[i][j] = 0.f;
    for (int k0 = 0; k0 < kend; k0 += 8) {
        float4 av = *(const float4*)(Ag + k0);
        float4 bv = *(const float4*)(Bg + (long)k0 * II);
        __syncthreads();
        As[lcol+0][lrow] = av.x; As[lcol+1][lrow] = av.y;
        As[lcol+2][lrow] = av.z; As[lcol+3][lrow] = av.w;
        *(float4*)&Bs[bkrow][bncol] = bv;
        __syncthreads();
        #pragma unroll
        for (int kk = 0; kk < 8; kk++) {
            float ar[8], br[8];
            #pragma unroll
            for (int i = 0; i < 8; i++) ar[i] = As[kk][ty*8 + i];
            #pragma unroll
            for (int j = 0; j < 8; j++) br[j] = Bs[kk][tx*8 + j];
            #pragma unroll
            for (int i = 0; i < 8; i++)
                #pragma unroll
                for (int j = 0; j < 8; j++)
                    accv[i][j] += ar[i] * br[j];
        }
    }
    const float* rz = Rn + (long)z * SS;
    #pragma unroll
    for (int i = 0; i < 8; i++) {
        int row = by*128 + ty*8 + i;
        float rnv = rz[row];
        float* Cr = C + (long)row * DHM + bx*128 + tx*8;
        #pragma unroll
        for (int j = 0; j < 8; j++)
            Cr[j] = accv[i][j] * rnv;
    }
}

// ---------------- mh_norm(dh=512) + (h+skip*xa)*silu(z) ----------------
__global__ void mh_mix(const float* __restrict__ H, const float* __restrict__ onw,
                       const float* __restrict__ skip, const float* __restrict__ xa,
                       const float* __restrict__ up, float* __restrict__ hmix)
{
    int bs = blockIdx.x, h = blockIdx.y;
    int b = bs >> 10;
    int s = bs & (SS - 1);
    const float* hp = H + ((long)(b*4 + h) * SS + s) * DHM;
    int tid = threadIdx.x;  // 128
    float4 v = ((const float4*)hp)[tid];
    float sm = v.x + v.y + v.z + v.w;
    float sq = v.x*v.x + v.y*v.y + v.z*v.z + v.w*v.w;
    __shared__ float s1[4], s2[4];
    sm = warpSum(sm); sq = warpSum(sq);
    if ((tid & 31) == 0) { s1[tid >> 5] = sm; s2[tid >> 5] = sq; }
    __syncthreads();
    float tot  = s1[0] + s1[1] + s1[2] + s1[3];
    float tot2 = s2[0] + s2[1] + s2[2] + s2[3];
    float mu = tot * (1.f / DHM);
    float rs = rsqrtf(tot2 * (1.f / DHM) - mu * mu + 1e-5f);
    float4 wv  = ((const float4*)onw)[h*128 + tid];
    float4 sk  = ((const float4*)skip)[h*128 + tid];
    float4 xav = ((const float4*)(xa + (long)bs * II))[h*128 + tid];
    float4 zv  = ((const float4*)(up + (long)bs * (2L*II) + II))[h*128 + tid];
    float4 o;
    o.x = ((v.x - mu)*rs*wv.x + sk.x*xav.x) * (zv.x / (1.f + __expf(-zv.x)));
    o.y = ((v.y - mu)*rs*wv.y + sk.y*xav.y) * (zv.y / (1.f + __expf(-zv.y)));
    o.z = ((v.z - mu)*rs*wv.z + sk.z*xav.z) * (zv.z / (1.f + __expf(-zv.z)));
    o.w = ((v.w - mu)*rs*wv.w + sk.w*xav.w) * (zv.w / (1.f + __expf(-zv.w)));
    ((float4*)(hmix + (long)bs * II))[h*128 + tid] = o;
}

// ============================================================================
// Cluster-split sLSTM scan: 16 clusters of 8 CTAs, one cluster per (b,h).
// CTA rank = g*2 + hf (gate g in {i,f,z,o}, half hf). Each CTA holds its
// 256x128 weight slice rk[h][:, g, hf*128:+128] resident in SMEM (128 KB).
// Per step: local matvec from SMEM -> DSMEM-write raws to rank hf ->
// cluster barrier -> ranks 0/1 run gate nonlinearity, DSMEM-broadcast new h
// to all 8 CTAs -> cluster barrier.
// ============================================================================
#define SCAN_SMEM_FLOATS (32768 + 256 + 512)

__device__ __forceinline__ uint32_t smem_addr_u32(const void* p) {
    return (uint32_t)__cvta_generic_to_shared(p);
}
__device__ __forceinline__ uint32_t mapa_u32(uint32_t addr, uint32_t rank) {
    uint32_t out;
    asm("mapa.shared::cluster.u32 %0, %1, %2;" : "=r"(out) : "r"(addr), "r"(rank));
    return out;
}
__device__ __forceinline__ void st_cluster_f32(uint32_t addr, float v) {
    asm volatile("st.shared::cluster.f32 [%0], %1;" :: "r"(addr), "f"(v) : "memory");
}
__device__ __forceinline__ void cluster_barrier() {
    asm volatile("barrier.cluster.arrive.aligned;" ::: "memory");
    asm volatile("barrier.cluster.wait.aligned;" ::: "memory");
}

__global__ void __launch_bounds__(128, 1) __cluster_dims__(8, 1, 1)
slstm_scan_cl(const float* __restrict__ pre, const float* __restrict__ rk,
              const float* __restrict__ rb, float* __restrict__ ys)
{
    extern __shared__ float sm[];
    float* W    = sm;                 // [256][128]
    float* sh_h = sm + 32768;         // [256]
    float* sraw = sm + 32768 + 256;   // [4][128], used on ranks 0/1

    const int z = blockIdx.x >> 3;    // (b,h) pair
    const int b = z >> 2, h = z & 3;
    uint32_t rank;
    asm("mov.u32 %0, %%cluster_ctarank;" : "=r"(rank));
    const int g  = rank >> 1;
    const int hf = rank & 1;
    const int tid = threadIdx.x;      // 128 threads; tid = e_local

    // Load weight slice: W[d][el] = rk[((h*256+d)*4+g)*256 + hf*128 + el]
    const float* rks = rk + ((long)h * 256 * 4 + g) * 256 + hf * 128;
    for (int idx = tid; idx < 32768; idx += 128) {
        int d = idx >> 7, el = idx & 127;
        W[idx] = rks[(long)d * 1024 + el];
    }
    for (int i = tid; i < 256; i += 128) sh_h[i] = 0.f;
    __syncthreads();

    const float rbv = rb[(h*4 + g) * DHS + hf*128 + tid];
    const float* pb = pre + ((long)(g*4 + h) * BS + (long)b * SS) * DHS + hf*128 + tid;
    float* yo = ys + (long)z * SS * DHS + hf*128 + tid;

    // Precompute DSMEM addresses
    const uint32_t raw_dst = mapa_u32(smem_addr_u32(&sraw[g*128 + tid]), (uint32_t)hf);
    uint32_t hdst[8];
    #pragma unroll
    for (int r = 0; r < 8; r++)
        hdst[r] = mapa_u32(smem_addr_u32(&sh_h[hf*128 + tid]), (uint32_t)r);

    const bool is_act = (rank < 2);
    float c = 0.f, n = 0.f, m = 0.f;

    // Ensure all CTAs' sh_h are initialized before any remote h writes
    cluster_barrier();

    float pv = pb[0];
    for (int s = 0; s < SS; s++) {
        // matvec: acc over 256 d, 4 split accumulators
        float a0 = 0.f, a1 = 0.f, a2 = 0.f, a3 = 0.f;
        const float* Wp = W + tid;
        #pragma unroll 8
        for (int d = 0; d < 256; d += 4) {
            float4 hv = *(const float4*)&sh_h[d];
            a0 += hv.x * Wp[(d+0) << 7];
            a1 += hv.y * Wp[(d+1) << 7];
            a2 += hv.z * Wp[(d+2) << 7];
            a3 += hv.w * Wp[(d+3) << 7];
        }
        float acc = pv + rbv + ((a0 + a1) + (a2 + a3));
        if (s + 1 < SS) pv = pb[(long)(s+1) * DHS];

        st_cluster_f32(raw_dst, acc);
        cluster_barrier();

        if (is_act) {
            float iraw = sraw[tid],       fraw = sraw[128 + tid];
            float zraw = sraw[256 + tid], oraw = sraw[384 + tid];
            float lf = m + fminf(fraw, 0.f) - log1pf(__expf(-fabsf(fraw)));
            float mn = fmaxf(iraw, lf);
            float ig_ = __expf(iraw - mn);
            float fg_ = __expf(lf - mn);
            c = fg_ * c + ig_ * tanhf(zraw);
            n = fg_ * n + ig_;
            m = mn;
            float hv = c / (n * (1.f + __expf(-oraw)));
            #pragma unroll
            for (int r = 0; r < 8; r++) st_cluster_f32(hdst[r], hv);
            yo[(long)s * DHS] = hv;
        }
        cluster_barrier();
    }
}

// ---------------- sLSTM group norm (256) + residual add ----------------
__global__ void slstm_gnorm(const float* __restrict__ ys, const float* __restrict__ gnw,
                            float* __restrict__ x)
{
    int bs = blockIdx.x, h = blockIdx.y;
    int b = bs >> 10, s = bs & (SS - 1);
    const float* yp = ys + ((long)(b*4 + h) * SS + s) * DHS;
    int tid = threadIdx.x;  // 64
    float4 v = ((const float4*)yp)[tid];
    float sm = v.x + v.y + v.z + v.w;
    float sq = v.x*v.x + v.y*v.y + v.z*v.z + v.w*v.w;
    __shared__ float s1[2], s2[2];
    sm = warpSum(sm); sq = warpSum(sq);
    if ((tid & 31) == 0) { s1[tid >> 5] = sm; s2[tid >> 5] = sq; }
    __syncthreads();
    float tot  = s1[0] + s1[1];
    float tot2 = s2[0] + s2[1];
    float mu = tot * (1.f / DHS);
    float rs = rsqrtf(tot2 * (1.f / DHS) - mu * mu + 1e-5f);
    float4 wv = ((const float4*)gnw)[h*64 + tid];
    float* xp = x + (long)bs * DD + h * DHS + tid * 4;
    float4 xv = *(float4*)xp;
    xv.x += (v.x - mu) * rs * wv.x;
    xv.y += (v.y - mu) * rs * wv.y;
    xv.z += (v.z - mu) * rs * wv.z;
    xv.w += (v.w - mu) * rs * wv.w;
    *(float4*)xp = xv;
}

// ---------------- FFN: act = gelu_exact(gate) * up ----------------
__global__ void gelu_mul(const float* __restrict__ f, float* __restrict__ a)
{
    long idx = (long)blockIdx.x * 256 + threadIdx.x;
    if (idx >= (long)BS * UU) return;
    long bs = idx / UU;
    int u = (int)(idx % UU);
    float g = f[bs * (2L*UU) + u];
    float p = f[bs * (2L*UU) + UU + u];
    a[idx] = 0.5f * g * (1.f + erff(g * 0.70710678118654752f)) * p;
}

// ---------------- host ----------------
static inline void gemm(const float* A, const float* B, float* C,
                        int M, int N, int K, int lda, int ldb, int ldc,
                        float alpha, const float* bias, int acc)
{
    dim3 grid(N / 128, M / 128);
    sgemm_nt<<<grid, 256>>>(A, B, C, M, N, K, lda, ldb, ldc, alpha, bias, acc);
}

extern "C" void kernel_launch(void* const* d_in, const int* in_sizes, int n_in,
                              void* d_out, int out_size)
{
    const int*   ids       = (const int*)  d_in[0];
    const float* emb       = (const float*)d_in[1];
    const float* m_ln_w    = (const float*)d_in[2];
    const float* m_up_w    = (const float*)d_in[3];
    const float* m_conv_w  = (const float*)d_in[4];
    const float* m_conv_b  = (const float*)d_in[5];
    const float* m_q_w     = (const float*)d_in[6];
    const float* m_k_w     = (const float*)d_in[7];
    const float* m_v_w     = (const float*)d_in[8];
    const float* m_ig_w    = (const float*)d_in[9];
    const float* m_ig_b    = (const float*)d_in[10];
    const float* m_fg_w    = (const float*)d_in[11];
    const float* m_fg_b    = (const float*)d_in[12];
    const float* m_skip    = (const float*)d_in[13];
    const float* m_on_w    = (const float*)d_in[14];
    const float* m_down_w  = (const float*)d_in[15];
    const float* s_ln_w    = (const float*)d_in[16];
    const float* s_conv_w  = (const float*)d_in[17];
    const float* s_conv_b  = (const float*)d_in[18];
    const float* s_iw      = (const float*)d_in[19];
    const float* s_fw      = (const float*)d_in[20];
    const float* s_zw      = (const float*)d_in[21];
    const float* s_ow      = (const float*)d_in[22];
    const float* s_rk      = (const float*)d_in[23];
    const float* s_rb      = (const float*)d_in[24];
    const float* s_gn_w    = (const float*)d_in[25];
    const float* s_ln2_w   = (const float*)d_in[26];
    const float* s_ffn_up  = (const float*)d_in[27];
    const float* s_ffn_dn  = (const float*)d_in[28];
    const float* post_ln_w = (const float*)d_in[29];
    const float* head_w    = (const float*)d_in[30];
    const float* head_b    = (const float*)d_in[31];
    float* out = (float*)d_out;

    float* pool = nullptr;
    cudaGetSymbolAddress((void**)&pool, g_pool);
    float* X   = pool + O_X;   float* XN  = pool + O_XN;  float* XC  = pool + O_XC;
    float* UP  = pool + O_UP;  float* XA  = pool + O_XA;
    float* Q_  = pool + O_Q;   float* K_  = pool + O_K;   float* V_  = pool + O_V;
    float* SC  = pool + O_SC;  float* HB  = pool + O_HB;  float* HM  = pool + O_HM;
    float* PRE = pool + O_PRE; float* YS  = pool + O_YS;
    float* FFN = pool + O_FFN; float* ACT = pool + O_ACT;
    float* IG  = pool + O_IG;  float* FG  = pool + O_FG;
    float* Aa  = pool + O_A;   float* RM  = pool + O_RM;
    float* EN  = pool + O_EN;  float* RN  = pool + O_RN;

    static int smem_set = 0;
    if (!smem_set) {
        cudaFuncSetAttribute(slstm_scan_cl,
                             cudaFuncAttributeMaxDynamicSharedMemorySize,
                             SCAN_SMEM_FLOATS * 4);
        smem_set = 1;
    }

    embed_k<<<BS, 256>>>(ids, emb, X);

    int mi = 0;
    for (int blk = 0; blk < 4; blk++) {
        if (blk == 1) {
            // ---------------- sLSTM block ----------------
            layernorm_k<<<BS, 256>>>(X, s_ln_w, XN);
            conv_silu<<<(BS * DD) / 256, 256>>>(XN, s_conv_w, s_conv_b, XC, DD, DD);
            sgemm_gates<<<dim3(2, 32, 16), 256>>>(XC, XN, s_iw, s_fw, s_zw, s_ow, PRE);
            slstm_scan_cl<<<128, 128, SCAN_SMEM_FLOATS * 4>>>(PRE, s_rk, s_rb, YS);
            slstm_gnorm<<<dim3(BS, 4), 64>>>(YS, s_gn_w, X);
            layernorm_k<<<BS, 256>>>(X, s_ln2_w, XN);
            gemm(XN, s_ffn_up, FFN, BS, 2*UU, DD, DD, DD, 2*UU, 1.f, nullptr, 0);
            gelu_mul<<<(int)(((long)BS*UU + 255) / 256), 256>>>(FFN, ACT);
            gemm(ACT, s_ffn_dn, X, BS, DD, UU, UU, UU, DD, 1.f, nullptr, 1);
        } else {
            // ---------------- mLSTM block ----------------
            layernorm_k<<<BS, 256>>>(X, m_ln_w + (long)mi*DD, XN);
            gemm(XN, m_up_w + (long)mi*4096*DD, UP, BS, 4096, DD, DD, DD, 4096,
                 1.f, nullptr, 0);
            conv_silu<<<(int)(((long)BS*II) / 256), 256>>>(
                UP, m_conv_w + (long)mi*II*4, m_conv_b + (long)mi*II, XA, II, 4096);
            headwise_qkv<<<(int)(((long)BS*512) / 256), 256>>>(
                XA, UP, m_q_w + (long)mi*512*16, m_k_w + (long)mi*512*16,
                m_v_w + (long)mi*512*16, Q_, K_, V_);
            igfg_k<<<BS, 256>>>(Q_, K_, V_,
                m_ig_w + (long)mi*4*6144, m_ig_b + (long)mi*4,
                m_fg_w + (long)mi*4*6144, m_fg_b + (long)mi*4, IG, FG);
            mlstm_prep<<<16, 256>>>(IG, FG, Aa, RM, EN);
            attn_qk<<<dim3(8, 8, 16), 256>>>(Q_, K_, SC, Aa, RM);
            attn_rowsum<<<dim3(SS, 16), 256>>>(SC, EN, RN);
            attn_av<<<dim3(4, 8, 16), 256>>>(SC, V_, RN, HB);
            mh_mix<<<dim3(BS, 4), 128>>>(HB, m_on_w + (long)mi*II,
                m_skip + (long)mi*II, XA, UP, HM);
            gemm(HM, m_down_w + (long)mi*DD*II, X, BS, DD, II, II, II, DD,
                 1.f, nullptr, 1);
            mi++;
        }
    }

    layernorm_k<<<BS, 256>>>(X, post_ln_w, XN);
    gemm(XN, head_w, out, BS, 256, DD, DD, DD, 256, 1.f, head_b, 0);
}

// round 6
// speedup vs baseline: 5.4625x; 1.5756x over previous
#include <cuda_runtime.h>
#include <cuda_bf16.h>
#include <math.h>
#include <stdint.h>

#define BB 4
#define SS 1024
#define DD 1024
#define II 2048
#define BS 4096
#define DHM 512
#define DHS 256
#define UU 1344

constexpr long SZ_X   = (long)BS * DD;
constexpr long SZ_UP  = (long)BS * 2 * II;
constexpr long SZ_I   = (long)BS * II;
constexpr long SZ_SC  = 16L * SS * SS;
constexpr long SZ_HB  = 16L * SS * DHM;
constexpr long SZ_PRE = 16L * BS * DHS;
constexpr long SZ_YS  = 16L * SS * DHS;
constexpr long SZ_FFN = (long)BS * 2 * UU;
constexpr long SZ_ACT = (long)BS * UU;
constexpr long SZ_V16 = 16L * SS;

constexpr long O_X   = 0;
constexpr long O_XN  = O_X   + SZ_X;
constexpr long O_XC  = O_XN  + SZ_X;
constexpr long O_UP  = O_XC  + SZ_X;
constexpr long O_XA  = O_UP  + SZ_UP;
constexpr long O_Q   = O_XA  + SZ_I;
constexpr long O_K   = O_Q   + SZ_I;
constexpr long O_V   = O_K   + SZ_I;
constexpr long O_SC  = O_V   + SZ_I;
constexpr long O_HB  = O_SC  + SZ_SC;
constexpr long O_HM  = O_HB  + SZ_HB;
constexpr long O_PRE = O_HM  + SZ_I;
constexpr long O_YS  = O_PRE + SZ_PRE;
constexpr long O_FFN = O_YS  + SZ_YS;
constexpr long O_ACT = O_FFN + SZ_FFN;
constexpr long O_IG  = O_ACT + SZ_ACT;
constexpr long O_FG  = O_IG  + SZ_V16;
constexpr long O_A   = O_FG  + SZ_V16;
constexpr long O_RM  = O_A   + SZ_V16;
constexpr long O_EN  = O_RM  + SZ_V16;
constexpr long O_RN  = O_EN  + SZ_V16;
constexpr long POOL_SZ = O_RN + SZ_V16;

__device__ float g_pool[POOL_SZ];

__device__ __forceinline__ float warpSum(float v) {
    #pragma unroll
    for (int o = 16; o > 0; o >>= 1) v += __shfl_down_sync(0xffffffffu, v, o);
    return v;
}

// ---------------- tf32 mma helpers ----------------
__device__ __forceinline__ uint32_t f2tf32(float f) {
    uint32_t r;
    asm("cvt.rna.tf32.f32 %0, %1;" : "=r"(r) : "f"(f));
    return r;
}
__device__ __forceinline__ void mma_tf32(float* c, const uint32_t* a, const uint32_t* b) {
    asm volatile(
        "mma.sync.aligned.m16n8k8.row.col.f32.tf32.tf32.f32 "
        "{%0,%1,%2,%3}, {%4,%5,%6,%7}, {%8,%9}, {%0,%1,%2,%3};"
        : "+f"(c[0]), "+f"(c[1]), "+f"(c[2]), "+f"(c[3])
        : "r"(a[0]), "r"(a[1]), "r"(a[2]), "r"(a[3]), "r"(b[0]), "r"(b[1]));
}
#define SPAD 36

// ---------------- embedding gather ----------------
__global__ void embed_k(const int* __restrict__ ids, const float* __restrict__ emb,
                        float* __restrict__ x)
{
    int bs = blockIdx.x;
    long id = ids[bs];
    ((float4*)(x + (long)bs * DD))[threadIdx.x] =
        ((const float4*)(emb + id * DD))[threadIdx.x];
}

// ---------------- LayerNorm width 1024, 256 thr/row ----------------
__global__ void layernorm_k(const float* __restrict__ x, const float* __restrict__ w,
                            float* __restrict__ y)
{
    long row = blockIdx.x;
    int tid = threadIdx.x;
    float4 v = ((const float4*)(x + row * DD))[tid];
    float s = v.x + v.y + v.z + v.w;
    float ss = v.x*v.x + v.y*v.y + v.z*v.z + v.w*v.w;
    __shared__ float sb[8], sb2[8];
    __shared__ float mu_s, rs_s;
    s = warpSum(s); ss = warpSum(ss);
    if ((tid & 31) == 0) { sb[tid >> 5] = s; sb2[tid >> 5] = ss; }
    __syncthreads();
    if (tid == 0) {
        float t = 0.f, t2 = 0.f;
        #pragma unroll
        for (int i = 0; i < 8; i++) { t += sb[i]; t2 += sb2[i]; }
        float mu = t * (1.f / DD);
        mu_s = mu;
        rs_s = rsqrtf(t2 * (1.f / DD) - mu * mu + 1e-5f);
    }
    __syncthreads();
    float mu = mu_s, rs = rs_s;
    float4 wv = ((const float4*)w)[tid];
    float4 o;
    o.x = (v.x - mu) * rs * wv.x;  o.y = (v.y - mu) * rs * wv.y;
    o.z = (v.z - mu) * rs * wv.z;  o.w = (v.w - mu) * rs * wv.w;
    ((float4*)(y + row * DD))[tid] = o;
}

// ============================================================================
// tf32 tensor-core GEMM NT: C = alpha*A(MxK)@B(NxK)^T [+bias][+=C]
// 128x128x32 tile, 8 warps (4 along M x 2 along N), warp tile 32x64.
// ============================================================================
__global__ void __launch_bounds__(256, 2) tgemm_nt(
    const float* __restrict__ A, const float* __restrict__ B, float* __restrict__ C,
    int M, int N, int K, int lda, int ldb, int ldc,
    float alpha, const float* __restrict__ bias, int acc)
{
    __shared__ float As[128 * SPAD];
    __shared__ float Bs[128 * SPAD];
    const int tid = threadIdx.x;
    const int lane = tid & 31, warp = tid >> 5;
    const int wm = warp & 3, wn = warp >> 2;
    const int g = lane >> 2, t = lane & 3;
    const int lr = tid >> 1, lc = (tid & 1) * 16;
    const float* Ag = A + (long)(blockIdx.y * 128 + lr) * lda + lc;
    const float* Bg = B + (long)(blockIdx.x * 128 + lr) * ldb + lc;

    float c[16][4];
    #pragma unroll
    for (int i = 0; i < 16; i++)
        #pragma unroll
        for (int j = 0; j < 4; j++) c[i][j] = 0.f;

    for (int k0 = 0; k0 < K; k0 += 32) {
        float4 a4[4], b4[4];
        #pragma unroll
        for (int i = 0; i < 4; i++) {
            a4[i] = *(const float4*)(Ag + k0 + i*4);
            b4[i] = *(const float4*)(Bg + k0 + i*4);
        }
        __syncthreads();
        #pragma unroll
        for (int i = 0; i < 4; i++) {
            uint4 av = make_uint4(f2tf32(a4[i].x), f2tf32(a4[i].y),
                                  f2tf32(a4[i].z), f2tf32(a4[i].w));
            uint4 bv = make_uint4(f2tf32(b4[i].x), f2tf32(b4[i].y),
                                  f2tf32(b4[i].z), f2tf32(b4[i].w));
            *(uint4*)&As[lr * SPAD + lc + i*4] = av;
            *(uint4*)&Bs[lr * SPAD + lc + i*4] = bv;
        }
        __syncthreads();
        #pragma unroll
        for (int kk = 0; kk < 4; kk++) {
            const int ks = kk * 8;
            uint32_t af[2][4], bf[8][2];
            #pragma unroll
            for (int mt = 0; mt < 2; mt++) {
                int r0 = wm*32 + mt*16 + g;
                af[mt][0] = __float_as_uint(As[r0 * SPAD + ks + t]);
                af[mt][1] = __float_as_uint(As[(r0+8) * SPAD + ks + t]);
                af[mt][2] = __float_as_uint(As[r0 * SPAD + ks + t + 4]);
                af[mt][3] = __float_as_uint(As[(r0+8) * SPAD + ks + t + 4]);
            }
            #pragma unroll
            for (int nt = 0; nt < 8; nt++) {
                int c0 = wn*64 + nt*8 + g;
                bf[nt][0] = __float_as_uint(Bs[c0 * SPAD + ks + t]);
                bf[nt][1] = __float_as_uint(Bs[c0 * SPAD + ks + t + 4]);
            }
            #pragma unroll
            for (int mt = 0; mt < 2; mt++)
                #pragma unroll
                for (int nt = 0; nt < 8; nt++)
                    mma_tf32(c[mt*8 + nt], af[mt], bf[nt]);
        }
    }
    #pragma unroll
    for (int mt = 0; mt < 2; mt++) {
        int row0 = blockIdx.y*128 + wm*32 + mt*16 + g;
        #pragma unroll
        for (int nt = 0; nt < 8; nt++) {
            int col0 = blockIdx.x*128 + wn*64 + nt*8 + 2*t;
            float* v = c[mt*8 + nt];
            float b0 = bias ? bias[col0] : 0.f, b1 = bias ? bias[col0+1] : 0.f;
            float* C0 = C + (long)row0 * ldc + col0;
            float* C1 = C + (long)(row0+8) * ldc + col0;
            float o0 = v[0]*alpha + b0, o1 = v[1]*alpha + b1;
            float o2 = v[2]*alpha + b0, o3 = v[3]*alpha + b1;
            if (acc) { o0 += C0[0]; o1 += C0[1]; o2 += C1[0]; o3 += C1[1]; }
            C0[0] = o0; C0[1] = o1; C1[0] = o2; C1[1] = o3;
        }
    }
}

// ============================================================================
// tf32 attention scores: SC = (q.k/sqrt(dh))*exp(a[t]-rm[s]), causal, tile-skip
// ============================================================================
__global__ void __launch_bounds__(256, 2) attn_qk(
    const float* __restrict__ Qb, const float* __restrict__ Kb,
    float* __restrict__ SC, const float* __restrict__ a_,
    const float* __restrict__ rm_)
{
    const int z = blockIdx.z;
    const int b = z >> 2, h = z & 3;
    const int bx = blockIdx.x, by = blockIdx.y;
    float* Cb = SC + (long)z * SS * SS;
    if (bx > by) {
        for (int i = threadIdx.x; i < 4096; i += 256) {
            int rr = i >> 5, cc = (i & 31) << 2;
            *(float4*)(Cb + (long)(by*128 + rr) * SS + bx*128 + cc) =
                make_float4(0.f, 0.f, 0.f, 0.f);
        }
        return;
    }
    const float* A = Qb + (long)b * SS * II + h * DHM;
    const float* B = Kb + (long)b * SS * II + h * DHM;
    __shared__ float As[128 * SPAD];
    __shared__ float Bs[128 * SPAD];
    const int tid = threadIdx.x;
    const int lane = tid & 31, warp = tid >> 5;
    const int wm = warp & 3, wn = warp >> 2;
    const int g = lane >> 2, t = lane & 3;
    const int lr = tid >> 1, lc = (tid & 1) * 16;
    const float* Ag = A + (long)(by*128 + lr) * II + lc;
    const float* Bg = B + (long)(bx*128 + lr) * II + lc;

    float c[16][4];
    #pragma unroll
    for (int i = 0; i < 16; i++)
        #pragma unroll
        for (int j = 0; j < 4; j++) c[i][j] = 0.f;

    for (int k0 = 0; k0 < DHM; k0 += 32) {
        float4 a4[4], b4[4];
        #pragma unroll
        for (int i = 0; i < 4; i++) {
            a4[i] = *(const float4*)(Ag + k0 + i*4);
            b4[i] = *(const float4*)(Bg + k0 + i*4);
        }
        __syncthreads();
        #pragma unroll
        for (int i = 0; i < 4; i++) {
            uint4 av = make_uint4(f2tf32(a4[i].x), f2tf32(a4[i].y),
                                  f2tf32(a4[i].z), f2tf32(a4[i].w));
            uint4 bv = make_uint4(f2tf32(b4[i].x), f2tf32(b4[i].y),
                                  f2tf32(b4[i].z), f2tf32(b4[i].w));
            *(uint4*)&As[lr * SPAD + lc + i*4] = av;
            *(uint4*)&Bs[lr * SPAD + lc + i*4] = bv;
        }
        __syncthreads();
        #pragma unroll
        for (int kk = 0; kk < 4; kk++) {
            const int ks = kk * 8;
            uint32_t af[2][4], bf[8][2];
            #pragma unroll
            for (int mt = 0; mt < 2; mt++) {
                int r0 = wm*32 + mt*16 + g;
                af[mt][0] = __float_as_uint(As[r0 * SPAD + ks + t]);
                af[mt][1] = __float_as_uint(As[(r0+8) * SPAD + ks + t]);
                af[mt][2] = __float_as_uint(As[r0 * SPAD + ks + t + 4]);
                af[mt][3] = __float_as_uint(As[(r0+8) * SPAD + ks + t + 4]);
            }
            #pragma unroll
            for (int nt = 0; nt < 8; nt++) {
                int c0 = wn*64 + nt*8 + g;
                bf[nt][0] = __float_as_uint(Bs[c0 * SPAD + ks + t]);
                bf[nt][1] = __float_as_uint(Bs[c0 * SPAD + ks + t + 4]);
            }
            #pragma unroll
            for (int mt = 0; mt < 2; mt++)
                #pragma unroll
                for (int nt = 0; nt < 8; nt++)
                    mma_tf32(c[mt*8 + nt], af[mt], bf[nt]);
        }
    }
    const float* az = a_ + (long)z * SS;
    const float* rz = rm_ + (long)z * SS;
    const float alpha = 0.04419417382415922f;  // 1/sqrt(512)
    #pragma unroll
    for (int mt = 0; mt < 2; mt++) {
        int row0 = by*128 + wm*32 + mt*16 + g;
        int row1 = row0 + 8;
        float rm0 = rz[row0], rm1 = rz[row1];
        #pragma unroll
        for (int nt = 0; nt < 8; nt++) {
            int col0 = bx*128 + wn*64 + nt*8 + 2*t;
            float av0 = az[col0], av1 = az[col0+1];
            float* v = c[mt*8 + nt];
            float* C0 = Cb + (long)row0 * SS + col0;
            float* C1 = Cb + (long)row1 * SS + col0;
            C0[0] = (col0   <= row0) ? v[0]*alpha*__expf(av0 - rm0) : 0.f;
            C0[1] = (col0+1 <= row0) ? v[1]*alpha*__expf(av1 - rm0) : 0.f;
            C1[0] = (col0   <= row1) ? v[2]*alpha*__expf(av0 - rm1) : 0.f;
            C1[1] = (col0+1 <= row1) ? v[3]*alpha*__expf(av1 - rm1) : 0.f;
        }
    }
}

// ============================================================================
// tf32 attention value GEMM (NN): H = rn[s] * SC @ V, K capped at diagonal
// ============================================================================
__global__ void __launch_bounds__(256, 2) attn_av(
    const float* __restrict__ SC, const float* __restrict__ Vb,
    const float* __restrict__ Rn, float* __restrict__ H)
{
    const int z = blockIdx.z;
    const int b = z >> 2, h = z & 3;
    const int bx = blockIdx.x, by = blockIdx.y;
    const float* A = SC + (long)z * SS * SS;
    const float* B = Vb + (long)b * SS * II + h * DHM;
    float* Cb = H + (long)z * SS * DHM;
    const int kend = (by + 1) * 128;
    __shared__ float As[128 * SPAD];
    __shared__ float Bs[128 * SPAD];
    const int tid = threadIdx.x;
    const int lane = tid & 31, warp = tid >> 5;
    const int wm = warp & 3, wn = warp >> 2;
    const int g = lane >> 2, t = lane & 3;
    const int lr = tid >> 1, lc = (tid & 1) * 16;
    const float* Ag = A + (long)(by*128 + lr) * SS + lc;
    const int bkr = tid >> 3;          // 0..31 (k row)
    const int bc4 = tid & 7;           // float4 col group
    const float* Bg = B + (long)bkr * II + bx*128;

    float c[16][4];
    #pragma unroll
    for (int i = 0; i < 16; i++)
        #pragma unroll
        for (int j = 0; j < 4; j++) c[i][j] = 0.f;

    for (int k0 = 0; k0 < kend; k0 += 32) {
        float4 a4[4], b4[4];
        #pragma unroll
        for (int i = 0; i < 4; i++) {
            a4[i] = *(const float4*)(Ag + k0 + i*4);
            b4[i] = *(const float4*)(Bg + (long)k0 * II + (bc4 + i*8) * 4);
        }
        __syncthreads();
        #pragma unroll
        for (int i = 0; i < 4; i++) {
            uint4 av = make_uint4(f2tf32(a4[i].x), f2tf32(a4[i].y),
                                  f2tf32(a4[i].z), f2tf32(a4[i].w));
            *(uint4*)&As[lr * SPAD + lc + i*4] = av;
            int coln = (bc4 + i*8) * 4;
            Bs[(coln+0) * SPAD + bkr] = __uint_as_float(f2tf32(b4[i].x));
            Bs[(coln+1) * SPAD + bkr] = __uint_as_float(f2tf32(b4[i].y));
            Bs[(coln+2) * SPAD + bkr] = __uint_as_float(f2tf32(b4[i].z));
            Bs[(coln+3) * SPAD + bkr] = __uint_as_float(f2tf32(b4[i].w));
        }
        __syncthreads();
        #pragma unroll
        for (int kk = 0; kk < 4; kk++) {
            const int ks = kk * 8;
            uint32_t af[2][4], bf[8][2];
            #pragma unroll
            for (int mt = 0; mt < 2; mt++) {
                int r0 = wm*32 + mt*16 + g;
                af[mt][0] = __float_as_uint(As[r0 * SPAD + ks + t]);
                af[mt][1] = __float_as_uint(As[(r0+8) * SPAD + ks + t]);
                af[mt][2] = __float_as_uint(As[r0 * SPAD + ks + t + 4]);
                af[mt][3] = __float_as_uint(As[(r0+8) * SPAD + ks + t + 4]);
            }
            #pragma unroll
            for (int nt = 0; nt < 8; nt++) {
                int c0 = wn*64 + nt*8 + g;
                bf[nt][0] = __float_as_uint(Bs[c0 * SPAD + ks + t]);
                bf[nt][1] = __float_as_uint(Bs[c0 * SPAD + ks + t + 4]);
            }
            #pragma unroll
            for (int mt = 0; mt < 2; mt++)
                #pragma unroll
                for (int nt = 0; nt < 8; nt++)
                    mma_tf32(c[mt*8 + nt], af[mt], bf[nt]);
        }
    }
    const float* rz = Rn + (long)z * SS;
    #pragma unroll
    for (int mt = 0; mt < 2; mt++) {
        int row0 = by*128 + wm*32 + mt*16 + g;
        int row1 = row0 + 8;
        float rn0 = rz[row0], rn1 = rz[row1];
        #pragma unroll
        for (int nt = 0; nt < 8; nt++) {
            int col0 = bx*128 + wn*64 + nt*8 + 2*t;
            float* v = c[mt*8 + nt];
            float* C0 = Cb + (long)row0 * DHM + col0;
            float* C1 = Cb + (long)row1 * DHM + col0;
            C0[0] = v[0]*rn0; C0[1] = v[1]*rn0;
            C1[0] = v[2]*rn1; C1[1] = v[3]*rn1;
        }
    }
}

// ---------------- batched sLSTM gate GEMMs (fp32, small) ----------------
__global__ void __launch_bounds__(256, 2) sgemm_gates(
    const float* __restrict__ XC, const float* __restrict__ XN,
    const float* __restrict__ iw, const float* __restrict__ fw,
    const float* __restrict__ zw, const float* __restrict__ ow,
    float* __restrict__ PRE)
{
    const int zz = blockIdx.z;
    const int g = zz >> 2, h = zz & 3;
    const float* A = ((g < 2) ? XC : XN) + h * 256;
    const float* W = (g == 0) ? iw : (g == 1) ? fw : (g == 2) ? zw : ow;
    const float* B = W + (long)h * 65536;
    float* C = PRE + (long)zz * BS * DHS;
    __shared__ float As[8][128];
    __shared__ float Bs[8][128];
    const int tid = threadIdx.x;
    const int lrow = tid >> 1;
    const int lcol = (tid & 1) << 2;
    const float* Ag = A + (long)(blockIdx.y * 128 + lrow) * DD + lcol;
    const float* Bg = B + (long)(blockIdx.x * 128 + lrow) * 256 + lcol;
    const int ty = tid >> 4, tx = tid & 15;
    float accv[8][8];
    #pragma unroll
    for (int i = 0; i < 8; i++)
        #pragma unroll
        for (int j = 0; j < 8; j++) accv[i][j] = 0.f;
    for (int k0 = 0; k0 < 256; k0 += 8) {
        float4 av = *(const float4*)(Ag + k0);
        float4 bv = *(const float4*)(Bg + k0);
        __syncthreads();
        As[lcol+0][lrow] = av.x; As[lcol+1][lrow] = av.y;
        As[lcol+2][lrow] = av.z; As[lcol+3][lrow] = av.w;
        Bs[lcol+0][lrow] = bv.x; Bs[lcol+1][lrow] = bv.y;
        Bs[lcol+2][lrow] = bv.z; Bs[lcol+3][lrow] = bv.w;
        __syncthreads();
        #pragma unroll
        for (int kk = 0; kk < 8; kk++) {
            float ar[8], br[8];
            #pragma unroll
            for (int i = 0; i < 8; i++) ar[i] = As[kk][ty*8 + i];
            #pragma unroll
            for (int j = 0; j < 8; j++) br[j] = Bs[kk][tx*8 + j];
            #pragma unroll
            for (int i = 0; i < 8; i++)
                #pragma unroll
                for (int j = 0; j < 8; j++)
                    accv[i][j] += ar[i] * br[j];
        }
    }
    #pragma unroll
    for (int i = 0; i < 8; i++) {
        long row = blockIdx.y * 128 + ty*8 + i;
        float* Cr = C + row * 256L + blockIdx.x * 128 + tx*8;
        #pragma unroll
        for (int j = 0; j < 8; j++)
            Cr[j] = accv[i][j];
    }
}

// ---------------- causal depthwise conv (K=4) + SiLU ----------------
__global__ void conv_silu(const float* __restrict__ in, const float* __restrict__ w,
                          const float* __restrict__ bias, float* __restrict__ out,
                          int C, int ldin)
{
    long idx = (long)blockIdx.x * 256 + threadIdx.x;
    if (idx >= (long)BS * C) return;
    int c = (int)(idx % C);
    long bs = idx / C;
    int s = (int)(bs & (SS - 1));
    float acc = bias[c];
    #pragma unroll
    for (int kk = 0; kk < 4; kk++) {
        int sp = s + kk - 3;
        if (sp >= 0) acc += in[(bs + kk - 3) * ldin + c] * w[c*4 + kk];
    }
    out[bs * (long)C + c] = acc / (1.f + __expf(-acc));
}

// ---------------- headwise 4x4 q,k from xa; v from xm(strided) ----------------
__global__ void headwise_qkv(const float* __restrict__ xa, const float* __restrict__ xm,
                             const float* __restrict__ qw, const float* __restrict__ kw,
                             const float* __restrict__ vw,
                             float* __restrict__ q, float* __restrict__ k,
                             float* __restrict__ v)
{
    long idx = (long)blockIdx.x * 256 + threadIdx.x;
    if (idx >= (long)BS * 512) return;
    int nb = (int)(idx & 511);
    long bs = idx >> 9;
    float4 xav = *(const float4*)(xa + bs * II + nb*4);
    float4 xmv = *(const float4*)(xm + bs * (2L*II) + nb*4);
    float xi[4] = {xav.x, xav.y, xav.z, xav.w};
    float xmi[4] = {xmv.x, xmv.y, xmv.z, xmv.w};
    float qo[4], ko[4], vo[4];
    #pragma unroll
    for (int o = 0; o < 4; o++) {
        float aq = 0.f, ak = 0.f, av = 0.f;
        #pragma unroll
        for (int i = 0; i < 4; i++) {
            aq += xi[i]  * qw[nb*16 + o*4 + i];
            ak += xi[i]  * kw[nb*16 + o*4 + i];
            av += xmi[i] * vw[nb*16 + o*4 + i];
        }
        qo[o] = aq; ko[o] = ak; vo[o] = av;
    }
    *(float4*)(q + bs * II + nb*4) = make_float4(qo[0], qo[1], qo[2], qo[3]);
    *(float4*)(k + bs * II + nb*4) = make_float4(ko[0], ko[1], ko[2], ko[3]);
    *(float4*)(v + bs * II + nb*4) = make_float4(vo[0], vo[1], vo[2], vo[3]);
}

// ---------------- ig/fg gate projections ----------------
__global__ void igfg_k(const float* __restrict__ q, const float* __restrict__ k,
                       const float* __restrict__ v,
                       const float* __restrict__ igw, const float* __restrict__ igb,
                       const float* __restrict__ fgw, const float* __restrict__ fgb,
                       float* __restrict__ ig, float* __restrict__ fg)
{
    long bs = blockIdx.x;
    int b = (int)(bs >> 10);
    int s = (int)(bs & (SS - 1));
    __shared__ float sx[3 * II];
    __shared__ float rbuf[2][8];
    int tid = threadIdx.x;
    for (int i = tid; i < II; i += 256) {
        sx[i]        = q[bs * II + i];
        sx[II + i]   = k[bs * II + i];
        sx[2*II + i] = v[bs * II + i];
    }
    __syncthreads();
    for (int h = 0; h < 4; h++) {
        float pi = 0.f, pf = 0.f;
        for (int j = tid; j < 3*II; j += 256) {
            float xv = sx[j];
            pi += xv * igw[h*(3*II) + j];
            pf += xv * fgw[h*(3*II) + j];
        }
        pi = warpSum(pi); pf = warpSum(pf);
        if ((tid & 31) == 0) { rbuf[0][tid >> 5] = pi; rbuf[1][tid >> 5] = pf; }
        __syncthreads();
        if (tid == 0) {
            float a = 0.f, bb = 0.f;
            #pragma unroll
            for (int w8 = 0; w8 < 8; w8++) { a += rbuf[0][w8]; bb += rbuf[1][w8]; }
            ig[(long)(b*4 + h) * SS + s] = a + igb[h];
            fg[(long)(b*4 + h) * SS + s] = bb + fgb[h];
        }
        __syncthreads();
    }
}

// ---------------- mLSTM decay prep ----------------
__global__ void mlstm_prep(const float* __restrict__ ig, const float* __restrict__ fg,
                           float* __restrict__ a, float* __restrict__ rm,
                           float* __restrict__ en)
{
    int z = blockIdx.x;
    int tid = threadIdx.x;  // 256
    __shared__ float slsig[SS], sig_s[SS];
    for (int i = tid; i < SS; i += 256) {
        float fv = fg[(long)z * SS + i];
        slsig[i] = fminf(fv, 0.f) - log1pf(__expf(-fabsf(fv)));
        sig_s[i] = ig[(long)z * SS + i];
    }
    __syncthreads();
    if (tid == 0) {
        float cs = 0.f, run = -1e30f;
        for (int s = 0; s < SS; s++) {
            cs += slsig[s];
            float av = sig_s[s] - cs;
            run = fmaxf(run, av);
            a[(long)z * SS + s]  = av;
            rm[(long)z * SS + s] = run;
            en[(long)z * SS + s] = __expf(-(cs + run));
        }
    }
}

// ---------------- row normalizer ----------------
__global__ void attn_rowsum(const float* __restrict__ sc, const float* __restrict__ en,
                            float* __restrict__ rn)
{
    int s = blockIdx.x, z = blockIdx.y;
    const float4* row = (const float4*)(sc + ((long)z * SS + s) * SS);
    int tid = threadIdx.x;
    float4 v = row[tid];
    float sm = v.x + v.y + v.z + v.w;
    __shared__ float sb[8];
    sm = warpSum(sm);
    if ((tid & 31) == 0) sb[tid >> 5] = sm;
    __syncthreads();
    if (tid == 0) {
        float t = 0.f;
        #pragma unroll
        for (int i = 0; i < 8; i++) t += sb[i];
        rn[(long)z * SS + s] = 1.f / (fmaxf(fabsf(t), en[(long)z * SS + s]) + 1e-6f);
    }
}

// ---------------- mh_norm(dh=512) + (h+skip*xa)*silu(z) ----------------
__global__ void mh_mix(const float* __restrict__ H, const float* __restrict__ onw,
                       const float* __restrict__ skip, const float* __restrict__ xa,
                       const float* __restrict__ up, float* __restrict__ hmix)
{
    int bs = blockIdx.x, h = blockIdx.y;
    int b = bs >> 10;
    int s = bs & (SS - 1);
    const float* hp = H + ((long)(b*4 + h) * SS + s) * DHM;
    int tid = threadIdx.x;  // 128
    float4 v = ((const float4*)hp)[tid];
    float sm = v.x + v.y + v.z + v.w;
    float sq = v.x*v.x + v.y*v.y + v.z*v.z + v.w*v.w;
    __shared__ float s1[4], s2[4];
    sm = warpSum(sm); sq = warpSum(sq);
    if ((tid & 31) == 0) { s1[tid >> 5] = sm; s2[tid >> 5] = sq; }
    __syncthreads();
    float tot  = s1[0] + s1[1] + s1[2] + s1[3];
    float tot2 = s2[0] + s2[1] + s2[2] + s2[3];
    float mu = tot * (1.f / DHM);
    float rs = rsqrtf(tot2 * (1.f / DHM) - mu * mu + 1e-5f);
    float4 wv  = ((const float4*)onw)[h*128 + tid];
    float4 sk  = ((const float4*)skip)[h*128 + tid];
    float4 xav = ((const float4*)(xa + (long)bs * II))[h*128 + tid];
    float4 zv  = ((const float4*)(up + (long)bs * (2L*II) + II))[h*128 + tid];
    float4 o;
    o.x = ((v.x - mu)*rs*wv.x + sk.x*xav.x) * (zv.x / (1.f + __expf(-zv.x)));
    o.y = ((v.y - mu)*rs*wv.y + sk.y*xav.y) * (zv.y / (1.f + __expf(-zv.y)));
    o.z = ((v.z - mu)*rs*wv.z + sk.z*xav.z) * (zv.z / (1.f + __expf(-zv.z)));
    o.w = ((v.w - mu)*rs*wv.w + sk.w*xav.w) * (zv.w / (1.f + __expf(-zv.w)));
    ((float4*)(hmix + (long)bs * II))[h*128 + tid] = o;
}

// ============================================================================
// Cluster-split sLSTM scan (unchanged from R5 win)
// ============================================================================
#define SCAN_SMEM_FLOATS (32768 + 256 + 512)

__device__ __forceinline__ uint32_t smem_addr_u32(const void* p) {
    return (uint32_t)__cvta_generic_to_shared(p);
}
__device__ __forceinline__ uint32_t mapa_u32(uint32_t addr, uint32_t rank) {
    uint32_t out;
    asm("mapa.shared::cluster.u32 %0, %1, %2;" : "=r"(out) : "r"(addr), "r"(rank));
    return out;
}
__device__ __forceinline__ void st_cluster_f32(uint32_t addr, float v) {
    asm volatile("st.shared::cluster.f32 [%0], %1;" :: "r"(addr), "f"(v) : "memory");
}
__device__ __forceinline__ void cluster_barrier() {
    asm volatile("barrier.cluster.arrive.aligned;" ::: "memory");
    asm volatile("barrier.cluster.wait.aligned;" ::: "memory");
}

__global__ void __launch_bounds__(128, 1) __cluster_dims__(8, 1, 1)
slstm_scan_cl(const float* __restrict__ pre, const float* __restrict__ rk,
              const float* __restrict__ rb, float* __restrict__ ys)
{
    extern __shared__ float sm[];
    float* W    = sm;
    float* sh_h = sm + 32768;
    float* sraw = sm + 32768 + 256;

    const int z = blockIdx.x >> 3;
    const int b = z >> 2, h = z & 3;
    uint32_t rank;
    asm("mov.u32 %0, %%cluster_ctarank;" : "=r"(rank));
    const int g  = rank >> 1;
    const int hf = rank & 1;
    const int tid = threadIdx.x;

    const float* rks = rk + ((long)h * 256 * 4 + g) * 256 + hf * 128;
    for (int idx = tid; idx < 32768; idx += 128) {
        int d = idx >> 7, el = idx & 127;
        W[idx] = rks[(long)d * 1024 + el];
    }
    for (int i = tid; i < 256; i += 128) sh_h[i] = 0.f;
    __syncthreads();

    const float rbv = rb[(h*4 + g) * DHS + hf*128 + tid];
    const float* pb = pre + ((long)(g*4 + h) * BS + (long)b * SS) * DHS + hf*128 + tid;
    float* yo = ys + (long)z * SS * DHS + hf*128 + tid;

    const uint32_t raw_dst = mapa_u32(smem_addr_u32(&sraw[g*128 + tid]), (uint32_t)hf);
    uint32_t hdst[8];
    #pragma unroll
    for (int r = 0; r < 8; r++)
        hdst[r] = mapa_u32(smem_addr_u32(&sh_h[hf*128 + tid]), (uint32_t)r);

    const bool is_act = (rank < 2);
    float c = 0.f, n = 0.f, m = 0.f;

    cluster_barrier();

    float pv = pb[0];
    for (int s = 0; s < SS; s++) {
        float a0 = 0.f, a1 = 0.f, a2 = 0.f, a3 = 0.f;
        const float* Wp = W + tid;
        #pragma unroll 8
        for (int d = 0; d < 256; d += 4) {
            float4 hv = *(const float4*)&sh_h[d];
            a0 += hv.x * Wp[(d+0) << 7];
            a1 += hv.y * Wp[(d+1) << 7];
            a2 += hv.z * Wp[(d+2) << 7];
            a3 += hv.w * Wp[(d+3) << 7];
        }
        float acc = pv + rbv + ((a0 + a1) + (a2 + a3));
        if (s + 1 < SS) pv = pb[(long)(s+1) * DHS];

        st_cluster_f32(raw_dst, acc);
        cluster_barrier();

        if (is_act) {
            float iraw = sraw[tid],       fraw = sraw[128 + tid];
            float zraw = sraw[256 + tid], oraw = sraw[384 + tid];
            float lf = m + fminf(fraw, 0.f) - log1pf(__expf(-fabsf(fraw)));
            float mn = fmaxf(iraw, lf);
            float ig_ = __expf(iraw - mn);
            float fg_ = __expf(lf - mn);
            c = fg_ * c + ig_ * tanhf(zraw);
            n = fg_ * n + ig_;
            m = mn;
            float hv = c / (n * (1.f + __expf(-oraw)));
            #pragma unroll
            for (int r = 0; r < 8; r++) st_cluster_f32(hdst[r], hv);
            yo[(long)s * DHS] = hv;
        }
        cluster_barrier();
    }
}

// ---------------- sLSTM group norm (256) + residual add ----------------
__global__ void slstm_gnorm(const float* __restrict__ ys, const float* __restrict__ gnw,
                            float* __restrict__ x)
{
    int bs = blockIdx.x, h = blockIdx.y;
    int b = bs >> 10, s = bs & (SS - 1);
    const float* yp = ys + ((long)(b*4 + h) * SS + s) * DHS;
    int tid = threadIdx.x;  // 64
    float4 v = ((const float4*)yp)[tid];
    float sm = v.x + v.y + v.z + v.w;
    float sq = v.x*v.x + v.y*v.y + v.z*v.z + v.w*v.w;
    __shared__ float s1[2], s2[2];
    sm = warpSum(sm); sq = warpSum(sq);
    if ((tid & 31) == 0) { s1[tid >> 5] = sm; s2[tid >> 5] = sq; }
    __syncthreads();
    float tot  = s1[0] + s1[1];
    float tot2 = s2[0] + s2[1];
    float mu = tot * (1.f / DHS);
    float rs = rsqrtf(tot2 * (1.f / DHS) - mu * mu + 1e-5f);
    float4 wv = ((const float4*)gnw)[h*64 + tid];
    float* xp = x + (long)bs * DD + h * DHS + tid * 4;
    float4 xv = *(float4*)xp;
    xv.x += (v.x - mu) * rs * wv.x;
    xv.y += (v.y - mu) * rs * wv.y;
    xv.z += (v.z - mu) * rs * wv.z;
    xv.w += (v.w - mu) * rs * wv.w;
    *(float4*)xp = xv;
}

// ---------------- FFN: act = gelu_exact(gate) * up ----------------
__global__ void gelu_mul(const float* __restrict__ f, float* __restrict__ a)
{
    long idx = (long)blockIdx.x * 256 + threadIdx.x;
    if (idx >= (long)BS * UU) return;
    long bs = idx / UU;
    int u = (int)(idx % UU);
    float g = f[bs * (2L*UU) + u];
    float p = f[bs * (2L*UU) + UU + u];
    a[idx] = 0.5f * g * (1.f + erff(g * 0.70710678118654752f)) * p;
}

// ---------------- host ----------------
static inline void gemm(const float* A, const float* B, float* C,
                        int M, int N, int K, int lda, int ldb, int ldc,
                        float alpha, const float* bias, int acc)
{
    dim3 grid(N / 128, M / 128);
    tgemm_nt<<<grid, 256>>>(A, B, C, M, N, K, lda, ldb, ldc, alpha, bias, acc);
}

extern "C" void kernel_launch(void* const* d_in, const int* in_sizes, int n_in,
                              void* d_out, int out_size)
{
    const int*   ids       = (const int*)  d_in[0];
    const float* emb       = (const float*)d_in[1];
    const float* m_ln_w    = (const float*)d_in[2];
    const float* m_up_w    = (const float*)d_in[3];
    const float* m_conv_w  = (const float*)d_in[4];
    const float* m_conv_b  = (const float*)d_in[5];
    const float* m_q_w     = (const float*)d_in[6];
    const float* m_k_w     = (const float*)d_in[7];
    const float* m_v_w     = (const float*)d_in[8];
    const float* m_ig_w    = (const float*)d_in[9];
    const float* m_ig_b    = (const float*)d_in[10];
    const float* m_fg_w    = (const float*)d_in[11];
    const float* m_fg_b    = (const float*)d_in[12];
    const float* m_skip    = (const float*)d_in[13];
    const float* m_on_w    = (const float*)d_in[14];
    const float* m_down_w  = (const float*)d_in[15];
    const float* s_ln_w    = (const float*)d_in[16];
    const float* s_conv_w  = (const float*)d_in[17];
    const float* s_conv_b  = (const float*)d_in[18];
    const float* s_iw      = (const float*)d_in[19];
    const float* s_fw      = (const float*)d_in[20];
    const float* s_zw      = (const float*)d_in[21];
    const float* s_ow      = (const float*)d_in[22];
    const float* s_rk      = (const float*)d_in[23];
    const float* s_rb      = (const float*)d_in[24];
    const float* s_gn_w    = (const float*)d_in[25];
    const float* s_ln2_w   = (const float*)d_in[26];
    const float* s_ffn_up  = (const float*)d_in[27];
    const float* s_ffn_dn  = (const float*)d_in[28];
    const float* post_ln_w = (const float*)d_in[29];
    const float* head_w    = (const float*)d_in[30];
    const float* head_b    = (const float*)d_in[31];
    float* out = (float*)d_out;

    float* pool = nullptr;
    cudaGetSymbolAddress((void**)&pool, g_pool);
    float* X   = pool + O_X;   float* XN  = pool + O_XN;  float* XC  = pool + O_XC;
    float* UP  = pool + O_UP;  float* XA  = pool + O_XA;
    float* Q_  = pool + O_Q;   float* K_  = pool + O_K;   float* V_  = pool + O_V;
    float* SC  = pool + O_SC;  float* HB  = pool + O_HB;  float* HM  = pool + O_HM;
    float* PRE = pool + O_PRE; float* YS  = pool + O_YS;
    float* FFN = pool + O_FFN; float* ACT = pool + O_ACT;
    float* IG  = pool + O_IG;  float* FG  = pool + O_FG;
    float* Aa  = pool + O_A;   float* RM  = pool + O_RM;
    float* EN  = pool + O_EN;  float* RN  = pool + O_RN;

    cudaFuncSetAttribute(slstm_scan_cl,
                         cudaFuncAttributeMaxDynamicSharedMemorySize,
                         SCAN_SMEM_FLOATS * 4);

    embed_k<<<BS, 256>>>(ids, emb, X);

    int mi = 0;
    for (int blk = 0; blk < 4; blk++) {
        if (blk == 1) {
            // ---------------- sLSTM block ----------------
            layernorm_k<<<BS, 256>>>(X, s_ln_w, XN);
            conv_silu<<<(BS * DD) / 256, 256>>>(XN, s_conv_w, s_conv_b, XC, DD, DD);
            sgemm_gates<<<dim3(2, 32, 16), 256>>>(XC, XN, s_iw, s_fw, s_zw, s_ow, PRE);
            slstm_scan_cl<<<128, 128, SCAN_SMEM_FLOATS * 4>>>(PRE, s_rk, s_rb, YS);
            slstm_gnorm<<<dim3(BS, 4), 64>>>(YS, s_gn_w, X);
            layernorm_k<<<BS, 256>>>(X, s_ln2_w, XN);
            gemm(XN, s_ffn_up, FFN, BS, 2*UU, DD, DD, DD, 2*UU, 1.f, nullptr, 0);
            gelu_mul<<<(int)(((long)BS*UU + 255) / 256), 256>>>(FFN, ACT);
            gemm(ACT, s_ffn_dn, X, BS, DD, UU, UU, UU, DD, 1.f, nullptr, 1);
        } else {
            // ---------------- mLSTM block ----------------
            layernorm_k<<<BS, 256>>>(X, m_ln_w + (long)mi*DD, XN);
            gemm(XN, m_up_w + (long)mi*4096*DD, UP, BS, 4096, DD, DD, DD, 4096,
                 1.f, nullptr, 0);
            conv_silu<<<(int)(((long)BS*II) / 256), 256>>>(
                UP, m_conv_w + (long)mi*II*4, m_conv_b + (long)mi*II, XA, II, 4096);
            headwise_qkv<<<(int)(((long)BS*512) / 256), 256>>>(
                XA, UP, m_q_w + (long)mi*512*16, m_k_w + (long)mi*512*16,
                m_v_w + (long)mi*512*16, Q_, K_, V_);
            igfg_k<<<BS, 256>>>(Q_, K_, V_,
                m_ig_w + (long)mi*4*6144, m_ig_b + (long)mi*4,
                m_fg_w + (long)mi*4*6144, m_fg_b + (long)mi*4, IG, FG);
            mlstm_prep<<<16, 256>>>(IG, FG, Aa, RM, EN);
            attn_qk<<<dim3(8, 8, 16), 256>>>(Q_, K_, SC, Aa, RM);
            attn_rowsum<<<dim3(SS, 16), 256>>>(SC, EN, RN);
            attn_av<<<dim3(4, 8, 16), 256>>>(SC, V_, RN, HB);
            mh_mix<<<dim3(BS, 4), 128>>>(HB, m_on_w + (long)mi*II,
                m_skip + (long)mi*II, XA, UP, HM);
            gemm(HM, m_down_w + (long)mi*DD*II, X, BS, DD, II, II, II, DD,
                 1.f, nullptr, 1);
            mi++;
        }
    }

    layernorm_k<<<BS, 256>>>(X, post_ln_w, XN);
    gemm(XN, head_w, out, BS, 256, DD, DD, DD, 256, 1.f, head_b, 0);
}

// round 7
// speedup vs baseline: 5.4840x; 1.0039x over previous
#include <cuda_runtime.h>
#include <cuda_bf16.h>
#include <math.h>
#include <stdint.h>

#define BB 4
#define SS 1024
#define DD 1024
#define II 2048
#define BS 4096
#define DHM 512
#define DHS 256
#define UU 1344

constexpr long SZ_X   = (long)BS * DD;
constexpr long SZ_UP  = (long)BS * 2 * II;
constexpr long SZ_I   = (long)BS * II;
constexpr long SZ_SC  = 16L * SS * SS;
constexpr long SZ_HB  = 16L * SS * DHM;
constexpr long SZ_PRE = 16L * BS * DHS;
constexpr long SZ_YS  = 16L * SS * DHS;
constexpr long SZ_FFN = (long)BS * 2 * UU;
constexpr long SZ_ACT = (long)BS * UU;
constexpr long SZ_V16 = 16L * SS;

constexpr long O_X   = 0;
constexpr long O_XN  = O_X   + SZ_X;
constexpr long O_XC  = O_XN  + SZ_X;
constexpr long O_UP  = O_XC  + SZ_X;
constexpr long O_XA  = O_UP  + SZ_UP;
constexpr long O_Q   = O_XA  + SZ_I;
constexpr long O_K   = O_Q   + SZ_I;
constexpr long O_V   = O_K   + SZ_I;
constexpr long O_SC  = O_V   + SZ_I;
constexpr long O_HB  = O_SC  + SZ_SC;
constexpr long O_HM  = O_HB  + SZ_HB;
constexpr long O_PRE = O_HM  + SZ_I;
constexpr long O_YS  = O_PRE + SZ_PRE;
constexpr long O_FFN = O_YS  + SZ_YS;
constexpr long O_ACT = O_FFN + SZ_FFN;
constexpr long O_IG  = O_ACT + SZ_ACT;
constexpr long O_FG  = O_IG  + SZ_V16;
constexpr long O_A   = O_FG  + SZ_V16;
constexpr long O_RM  = O_A   + SZ_V16;
constexpr long O_EN  = O_RM  + SZ_V16;
constexpr long O_RN  = O_EN  + SZ_V16;
constexpr long POOL_SZ = O_RN + SZ_V16;

__device__ float g_pool[POOL_SZ];

__device__ __forceinline__ float warpSum(float v) {
    #pragma unroll
    for (int o = 16; o > 0; o >>= 1) v += __shfl_down_sync(0xffffffffu, v, o);
    return v;
}

// ---------------- tf32 mma helpers ----------------
__device__ __forceinline__ uint32_t f2tf32(float f) {
    uint32_t r;
    asm("cvt.rna.tf32.f32 %0, %1;" : "=r"(r) : "f"(f));
    return r;
}
__device__ __forceinline__ void mma_tf32(float* c, const uint32_t* a, const uint32_t* b) {
    asm volatile(
        "mma.sync.aligned.m16n8k8.row.col.f32.tf32.tf32.f32 "
        "{%0,%1,%2,%3}, {%4,%5,%6,%7}, {%8,%9}, {%0,%1,%2,%3};"
        : "+f"(c[0]), "+f"(c[1]), "+f"(c[2]), "+f"(c[3])
        : "r"(a[0]), "r"(a[1]), "r"(a[2]), "r"(a[3]), "r"(b[0]), "r"(b[1]));
}
#define SPAD 36

// ---------------- embedding gather ----------------
__global__ void embed_k(const int* __restrict__ ids, const float* __restrict__ emb,
                        float* __restrict__ x)
{
    int bs = blockIdx.x;
    long id = ids[bs];
    ((float4*)(x + (long)bs * DD))[threadIdx.x] =
        ((const float4*)(emb + id * DD))[threadIdx.x];
}

// ---------------- LayerNorm width 1024, 256 thr/row ----------------
__global__ void layernorm_k(const float* __restrict__ x, const float* __restrict__ w,
                            float* __restrict__ y)
{
    long row = blockIdx.x;
    int tid = threadIdx.x;
    float4 v = ((const float4*)(x + row * DD))[tid];
    float s = v.x + v.y + v.z + v.w;
    float ss = v.x*v.x + v.y*v.y + v.z*v.z + v.w*v.w;
    __shared__ float sb[8], sb2[8];
    __shared__ float mu_s, rs_s;
    s = warpSum(s); ss = warpSum(ss);
    if ((tid & 31) == 0) { sb[tid >> 5] = s; sb2[tid >> 5] = ss; }
    __syncthreads();
    if (tid == 0) {
        float t = 0.f, t2 = 0.f;
        #pragma unroll
        for (int i = 0; i < 8; i++) { t += sb[i]; t2 += sb2[i]; }
        float mu = t * (1.f / DD);
        mu_s = mu;
        rs_s = rsqrtf(t2 * (1.f / DD) - mu * mu + 1e-5f);
    }
    __syncthreads();
    float mu = mu_s, rs = rs_s;
    float4 wv = ((const float4*)w)[tid];
    float4 o;
    o.x = (v.x - mu) * rs * wv.x;  o.y = (v.y - mu) * rs * wv.y;
    o.z = (v.z - mu) * rs * wv.z;  o.w = (v.w - mu) * rs * wv.w;
    ((float4*)(y + row * DD))[tid] = o;
}

// ============================================================================
// tf32 tensor-core GEMM NT, register-prefetch pipelined.
// C = alpha*A(MxK)@B(NxK)^T [+bias][+=C]; 128x128x32 tile, 8 warps.
// ============================================================================
__global__ void __launch_bounds__(256, 2) tgemm_nt(
    const float* __restrict__ A, const float* __restrict__ B, float* __restrict__ C,
    int M, int N, int K, int lda, int ldb, int ldc,
    float alpha, const float* __restrict__ bias, int acc)
{
    __shared__ float As[128 * SPAD];
    __shared__ float Bs[128 * SPAD];
    const int tid = threadIdx.x;
    const int lane = tid & 31, warp = tid >> 5;
    const int wm = warp & 3, wn = warp >> 2;
    const int g = lane >> 2, t = lane & 3;
    const int lr = tid >> 1, lc = (tid & 1) * 16;
    const float* Ag = A + (long)(blockIdx.y * 128 + lr) * lda + lc;
    const float* Bg = B + (long)(blockIdx.x * 128 + lr) * ldb + lc;

    float c[16][4];
    #pragma unroll
    for (int i = 0; i < 16; i++)
        #pragma unroll
        for (int j = 0; j < 4; j++) c[i][j] = 0.f;

    float4 a4[4], b4[4];
    #pragma unroll
    for (int i = 0; i < 4; i++) {
        a4[i] = *(const float4*)(Ag + i*4);
        b4[i] = *(const float4*)(Bg + i*4);
    }
    const int nk = K >> 5;
    for (int kt = 0; kt < nk; kt++) {
        __syncthreads();
        #pragma unroll
        for (int i = 0; i < 4; i++) {
            uint4 av = make_uint4(f2tf32(a4[i].x), f2tf32(a4[i].y),
                                  f2tf32(a4[i].z), f2tf32(a4[i].w));
            uint4 bv = make_uint4(f2tf32(b4[i].x), f2tf32(b4[i].y),
                                  f2tf32(b4[i].z), f2tf32(b4[i].w));
            *(uint4*)&As[lr * SPAD + lc + i*4] = av;
            *(uint4*)&Bs[lr * SPAD + lc + i*4] = bv;
        }
        __syncthreads();
        if (kt + 1 < nk) {
            const int k0 = (kt + 1) << 5;
            #pragma unroll
            for (int i = 0; i < 4; i++) {
                a4[i] = *(const float4*)(Ag + k0 + i*4);
                b4[i] = *(const float4*)(Bg + k0 + i*4);
            }
        }
        #pragma unroll
        for (int kk = 0; kk < 4; kk++) {
            const int ks = kk * 8;
            uint32_t af[2][4], bf[8][2];
            #pragma unroll
            for (int mt = 0; mt < 2; mt++) {
                int r0 = wm*32 + mt*16 + g;
                af[mt][0] = __float_as_uint(As[r0 * SPAD + ks + t]);
                af[mt][1] = __float_as_uint(As[(r0+8) * SPAD + ks + t]);
                af[mt][2] = __float_as_uint(As[r0 * SPAD + ks + t + 4]);
                af[mt][3] = __float_as_uint(As[(r0+8) * SPAD + ks + t + 4]);
            }
            #pragma unroll
            for (int nt = 0; nt < 8; nt++) {
                int c0 = wn*64 + nt*8 + g;
                bf[nt][0] = __float_as_uint(Bs[c0 * SPAD + ks + t]);
                bf[nt][1] = __float_as_uint(Bs[c0 * SPAD + ks + t + 4]);
            }
            #pragma unroll
            for (int mt = 0; mt < 2; mt++)
                #pragma unroll
                for (int nt = 0; nt < 8; nt++)
                    mma_tf32(c[mt*8 + nt], af[mt], bf[nt]);
        }
    }
    #pragma unroll
    for (int mt = 0; mt < 2; mt++) {
        int row0 = blockIdx.y*128 + wm*32 + mt*16 + g;
        #pragma unroll
        for (int nt = 0; nt < 8; nt++) {
            int col0 = blockIdx.x*128 + wn*64 + nt*8 + 2*t;
            float* v = c[mt*8 + nt];
            float b0 = bias ? bias[col0] : 0.f, b1 = bias ? bias[col0+1] : 0.f;
            float* C0 = C + (long)row0 * ldc + col0;
            float* C1 = C + (long)(row0+8) * ldc + col0;
            float o0 = v[0]*alpha + b0, o1 = v[1]*alpha + b1;
            float o2 = v[2]*alpha + b0, o3 = v[3]*alpha + b1;
            if (acc) { o0 += C0[0]; o1 += C0[1]; o2 += C1[0]; o3 += C1[1]; }
            C0[0] = o0; C0[1] = o1; C1[0] = o2; C1[1] = o3;
        }
    }
}

// ============================================================================
// tf32 attention scores, pipelined: SC = (q.k/sqrt(dh))*exp(a[t]-rm[s])
// ============================================================================
__global__ void __launch_bounds__(256, 2) attn_qk(
    const float* __restrict__ Qb, const float* __restrict__ Kb,
    float* __restrict__ SC, const float* __restrict__ a_,
    const float* __restrict__ rm_)
{
    const int z = blockIdx.z;
    const int b = z >> 2, h = z & 3;
    const int bx = blockIdx.x, by = blockIdx.y;
    float* Cb = SC + (long)z * SS * SS;
    if (bx > by) {
        for (int i = threadIdx.x; i < 4096; i += 256) {
            int rr = i >> 5, cc = (i & 31) << 2;
            *(float4*)(Cb + (long)(by*128 + rr) * SS + bx*128 + cc) =
                make_float4(0.f, 0.f, 0.f, 0.f);
        }
        return;
    }
    const float* A = Qb + (long)b * SS * II + h * DHM;
    const float* B = Kb + (long)b * SS * II + h * DHM;
    __shared__ float As[128 * SPAD];
    __shared__ float Bs[128 * SPAD];
    const int tid = threadIdx.x;
    const int lane = tid & 31, warp = tid >> 5;
    const int wm = warp & 3, wn = warp >> 2;
    const int g = lane >> 2, t = lane & 3;
    const int lr = tid >> 1, lc = (tid & 1) * 16;
    const float* Ag = A + (long)(by*128 + lr) * II + lc;
    const float* Bg = B + (long)(bx*128 + lr) * II + lc;

    float c[16][4];
    #pragma unroll
    for (int i = 0; i < 16; i++)
        #pragma unroll
        for (int j = 0; j < 4; j++) c[i][j] = 0.f;

    float4 a4[4], b4[4];
    #pragma unroll
    for (int i = 0; i < 4; i++) {
        a4[i] = *(const float4*)(Ag + i*4);
        b4[i] = *(const float4*)(Bg + i*4);
    }
    const int nk = DHM >> 5;
    for (int kt = 0; kt < nk; kt++) {
        __syncthreads();
        #pragma unroll
        for (int i = 0; i < 4; i++) {
            uint4 av = make_uint4(f2tf32(a4[i].x), f2tf32(a4[i].y),
                                  f2tf32(a4[i].z), f2tf32(a4[i].w));
            uint4 bv = make_uint4(f2tf32(b4[i].x), f2tf32(b4[i].y),
                                  f2tf32(b4[i].z), f2tf32(b4[i].w));
            *(uint4*)&As[lr * SPAD + lc + i*4] = av;
            *(uint4*)&Bs[lr * SPAD + lc + i*4] = bv;
        }
        __syncthreads();
        if (kt + 1 < nk) {
            const int k0 = (kt + 1) << 5;
            #pragma unroll
            for (int i = 0; i < 4; i++) {
                a4[i] = *(const float4*)(Ag + k0 + i*4);
                b4[i] = *(const float4*)(Bg + k0 + i*4);
            }
        }
        #pragma unroll
        for (int kk = 0; kk < 4; kk++) {
            const int ks = kk * 8;
            uint32_t af[2][4], bf[8][2];
            #pragma unroll
            for (int mt = 0; mt < 2; mt++) {
                int r0 = wm*32 + mt*16 + g;
                af[mt][0] = __float_as_uint(As[r0 * SPAD + ks + t]);
                af[mt][1] = __float_as_uint(As[(r0+8) * SPAD + ks + t]);
                af[mt][2] = __float_as_uint(As[r0 * SPAD + ks + t + 4]);
                af[mt][3] = __float_as_uint(As[(r0+8) * SPAD + ks + t + 4]);
            }
            #pragma unroll
            for (int nt = 0; nt < 8; nt++) {
                int c0 = wn*64 + nt*8 + g;
                bf[nt][0] = __float_as_uint(Bs[c0 * SPAD + ks + t]);
                bf[nt][1] = __float_as_uint(Bs[c0 * SPAD + ks + t + 4]);
            }
            #pragma unroll
            for (int mt = 0; mt < 2; mt++)
                #pragma unroll
                for (int nt = 0; nt < 8; nt++)
                    mma_tf32(c[mt*8 + nt], af[mt], bf[nt]);
        }
    }
    const float* az = a_ + (long)z * SS;
    const float* rz = rm_ + (long)z * SS;
    const float alpha = 0.04419417382415922f;  // 1/sqrt(512)
    #pragma unroll
    for (int mt = 0; mt < 2; mt++) {
        int row0 = by*128 + wm*32 + mt*16 + g;
        int row1 = row0 + 8;
        float rm0 = rz[row0], rm1 = rz[row1];
        #pragma unroll
        for (int nt = 0; nt < 8; nt++) {
            int col0 = bx*128 + wn*64 + nt*8 + 2*t;
            float av0 = az[col0], av1 = az[col0+1];
            float* v = c[mt*8 + nt];
            float* C0 = Cb + (long)row0 * SS + col0;
            float* C1 = Cb + (long)row1 * SS + col0;
            C0[0] = (col0   <= row0) ? v[0]*alpha*__expf(av0 - rm0) : 0.f;
            C0[1] = (col0+1 <= row0) ? v[1]*alpha*__expf(av1 - rm0) : 0.f;
            C1[0] = (col0   <= row1) ? v[2]*alpha*__expf(av0 - rm1) : 0.f;
            C1[1] = (col0+1 <= row1) ? v[3]*alpha*__expf(av1 - rm1) : 0.f;
        }
    }
}

// ============================================================================
// tf32 attention value GEMM (NN), pipelined: H = rn[s]*SC@V, K capped at diag
// ============================================================================
__global__ void __launch_bounds__(256, 2) attn_av(
    const float* __restrict__ SC, const float* __restrict__ Vb,
    const float* __restrict__ Rn, float* __restrict__ H)
{
    const int z = blockIdx.z;
    const int b = z >> 2, h = z & 3;
    const int bx = blockIdx.x, by = blockIdx.y;
    const float* A = SC + (long)z * SS * SS;
    const float* B = Vb + (long)b * SS * II + h * DHM;
    float* Cb = H + (long)z * SS * DHM;
    const int kend = (by + 1) * 128;
    __shared__ float As[128 * SPAD];
    __shared__ float Bs[128 * SPAD];
    const int tid = threadIdx.x;
    const int lane = tid & 31, warp = tid >> 5;
    const int wm = warp & 3, wn = warp >> 2;
    const int g = lane >> 2, t = lane & 3;
    const int lr = tid >> 1, lc = (tid & 1) * 16;
    const float* Ag = A + (long)(by*128 + lr) * SS + lc;
    const int bkr = tid >> 3;
    const int bc4 = tid & 7;
    const float* Bg = B + (long)bkr * II + bx*128;

    float c[16][4];
    #pragma unroll
    for (int i = 0; i < 16; i++)
        #pragma unroll
        for (int j = 0; j < 4; j++) c[i][j] = 0.f;

    float4 a4[4], b4[4];
    #pragma unroll
    for (int i = 0; i < 4; i++) {
        a4[i] = *(const float4*)(Ag + i*4);
        b4[i] = *(const float4*)(Bg + (bc4 + i*8) * 4);
    }
    const int nk = kend >> 5;
    for (int kt = 0; kt < nk; kt++) {
        __syncthreads();
        #pragma unroll
        for (int i = 0; i < 4; i++) {
            uint4 av = make_uint4(f2tf32(a4[i].x), f2tf32(a4[i].y),
                                  f2tf32(a4[i].z), f2tf32(a4[i].w));
            *(uint4*)&As[lr * SPAD + lc + i*4] = av;
            int coln = (bc4 + i*8) * 4;
            Bs[(coln+0) * SPAD + bkr] = __uint_as_float(f2tf32(b4[i].x));
            Bs[(coln+1) * SPAD + bkr] = __uint_as_float(f2tf32(b4[i].y));
            Bs[(coln+2) * SPAD + bkr] = __uint_as_float(f2tf32(b4[i].z));
            Bs[(coln+3) * SPAD + bkr] = __uint_as_float(f2tf32(b4[i].w));
        }
        __syncthreads();
        if (kt + 1 < nk) {
            const int k0 = (kt + 1) << 5;
            #pragma unroll
            for (int i = 0; i < 4; i++) {
                a4[i] = *(const float4*)(Ag + k0 + i*4);
                b4[i] = *(const float4*)(Bg + (long)k0 * II + (bc4 + i*8) * 4);
            }
        }
        #pragma unroll
        for (int kk = 0; kk < 4; kk++) {
            const int ks = kk * 8;
            uint32_t af[2][4], bf[8][2];
            #pragma unroll
            for (int mt = 0; mt < 2; mt++) {
                int r0 = wm*32 + mt*16 + g;
                af[mt][0] = __float_as_uint(As[r0 * SPAD + ks + t]);
                af[mt][1] = __float_as_uint(As[(r0+8) * SPAD + ks + t]);
                af[mt][2] = __float_as_uint(As[r0 * SPAD + ks + t + 4]);
                af[mt][3] = __float_as_uint(As[(r0+8) * SPAD + ks + t + 4]);
            }
            #pragma unroll
            for (int nt = 0; nt < 8; nt++) {
                int c0 = wn*64 + nt*8 + g;
                bf[nt][0] = __float_as_uint(Bs[c0 * SPAD + ks + t]);
                bf[nt][1] = __float_as_uint(Bs[c0 * SPAD + ks + t + 4]);
            }
            #pragma unroll
            for (int mt = 0; mt < 2; mt++)
                #pragma unroll
                for (int nt = 0; nt < 8; nt++)
                    mma_tf32(c[mt*8 + nt], af[mt], bf[nt]);
        }
    }
    const float* rz = Rn + (long)z * SS;
    #pragma unroll
    for (int mt = 0; mt < 2; mt++) {
        int row0 = by*128 + wm*32 + mt*16 + g;
        int row1 = row0 + 8;
        float rn0 = rz[row0], rn1 = rz[row1];
        #pragma unroll
        for (int nt = 0; nt < 8; nt++) {
            int col0 = bx*128 + wn*64 + nt*8 + 2*t;
            float* v = c[mt*8 + nt];
            float* C0 = Cb + (long)row0 * DHM + col0;
            float* C1 = Cb + (long)row1 * DHM + col0;
            C0[0] = v[0]*rn0; C0[1] = v[1]*rn0;
            C1[0] = v[2]*rn1; C1[1] = v[3]*rn1;
        }
    }
}

// ---------------- batched sLSTM gate GEMMs (fp32, small) ----------------
__global__ void __launch_bounds__(256, 2) sgemm_gates(
    const float* __restrict__ XC, const float* __restrict__ XN,
    const float* __restrict__ iw, const float* __restrict__ fw,
    const float* __restrict__ zw, const float* __restrict__ ow,
    float* __restrict__ PRE)
{
    const int zz = blockIdx.z;
    const int g = zz >> 2, h = zz & 3;
    const float* A = ((g < 2) ? XC : XN) + h * 256;
    const float* W = (g == 0) ? iw : (g == 1) ? fw : (g == 2) ? zw : ow;
    const float* B = W + (long)h * 65536;
    float* C = PRE + (long)zz * BS * DHS;
    __shared__ float As[8][128];
    __shared__ float Bs[8][128];
    const int tid = threadIdx.x;
    const int lrow = tid >> 1;
    const int lcol = (tid & 1) << 2;
    const float* Ag = A + (long)(blockIdx.y * 128 + lrow) * DD + lcol;
    const float* Bg = B + (long)(blockIdx.x * 128 + lrow) * 256 + lcol;
    const int ty = tid >> 4, tx = tid & 15;
    float accv[8][8];
    #pragma unroll
    for (int i = 0; i < 8; i++)
        #pragma unroll
        for (int j = 0; j < 8; j++) accv[i][j] = 0.f;
    for (int k0 = 0; k0 < 256; k0 += 8) {
        float4 av = *(const float4*)(Ag + k0);
        float4 bv = *(const float4*)(Bg + k0);
        __syncthreads();
        As[lcol+0][lrow] = av.x; As[lcol+1][lrow] = av.y;
        As[lcol+2][lrow] = av.z; As[lcol+3][lrow] = av.w;
        Bs[lcol+0][lrow] = bv.x; Bs[lcol+1][lrow] = bv.y;
        Bs[lcol+2][lrow] = bv.z; Bs[lcol+3][lrow] = bv.w;
        __syncthreads();
        #pragma unroll
        for (int kk = 0; kk < 8; kk++) {
            float ar[8], br[8];
            #pragma unroll
            for (int i = 0; i < 8; i++) ar[i] = As[kk][ty*8 + i];
            #pragma unroll
            for (int j = 0; j < 8; j++) br[j] = Bs[kk][tx*8 + j];
            #pragma unroll
            for (int i = 0; i < 8; i++)
                #pragma unroll
                for (int j = 0; j < 8; j++)
                    accv[i][j] += ar[i] * br[j];
        }
    }
    #pragma unroll
    for (int i = 0; i < 8; i++) {
        long row = blockIdx.y * 128 + ty*8 + i;
        float* Cr = C + row * 256L + blockIdx.x * 128 + tx*8;
        #pragma unroll
        for (int j = 0; j < 8; j++)
            Cr[j] = accv[i][j];
    }
}

// ---------------- causal depthwise conv (K=4) + SiLU ----------------
__global__ void conv_silu(const float* __restrict__ in, const float* __restrict__ w,
                          const float* __restrict__ bias, float* __restrict__ out,
                          int C, int ldin)
{
    long idx = (long)blockIdx.x * 256 + threadIdx.x;
    if (idx >= (long)BS * C) return;
    int c = (int)(idx % C);
    long bs = idx / C;
    int s = (int)(bs & (SS - 1));
    float acc = bias[c];
    #pragma unroll
    for (int kk = 0; kk < 4; kk++) {
        int sp = s + kk - 3;
        if (sp >= 0) acc += in[(bs + kk - 3) * ldin + c] * w[c*4 + kk];
    }
    out[bs * (long)C + c] = acc / (1.f + __expf(-acc));
}

// ---------------- headwise 4x4 q,k from xa; v from xm(strided) ----------------
__global__ void headwise_qkv(const float* __restrict__ xa, const float* __restrict__ xm,
                             const float* __restrict__ qw, const float* __restrict__ kw,
                             const float* __restrict__ vw,
                             float* __restrict__ q, float* __restrict__ k,
                             float* __restrict__ v)
{
    long idx = (long)blockIdx.x * 256 + threadIdx.x;
    if (idx >= (long)BS * 512) return;
    int nb = (int)(idx & 511);
    long bs = idx >> 9;
    float4 xav = *(const float4*)(xa + bs * II + nb*4);
    float4 xmv = *(const float4*)(xm + bs * (2L*II) + nb*4);
    float xi[4] = {xav.x, xav.y, xav.z, xav.w};
    float xmi[4] = {xmv.x, xmv.y, xmv.z, xmv.w};
    float qo[4], ko[4], vo[4];
    #pragma unroll
    for (int o = 0; o < 4; o++) {
        float aq = 0.f, ak = 0.f, av = 0.f;
        #pragma unroll
        for (int i = 0; i < 4; i++) {
            aq += xi[i]  * qw[nb*16 + o*4 + i];
            ak += xi[i]  * kw[nb*16 + o*4 + i];
            av += xmi[i] * vw[nb*16 + o*4 + i];
        }
        qo[o] = aq; ko[o] = ak; vo[o] = av;
    }
    *(float4*)(q + bs * II + nb*4) = make_float4(qo[0], qo[1], qo[2], qo[3]);
    *(float4*)(k + bs * II + nb*4) = make_float4(ko[0], ko[1], ko[2], ko[3]);
    *(float4*)(v + bs * II + nb*4) = make_float4(vo[0], vo[1], vo[2], vo[3]);
}

// ---------------- ig/fg gate projections ----------------
__global__ void igfg_k(const float* __restrict__ q, const float* __restrict__ k,
                       const float* __restrict__ v,
                       const float* __restrict__ igw, const float* __restrict__ igb,
                       const float* __restrict__ fgw, const float* __restrict__ fgb,
                       float* __restrict__ ig, float* __restrict__ fg)
{
    long bs = blockIdx.x;
    int b = (int)(bs >> 10);
    int s = (int)(bs & (SS - 1));
    __shared__ float sx[3 * II];
    __shared__ float rbuf[2][8];
    int tid = threadIdx.x;
    for (int i = tid; i < II; i += 256) {
        sx[i]        = q[bs * II + i];
        sx[II + i]   = k[bs * II + i];
        sx[2*II + i] = v[bs * II + i];
    }
    __syncthreads();
    for (int h = 0; h < 4; h++) {
        float pi = 0.f, pf = 0.f;
        for (int j = tid; j < 3*II; j += 256) {
            float xv = sx[j];
            pi += xv * igw[h*(3*II) + j];
            pf += xv * fgw[h*(3*II) + j];
        }
        pi = warpSum(pi); pf = warpSum(pf);
        if ((tid & 31) == 0) { rbuf[0][tid >> 5] = pi; rbuf[1][tid >> 5] = pf; }
        __syncthreads();
        if (tid == 0) {
            float a = 0.f, bb = 0.f;
            #pragma unroll
            for (int w8 = 0; w8 < 8; w8++) { a += rbuf[0][w8]; bb += rbuf[1][w8]; }
            ig[(long)(b*4 + h) * SS + s] = a + igb[h];
            fg[(long)(b*4 + h) * SS + s] = bb + fgb[h];
        }
        __syncthreads();
    }
}

// ---------------- mLSTM decay prep ----------------
__global__ void mlstm_prep(const float* __restrict__ ig, const float* __restrict__ fg,
                           float* __restrict__ a, float* __restrict__ rm,
                           float* __restrict__ en)
{
    int z = blockIdx.x;
    int tid = threadIdx.x;  // 256
    __shared__ float slsig[SS], sig_s[SS];
    for (int i = tid; i < SS; i += 256) {
        float fv = fg[(long)z * SS + i];
        slsig[i] = fminf(fv, 0.f) - log1pf(__expf(-fabsf(fv)));
        sig_s[i] = ig[(long)z * SS + i];
    }
    __syncthreads();
    if (tid == 0) {
        float cs = 0.f, run = -1e30f;
        for (int s = 0; s < SS; s++) {
            cs += slsig[s];
            float av = sig_s[s] - cs;
            run = fmaxf(run, av);
            a[(long)z * SS + s]  = av;
            rm[(long)z * SS + s] = run;
            en[(long)z * SS + s] = __expf(-(cs + run));
        }
    }
}

// ---------------- row normalizer ----------------
__global__ void attn_rowsum(const float* __restrict__ sc, const float* __restrict__ en,
                            float* __restrict__ rn)
{
    int s = blockIdx.x, z = blockIdx.y;
    const float4* row = (const float4*)(sc + ((long)z * SS + s) * SS);
    int tid = threadIdx.x;
    float4 v = row[tid];
    float sm = v.x + v.y + v.z + v.w;
    __shared__ float sb[8];
    sm = warpSum(sm);
    if ((tid & 31) == 0) sb[tid >> 5] = sm;
    __syncthreads();
    if (tid == 0) {
        float t = 0.f;
        #pragma unroll
        for (int i = 0; i < 8; i++) t += sb[i];
        rn[(long)z * SS + s] = 1.f / (fmaxf(fabsf(t), en[(long)z * SS + s]) + 1e-6f);
    }
}

// ---------------- mh_norm(dh=512) + (h+skip*xa)*silu(z) ----------------
__global__ void mh_mix(const float* __restrict__ H, const float* __restrict__ onw,
                       const float* __restrict__ skip, const float* __restrict__ xa,
                       const float* __restrict__ up, float* __restrict__ hmix)
{
    int bs = blockIdx.x, h = blockIdx.y;
    int b = bs >> 10;
    int s = bs & (SS - 1);
    const float* hp = H + ((long)(b*4 + h) * SS + s) * DHM;
    int tid = threadIdx.x;  // 128
    float4 v = ((const float4*)hp)[tid];
    float sm = v.x + v.y + v.z + v.w;
    float sq = v.x*v.x + v.y*v.y + v.z*v.z + v.w*v.w;
    __shared__ float s1[4], s2[4];
    sm = warpSum(sm); sq = warpSum(sq);
    if ((tid & 31) == 0) { s1[tid >> 5] = sm; s2[tid >> 5] = sq; }
    __syncthreads();
    float tot  = s1[0] + s1[1] + s1[2] + s1[3];
    float tot2 = s2[0] + s2[1] + s2[2] + s2[3];
    float mu = tot * (1.f / DHM);
    float rs = rsqrtf(tot2 * (1.f / DHM) - mu * mu + 1e-5f);
    float4 wv  = ((const float4*)onw)[h*128 + tid];
    float4 sk  = ((const float4*)skip)[h*128 + tid];
    float4 xav = ((const float4*)(xa + (long)bs * II))[h*128 + tid];
    float4 zv  = ((const float4*)(up + (long)bs * (2L*II) + II))[h*128 + tid];
    float4 o;
    o.x = ((v.x - mu)*rs*wv.x + sk.x*xav.x) * (zv.x / (1.f + __expf(-zv.x)));
    o.y = ((v.y - mu)*rs*wv.y + sk.y*xav.y) * (zv.y / (1.f + __expf(-zv.y)));
    o.z = ((v.z - mu)*rs*wv.z + sk.z*xav.z) * (zv.z / (1.f + __expf(-zv.z)));
    o.w = ((v.w - mu)*rs*wv.w + sk.w*xav.w) * (zv.w / (1.f + __expf(-zv.w)));
    ((float4*)(hmix + (long)bs * II))[h*128 + tid] = o;
}

// ============================================================================
// Cluster-split sLSTM scan (unchanged from R5 win)
// ============================================================================
#define SCAN_SMEM_FLOATS (32768 + 256 + 512)

__device__ __forceinline__ uint32_t smem_addr_u32(const void* p) {
    return (uint32_t)__cvta_generic_to_shared(p);
}
__device__ __forceinline__ uint32_t mapa_u32(uint32_t addr, uint32_t rank) {
    uint32_t out;
    asm("mapa.shared::cluster.u32 %0, %1, %2;" : "=r"(out) : "r"(addr), "r"(rank));
    return out;
}
__device__ __forceinline__ void st_cluster_f32(uint32_t addr, float v) {
    asm volatile("st.shared::cluster.f32 [%0], %1;" :: "r"(addr), "f"(v) : "memory");
}
__device__ __forceinline__ void cluster_barrier() {
    asm volatile("barrier.cluster.arrive.aligned;" ::: "memory");
    asm volatile("barrier.cluster.wait.aligned;" ::: "memory");
}

__global__ void __launch_bounds__(128, 1) __cluster_dims__(8, 1, 1)
slstm_scan_cl(const float* __restrict__ pre, const float* __restrict__ rk,
              const float* __restrict__ rb, float* __restrict__ ys)
{
    extern __shared__ float sm[];
    float* W    = sm;
    float* sh_h = sm + 32768;
    float* sraw = sm + 32768 + 256;

    const int z = blockIdx.x >> 3;
    const int b = z >> 2, h = z & 3;
    uint32_t rank;
    asm("mov.u32 %0, %%cluster_ctarank;" : "=r"(rank));
    const int g  = rank >> 1;
    const int hf = rank & 1;
    const int tid = threadIdx.x;

    const float* rks = rk + ((long)h * 256 * 4 + g) * 256 + hf * 128;
    for (int idx = tid; idx < 32768; idx += 128) {
        int d = idx >> 7, el = idx & 127;
        W[idx] = rks[(long)d * 1024 + el];
    }
    for (int i = tid; i < 256; i += 128) sh_h[i] = 0.f;
    __syncthreads();

    const float rbv = rb[(h*4 + g) * DHS + hf*128 + tid];
    const float* pb = pre + ((long)(g*4 + h) * BS + (long)b * SS) * DHS + hf*128 + tid;
    float* yo = ys + (long)z * SS * DHS + hf*128 + tid;

    const uint32_t raw_dst = mapa_u32(smem_addr_u32(&sraw[g*128 + tid]), (uint32_t)hf);
    uint32_t hdst[8];
    #pragma unroll
    for (int r = 0; r < 8; r++)
        hdst[r] = mapa_u32(smem_addr_u32(&sh_h[hf*128 + tid]), (uint32_t)r);

    const bool is_act = (rank < 2);
    float c = 0.f, n = 0.f, m = 0.f;

    cluster_barrier();

    float pv = pb[0];
    for (int s = 0; s < SS; s++) {
        float a0 = 0.f, a1 = 0.f, a2 = 0.f, a3 = 0.f;
        const float* Wp = W + tid;
        #pragma unroll 8
        for (int d = 0; d < 256; d += 4) {
            float4 hv = *(const float4*)&sh_h[d];
            a0 += hv.x * Wp[(d+0) << 7];
            a1 += hv.y * Wp[(d+1) << 7];
            a2 += hv.z * Wp[(d+2) << 7];
            a3 += hv.w * Wp[(d+3) << 7];
        }
        float acc = pv + rbv + ((a0 + a1) + (a2 + a3));
        if (s + 1 < SS) pv = pb[(long)(s+1) * DHS];

        st_cluster_f32(raw_dst, acc);
        cluster_barrier();

        if (is_act) {
            float iraw = sraw[tid],       fraw = sraw[128 + tid];
            float zraw = sraw[256 + tid], oraw = sraw[384 + tid];
            float lf = m + fminf(fraw, 0.f) - log1pf(__expf(-fabsf(fraw)));
            float mn = fmaxf(iraw, lf);
            float ig_ = __expf(iraw - mn);
            float fg_ = __expf(lf - mn);
            c = fg_ * c + ig_ * tanhf(zraw);
            n = fg_ * n + ig_;
            m = mn;
            float hv = c / (n * (1.f + __expf(-oraw)));
            #pragma unroll
            for (int r = 0; r < 8; r++) st_cluster_f32(hdst[r], hv);
            yo[(long)s * DHS] = hv;
        }
        cluster_barrier();
    }
}

// ---------------- sLSTM group norm (256) + residual add ----------------
__global__ void slstm_gnorm(const float* __restrict__ ys, const float* __restrict__ gnw,
                            float* __restrict__ x)
{
    int bs = blockIdx.x, h = blockIdx.y;
    int b = bs >> 10, s = bs & (SS - 1);
    const float* yp = ys + ((long)(b*4 + h) * SS + s) * DHS;
    int tid = threadIdx.x;  // 64
    float4 v = ((const float4*)yp)[tid];
    float sm = v.x + v.y + v.z + v.w;
    float sq = v.x*v.x + v.y*v.y + v.z*v.z + v.w*v.w;
    __shared__ float s1[2], s2[2];
    sm = warpSum(sm); sq = warpSum(sq);
    if ((tid & 31) == 0) { s1[tid >> 5] = sm; s2[tid >> 5] = sq; }
    __syncthreads();
    float tot  = s1[0] + s1[1];
    float tot2 = s2[0] + s2[1];
    float mu = tot * (1.f / DHS);
    float rs = rsqrtf(tot2 * (1.f / DHS) - mu * mu + 1e-5f);
    float4 wv = ((const float4*)gnw)[h*64 + tid];
    float* xp = x + (long)bs * DD + h * DHS + tid * 4;
    float4 xv = *(float4*)xp;
    xv.x += (v.x - mu) * rs * wv.x;
    xv.y += (v.y - mu) * rs * wv.y;
    xv.z += (v.z - mu) * rs * wv.z;
    xv.w += (v.w - mu) * rs * wv.w;
    *(float4*)xp = xv;
}

// ---------------- FFN: act = gelu_exact(gate) * up ----------------
__global__ void gelu_mul(const float* __restrict__ f, float* __restrict__ a)
{
    long idx = (long)blockIdx.x * 256 + threadIdx.x;
    if (idx >= (long)BS * UU) return;
    long bs = idx / UU;
    int u = (int)(idx % UU);
    float g = f[bs * (2L*UU) + u];
    float p = f[bs * (2L*UU) + UU + u];
    a[idx] = 0.5f * g * (1.f + erff(g * 0.70710678118654752f)) * p;
}

// ---------------- host ----------------
static inline void gemm(const float* A, const float* B, float* C,
                        int M, int N, int K, int lda, int ldb, int ldc,
                        float alpha, const float* bias, int acc)
{
    dim3 grid(N / 128, M / 128);
    tgemm_nt<<<grid, 256>>>(A, B, C, M, N, K, lda, ldb, ldc, alpha, bias, acc);
}

extern "C" void kernel_launch(void* const* d_in, const int* in_sizes, int n_in,
                              void* d_out, int out_size)
{
    const int*   ids       = (const int*)  d_in[0];
    const float* emb       = (const float*)d_in[1];
    const float* m_ln_w    = (const float*)d_in[2];
    const float* m_up_w    = (const float*)d_in[3];
    const float* m_conv_w  = (const float*)d_in[4];
    const float* m_conv_b  = (const float*)d_in[5];
    const float* m_q_w     = (const float*)d_in[6];
    const float* m_k_w     = (const float*)d_in[7];
    const float* m_v_w     = (const float*)d_in[8];
    const float* m_ig_w    = (const float*)d_in[9];
    const float* m_ig_b    = (const float*)d_in[10];
    const float* m_fg_w    = (const float*)d_in[11];
    const float* m_fg_b    = (const float*)d_in[12];
    const float* m_skip    = (const float*)d_in[13];
    const float* m_on_w    = (const float*)d_in[14];
    const float* m_down_w  = (const float*)d_in[15];
    const float* s_ln_w    = (const float*)d_in[16];
    const float* s_conv_w  = (const float*)d_in[17];
    const float* s_conv_b  = (const float*)d_in[18];
    const float* s_iw      = (const float*)d_in[19];
    const float* s_fw      = (const float*)d_in[20];
    const float* s_zw      = (const float*)d_in[21];
    const float* s_ow      = (const float*)d_in[22];
    const float* s_rk      = (const float*)d_in[23];
    const float* s_rb      = (const float*)d_in[24];
    const float* s_gn_w    = (const float*)d_in[25];
    const float* s_ln2_w   = (const float*)d_in[26];
    const float* s_ffn_up  = (const float*)d_in[27];
    const float* s_ffn_dn  = (const float*)d_in[28];
    const float* post_ln_w = (const float*)d_in[29];
    const float* head_w    = (const float*)d_in[30];
    const float* head_b    = (const float*)d_in[31];
    float* out = (float*)d_out;

    float* pool = nullptr;
    cudaGetSymbolAddress((void**)&pool, g_pool);
    float* X   = pool + O_X;   float* XN  = pool + O_XN;  float* XC  = pool + O_XC;
    float* UP  = pool + O_UP;  float* XA  = pool + O_XA;
    float* Q_  = pool + O_Q;   float* K_  = pool + O_K;   float* V_  = pool + O_V;
    float* SC  = pool + O_SC;  float* HB  = pool + O_HB;  float* HM  = pool + O_HM;
    float* PRE = pool + O_PRE; float* YS  = pool + O_YS;
    float* FFN = pool + O_FFN; float* ACT = pool + O_ACT;
    float* IG  = pool + O_IG;  float* FG  = pool + O_FG;
    float* Aa  = pool + O_A;   float* RM  = pool + O_RM;
    float* EN  = pool + O_EN;  float* RN  = pool + O_RN;

    cudaFuncSetAttribute(slstm_scan_cl,
                         cudaFuncAttributeMaxDynamicSharedMemorySize,
                         SCAN_SMEM_FLOATS * 4);

    embed_k<<<BS, 256>>>(ids, emb, X);

    int mi = 0;
    for (int blk = 0; blk < 4; blk++) {
        if (blk == 1) {
            // ---------------- sLSTM block ----------------
            layernorm_k<<<BS, 256>>>(X, s_ln_w, XN);
            conv_silu<<<(BS * DD) / 256, 256>>>(XN, s_conv_w, s_conv_b, XC, DD, DD);
            sgemm_gates<<<dim3(2, 32, 16), 256>>>(XC, XN, s_iw, s_fw, s_zw, s_ow, PRE);
            slstm_scan_cl<<<128, 128, SCAN_SMEM_FLOATS * 4>>>(PRE, s_rk, s_rb, YS);
            slstm_gnorm<<<dim3(BS, 4), 64>>>(YS, s_gn_w, X);
            layernorm_k<<<BS, 256>>>(X, s_ln2_w, XN);
            gemm(XN, s_ffn_up, FFN, BS, 2*UU, DD, DD, DD, 2*UU, 1.f, nullptr, 0);
            gelu_mul<<<(int)(((long)BS*UU + 255) / 256), 256>>>(FFN, ACT);
            gemm(ACT, s_ffn_dn, X, BS, DD, UU, UU, UU, DD, 1.f, nullptr, 1);
        } else {
            // ---------------- mLSTM block ----------------
            layernorm_k<<<BS, 256>>>(X, m_ln_w + (long)mi*DD, XN);
            gemm(XN, m_up_w + (long)mi*4096*DD, UP, BS, 4096, DD, DD, DD, 4096,
                 1.f, nullptr, 0);
            conv_silu<<<(int)(((long)BS*II) / 256), 256>>>(
                UP, m_conv_w + (long)mi*II*4, m_conv_b + (long)mi*II, XA, II, 4096);
            headwise_qkv<<<(int)(((long)BS*512) / 256), 256>>>(
                XA, UP, m_q_w + (long)mi*512*16, m_k_w + (long)mi*512*16,
                m_v_w + (long)mi*512*16, Q_, K_, V_);
            igfg_k<<<BS, 256>>>(Q_, K_, V_,
                m_ig_w + (long)mi*4*6144, m_ig_b + (long)mi*4,
                m_fg_w + (long)mi*4*6144, m_fg_b + (long)mi*4, IG, FG);
            mlstm_prep<<<16, 256>>>(IG, FG, Aa, RM, EN);
            attn_qk<<<dim3(8, 8, 16), 256>>>(Q_, K_, SC, Aa, RM);
            attn_rowsum<<<dim3(SS, 16), 256>>>(SC, EN, RN);
            attn_av<<<dim3(4, 8, 16), 256>>>(SC, V_, RN, HB);
            mh_mix<<<dim3(BS, 4), 128>>>(HB, m_on_w + (long)mi*II,
                m_skip + (long)mi*II, XA, UP, HM);
            gemm(HM, m_down_w + (long)mi*DD*II, X, BS, DD, II, II, II, DD,
                 1.f, nullptr, 1);
            mi++;
        }
    }

    layernorm_k<<<BS, 256>>>(X, post_ln_w, XN);
    gemm(XN, head_w, out, BS, 256, DD, DD, DD, 256, 1.f, head_b, 0);
}

// round 8
// speedup vs baseline: 5.4862x; 1.0004x over previous
#include <cuda_runtime.h>
#include <cuda_bf16.h>
#include <math.h>
#include <stdint.h>

#define BB 4
#define SS 1024
#define DD 1024
#define II 2048
#define BS 4096
#define DHM 512
#define DHS 256
#define UU 1344

constexpr long SZ_X   = (long)BS * DD;
constexpr long SZ_UP  = (long)BS * 2 * II;
constexpr long SZ_I   = (long)BS * II;
constexpr long SZ_SC  = 16L * SS * SS;
constexpr long SZ_HB  = 16L * SS * DHM;
constexpr long SZ_PRE = 16L * BS * DHS;
constexpr long SZ_YS  = 16L * SS * DHS;
constexpr long SZ_FFN = (long)BS * 2 * UU;
constexpr long SZ_ACT = (long)BS * UU;
constexpr long SZ_V16 = 16L * SS;

constexpr long O_X   = 0;
constexpr long O_XN  = O_X   + SZ_X;
constexpr long O_XC  = O_XN  + SZ_X;
constexpr long O_UP  = O_XC  + SZ_X;
constexpr long O_XA  = O_UP  + SZ_UP;
constexpr long O_Q   = O_XA  + SZ_I;
constexpr long O_K   = O_Q   + SZ_I;
constexpr long O_V   = O_K   + SZ_I;
constexpr long O_SC  = O_V   + SZ_I;
constexpr long O_HB  = O_SC  + SZ_SC;
constexpr long O_HM  = O_HB  + SZ_HB;
constexpr long O_PRE = O_HM  + SZ_I;
constexpr long O_YS  = O_PRE + SZ_PRE;
constexpr long O_FFN = O_YS  + SZ_YS;
constexpr long O_ACT = O_FFN + SZ_FFN;
constexpr long O_IG  = O_ACT + SZ_ACT;
constexpr long O_FG  = O_IG  + SZ_V16;
constexpr long O_A   = O_FG  + SZ_V16;
constexpr long O_RM  = O_A   + SZ_V16;
constexpr long O_EN  = O_RM  + SZ_V16;
constexpr long O_RNS = O_EN  + SZ_V16;
constexpr long POOL_SZ = O_RNS + SZ_V16;

__device__ float g_pool[POOL_SZ];

__device__ __forceinline__ float warpSum(float v) {
    #pragma unroll
    for (int o = 16; o > 0; o >>= 1) v += __shfl_down_sync(0xffffffffu, v, o);
    return v;
}

// ---------------- tf32 mma helpers ----------------
__device__ __forceinline__ uint32_t f2tf32(float f) {
    uint32_t r;
    asm("cvt.rna.tf32.f32 %0, %1;" : "=r"(r) : "f"(f));
    return r;
}
__device__ __forceinline__ void mma_tf32(float* c, const uint32_t* a, const uint32_t* b) {
    asm volatile(
        "mma.sync.aligned.m16n8k8.row.col.f32.tf32.tf32.f32 "
        "{%0,%1,%2,%3}, {%4,%5,%6,%7}, {%8,%9}, {%0,%1,%2,%3};"
        : "+f"(c[0]), "+f"(c[1]), "+f"(c[2]), "+f"(c[3])
        : "r"(a[0]), "r"(a[1]), "r"(a[2]), "r"(a[3]), "r"(b[0]), "r"(b[1]));
}
#define SPAD 36
#define STAGE_FLOATS (128 * SPAD)
#define TG_SMEM (4 * STAGE_FLOATS * 4)   // 2 stages x (A+B) in bytes

__device__ __forceinline__ void cp16(uint32_t dst, const float* src) {
    asm volatile("cp.async.cg.shared.global [%0], [%1], 16;" :: "r"(dst), "l"(src));
}
__device__ __forceinline__ void cp_commit() {
    asm volatile("cp.async.commit_group;" ::: "memory");
}
__device__ __forceinline__ void cp_wait1() {
    asm volatile("cp.async.wait_group 1;" ::: "memory");
}
__device__ __forceinline__ void cp_wait0() {
    asm volatile("cp.async.wait_group 0;" ::: "memory");
}

// ---------------- embedding gather ----------------
__global__ void embed_k(const int* __restrict__ ids, const float* __restrict__ emb,
                        float* __restrict__ x)
{
    int bs = blockIdx.x;
    long id = ids[bs];
    ((float4*)(x + (long)bs * DD))[threadIdx.x] =
        ((const float4*)(emb + id * DD))[threadIdx.x];
}

// ---------------- LayerNorm width 1024, 256 thr/row ----------------
__global__ void layernorm_k(const float* __restrict__ x, const float* __restrict__ w,
                            float* __restrict__ y)
{
    long row = blockIdx.x;
    int tid = threadIdx.x;
    float4 v = ((const float4*)(x + row * DD))[tid];
    float s = v.x + v.y + v.z + v.w;
    float ss = v.x*v.x + v.y*v.y + v.z*v.z + v.w*v.w;
    __shared__ float sb[8], sb2[8];
    __shared__ float mu_s, rs_s;
    s = warpSum(s); ss = warpSum(ss);
    if ((tid & 31) == 0) { sb[tid >> 5] = s; sb2[tid >> 5] = ss; }
    __syncthreads();
    if (tid == 0) {
        float t = 0.f, t2 = 0.f;
        #pragma unroll
        for (int i = 0; i < 8; i++) { t += sb[i]; t2 += sb2[i]; }
        float mu = t * (1.f / DD);
        mu_s = mu;
        rs_s = rsqrtf(t2 * (1.f / DD) - mu * mu + 1e-5f);
    }
    __syncthreads();
    float mu = mu_s, rs = rs_s;
    float4 wv = ((const float4*)w)[tid];
    float4 o;
    o.x = (v.x - mu) * rs * wv.x;  o.y = (v.y - mu) * rs * wv.y;
    o.z = (v.z - mu) * rs * wv.z;  o.w = (v.w - mu) * rs * wv.w;
    ((float4*)(y + row * DD))[tid] = o;
}

// ============================================================================
// tf32 GEMM NT, cp.async double-buffered. C = alpha*A@B^T [+bias][+=C]
// ============================================================================
__global__ void __launch_bounds__(256, 2) tgemm_nt(
    const float* __restrict__ A, const float* __restrict__ B, float* __restrict__ C,
    int M, int N, int K, int lda, int ldb, int ldc,
    float alpha, const float* __restrict__ bias, int acc)
{
    extern __shared__ float smem[];
    float* As = smem;                      // [2][STAGE_FLOATS]
    float* Bs = smem + 2 * STAGE_FLOATS;
    const int tid = threadIdx.x;
    const int lane = tid & 31, warp = tid >> 5;
    const int wm = warp & 3, wn = warp >> 2;
    const int g = lane >> 2, t = lane & 3;
    const int lr = tid >> 1, lc = (tid & 1) * 16;
    const float* Ag = A + (long)(blockIdx.y * 128 + lr) * lda + lc;
    const float* Bg = B + (long)(blockIdx.x * 128 + lr) * ldb + lc;
    const uint32_t sA = (uint32_t)__cvta_generic_to_shared(As + lr * SPAD + lc);
    const uint32_t sB = (uint32_t)__cvta_generic_to_shared(Bs + lr * SPAD + lc);
    const uint32_t stageB = STAGE_FLOATS * 4;

    float c[16][4];
    #pragma unroll
    for (int i = 0; i < 16; i++)
        #pragma unroll
        for (int j = 0; j < 4; j++) c[i][j] = 0.f;

    // prologue: stage 0
    #pragma unroll
    for (int i = 0; i < 4; i++) {
        cp16(sA + i*16, Ag + i*4);
        cp16(sB + i*16, Bg + i*4);
    }
    cp_commit();

    const int nk = K >> 5;
    for (int kt = 0; kt < nk; kt++) {
        if (kt + 1 < nk) {
            const int k0 = (kt + 1) << 5;
            const uint32_t so = ((kt + 1) & 1) * stageB;
            #pragma unroll
            for (int i = 0; i < 4; i++) {
                cp16(sA + so + i*16, Ag + k0 + i*4);
                cp16(sB + so + i*16, Bg + k0 + i*4);
            }
            cp_commit();
            cp_wait1();
        } else {
            cp_wait0();
        }
        __syncthreads();
        const float* Ab = As + (kt & 1) * STAGE_FLOATS;
        const float* Bb = Bs + (kt & 1) * STAGE_FLOATS;
        #pragma unroll
        for (int kk = 0; kk < 4; kk++) {
            const int ks = kk * 8;
            uint32_t af[2][4], bf[8][2];
            #pragma unroll
            for (int mt = 0; mt < 2; mt++) {
                int r0 = wm*32 + mt*16 + g;
                af[mt][0] = __float_as_uint(Ab[r0 * SPAD + ks + t]);
                af[mt][1] = __float_as_uint(Ab[(r0+8) * SPAD + ks + t]);
                af[mt][2] = __float_as_uint(Ab[r0 * SPAD + ks + t + 4]);
                af[mt][3] = __float_as_uint(Ab[(r0+8) * SPAD + ks + t + 4]);
            }
            #pragma unroll
            for (int nt = 0; nt < 8; nt++) {
                int c0 = wn*64 + nt*8 + g;
                bf[nt][0] = __float_as_uint(Bb[c0 * SPAD + ks + t]);
                bf[nt][1] = __float_as_uint(Bb[c0 * SPAD + ks + t + 4]);
            }
            #pragma unroll
            for (int mt = 0; mt < 2; mt++)
                #pragma unroll
                for (int nt = 0; nt < 8; nt++)
                    mma_tf32(c[mt*8 + nt], af[mt], bf[nt]);
        }
        __syncthreads();
    }
    #pragma unroll
    for (int mt = 0; mt < 2; mt++) {
        int row0 = blockIdx.y*128 + wm*32 + mt*16 + g;
        #pragma unroll
        for (int nt = 0; nt < 8; nt++) {
            int col0 = blockIdx.x*128 + wn*64 + nt*8 + 2*t;
            float* v = c[mt*8 + nt];
            float b0 = bias ? bias[col0] : 0.f, b1 = bias ? bias[col0+1] : 0.f;
            float* C0 = C + (long)row0 * ldc + col0;
            float* C1 = C + (long)(row0+8) * ldc + col0;
            float o0 = v[0]*alpha + b0, o1 = v[1]*alpha + b1;
            float o2 = v[2]*alpha + b0, o3 = v[3]*alpha + b1;
            if (acc) { o0 += C0[0]; o1 += C0[1]; o2 += C1[0]; o3 += C1[1]; }
            C0[0] = o0; C0[1] = o1; C1[0] = o2; C1[1] = o3;
        }
    }
}

// ============================================================================
// tf32 attention scores, cp.async pipelined, lower-triangle-only grid,
// fused row-sum atomics. SC = (q.k/sqrt(dh))*exp(a[t]-rm[s]).
// ============================================================================
__global__ void __launch_bounds__(256, 2) attn_qk(
    const float* __restrict__ Qb, const float* __restrict__ Kb,
    float* __restrict__ SC, const float* __restrict__ a_,
    const float* __restrict__ rm_, float* __restrict__ rns)
{
    const int z = blockIdx.z;
    const int b = z >> 2, h = z & 3;
    int by = 0;
    {
        int tix = blockIdx.x;
        while ((by + 1) * (by + 2) / 2 <= tix) by++;
        tix -= by * (by + 1) / 2;
        // tix is bx
        #define BX tix
        float* Cb = SC + (long)z * SS * SS;
        const float* A = Qb + (long)b * SS * II + h * DHM;
        const float* B = Kb + (long)b * SS * II + h * DHM;
        extern __shared__ float smem[];
        float* As = smem;
        float* Bs = smem + 2 * STAGE_FLOATS;
        const int tid = threadIdx.x;
        const int lane = tid & 31, warp = tid >> 5;
        const int wm = warp & 3, wn = warp >> 2;
        const int g = lane >> 2, t = lane & 3;
        const int lr = tid >> 1, lc = (tid & 1) * 16;
        const float* Ag = A + (long)(by*128 + lr) * II + lc;
        const float* Bg = B + (long)(BX*128 + lr) * II + lc;
        const uint32_t sA = (uint32_t)__cvta_generic_to_shared(As + lr * SPAD + lc);
        const uint32_t sB = (uint32_t)__cvta_generic_to_shared(Bs + lr * SPAD + lc);
        const uint32_t stageB = STAGE_FLOATS * 4;

        float c[16][4];
        #pragma unroll
        for (int i = 0; i < 16; i++)
            #pragma unroll
            for (int j = 0; j < 4; j++) c[i][j] = 0.f;

        #pragma unroll
        for (int i = 0; i < 4; i++) {
            cp16(sA + i*16, Ag + i*4);
            cp16(sB + i*16, Bg + i*4);
        }
        cp_commit();

        const int nk = DHM >> 5;
        for (int kt = 0; kt < nk; kt++) {
            if (kt + 1 < nk) {
                const int k0 = (kt + 1) << 5;
                const uint32_t so = ((kt + 1) & 1) * stageB;
                #pragma unroll
                for (int i = 0; i < 4; i++) {
                    cp16(sA + so + i*16, Ag + k0 + i*4);
                    cp16(sB + so + i*16, Bg + k0 + i*4);
                }
                cp_commit();
                cp_wait1();
            } else {
                cp_wait0();
            }
            __syncthreads();
            const float* Ab = As + (kt & 1) * STAGE_FLOATS;
            const float* Bb = Bs + (kt & 1) * STAGE_FLOATS;
            #pragma unroll
            for (int kk = 0; kk < 4; kk++) {
                const int ks = kk * 8;
                uint32_t af[2][4], bf[8][2];
                #pragma unroll
                for (int mt = 0; mt < 2; mt++) {
                    int r0 = wm*32 + mt*16 + g;
                    af[mt][0] = __float_as_uint(Ab[r0 * SPAD + ks + t]);
                    af[mt][1] = __float_as_uint(Ab[(r0+8) * SPAD + ks + t]);
                    af[mt][2] = __float_as_uint(Ab[r0 * SPAD + ks + t + 4]);
                    af[mt][3] = __float_as_uint(Ab[(r0+8) * SPAD + ks + t + 4]);
                }
                #pragma unroll
                for (int nt = 0; nt < 8; nt++) {
                    int c0 = wn*64 + nt*8 + g;
                    bf[nt][0] = __float_as_uint(Bb[c0 * SPAD + ks + t]);
                    bf[nt][1] = __float_as_uint(Bb[c0 * SPAD + ks + t + 4]);
                }
                #pragma unroll
                for (int mt = 0; mt < 2; mt++)
                    #pragma unroll
                    for (int nt = 0; nt < 8; nt++)
                        mma_tf32(c[mt*8 + nt], af[mt], bf[nt]);
            }
            __syncthreads();
        }
        const float* az = a_ + (long)z * SS;
        const float* rz = rm_ + (long)z * SS;
        const float alpha = 0.04419417382415922f;  // 1/sqrt(512)
        float rsum[2][2] = {{0.f, 0.f}, {0.f, 0.f}};
        #pragma unroll
        for (int mt = 0; mt < 2; mt++) {
            int row0 = by*128 + wm*32 + mt*16 + g;
            int row1 = row0 + 8;
            float rm0 = rz[row0], rm1 = rz[row1];
            #pragma unroll
            for (int nt = 0; nt < 8; nt++) {
                int col0 = BX*128 + wn*64 + nt*8 + 2*t;
                float av0 = az[col0], av1 = az[col0+1];
                float* v = c[mt*8 + nt];
                float o00 = (col0   <= row0) ? v[0]*alpha*__expf(av0 - rm0) : 0.f;
                float o01 = (col0+1 <= row0) ? v[1]*alpha*__expf(av1 - rm0) : 0.f;
                float o10 = (col0   <= row1) ? v[2]*alpha*__expf(av0 - rm1) : 0.f;
                float o11 = (col0+1 <= row1) ? v[3]*alpha*__expf(av1 - rm1) : 0.f;
                float* C0 = Cb + (long)row0 * SS + col0;
                float* C1 = Cb + (long)row1 * SS + col0;
                C0[0] = o00; C0[1] = o01;
                C1[0] = o10; C1[1] = o11;
                rsum[mt][0] += o00 + o01;
                rsum[mt][1] += o10 + o11;
            }
        }
        // reduce across the 4 t-lanes of each g-group, atomically accumulate
        #pragma unroll
        for (int mt = 0; mt < 2; mt++) {
            #pragma unroll
            for (int rr = 0; rr < 2; rr++) {
                float v = rsum[mt][rr];
                v += __shfl_xor_sync(0xffffffffu, v, 1);
                v += __shfl_xor_sync(0xffffffffu, v, 2);
                if (t == 0) {
                    int row = by*128 + wm*32 + mt*16 + g + rr*8;
                    atomicAdd(&rns[(long)z * SS + row], v);
                }
            }
        }
        #undef BX
    }
}

// ============================================================================
// tf32 attention value GEMM (NN), K capped at diagonal, rn computed inline.
// ============================================================================
__global__ void __launch_bounds__(256, 2) attn_av(
    const float* __restrict__ SC, const float* __restrict__ Vb,
    const float* __restrict__ rns, const float* __restrict__ en,
    float* __restrict__ H)
{
    const int z = blockIdx.z;
    const int b = z >> 2, h = z & 3;
    const int bx = blockIdx.x, by = blockIdx.y;
    const float* A = SC + (long)z * SS * SS;
    const float* B = Vb + (long)b * SS * II + h * DHM;
    float* Cb = H + (long)z * SS * DHM;
    const int kend = (by + 1) * 128;
    __shared__ float As[128 * SPAD];
    __shared__ float Bs[128 * SPAD];
    const int tid = threadIdx.x;
    const int lane = tid & 31, warp = tid >> 5;
    const int wm = warp & 3, wn = warp >> 2;
    const int g = lane >> 2, t = lane & 3;
    const int lr = tid >> 1, lc = (tid & 1) * 16;
    const float* Ag = A + (long)(by*128 + lr) * SS + lc;
    const int bkr = tid >> 3;
    const int bc4 = tid & 7;
    const float* Bg = B + (long)bkr * II + bx*128;

    float c[16][4];
    #pragma unroll
    for (int i = 0; i < 16; i++)
        #pragma unroll
        for (int j = 0; j < 4; j++) c[i][j] = 0.f;

    float4 a4[4], b4[4];
    #pragma unroll
    for (int i = 0; i < 4; i++) {
        a4[i] = *(const float4*)(Ag + i*4);
        b4[i] = *(const float4*)(Bg + (bc4 + i*8) * 4);
    }
    const int nk = kend >> 5;
    for (int kt = 0; kt < nk; kt++) {
        __syncthreads();
        #pragma unroll
        for (int i = 0; i < 4; i++) {
            *(float4*)&As[lr * SPAD + lc + i*4] = a4[i];
            int coln = (bc4 + i*8) * 4;
            Bs[(coln+0) * SPAD + bkr] = b4[i].x;
            Bs[(coln+1) * SPAD + bkr] = b4[i].y;
            Bs[(coln+2) * SPAD + bkr] = b4[i].z;
            Bs[(coln+3) * SPAD + bkr] = b4[i].w;
        }
        __syncthreads();
        if (kt + 1 < nk) {
            const int k0 = (kt + 1) << 5;
            #pragma unroll
            for (int i = 0; i < 4; i++) {
                a4[i] = *(const float4*)(Ag + k0 + i*4);
                b4[i] = *(const float4*)(Bg + (long)k0 * II + (bc4 + i*8) * 4);
            }
        }
        #pragma unroll
        for (int kk = 0; kk < 4; kk++) {
            const int ks = kk * 8;
            uint32_t af[2][4], bf[8][2];
            #pragma unroll
            for (int mt = 0; mt < 2; mt++) {
                int r0 = wm*32 + mt*16 + g;
                af[mt][0] = __float_as_uint(As[r0 * SPAD + ks + t]);
                af[mt][1] = __float_as_uint(As[(r0+8) * SPAD + ks + t]);
                af[mt][2] = __float_as_uint(As[r0 * SPAD + ks + t + 4]);
                af[mt][3] = __float_as_uint(As[(r0+8) * SPAD + ks + t + 4]);
            }
            #pragma unroll
            for (int nt = 0; nt < 8; nt++) {
                int c0 = wn*64 + nt*8 + g;
                bf[nt][0] = __float_as_uint(Bs[c0 * SPAD + ks + t]);
                bf[nt][1] = __float_as_uint(Bs[c0 * SPAD + ks + t + 4]);
            }
            #pragma unroll
            for (int mt = 0; mt < 2; mt++)
                #pragma unroll
                for (int nt = 0; nt < 8; nt++)
                    mma_tf32(c[mt*8 + nt], af[mt], bf[nt]);
        }
    }
    const float* rz = rns + (long)z * SS;
    const float* ez = en + (long)z * SS;
    #pragma unroll
    for (int mt = 0; mt < 2; mt++) {
        int row0 = by*128 + wm*32 + mt*16 + g;
        int row1 = row0 + 8;
        float rn0 = 1.f / (fmaxf(fabsf(rz[row0]), ez[row0]) + 1e-6f);
        float rn1 = 1.f / (fmaxf(fabsf(rz[row1]), ez[row1]) + 1e-6f);
        #pragma unroll
        for (int nt = 0; nt < 8; nt++) {
            int col0 = bx*128 + wn*64 + nt*8 + 2*t;
            float* v = c[mt*8 + nt];
            float* C0 = Cb + (long)row0 * DHM + col0;
            float* C1 = Cb + (long)row1 * DHM + col0;
            C0[0] = v[0]*rn0; C0[1] = v[1]*rn0;
            C1[0] = v[2]*rn1; C1[1] = v[3]*rn1;
        }
    }
}

// ---------------- batched sLSTM gate GEMMs (fp32, small) ----------------
__global__ void __launch_bounds__(256, 2) sgemm_gates(
    const float* __restrict__ XC, const float* __restrict__ XN,
    const float* __restrict__ iw, const float* __restrict__ fw,
    const float* __restrict__ zw, const float* __restrict__ ow,
    float* __restrict__ PRE)
{
    const int zz = blockIdx.z;
    const int g = zz >> 2, h = zz & 3;
    const float* A = ((g < 2) ? XC : XN) + h * 256;
    const float* W = (g == 0) ? iw : (g == 1) ? fw : (g == 2) ? zw : ow;
    const float* B = W + (long)h * 65536;
    float* C = PRE + (long)zz * BS * DHS;
    __shared__ float As[8][128];
    __shared__ float Bs[8][128];
    const int tid = threadIdx.x;
    const int lrow = tid >> 1;
    const int lcol = (tid & 1) << 2;
    const float* Ag = A + (long)(blockIdx.y * 128 + lrow) * DD + lcol;
    const float* Bg = B + (long)(blockIdx.x * 128 + lrow) * 256 + lcol;
    const int ty = tid >> 4, tx = tid & 15;
    float accv[8][8];
    #pragma unroll
    for (int i = 0; i < 8; i++)
        #pragma unroll
        for (int j = 0; j < 8; j++) accv[i][j] = 0.f;
    for (int k0 = 0; k0 < 256; k0 += 8) {
        float4 av = *(const float4*)(Ag + k0);
        float4 bv = *(const float4*)(Bg + k0);
        __syncthreads();
        As[lcol+0][lrow] = av.x; As[lcol+1][lrow] = av.y;
        As[lcol+2][lrow] = av.z; As[lcol+3][lrow] = av.w;
        Bs[lcol+0][lrow] = bv.x; Bs[lcol+1][lrow] = bv.y;
        Bs[lcol+2][lrow] = bv.z; Bs[lcol+3][lrow] = bv.w;
        __syncthreads();
        #pragma unroll
        for (int kk = 0; kk < 8; kk++) {
            float ar[8], br[8];
            #pragma unroll
            for (int i = 0; i < 8; i++) ar[i] = As[kk][ty*8 + i];
            #pragma unroll
            for (int j = 0; j < 8; j++) br[j] = Bs[kk][tx*8 + j];
            #pragma unroll
            for (int i = 0; i < 8; i++)
                #pragma unroll
                for (int j = 0; j < 8; j++)
                    accv[i][j] += ar[i] * br[j];
        }
    }
    #pragma unroll
    for (int i = 0; i < 8; i++) {
        long row = blockIdx.y * 128 + ty*8 + i;
        float* Cr = C + row * 256L + blockIdx.x * 128 + tx*8;
        #pragma unroll
        for (int j = 0; j < 8; j++)
            Cr[j] = accv[i][j];
    }
}

// ---------------- causal depthwise conv (K=4) + SiLU, compile-time C ----------------
template<int C, int LDIN>
__global__ void conv_silu_t(const float* __restrict__ in, const float* __restrict__ w,
                            const float* __restrict__ bias, float* __restrict__ out)
{
    long idx = (long)blockIdx.x * 256 + threadIdx.x;
    if (idx >= (long)BS * C) return;
    int c = (int)(idx & (C - 1));
    long bs = idx / C;
    int s = (int)(bs & (SS - 1));
    float acc = bias[c];
    #pragma unroll
    for (int kk = 0; kk < 4; kk++) {
        int sp = s + kk - 3;
        if (sp >= 0) acc += in[(bs + kk - 3) * (long)LDIN + c] * w[c*4 + kk];
    }
    out[bs * (long)C + c] = acc / (1.f + __expf(-acc));
}

// ---------------- headwise 4x4 q,k from xa; v from xm(strided) ----------------
__global__ void headwise_qkv(const float* __restrict__ xa, const float* __restrict__ xm,
                             const float* __restrict__ qw, const float* __restrict__ kw,
                             const float* __restrict__ vw,
                             float* __restrict__ q, float* __restrict__ k,
                             float* __restrict__ v)
{
    long idx = (long)blockIdx.x * 256 + threadIdx.x;
    if (idx >= (long)BS * 512) return;
    int nb = (int)(idx & 511);
    long bs = idx >> 9;
    float4 xav = *(const float4*)(xa + bs * II + nb*4);
    float4 xmv = *(const float4*)(xm + bs * (2L*II) + nb*4);
    float xi[4] = {xav.x, xav.y, xav.z, xav.w};
    float xmi[4] = {xmv.x, xmv.y, xmv.z, xmv.w};
    float qo[4], ko[4], vo[4];
    #pragma unroll
    for (int o = 0; o < 4; o++) {
        float aq = 0.f, ak = 0.f, av = 0.f;
        #pragma unroll
        for (int i = 0; i < 4; i++) {
            aq += xi[i]  * qw[nb*16 + o*4 + i];
            ak += xi[i]  * kw[nb*16 + o*4 + i];
            av += xmi[i] * vw[nb*16 + o*4 + i];
        }
        qo[o] = aq; ko[o] = ak; vo[o] = av;
    }
    *(float4*)(q + bs * II + nb*4) = make_float4(qo[0], qo[1], qo[2], qo[3]);
    *(float4*)(k + bs * II + nb*4) = make_float4(ko[0], ko[1], ko[2], ko[3]);
    *(float4*)(v + bs * II + nb*4) = make_float4(vo[0], vo[1], vo[2], vo[3]);
}

// ---------------- ig/fg gate projections (float4) ----------------
__global__ void igfg_k(const float* __restrict__ q, const float* __restrict__ k,
                       const float* __restrict__ v,
                       const float* __restrict__ igw, const float* __restrict__ igb,
                       const float* __restrict__ fgw, const float* __restrict__ fgb,
                       float* __restrict__ ig, float* __restrict__ fg)
{
    long bs = blockIdx.x;
    int b = (int)(bs >> 10);
    int s = (int)(bs & (SS - 1));
    __shared__ float sx[3 * II];
    __shared__ float rbuf[2][8];
    int tid = threadIdx.x;
    for (int i = tid; i < II / 4; i += 256) {
        ((float4*)sx)[i]            = ((const float4*)(q + bs * II))[i];
        ((float4*)sx)[II/4 + i]     = ((const float4*)(k + bs * II))[i];
        ((float4*)sx)[II/2 + i]     = ((const float4*)(v + bs * II))[i];
    }
    __syncthreads();
    const float4* sx4 = (const float4*)sx;
    for (int h = 0; h < 4; h++) {
        const float4* iw4 = (const float4*)(igw + h * (3*II));
        const float4* fw4 = (const float4*)(fgw + h * (3*II));
        float pi = 0.f, pf = 0.f;
        for (int j = tid; j < (3*II)/4; j += 256) {
            float4 xv = sx4[j];
            float4 wi = iw4[j];
            float4 wf = fw4[j];
            pi += xv.x*wi.x + xv.y*wi.y + xv.z*wi.z + xv.w*wi.w;
            pf += xv.x*wf.x + xv.y*wf.y + xv.z*wf.z + xv.w*wf.w;
        }
        pi = warpSum(pi); pf = warpSum(pf);
        if ((tid & 31) == 0) { rbuf[0][tid >> 5] = pi; rbuf[1][tid >> 5] = pf; }
        __syncthreads();
        if (tid == 0) {
            float a = 0.f, bb = 0.f;
            #pragma unroll
            for (int w8 = 0; w8 < 8; w8++) { a += rbuf[0][w8]; bb += rbuf[1][w8]; }
            ig[(long)(b*4 + h) * SS + s] = a + igb[h];
            fg[(long)(b*4 + h) * SS + s] = bb + fgb[h];
        }
        __syncthreads();
    }
}

// ---------------- mLSTM decay prep (+ zero RNS) ----------------
__global__ void mlstm_prep(const float* __restrict__ ig, const float* __restrict__ fg,
                           float* __restrict__ a, float* __restrict__ rm,
                           float* __restrict__ en, float* __restrict__ rns)
{
    int z = blockIdx.x;
    int tid = threadIdx.x;  // 256
    __shared__ float slsig[SS], sig_s[SS];
    for (int i = tid; i < SS; i += 256) {
        float fv = fg[(long)z * SS + i];
        slsig[i] = fminf(fv, 0.f) - log1pf(__expf(-fabsf(fv)));
        sig_s[i] = ig[(long)z * SS + i];
        rns[(long)z * SS + i] = 0.f;
    }
    __syncthreads();
    if (tid == 0) {
        float cs = 0.f, run = -1e30f;
        for (int s = 0; s < SS; s++) {
            cs += slsig[s];
            float av = sig_s[s] - cs;
            run = fmaxf(run, av);
            a[(long)z * SS + s]  = av;
            rm[(long)z * SS + s] = run;
            en[(long)z * SS + s] = __expf(-(cs + run));
        }
    }
}

// ---------------- mh_norm(dh=512) + (h+skip*xa)*silu(z) ----------------
__global__ void mh_mix(const float* __restrict__ H, const float* __restrict__ onw,
                       const float* __restrict__ skip, const float* __restrict__ xa,
                       const float* __restrict__ up, float* __restrict__ hmix)
{
    int bs = blockIdx.x, h = blockIdx.y;
    int b = bs >> 10;
    int s = bs & (SS - 1);
    const float* hp = H + ((long)(b*4 + h) * SS + s) * DHM;
    int tid = threadIdx.x;  // 128
    float4 v = ((const float4*)hp)[tid];
    float sm = v.x + v.y + v.z + v.w;
    float sq = v.x*v.x + v.y*v.y + v.z*v.z + v.w*v.w;
    __shared__ float s1[4], s2[4];
    sm = warpSum(sm); sq = warpSum(sq);
    if ((tid & 31) == 0) { s1[tid >> 5] = sm; s2[tid >> 5] = sq; }
    __syncthreads();
    float tot  = s1[0] + s1[1] + s1[2] + s1[3];
    float tot2 = s2[0] + s2[1] + s2[2] + s2[3];
    float mu = tot * (1.f / DHM);
    float rs = rsqrtf(tot2 * (1.f / DHM) - mu * mu + 1e-5f);
    float4 wv  = ((const float4*)onw)[h*128 + tid];
    float4 sk  = ((const float4*)skip)[h*128 + tid];
    float4 xav = ((const float4*)(xa + (long)bs * II))[h*128 + tid];
    float4 zv  = ((const float4*)(up + (long)bs * (2L*II) + II))[h*128 + tid];
    float4 o;
    o.x = ((v.x - mu)*rs*wv.x + sk.x*xav.x) * (zv.x / (1.f + __expf(-zv.x)));
    o.y = ((v.y - mu)*rs*wv.y + sk.y*xav.y) * (zv.y / (1.f + __expf(-zv.y)));
    o.z = ((v.z - mu)*rs*wv.z + sk.z*xav.z) * (zv.z / (1.f + __expf(-zv.z)));
    o.w = ((v.w - mu)*rs*wv.w + sk.w*xav.w) * (zv.w / (1.f + __expf(-zv.w)));
    ((float4*)(hmix + (long)bs * II))[h*128 + tid] = o;
}

// ============================================================================
// Cluster-split sLSTM scan (unchanged from R5 win)
// ============================================================================
#define SCAN_SMEM_FLOATS (32768 + 256 + 512)

__device__ __forceinline__ uint32_t smem_addr_u32(const void* p) {
    return (uint32_t)__cvta_generic_to_shared(p);
}
__device__ __forceinline__ uint32_t mapa_u32(uint32_t addr, uint32_t rank) {
    uint32_t out;
    asm("mapa.shared::cluster.u32 %0, %1, %2;" : "=r"(out) : "r"(addr), "r"(rank));
    return out;
}
__device__ __forceinline__ void st_cluster_f32(uint32_t addr, float v) {
    asm volatile("st.shared::cluster.f32 [%0], %1;" :: "r"(addr), "f"(v) : "memory");
}
__device__ __forceinline__ void cluster_barrier() {
    asm volatile("barrier.cluster.arrive.aligned;" ::: "memory");
    asm volatile("barrier.cluster.wait.aligned;" ::: "memory");
}

__global__ void __launch_bounds__(128, 1) __cluster_dims__(8, 1, 1)
slstm_scan_cl(const float* __restrict__ pre, const float* __restrict__ rk,
              const float* __restrict__ rb, float* __restrict__ ys)
{
    extern __shared__ float sm[];
    float* W    = sm;
    float* sh_h = sm + 32768;
    float* sraw = sm + 32768 + 256;

    const int z = blockIdx.x >> 3;
    const int b = z >> 2, h = z & 3;
    uint32_t rank;
    asm("mov.u32 %0, %%cluster_ctarank;" : "=r"(rank));
    const int g  = rank >> 1;
    const int hf = rank & 1;
    const int tid = threadIdx.x;

    const float* rks = rk + ((long)h * 256 * 4 + g) * 256 + hf * 128;
    for (int idx = tid; idx < 32768; idx += 128) {
        int d = idx >> 7, el = idx & 127;
        W[idx] = rks[(long)d * 1024 + el];
    }
    for (int i = tid; i < 256; i += 128) sh_h[i] = 0.f;
    __syncthreads();

    const float rbv = rb[(h*4 + g) * DHS + hf*128 + tid];
    const float* pb = pre + ((long)(g*4 + h) * BS + (long)b * SS) * DHS + hf*128 + tid;
    float* yo = ys + (long)z * SS * DHS + hf*128 + tid;

    const uint32_t raw_dst = mapa_u32(smem_addr_u32(&sraw[g*128 + tid]), (uint32_t)hf);
    uint32_t hdst[8];
    #pragma unroll
    for (int r = 0; r < 8; r++)
        hdst[r] = mapa_u32(smem_addr_u32(&sh_h[hf*128 + tid]), (uint32_t)r);

    const bool is_act = (rank < 2);
    float c = 0.f, n = 0.f, m = 0.f;

    cluster_barrier();

    float pv = pb[0];
    for (int s = 0; s < SS; s++) {
        float a0 = 0.f, a1 = 0.f, a2 = 0.f, a3 = 0.f;
        const float* Wp = W + tid;
        #pragma unroll 8
        for (int d = 0; d < 256; d += 4) {
            float4 hv = *(const float4*)&sh_h[d];
            a0 += hv.x * Wp[(d+0) << 7];
            a1 += hv.y * Wp[(d+1) << 7];
            a2 += hv.z * Wp[(d+2) << 7];
            a3 += hv.w * Wp[(d+3) << 7];
        }
        float acc = pv + rbv + ((a0 + a1) + (a2 + a3));
        if (s + 1 < SS) pv = pb[(long)(s+1) * DHS];

        st_cluster_f32(raw_dst, acc);
        cluster_barrier();

        if (is_act) {
            float iraw = sraw[tid],       fraw = sraw[128 + tid];
            float zraw = sraw[256 + tid], oraw = sraw[384 + tid];
            float lf = m + fminf(fraw, 0.f) - log1pf(__expf(-fabsf(fraw)));
            float mn = fmaxf(iraw, lf);
            float ig_ = __expf(iraw - mn);
            float fg_ = __expf(lf - mn);
            c = fg_ * c + ig_ * tanhf(zraw);
            n = fg_ * n + ig_;
            m = mn;
            float hv = c / (n * (1.f + __expf(-oraw)));
            #pragma unroll
            for (int r = 0; r < 8; r++) st_cluster_f32(hdst[r], hv);
            yo[(long)s * DHS] = hv;
        }
        cluster_barrier();
    }
}

// ---------------- sLSTM group norm (256) + residual add ----------------
__global__ void slstm_gnorm(const float* __restrict__ ys, const float* __restrict__ gnw,
                            float* __restrict__ x)
{
    int bs = blockIdx.x, h = blockIdx.y;
    int b = bs >> 10, s = bs & (SS - 1);
    const float* yp = ys + ((long)(b*4 + h) * SS + s) * DHS;
    int tid = threadIdx.x;  // 64
    float4 v = ((const float4*)yp)[tid];
    float sm = v.x + v.y + v.z + v.w;
    float sq = v.x*v.x + v.y*v.y + v.z*v.z + v.w*v.w;
    __shared__ float s1[2], s2[2];
    sm = warpSum(sm); sq = warpSum(sq);
    if ((tid & 31) == 0) { s1[tid >> 5] = sm; s2[tid >> 5] = sq; }
    __syncthreads();
    float tot  = s1[0] + s1[1];
    float tot2 = s2[0] + s2[1];
    float mu = tot * (1.f / DHS);
    float rs = rsqrtf(tot2 * (1.f / DHS) - mu * mu + 1e-5f);
    float4 wv = ((const float4*)gnw)[h*64 + tid];
    float* xp = x + (long)bs * DD + h * DHS + tid * 4;
    float4 xv = *(float4*)xp;
    xv.x += (v.x - mu) * rs * wv.x;
    xv.y += (v.y - mu) * rs * wv.y;
    xv.z += (v.z - mu) * rs * wv.z;
    xv.w += (v.w - mu) * rs * wv.w;
    *(float4*)xp = xv;
}

// ---------------- FFN: act = gelu_exact(gate) * up ----------------
__global__ void gelu_mul(const float* __restrict__ f, float* __restrict__ a)
{
    long idx = (long)blockIdx.x * 256 + threadIdx.x;
    if (idx >= (long)BS * UU) return;
    long bs = idx / UU;
    int u = (int)(idx % UU);
    float g = f[bs * (2L*UU) + u];
    float p = f[bs * (2L*UU) + UU + u];
    a[idx] = 0.5f * g * (1.f + erff(g * 0.70710678118654752f)) * p;
}

// ---------------- host ----------------
static inline void gemm(const float* A, const float* B, float* C,
                        int M, int N, int K, int lda, int ldb, int ldc,
                        float alpha, const float* bias, int acc)
{
    dim3 grid(N / 128, M / 128);
    tgemm_nt<<<grid, 256, TG_SMEM>>>(A, B, C, M, N, K, lda, ldb, ldc, alpha, bias, acc);
}

extern "C" void kernel_launch(void* const* d_in, const int* in_sizes, int n_in,
                              void* d_out, int out_size)
{
    const int*   ids       = (const int*)  d_in[0];
    const float* emb       = (const float*)d_in[1];
    const float* m_ln_w    = (const float*)d_in[2];
    const float* m_up_w    = (const float*)d_in[3];
    const float* m_conv_w  = (const float*)d_in[4];
    const float* m_conv_b  = (const float*)d_in[5];
    const float* m_q_w     = (const float*)d_in[6];
    const float* m_k_w     = (const float*)d_in[7];
    const float* m_v_w     = (const float*)d_in[8];
    const float* m_ig_w    = (const float*)d_in[9];
    const float* m_ig_b    = (const float*)d_in[10];
    const float* m_fg_w    = (const float*)d_in[11];
    const float* m_fg_b    = (const float*)d_in[12];
    const float* m_skip    = (const float*)d_in[13];
    const float* m_on_w    = (const float*)d_in[14];
    const float* m_down_w  = (const float*)d_in[15];
    const float* s_ln_w    = (const float*)d_in[16];
    const float* s_conv_w  = (const float*)d_in[17];
    const float* s_conv_b  = (const float*)d_in[18];
    const float* s_iw      = (const float*)d_in[19];
    const float* s_fw      = (const float*)d_in[20];
    const float* s_zw      = (const float*)d_in[21];
    const float* s_ow      = (const float*)d_in[22];
    const float* s_rk      = (const float*)d_in[23];
    const float* s_rb      = (const float*)d_in[24];
    const float* s_gn_w    = (const float*)d_in[25];
    const float* s_ln2_w   = (const float*)d_in[26];
    const float* s_ffn_up  = (const float*)d_in[27];
    const float* s_ffn_dn  = (const float*)d_in[28];
    const float* post_ln_w = (const float*)d_in[29];
    const float* head_w    = (const float*)d_in[30];
    const float* head_b    = (const float*)d_in[31];
    float* out = (float*)d_out;

    float* pool = nullptr;
    cudaGetSymbolAddress((void**)&pool, g_pool);
    float* X   = pool + O_X;   float* XN  = pool + O_XN;  float* XC  = pool + O_XC;
    float* UP  = pool + O_UP;  float* XA  = pool + O_XA;
    float* Q_  = pool + O_Q;   float* K_  = pool + O_K;   float* V_  = pool + O_V;
    float* SC  = pool + O_SC;  float* HB  = pool + O_HB;  float* HM  = pool + O_HM;
    float* PRE = pool + O_PRE; float* YS  = pool + O_YS;
    float* FFN = pool + O_FFN; float* ACT = pool + O_ACT;
    float* IG  = pool + O_IG;  float* FG  = pool + O_FG;
    float* Aa  = pool + O_A;   float* RM  = pool + O_RM;
    float* EN  = pool + O_EN;  float* RNS = pool + O_RNS;

    cudaFuncSetAttribute(slstm_scan_cl,
                         cudaFuncAttributeMaxDynamicSharedMemorySize,
                         SCAN_SMEM_FLOATS * 4);
    cudaFuncSetAttribute(tgemm_nt,
                         cudaFuncAttributeMaxDynamicSharedMemorySize, TG_SMEM);
    cudaFuncSetAttribute(attn_qk,
                         cudaFuncAttributeMaxDynamicSharedMemorySize, TG_SMEM);

    embed_k<<<BS, 256>>>(ids, emb, X);

    int mi = 0;
    for (int blk = 0; blk < 4; blk++) {
        if (blk == 1) {
            // ---------------- sLSTM block ----------------
            layernorm_k<<<BS, 256>>>(X, s_ln_w, XN);
            conv_silu_t<DD, DD><<<(BS * DD) / 256, 256>>>(XN, s_conv_w, s_conv_b, XC);
            sgemm_gates<<<dim3(2, 32, 16), 256>>>(XC, XN, s_iw, s_fw, s_zw, s_ow, PRE);
            slstm_scan_cl<<<128, 128, SCAN_SMEM_FLOATS * 4>>>(PRE, s_rk, s_rb, YS);
            slstm_gnorm<<<dim3(BS, 4), 64>>>(YS, s_gn_w, X);
            layernorm_k<<<BS, 256>>>(X, s_ln2_w, XN);
            gemm(XN, s_ffn_up, FFN, BS, 2*UU, DD, DD, DD, 2*UU, 1.f, nullptr, 0);
            gelu_mul<<<(int)(((long)BS*UU + 255) / 256), 256>>>(FFN, ACT);
            gemm(ACT, s_ffn_dn, X, BS, DD, UU, UU, UU, DD, 1.f, nullptr, 1);
        } else {
            // ---------------- mLSTM block ----------------
            layernorm_k<<<BS, 256>>>(X, m_ln_w + (long)mi*DD, XN);
            gemm(XN, m_up_w + (long)mi*4096*DD, UP, BS, 4096, DD, DD, DD, 4096,
                 1.f, nullptr, 0);
            conv_silu_t<II, 4096><<<(int)(((long)BS*II) / 256), 256>>>(
                UP, m_conv_w + (long)mi*II*4, m_conv_b + (long)mi*II, XA);
            headwise_qkv<<<(int)(((long)BS*512) / 256), 256>>>(
                XA, UP, m_q_w + (long)mi*512*16, m_k_w + (long)mi*512*16,
                m_v_w + (long)mi*512*16, Q_, K_, V_);
            igfg_k<<<BS, 256>>>(Q_, K_, V_,
                m_ig_w + (long)mi*4*6144, m_ig_b + (long)mi*4,
                m_fg_w + (long)mi*4*6144, m_fg_b + (long)mi*4, IG, FG);
            mlstm_prep<<<16, 256>>>(IG, FG, Aa, RM, EN, RNS);
            attn_qk<<<dim3(36, 1, 16), 256, TG_SMEM>>>(Q_, K_, SC, Aa, RM, RNS);
            attn_av<<<dim3(4, 8, 16), 256>>>(SC, V_, RNS, EN, HB);
            mh_mix<<<dim3(BS, 4), 128>>>(HB, m_on_w + (long)mi*II,
                m_skip + (long)mi*II, XA, UP, HM);
            gemm(HM, m_down_w + (long)mi*DD*II, X, BS, DD, II, II, II, DD,
                 1.f, nullptr, 1);
            mi++;
        }
    }

    layernorm_k<<<BS, 256>>>(X, post_ln_w, XN);
    gemm(XN, head_w, out, BS, 256, DD, DD, DD, 256, 1.f, head_b, 0);
}

// round 9
// speedup vs baseline: 5.9631x; 1.0869x over previous
#include <cuda_runtime.h>
#include <cuda_bf16.h>
#include <math.h>
#include <stdint.h>

#define BB 4
#define SS 1024
#define DD 1024
#define II 2048
#define BS 4096
#define DHM 512
#define DHS 256
#define UU 1344

constexpr long SZ_X   = (long)BS * DD;
constexpr long SZ_UP  = (long)BS * 2 * II;
constexpr long SZ_I   = (long)BS * II;
constexpr long SZ_SC  = 16L * SS * SS;
constexpr long SZ_HB  = 16L * SS * DHM;
constexpr long SZ_PRE = 16L * BS * DHS;
constexpr long SZ_YS  = 16L * SS * DHS;
constexpr long SZ_FFN = (long)BS * 2 * UU;
constexpr long SZ_ACT = (long)BS * UU;
constexpr long SZ_V16 = 16L * SS;

constexpr long O_X   = 0;
constexpr long O_XN  = O_X   + SZ_X;
constexpr long O_XC  = O_XN  + SZ_X;
constexpr long O_UP  = O_XC  + SZ_X;
constexpr long O_XA  = O_UP  + SZ_UP;
constexpr long O_Q   = O_XA  + SZ_I;
constexpr long O_K   = O_Q   + SZ_I;
constexpr long O_V   = O_K   + SZ_I;
constexpr long O_SC  = O_V   + SZ_I;
constexpr long O_HB  = O_SC  + SZ_SC;
constexpr long O_HM  = O_HB  + SZ_HB;
constexpr long O_PRE = O_HM  + SZ_I;
constexpr long O_YS  = O_PRE + SZ_PRE;
constexpr long O_FFN = O_YS  + SZ_YS;
constexpr long O_ACT = O_FFN + SZ_FFN;
constexpr long O_IG  = O_ACT + SZ_ACT;
constexpr long O_FG  = O_IG  + SZ_V16;
constexpr long O_A   = O_FG  + SZ_V16;
constexpr long O_RM  = O_A   + SZ_V16;
constexpr long O_EN  = O_RM  + SZ_V16;
constexpr long O_RNS = O_EN  + SZ_V16;
constexpr long POOL_SZ = O_RNS + SZ_V16;

__device__ float g_pool[POOL_SZ];

__device__ __forceinline__ float warpSum(float v) {
    #pragma unroll
    for (int o = 16; o > 0; o >>= 1) v += __shfl_down_sync(0xffffffffu, v, o);
    return v;
}

// ---------------- tf32 mma helpers ----------------
__device__ __forceinline__ uint32_t f2tf32(float f) {
    uint32_t r;
    asm("cvt.rna.tf32.f32 %0, %1;" : "=r"(r) : "f"(f));
    return r;
}
__device__ __forceinline__ void mma_tf32(float* c, const uint32_t* a, const uint32_t* b) {
    asm volatile(
        "mma.sync.aligned.m16n8k8.row.col.f32.tf32.tf32.f32 "
        "{%0,%1,%2,%3}, {%4,%5,%6,%7}, {%8,%9}, {%0,%1,%2,%3};"
        : "+f"(c[0]), "+f"(c[1]), "+f"(c[2]), "+f"(c[3])
        : "r"(a[0]), "r"(a[1]), "r"(a[2]), "r"(a[3]), "r"(b[0]), "r"(b[1]));
}
#define SPAD 36

// ---------------- embedding gather ----------------
__global__ void embed_k(const int* __restrict__ ids, const float* __restrict__ emb,
                        float* __restrict__ x)
{
    int bs = blockIdx.x;
    long id = ids[bs];
    ((float4*)(x + (long)bs * DD))[threadIdx.x] =
        ((const float4*)(emb + id * DD))[threadIdx.x];
}

// ---------------- LayerNorm width 1024, 256 thr/row ----------------
__global__ void layernorm_k(const float* __restrict__ x, const float* __restrict__ w,
                            float* __restrict__ y)
{
    long row = blockIdx.x;
    int tid = threadIdx.x;
    float4 v = ((const float4*)(x + row * DD))[tid];
    float s = v.x + v.y + v.z + v.w;
    float ss = v.x*v.x + v.y*v.y + v.z*v.z + v.w*v.w;
    __shared__ float sb[8], sb2[8];
    __shared__ float mu_s, rs_s;
    s = warpSum(s); ss = warpSum(ss);
    if ((tid & 31) == 0) { sb[tid >> 5] = s; sb2[tid >> 5] = ss; }
    __syncthreads();
    if (tid == 0) {
        float t = 0.f, t2 = 0.f;
        #pragma unroll
        for (int i = 0; i < 8; i++) { t += sb[i]; t2 += sb2[i]; }
        float mu = t * (1.f / DD);
        mu_s = mu;
        rs_s = rsqrtf(t2 * (1.f / DD) - mu * mu + 1e-5f);
    }
    __syncthreads();
    float mu = mu_s, rs = rs_s;
    float4 wv = ((const float4*)w)[tid];
    float4 o;
    o.x = (v.x - mu) * rs * wv.x;  o.y = (v.y - mu) * rs * wv.y;
    o.z = (v.z - mu) * rs * wv.z;  o.w = (v.w - mu) * rs * wv.w;
    ((float4*)(y + row * DD))[tid] = o;
}

// ============================================================================
// tf32 GEMM NT (R7-style: LDG prefetch + cvt.rna + STS).
// C = alpha*A@B^T [+bias][+=C]; 128x128x32 tile, 8 warps.
// ============================================================================
__global__ void __launch_bounds__(256, 2) tgemm_nt(
    const float* __restrict__ A, const float* __restrict__ B, float* __restrict__ C,
    int M, int N, int K, int lda, int ldb, int ldc,
    float alpha, const float* __restrict__ bias, int acc)
{
    __shared__ float As[128 * SPAD];
    __shared__ float Bs[128 * SPAD];
    const int tid = threadIdx.x;
    const int lane = tid & 31, warp = tid >> 5;
    const int wm = warp & 3, wn = warp >> 2;
    const int g = lane >> 2, t = lane & 3;
    const int lr = tid >> 1, lc = (tid & 1) * 16;
    const float* Ag = A + (long)(blockIdx.y * 128 + lr) * lda + lc;
    const float* Bg = B + (long)(blockIdx.x * 128 + lr) * ldb + lc;

    float c[16][4];
    #pragma unroll
    for (int i = 0; i < 16; i++)
        #pragma unroll
        for (int j = 0; j < 4; j++) c[i][j] = 0.f;

    float4 a4[4], b4[4];
    #pragma unroll
    for (int i = 0; i < 4; i++) {
        a4[i] = *(const float4*)(Ag + i*4);
        b4[i] = *(const float4*)(Bg + i*4);
    }
    const int nk = K >> 5;
    for (int kt = 0; kt < nk; kt++) {
        __syncthreads();
        #pragma unroll
        for (int i = 0; i < 4; i++) {
            uint4 av = make_uint4(f2tf32(a4[i].x), f2tf32(a4[i].y),
                                  f2tf32(a4[i].z), f2tf32(a4[i].w));
            uint4 bv = make_uint4(f2tf32(b4[i].x), f2tf32(b4[i].y),
                                  f2tf32(b4[i].z), f2tf32(b4[i].w));
            *(uint4*)&As[lr * SPAD + lc + i*4] = av;
            *(uint4*)&Bs[lr * SPAD + lc + i*4] = bv;
        }
        __syncthreads();
        if (kt + 1 < nk) {
            const int k0 = (kt + 1) << 5;
            #pragma unroll
            for (int i = 0; i < 4; i++) {
                a4[i] = *(const float4*)(Ag + k0 + i*4);
                b4[i] = *(const float4*)(Bg + k0 + i*4);
            }
        }
        #pragma unroll
        for (int kk = 0; kk < 4; kk++) {
            const int ks = kk * 8;
            uint32_t af[2][4], bf[8][2];
            #pragma unroll
            for (int mt = 0; mt < 2; mt++) {
                int r0 = wm*32 + mt*16 + g;
                af[mt][0] = __float_as_uint(As[r0 * SPAD + ks + t]);
                af[mt][1] = __float_as_uint(As[(r0+8) * SPAD + ks + t]);
                af[mt][2] = __float_as_uint(As[r0 * SPAD + ks + t + 4]);
                af[mt][3] = __float_as_uint(As[(r0+8) * SPAD + ks + t + 4]);
            }
            #pragma unroll
            for (int nt = 0; nt < 8; nt++) {
                int c0 = wn*64 + nt*8 + g;
                bf[nt][0] = __float_as_uint(Bs[c0 * SPAD + ks + t]);
                bf[nt][1] = __float_as_uint(Bs[c0 * SPAD + ks + t + 4]);
            }
            #pragma unroll
            for (int mt = 0; mt < 2; mt++)
                #pragma unroll
                for (int nt = 0; nt < 8; nt++)
                    mma_tf32(c[mt*8 + nt], af[mt], bf[nt]);
        }
    }
    #pragma unroll
    for (int mt = 0; mt < 2; mt++) {
        int row0 = blockIdx.y*128 + wm*32 + mt*16 + g;
        #pragma unroll
        for (int nt = 0; nt < 8; nt++) {
            int col0 = blockIdx.x*128 + wn*64 + nt*8 + 2*t;
            float* v = c[mt*8 + nt];
            float b0 = bias ? bias[col0] : 0.f, b1 = bias ? bias[col0+1] : 0.f;
            float* C0 = C + (long)row0 * ldc + col0;
            float* C1 = C + (long)(row0+8) * ldc + col0;
            float o0 = v[0]*alpha + b0, o1 = v[1]*alpha + b1;
            float o2 = v[2]*alpha + b0, o3 = v[3]*alpha + b1;
            if (acc) { o0 += C0[0]; o1 += C0[1]; o2 += C1[0]; o3 += C1[1]; }
            C0[0] = o0; C0[1] = o1; C1[0] = o2; C1[1] = o3;
        }
    }
}

// ============================================================================
// tf32 attention scores (R7 loader + cvt.rna), triangle grid, fused row-sums.
// ============================================================================
__global__ void __launch_bounds__(256, 2) attn_qk(
    const float* __restrict__ Qb, const float* __restrict__ Kb,
    float* __restrict__ SC, const float* __restrict__ a_,
    const float* __restrict__ rm_, float* __restrict__ rns)
{
    const int z = blockIdx.z;
    const int b = z >> 2, h = z & 3;
    int by = 0;
    int bx = blockIdx.x;
    while ((by + 1) * (by + 2) / 2 <= bx) by++;
    bx -= by * (by + 1) / 2;

    float* Cb = SC + (long)z * SS * SS;
    const float* A = Qb + (long)b * SS * II + h * DHM;
    const float* B = Kb + (long)b * SS * II + h * DHM;
    __shared__ float As[128 * SPAD];
    __shared__ float Bs[128 * SPAD];
    const int tid = threadIdx.x;
    const int lane = tid & 31, warp = tid >> 5;
    const int wm = warp & 3, wn = warp >> 2;
    const int g = lane >> 2, t = lane & 3;
    const int lr = tid >> 1, lc = (tid & 1) * 16;
    const float* Ag = A + (long)(by*128 + lr) * II + lc;
    const float* Bg = B + (long)(bx*128 + lr) * II + lc;

    float c[16][4];
    #pragma unroll
    for (int i = 0; i < 16; i++)
        #pragma unroll
        for (int j = 0; j < 4; j++) c[i][j] = 0.f;

    float4 a4[4], b4[4];
    #pragma unroll
    for (int i = 0; i < 4; i++) {
        a4[i] = *(const float4*)(Ag + i*4);
        b4[i] = *(const float4*)(Bg + i*4);
    }
    const int nk = DHM >> 5;
    for (int kt = 0; kt < nk; kt++) {
        __syncthreads();
        #pragma unroll
        for (int i = 0; i < 4; i++) {
            uint4 av = make_uint4(f2tf32(a4[i].x), f2tf32(a4[i].y),
                                  f2tf32(a4[i].z), f2tf32(a4[i].w));
            uint4 bv = make_uint4(f2tf32(b4[i].x), f2tf32(b4[i].y),
                                  f2tf32(b4[i].z), f2tf32(b4[i].w));
            *(uint4*)&As[lr * SPAD + lc + i*4] = av;
            *(uint4*)&Bs[lr * SPAD + lc + i*4] = bv;
        }
        __syncthreads();
        if (kt + 1 < nk) {
            const int k0 = (kt + 1) << 5;
            #pragma unroll
            for (int i = 0; i < 4; i++) {
                a4[i] = *(const float4*)(Ag + k0 + i*4);
                b4[i] = *(const float4*)(Bg + k0 + i*4);
            }
        }
        #pragma unroll
        for (int kk = 0; kk < 4; kk++) {
            const int ks = kk * 8;
            uint32_t af[2][4], bf[8][2];
            #pragma unroll
            for (int mt = 0; mt < 2; mt++) {
                int r0 = wm*32 + mt*16 + g;
                af[mt][0] = __float_as_uint(As[r0 * SPAD + ks + t]);
                af[mt][1] = __float_as_uint(As[(r0+8) * SPAD + ks + t]);
                af[mt][2] = __float_as_uint(As[r0 * SPAD + ks + t + 4]);
                af[mt][3] = __float_as_uint(As[(r0+8) * SPAD + ks + t + 4]);
            }
            #pragma unroll
            for (int nt = 0; nt < 8; nt++) {
                int c0 = wn*64 + nt*8 + g;
                bf[nt][0] = __float_as_uint(Bs[c0 * SPAD + ks + t]);
                bf[nt][1] = __float_as_uint(Bs[c0 * SPAD + ks + t + 4]);
            }
            #pragma unroll
            for (int mt = 0; mt < 2; mt++)
                #pragma unroll
                for (int nt = 0; nt < 8; nt++)
                    mma_tf32(c[mt*8 + nt], af[mt], bf[nt]);
        }
    }
    const float* az = a_ + (long)z * SS;
    const float* rz = rm_ + (long)z * SS;
    const float alpha = 0.04419417382415922f;  // 1/sqrt(512)
    float rsum[2][2] = {{0.f, 0.f}, {0.f, 0.f}};
    #pragma unroll
    for (int mt = 0; mt < 2; mt++) {
        int row0 = by*128 + wm*32 + mt*16 + g;
        int row1 = row0 + 8;
        float rm0 = rz[row0], rm1 = rz[row1];
        #pragma unroll
        for (int nt = 0; nt < 8; nt++) {
            int col0 = bx*128 + wn*64 + nt*8 + 2*t;
            float av0 = az[col0], av1 = az[col0+1];
            float* v = c[mt*8 + nt];
            float o00 = (col0   <= row0) ? v[0]*alpha*__expf(av0 - rm0) : 0.f;
            float o01 = (col0+1 <= row0) ? v[1]*alpha*__expf(av1 - rm0) : 0.f;
            float o10 = (col0   <= row1) ? v[2]*alpha*__expf(av0 - rm1) : 0.f;
            float o11 = (col0+1 <= row1) ? v[3]*alpha*__expf(av1 - rm1) : 0.f;
            float* C0 = Cb + (long)row0 * SS + col0;
            float* C1 = Cb + (long)row1 * SS + col0;
            C0[0] = o00; C0[1] = o01;
            C1[0] = o10; C1[1] = o11;
            rsum[mt][0] += o00 + o01;
            rsum[mt][1] += o10 + o11;
        }
    }
    #pragma unroll
    for (int mt = 0; mt < 2; mt++) {
        #pragma unroll
        for (int rr = 0; rr < 2; rr++) {
            float v = rsum[mt][rr];
            v += __shfl_xor_sync(0xffffffffu, v, 1);
            v += __shfl_xor_sync(0xffffffffu, v, 2);
            if (t == 0) {
                int row = by*128 + wm*32 + mt*16 + g + rr*8;
                atomicAdd(&rns[(long)z * SS + row], v);
            }
        }
    }
}

// ============================================================================
// tf32 attention value GEMM (NN), K capped at diagonal, rn inline, cvt.rna.
// ============================================================================
__global__ void __launch_bounds__(256, 2) attn_av(
    const float* __restrict__ SC, const float* __restrict__ Vb,
    const float* __restrict__ rns, const float* __restrict__ en,
    float* __restrict__ H)
{
    const int z = blockIdx.z;
    const int b = z >> 2, h = z & 3;
    const int bx = blockIdx.x, by = blockIdx.y;
    const float* A = SC + (long)z * SS * SS;
    const float* B = Vb + (long)b * SS * II + h * DHM;
    float* Cb = H + (long)z * SS * DHM;
    const int kend = (by + 1) * 128;
    __shared__ float As[128 * SPAD];
    __shared__ float Bs[128 * SPAD];
    const int tid = threadIdx.x;
    const int lane = tid & 31, warp = tid >> 5;
    const int wm = warp & 3, wn = warp >> 2;
    const int g = lane >> 2, t = lane & 3;
    const int lr = tid >> 1, lc = (tid & 1) * 16;
    const float* Ag = A + (long)(by*128 + lr) * SS + lc;
    const int bkr = tid >> 3;
    const int bc4 = tid & 7;
    const float* Bg = B + (long)bkr * II + bx*128;

    float c[16][4];
    #pragma unroll
    for (int i = 0; i < 16; i++)
        #pragma unroll
        for (int j = 0; j < 4; j++) c[i][j] = 0.f;

    float4 a4[4], b4[4];
    #pragma unroll
    for (int i = 0; i < 4; i++) {
        a4[i] = *(const float4*)(Ag + i*4);
        b4[i] = *(const float4*)(Bg + (bc4 + i*8) * 4);
    }
    const int nk = kend >> 5;
    for (int kt = 0; kt < nk; kt++) {
        __syncthreads();
        #pragma unroll
        for (int i = 0; i < 4; i++) {
            uint4 av = make_uint4(f2tf32(a4[i].x), f2tf32(a4[i].y),
                                  f2tf32(a4[i].z), f2tf32(a4[i].w));
            *(uint4*)&As[lr * SPAD + lc + i*4] = av;
            int coln = (bc4 + i*8) * 4;
            Bs[(coln+0) * SPAD + bkr] = __uint_as_float(f2tf32(b4[i].x));
            Bs[(coln+1) * SPAD + bkr] = __uint_as_float(f2tf32(b4[i].y));
            Bs[(coln+2) * SPAD + bkr] = __uint_as_float(f2tf32(b4[i].z));
            Bs[(coln+3) * SPAD + bkr] = __uint_as_float(f2tf32(b4[i].w));
        }
        __syncthreads();
        if (kt + 1 < nk) {
            const int k0 = (kt + 1) << 5;
            #pragma unroll
            for (int i = 0; i < 4; i++) {
                a4[i] = *(const float4*)(Ag + k0 + i*4);
                b4[i] = *(const float4*)(Bg + (long)k0 * II + (bc4 + i*8) * 4);
            }
        }
        #pragma unroll
        for (int kk = 0; kk < 4; kk++) {
            const int ks = kk * 8;
            uint32_t af[2][4], bf[8][2];
            #pragma unroll
            for (int mt = 0; mt < 2; mt++) {
                int r0 = wm*32 + mt*16 + g;
                af[mt][0] = __float_as_uint(As[r0 * SPAD + ks + t]);
                af[mt][1] = __float_as_uint(As[(r0+8) * SPAD + ks + t]);
                af[mt][2] = __float_as_uint(As[r0 * SPAD + ks + t + 4]);
                af[mt][3] = __float_as_uint(As[(r0+8) * SPAD + ks + t + 4]);
            }
            #pragma unroll
            for (int nt = 0; nt < 8; nt++) {
                int c0 = wn*64 + nt*8 + g;
                bf[nt][0] = __float_as_uint(Bs[c0 * SPAD + ks + t]);
                bf[nt][1] = __float_as_uint(Bs[c0 * SPAD + ks + t + 4]);
            }
            #pragma unroll
            for (int mt = 0; mt < 2; mt++)
                #pragma unroll
                for (int nt = 0; nt < 8; nt++)
                    mma_tf32(c[mt*8 + nt], af[mt], bf[nt]);
        }
    }
    const float* rz = rns + (long)z * SS;
    const float* ez = en + (long)z * SS;
    #pragma unroll
    for (int mt = 0; mt < 2; mt++) {
        int row0 = by*128 + wm*32 + mt*16 + g;
        int row1 = row0 + 8;
        float rn0 = 1.f / (fmaxf(fabsf(rz[row0]), ez[row0]) + 1e-6f);
        float rn1 = 1.f / (fmaxf(fabsf(rz[row1]), ez[row1]) + 1e-6f);
        #pragma unroll
        for (int nt = 0; nt < 8; nt++) {
            int col0 = bx*128 + wn*64 + nt*8 + 2*t;
            float* v = c[mt*8 + nt];
            float* C0 = Cb + (long)row0 * DHM + col0;
            float* C1 = Cb + (long)row1 * DHM + col0;
            C0[0] = v[0]*rn0; C0[1] = v[1]*rn0;
            C1[0] = v[2]*rn1; C1[1] = v[3]*rn1;
        }
    }
}

// ---------------- batched sLSTM gate GEMMs (fp32, small) ----------------
__global__ void __launch_bounds__(256, 2) sgemm_gates(
    const float* __restrict__ XC, const float* __restrict__ XN,
    const float* __restrict__ iw, const float* __restrict__ fw,
    const float* __restrict__ zw, const float* __restrict__ ow,
    float* __restrict__ PRE)
{
    const int zz = blockIdx.z;
    const int g = zz >> 2, h = zz & 3;
    const float* A = ((g < 2) ? XC : XN) + h * 256;
    const float* W = (g == 0) ? iw : (g == 1) ? fw : (g == 2) ? zw : ow;
    const float* B = W + (long)h * 65536;
    float* C = PRE + (long)zz * BS * DHS;
    __shared__ float As[8][128];
    __shared__ float Bs[8][128];
    const int tid = threadIdx.x;
    const int lrow = tid >> 1;
    const int lcol = (tid & 1) << 2;
    const float* Ag = A + (long)(blockIdx.y * 128 + lrow) * DD + lcol;
    const float* Bg = B + (long)(blockIdx.x * 128 + lrow) * 256 + lcol;
    const int ty = tid >> 4, tx = tid & 15;
    float accv[8][8];
    #pragma unroll
    for (int i = 0; i < 8; i++)
        #pragma unroll
        for (int j = 0; j < 8; j++) accv[i][j] = 0.f;
    for (int k0 = 0; k0 < 256; k0 += 8) {
        float4 av = *(const float4*)(Ag + k0);
        float4 bv = *(const float4*)(Bg + k0);
        __syncthreads();
        As[lcol+0][lrow] = av.x; As[lcol+1][lrow] = av.y;
        As[lcol+2][lrow] = av.z; As[lcol+3][lrow] = av.w;
        Bs[lcol+0][lrow] = bv.x; Bs[lcol+1][lrow] = bv.y;
        Bs[lcol+2][lrow] = bv.z; Bs[lcol+3][lrow] = bv.w;
        __syncthreads();
        #pragma unroll
        for (int kk = 0; kk < 8; kk++) {
            float ar[8], br[8];
            #pragma unroll
            for (int i = 0; i < 8; i++) ar[i] = As[kk][ty*8 + i];
            #pragma unroll
            for (int j = 0; j < 8; j++) br[j] = Bs[kk][tx*8 + j];
            #pragma unroll
            for (int i = 0; i < 8; i++)
                #pragma unroll
                for (int j = 0; j < 8; j++)
                    accv[i][j] += ar[i] * br[j];
        }
    }
    #pragma unroll
    for (int i = 0; i < 8; i++) {
        long row = blockIdx.y * 128 + ty*8 + i;
        float* Cr = C + row * 256L + blockIdx.x * 128 + tx*8;
        #pragma unroll
        for (int j = 0; j < 8; j++)
            Cr[j] = accv[i][j];
    }
}

// ---------------- causal depthwise conv (K=4) + SiLU, compile-time C ----------------
template<int C, int LDIN>
__global__ void conv_silu_t(const float* __restrict__ in, const float* __restrict__ w,
                            const float* __restrict__ bias, float* __restrict__ out)
{
    long idx = (long)blockIdx.x * 256 + threadIdx.x;
    if (idx >= (long)BS * C) return;
    int c = (int)(idx & (C - 1));
    long bs = idx / C;
    int s = (int)(bs & (SS - 1));
    float acc = bias[c];
    #pragma unroll
    for (int kk = 0; kk < 4; kk++) {
        int sp = s + kk - 3;
        if (sp >= 0) acc += in[(bs + kk - 3) * (long)LDIN + c] * w[c*4 + kk];
    }
    out[bs * (long)C + c] = acc / (1.f + __expf(-acc));
}

// ---------------- headwise 4x4 q,k from xa; v from xm(strided) ----------------
__global__ void headwise_qkv(const float* __restrict__ xa, const float* __restrict__ xm,
                             const float* __restrict__ qw, const float* __restrict__ kw,
                             const float* __restrict__ vw,
                             float* __restrict__ q, float* __restrict__ k,
                             float* __restrict__ v)
{
    long idx = (long)blockIdx.x * 256 + threadIdx.x;
    if (idx >= (long)BS * 512) return;
    int nb = (int)(idx & 511);
    long bs = idx >> 9;
    float4 xav = *(const float4*)(xa + bs * II + nb*4);
    float4 xmv = *(const float4*)(xm + bs * (2L*II) + nb*4);
    float xi[4] = {xav.x, xav.y, xav.z, xav.w};
    float xmi[4] = {xmv.x, xmv.y, xmv.z, xmv.w};
    float qo[4], ko[4], vo[4];
    #pragma unroll
    for (int o = 0; o < 4; o++) {
        float aq = 0.f, ak = 0.f, av = 0.f;
        #pragma unroll
        for (int i = 0; i < 4; i++) {
            aq += xi[i]  * qw[nb*16 + o*4 + i];
            ak += xi[i]  * kw[nb*16 + o*4 + i];
            av += xmi[i] * vw[nb*16 + o*4 + i];
        }
        qo[o] = aq; ko[o] = ak; vo[o] = av;
    }
    *(float4*)(q + bs * II + nb*4) = make_float4(qo[0], qo[1], qo[2], qo[3]);
    *(float4*)(k + bs * II + nb*4) = make_float4(ko[0], ko[1], ko[2], ko[3]);
    *(float4*)(v + bs * II + nb*4) = make_float4(vo[0], vo[1], vo[2], vo[3]);
}

// ---------------- ig/fg gate projections (float4) ----------------
__global__ void igfg_k(const float* __restrict__ q, const float* __restrict__ k,
                       const float* __restrict__ v,
                       const float* __restrict__ igw, const float* __restrict__ igb,
                       const float* __restrict__ fgw, const float* __restrict__ fgb,
                       float* __restrict__ ig, float* __restrict__ fg)
{
    long bs = blockIdx.x;
    int b = (int)(bs >> 10);
    int s = (int)(bs & (SS - 1));
    __shared__ float sx[3 * II];
    __shared__ float rbuf[2][8];
    int tid = threadIdx.x;
    for (int i = tid; i < II / 4; i += 256) {
        ((float4*)sx)[i]        = ((const float4*)(q + bs * II))[i];
        ((float4*)sx)[II/4 + i] = ((const float4*)(k + bs * II))[i];
        ((float4*)sx)[II/2 + i] = ((const float4*)(v + bs * II))[i];
    }
    __syncthreads();
    const float4* sx4 = (const float4*)sx;
    for (int h = 0; h < 4; h++) {
        const float4* iw4 = (const float4*)(igw + h * (3*II));
        const float4* fw4 = (const float4*)(fgw + h * (3*II));
        float pi = 0.f, pf = 0.f;
        for (int j = tid; j < (3*II)/4; j += 256) {
            float4 xv = sx4[j];
            float4 wi = iw4[j];
            float4 wf = fw4[j];
            pi += xv.x*wi.x + xv.y*wi.y + xv.z*wi.z + xv.w*wi.w;
            pf += xv.x*wf.x + xv.y*wf.y + xv.z*wf.z + xv.w*wf.w;
        }
        pi = warpSum(pi); pf = warpSum(pf);
        if ((tid & 31) == 0) { rbuf[0][tid >> 5] = pi; rbuf[1][tid >> 5] = pf; }
        __syncthreads();
        if (tid == 0) {
            float a = 0.f, bb = 0.f;
            #pragma unroll
            for (int w8 = 0; w8 < 8; w8++) { a += rbuf[0][w8]; bb += rbuf[1][w8]; }
            ig[(long)(b*4 + h) * SS + s] = a + igb[h];
            fg[(long)(b*4 + h) * SS + s] = bb + fgb[h];
        }
        __syncthreads();
    }
}

// ---------------- mLSTM decay prep (+ zero RNS) ----------------
__global__ void mlstm_prep(const float* __restrict__ ig, const float* __restrict__ fg,
                           float* __restrict__ a, float* __restrict__ rm,
                           float* __restrict__ en, float* __restrict__ rns)
{
    int z = blockIdx.x;
    int tid = threadIdx.x;  // 256
    __shared__ float slsig[SS], sig_s[SS];
    for (int i = tid; i < SS; i += 256) {
        float fv = fg[(long)z * SS + i];
        slsig[i] = fminf(fv, 0.f) - log1pf(__expf(-fabsf(fv)));
        sig_s[i] = ig[(long)z * SS + i];
        rns[(long)z * SS + i] = 0.f;
    }
    __syncthreads();
    if (tid == 0) {
        float cs = 0.f, run = -1e30f;
        for (int s = 0; s < SS; s++) {
            cs += slsig[s];
            float av = sig_s[s] - cs;
            run = fmaxf(run, av);
            a[(long)z * SS + s]  = av;
            rm[(long)z * SS + s] = run;
            en[(long)z * SS + s] = __expf(-(cs + run));
        }
    }
}

// ---------------- mh_norm(dh=512) + (h+skip*xa)*silu(z) ----------------
__global__ void mh_mix(const float* __restrict__ H, const float* __restrict__ onw,
                       const float* __restrict__ skip, const float* __restrict__ xa,
                       const float* __restrict__ up, float* __restrict__ hmix)
{
    int bs = blockIdx.x, h = blockIdx.y;
    int b = bs >> 10;
    int s = bs & (SS - 1);
    const float* hp = H + ((long)(b*4 + h) * SS + s) * DHM;
    int tid = threadIdx.x;  // 128
    float4 v = ((const float4*)hp)[tid];
    float sm = v.x + v.y + v.z + v.w;
    float sq = v.x*v.x + v.y*v.y + v.z*v.z + v.w*v.w;
    __shared__ float s1[4], s2[4];
    sm = warpSum(sm); sq = warpSum(sq);
    if ((tid & 31) == 0) { s1[tid >> 5] = sm; s2[tid >> 5] = sq; }
    __syncthreads();
    float tot  = s1[0] + s1[1] + s1[2] + s1[3];
    float tot2 = s2[0] + s2[1] + s2[2] + s2[3];
    float mu = tot * (1.f / DHM);
    float rs = rsqrtf(tot2 * (1.f / DHM) - mu * mu + 1e-5f);
    float4 wv  = ((const float4*)onw)[h*128 + tid];
    float4 sk  = ((const float4*)skip)[h*128 + tid];
    float4 xav = ((const float4*)(xa + (long)bs * II))[h*128 + tid];
    float4 zv  = ((const float4*)(up + (long)bs * (2L*II) + II))[h*128 + tid];
    float4 o;
    o.x = ((v.x - mu)*rs*wv.x + sk.x*xav.x) * (zv.x / (1.f + __expf(-zv.x)));
    o.y = ((v.y - mu)*rs*wv.y + sk.y*xav.y) * (zv.y / (1.f + __expf(-zv.y)));
    o.z = ((v.z - mu)*rs*wv.z + sk.z*xav.z) * (zv.z / (1.f + __expf(-zv.z)));
    o.w = ((v.w - mu)*rs*wv.w + sk.w*xav.w) * (zv.w / (1.f + __expf(-zv.w)));
    ((float4*)(hmix + (long)bs * II))[h*128 + tid] = o;
}

// ============================================================================
// Cluster-split sLSTM scan, single barrier per step.
// All 8 CTAs broadcast their 128 raws to everyone (double-buffered sraw),
// ONE cluster barrier, then every CTA redundantly computes the full
// activation locally (2 elems/thread) -> local sh_h, local syncthreads.
// Only rank 0 writes ys.
// ============================================================================
#define SCAN_SMEM_FLOATS (32768 + 256 + 2048)

__device__ __forceinline__ uint32_t smem_addr_u32(const void* p) {
    return (uint32_t)__cvta_generic_to_shared(p);
}
__device__ __forceinline__ uint32_t mapa_u32(uint32_t addr, uint32_t rank) {
    uint32_t out;
    asm("mapa.shared::cluster.u32 %0, %1, %2;" : "=r"(out) : "r"(addr), "r"(rank));
    return out;
}
__device__ __forceinline__ void st_cluster_f32(uint32_t addr, float v) {
    asm volatile("st.shared::cluster.f32 [%0], %1;" :: "r"(addr), "f"(v) : "memory");
}
__device__ __forceinline__ void cluster_barrier() {
    asm volatile("barrier.cluster.arrive.aligned;" ::: "memory");
    asm volatile("barrier.cluster.wait.aligned;" ::: "memory");
}

__global__ void __launch_bounds__(128, 1) __cluster_dims__(8, 1, 1)
slstm_scan_cl(const float* __restrict__ pre, const float* __restrict__ rk,
              const float* __restrict__ rb, float* __restrict__ ys)
{
    extern __shared__ float sm[];
    float* W    = sm;                 // [256][128]
    float* sh_h = sm + 32768;         // [256] (local only)
    float* sraw = sm + 32768 + 256;   // [2][4][256] double-buffered raws

    const int z = blockIdx.x >> 3;
    const int b = z >> 2, h = z & 3;
    uint32_t rank;
    asm("mov.u32 %0, %%cluster_ctarank;" : "=r"(rank));
    const int g  = rank >> 1;
    const int hf = rank & 1;
    const int tid = threadIdx.x;

    const float* rks = rk + ((long)h * 256 * 4 + g) * 256 + hf * 128;
    for (int idx = tid; idx < 32768; idx += 128) {
        int d = idx >> 7, el = idx & 127;
        W[idx] = rks[(long)d * 1024 + el];
    }
    for (int i = tid; i < 256; i += 128) sh_h[i] = 0.f;
    __syncthreads();

    const float rbv = rb[(h*4 + g) * DHS + hf*128 + tid];
    const float* pb = pre + ((long)(g*4 + h) * BS + (long)b * SS) * DHS + hf*128 + tid;
    float* yo = ys + (long)z * SS * DHS;

    // remote destinations for this thread's raw value in all 8 CTAs
    uint32_t rdst[8];
    #pragma unroll
    for (int r = 0; r < 8; r++)
        rdst[r] = mapa_u32(smem_addr_u32(&sraw[g*256 + hf*128 + tid]), (uint32_t)r);

    // per-thread state for e0 = tid, e1 = tid + 128 (redundant across CTAs)
    float c0 = 0.f, n0 = 0.f, m0 = 0.f;
    float c1 = 0.f, n1 = 0.f, m1 = 0.f;

    cluster_barrier();   // entry alignment

    float pv = pb[0];
    for (int s = 0; s < SS; s++) {
        const uint32_t po = (uint32_t)(s & 1) << 12;  // 1024 floats = 4096 B
        // matvec over local W slice
        float a0 = 0.f, a1 = 0.f, a2 = 0.f, a3 = 0.f;
        const float* Wp = W + tid;
        #pragma unroll 8
        for (int d = 0; d < 256; d += 4) {
            float4 hv = *(const float4*)&sh_h[d];
            a0 += hv.x * Wp[(d+0) << 7];
            a1 += hv.y * Wp[(d+1) << 7];
            a2 += hv.z * Wp[(d+2) << 7];
            a3 += hv.w * Wp[(d+3) << 7];
        }
        float acc = pv + rbv + ((a0 + a1) + (a2 + a3));
        if (s + 1 < SS) pv = pb[(long)(s+1) * DHS];

        #pragma unroll
        for (int r = 0; r < 8; r++) st_cluster_f32(rdst[r] + po, acc);
        cluster_barrier();

        const float* rw = sraw + (s & 1) * 1024;
        // element e0 = tid
        {
            float iraw = rw[tid],       fraw = rw[256 + tid];
            float zraw = rw[512 + tid], oraw = rw[768 + tid];
            float lf = m0 + fminf(fraw, 0.f) - log1pf(__expf(-fabsf(fraw)));
            float mn = fmaxf(iraw, lf);
            float ig_ = __expf(iraw - mn);
            float fg_ = __expf(lf - mn);
            c0 = fg_ * c0 + ig_ * tanhf(zraw);
            n0 = fg_ * n0 + ig_;
            m0 = mn;
            float hv = c0 / (n0 * (1.f + __expf(-oraw)));
            sh_h[tid] = hv;
            if (rank == 0) yo[(long)s * DHS + tid] = hv;
        }
        // element e1 = tid + 128
        {
            float iraw = rw[128 + tid], fraw = rw[384 + tid];
            float zraw = rw[640 + tid], oraw = rw[896 + tid];
            float lf = m1 + fminf(fraw, 0.f) - log1pf(__expf(-fabsf(fraw)));
            float mn = fmaxf(iraw, lf);
            float ig_ = __expf(iraw - mn);
            float fg_ = __expf(lf - mn);
            c1 = fg_ * c1 + ig_ * tanhf(zraw);
            n1 = fg_ * n1 + ig_;
            m1 = mn;
            float hv = c1 / (n1 * (1.f + __expf(-oraw)));
            sh_h[128 + tid] = hv;
            if (rank == 0) yo[(long)s * DHS + 128 + tid] = hv;
        }
        __syncthreads();   // local: sh_h ready for next matvec
    }
}

// ---------------- sLSTM group norm (256) + residual add ----------------
__global__ void slstm_gnorm(const float* __restrict__ ys, const float* __restrict__ gnw,
                            float* __restrict__ x)
{
    int bs = blockIdx.x, h = blockIdx.y;
    int b = bs >> 10, s = bs & (SS - 1);
    const float* yp = ys + ((long)(b*4 + h) * SS + s) * DHS;
    int tid = threadIdx.x;  // 64
    float4 v = ((const float4*)yp)[tid];
    float sm = v.x + v.y + v.z + v.w;
    float sq = v.x*v.x + v.y*v.y + v.z*v.z + v.w*v.w;
    __shared__ float s1[2], s2[2];
    sm = warpSum(sm); sq = warpSum(sq);
    if ((tid & 31) == 0) { s1[tid >> 5] = sm; s2[tid >> 5] = sq; }
    __syncthreads();
    float tot  = s1[0] + s1[1];
    float tot2 = s2[0] + s2[1];
    float mu = tot * (1.f / DHS);
    float rs = rsqrtf(tot2 * (1.f / DHS) - mu * mu + 1e-5f);
    float4 wv = ((const float4*)gnw)[h*64 + tid];
    float* xp = x + (long)bs * DD + h * DHS + tid * 4;
    float4 xv = *(float4*)xp;
    xv.x += (v.x - mu) * rs * wv.x;
    xv.y += (v.y - mu) * rs * wv.y;
    xv.z += (v.z - mu) * rs * wv.z;
    xv.w += (v.w - mu) * rs * wv.w;
    *(float4*)xp = xv;
}

// ---------------- FFN: act = gelu_exact(gate) * up ----------------
__global__ void gelu_mul(const float* __restrict__ f, float* __restrict__ a)
{
    long idx = (long)blockIdx.x * 256 + threadIdx.x;
    if (idx >= (long)BS * UU) return;
    long bs = idx / UU;
    int u = (int)(idx % UU);
    float g = f[bs * (2L*UU) + u];
    float p = f[bs * (2L*UU) + UU + u];
    a[idx] = 0.5f * g * (1.f + erff(g * 0.70710678118654752f)) * p;
}

// ---------------- host ----------------
static inline void gemm(const float* A, const float* B, float* C,
                        int M, int N, int K, int lda, int ldb, int ldc,
                        float alpha, const float* bias, int acc)
{
    dim3 grid(N / 128, M / 128);
    tgemm_nt<<<grid, 256>>>(A, B, C, M, N, K, lda, ldb, ldc, alpha, bias, acc);
}

extern "C" void kernel_launch(void* const* d_in, const int* in_sizes, int n_in,
                              void* d_out, int out_size)
{
    const int*   ids       = (const int*)  d_in[0];
    const float* emb       = (const float*)d_in[1];
    const float* m_ln_w    = (const float*)d_in[2];
    const float* m_up_w    = (const float*)d_in[3];
    const float* m_conv_w  = (const float*)d_in[4];
    const float* m_conv_b  = (const float*)d_in[5];
    const float* m_q_w     = (const float*)d_in[6];
    const float* m_k_w     = (const float*)d_in[7];
    const float* m_v_w     = (const float*)d_in[8];
    const float* m_ig_w    = (const float*)d_in[9];
    const float* m_ig_b    = (const float*)d_in[10];
    const float* m_fg_w    = (const float*)d_in[11];
    const float* m_fg_b    = (const float*)d_in[12];
    const float* m_skip    = (const float*)d_in[13];
    const float* m_on_w    = (const float*)d_in[14];
    const float* m_down_w  = (const float*)d_in[15];
    const float* s_ln_w    = (const float*)d_in[16];
    const float* s_conv_w  = (const float*)d_in[17];
    const float* s_conv_b  = (const float*)d_in[18];
    const float* s_iw      = (const float*)d_in[19];
    const float* s_fw      = (const float*)d_in[20];
    const float* s_zw      = (const float*)d_in[21];
    const float* s_ow      = (const float*)d_in[22];
    const float* s_rk      = (const float*)d_in[23];
    const float* s_rb      = (const float*)d_in[24];
    const float* s_gn_w    = (const float*)d_in[25];
    const float* s_ln2_w   = (const float*)d_in[26];
    const float* s_ffn_up  = (const float*)d_in[27];
    const float* s_ffn_dn  = (const float*)d_in[28];
    const float* post_ln_w = (const float*)d_in[29];
    const float* head_w    = (const float*)d_in[30];
    const float* head_b    = (const float*)d_in[31];
    float* out = (float*)d_out;

    float* pool = nullptr;
    cudaGetSymbolAddress((void**)&pool, g_pool);
    float* X   = pool + O_X;   float* XN  = pool + O_XN;  float* XC  = pool + O_XC;
    float* UP  = pool + O_UP;  float* XA  = pool + O_XA;
    float* Q_  = pool + O_Q;   float* K_  = pool + O_K;   float* V_  = pool + O_V;
    float* SC  = pool + O_SC;  float* HB  = pool + O_HB;  float* HM  = pool + O_HM;
    float* PRE = pool + O_PRE; float* YS  = pool + O_YS;
    float* FFN = pool + O_FFN; float* ACT = pool + O_ACT;
    float* IG  = pool + O_IG;  float* FG  = pool + O_FG;
    float* Aa  = pool + O_A;   float* RM  = pool + O_RM;
    float* EN  = pool + O_EN;  float* RNS = pool + O_RNS;

    cudaFuncSetAttribute(slstm_scan_cl,
                         cudaFuncAttributeMaxDynamicSharedMemorySize,
                         SCAN_SMEM_FLOATS * 4);

    embed_k<<<BS, 256>>>(ids, emb, X);

    int mi = 0;
    for (int blk = 0; blk < 4; blk++) {
        if (blk == 1) {
            // ---------------- sLSTM block ----------------
            layernorm_k<<<BS, 256>>>(X, s_ln_w, XN);
            conv_silu_t<DD, DD><<<(BS * DD) / 256, 256>>>(XN, s_conv_w, s_conv_b, XC);
            sgemm_gates<<<dim3(2, 32, 16), 256>>>(XC, XN, s_iw, s_fw, s_zw, s_ow, PRE);
            slstm_scan_cl<<<128, 128, SCAN_SMEM_FLOATS * 4>>>(PRE, s_rk, s_rb, YS);
            slstm_gnorm<<<dim3(BS, 4), 64>>>(YS, s_gn_w, X);
            layernorm_k<<<BS, 256>>>(X, s_ln2_w, XN);
            gemm(XN, s_ffn_up, FFN, BS, 2*UU, DD, DD, DD, 2*UU, 1.f, nullptr, 0);
            gelu_mul<<<(int)(((long)BS*UU + 255) / 256), 256>>>(FFN, ACT);
            gemm(ACT, s_ffn_dn, X, BS, DD, UU, UU, UU, DD, 1.f, nullptr, 1);
        } else {
            // ---------------- mLSTM block ----------------
            layernorm_k<<<BS, 256>>>(X, m_ln_w + (long)mi*DD, XN);
            gemm(XN, m_up_w + (long)mi*4096*DD, UP, BS, 4096, DD, DD, DD, 4096,
                 1.f, nullptr, 0);
            conv_silu_t<II, 4096><<<(int)(((long)BS*II) / 256), 256>>>(
                UP, m_conv_w + (long)mi*II*4, m_conv_b + (long)mi*II, XA);
            headwise_qkv<<<(int)(((long)BS*512) / 256), 256>>>(
                XA, UP, m_q_w + (long)mi*512*16, m_k_w + (long)mi*512*16,
                m_v_w + (long)mi*512*16, Q_, K_, V_);
            igfg_k<<<BS, 256>>>(Q_, K_, V_,
                m_ig_w + (long)mi*4*6144, m_ig_b + (long)mi*4,
                m_fg_w + (long)mi*4*6144, m_fg_b + (long)mi*4, IG, FG);
            mlstm_prep<<<16, 256>>>(IG, FG, Aa, RM, EN, RNS);
            attn_qk<<<dim3(36, 1, 16), 256>>>(Q_, K_, SC, Aa, RM, RNS);
            attn_av<<<dim3(4, 8, 16), 256>>>(SC, V_, RNS, EN, HB);
            mh_mix<<<dim3(BS, 4), 128>>>(HB, m_on_w + (long)mi*II,
                m_skip + (long)mi*II, XA, UP, HM);
            gemm(HM, m_down_w + (long)mi*DD*II, X, BS, DD, II, II, II, DD,
                 1.f, nullptr, 1);
            mi++;
        }
    }

    layernorm_k<<<BS, 256>>>(X, post_ln_w, XN);
    gemm(XN, head_w, out, BS, 256, DD, DD, DD, 256, 1.f, head_b, 0);
}

// round 10
// speedup vs baseline: 6.1176x; 1.0259x over previous
#include <cuda_runtime.h>
#include <cuda_bf16.h>
#include <math.h>
#include <stdint.h>

#define BB 4
#define SS 1024
#define DD 1024
#define II 2048
#define BS 4096
#define DHM 512
#define DHS 256
#define UU 1344

constexpr long SZ_X   = (long)BS * DD;
constexpr long SZ_UP  = (long)BS * 2 * II;
constexpr long SZ_I   = (long)BS * II;
constexpr long SZ_SC  = 16L * SS * SS;
constexpr long SZ_HB  = 16L * SS * DHM;
constexpr long SZ_PRE = 16L * BS * DHS;
constexpr long SZ_YS  = 16L * SS * DHS;
constexpr long SZ_FFN = (long)BS * 2 * UU;
constexpr long SZ_ACT = (long)BS * UU;
constexpr long SZ_V16 = 16L * SS;

constexpr long O_X   = 0;
constexpr long O_XN  = O_X   + SZ_X;
constexpr long O_XC  = O_XN  + SZ_X;
constexpr long O_UP  = O_XC  + SZ_X;
constexpr long O_XA  = O_UP  + SZ_UP;
constexpr long O_Q   = O_XA  + SZ_I;
constexpr long O_K   = O_Q   + SZ_I;
constexpr long O_V   = O_K   + SZ_I;
constexpr long O_SC  = O_V   + SZ_I;
constexpr long O_HB  = O_SC  + SZ_SC;
constexpr long O_HM  = O_HB  + SZ_HB;
constexpr long O_PRE = O_HM  + SZ_I;
constexpr long O_YS  = O_PRE + SZ_PRE;
constexpr long O_FFN = O_YS  + SZ_YS;
constexpr long O_ACT = O_FFN + SZ_FFN;
constexpr long O_IG  = O_ACT + SZ_ACT;
constexpr long O_FG  = O_IG  + SZ_V16;
constexpr long O_A   = O_FG  + SZ_V16;
constexpr long O_RM  = O_A   + SZ_V16;
constexpr long O_EN  = O_RM  + SZ_V16;
constexpr long O_RNS = O_EN  + SZ_V16;
constexpr long POOL_SZ = O_RNS + SZ_V16;

__device__ float g_pool[POOL_SZ];

__device__ __forceinline__ float warpSum(float v) {
    #pragma unroll
    for (int o = 16; o > 0; o >>= 1) v += __shfl_down_sync(0xffffffffu, v, o);
    return v;
}

// ---------------- tf32 mma helpers ----------------
__device__ __forceinline__ uint32_t f2tf32(float f) {
    uint32_t r;
    asm("cvt.rna.tf32.f32 %0, %1;" : "=r"(r) : "f"(f));
    return r;
}
__device__ __forceinline__ void mma_tf32(float* c, const uint32_t* a, const uint32_t* b) {
    asm volatile(
        "mma.sync.aligned.m16n8k8.row.col.f32.tf32.tf32.f32 "
        "{%0,%1,%2,%3}, {%4,%5,%6,%7}, {%8,%9}, {%0,%1,%2,%3};"
        : "+f"(c[0]), "+f"(c[1]), "+f"(c[2]), "+f"(c[3])
        : "r"(a[0]), "r"(a[1]), "r"(a[2]), "r"(a[3]), "r"(b[0]), "r"(b[1]));
}
#define SPAD 36

// ---------------- f32x2 helpers ----------------
typedef unsigned long long ull;
__device__ __forceinline__ ull pack2(float a, float b) {
    ull r; asm("mov.b64 %0, {%1,%2};" : "=l"(r) : "f"(a), "f"(b)); return r;
}
__device__ __forceinline__ ull fma2(ull a, ull b, ull c) {
    ull r; asm("fma.rn.f32x2 %0, %1, %2, %3;" : "=l"(r) : "l"(a), "l"(b), "l"(c)); return r;
}
__device__ __forceinline__ ull add2(ull a, ull b) {
    ull r; asm("add.rn.f32x2 %0, %1, %2;" : "=l"(r) : "l"(a), "l"(b)); return r;
}
__device__ __forceinline__ void unpack2(ull v, float& a, float& b) {
    asm("mov.b64 {%0,%1}, %2;" : "=f"(a), "=f"(b) : "l"(v));
}
union F4U { float4 f; ull u[2]; };

// ---------------- embedding gather ----------------
__global__ void embed_k(const int* __restrict__ ids, const float* __restrict__ emb,
                        float* __restrict__ x)
{
    int bs = blockIdx.x;
    long id = ids[bs];
    ((float4*)(x + (long)bs * DD))[threadIdx.x] =
        ((const float4*)(emb + id * DD))[threadIdx.x];
}

// ---------------- LayerNorm width 1024, 256 thr/row ----------------
__global__ void layernorm_k(const float* __restrict__ x, const float* __restrict__ w,
                            float* __restrict__ y)
{
    long row = blockIdx.x;
    int tid = threadIdx.x;
    float4 v = ((const float4*)(x + row * DD))[tid];
    float s = v.x + v.y + v.z + v.w;
    float ss = v.x*v.x + v.y*v.y + v.z*v.z + v.w*v.w;
    __shared__ float sb[8], sb2[8];
    __shared__ float mu_s, rs_s;
    s = warpSum(s); ss = warpSum(ss);
    if ((tid & 31) == 0) { sb[tid >> 5] = s; sb2[tid >> 5] = ss; }
    __syncthreads();
    if (tid == 0) {
        float t = 0.f, t2 = 0.f;
        #pragma unroll
        for (int i = 0; i < 8; i++) { t += sb[i]; t2 += sb2[i]; }
        float mu = t * (1.f / DD);
        mu_s = mu;
        rs_s = rsqrtf(t2 * (1.f / DD) - mu * mu + 1e-5f);
    }
    __syncthreads();
    float mu = mu_s, rs = rs_s;
    float4 wv = ((const float4*)w)[tid];
    float4 o;
    o.x = (v.x - mu) * rs * wv.x;  o.y = (v.y - mu) * rs * wv.y;
    o.z = (v.z - mu) * rs * wv.z;  o.w = (v.w - mu) * rs * wv.w;
    ((float4*)(y + row * DD))[tid] = o;
}

// ============================================================================
// tf32 GEMM NT (LDG prefetch + cvt.rna + STS). C = alpha*A@B^T [+bias][+=C]
// ============================================================================
__global__ void __launch_bounds__(256, 2) tgemm_nt(
    const float* __restrict__ A, const float* __restrict__ B, float* __restrict__ C,
    int M, int N, int K, int lda, int ldb, int ldc,
    float alpha, const float* __restrict__ bias, int acc)
{
    __shared__ float As[128 * SPAD];
    __shared__ float Bs[128 * SPAD];
    const int tid = threadIdx.x;
    const int lane = tid & 31, warp = tid >> 5;
    const int wm = warp & 3, wn = warp >> 2;
    const int g = lane >> 2, t = lane & 3;
    const int lr = tid >> 1, lc = (tid & 1) * 16;
    const float* Ag = A + (long)(blockIdx.y * 128 + lr) * lda + lc;
    const float* Bg = B + (long)(blockIdx.x * 128 + lr) * ldb + lc;

    float c[16][4];
    #pragma unroll
    for (int i = 0; i < 16; i++)
        #pragma unroll
        for (int j = 0; j < 4; j++) c[i][j] = 0.f;

    float4 a4[4], b4[4];
    #pragma unroll
    for (int i = 0; i < 4; i++) {
        a4[i] = *(const float4*)(Ag + i*4);
        b4[i] = *(const float4*)(Bg + i*4);
    }
    const int nk = K >> 5;
    for (int kt = 0; kt < nk; kt++) {
        __syncthreads();
        #pragma unroll
        for (int i = 0; i < 4; i++) {
            uint4 av = make_uint4(f2tf32(a4[i].x), f2tf32(a4[i].y),
                                  f2tf32(a4[i].z), f2tf32(a4[i].w));
            uint4 bv = make_uint4(f2tf32(b4[i].x), f2tf32(b4[i].y),
                                  f2tf32(b4[i].z), f2tf32(b4[i].w));
            *(uint4*)&As[lr * SPAD + lc + i*4] = av;
            *(uint4*)&Bs[lr * SPAD + lc + i*4] = bv;
        }
        __syncthreads();
        if (kt + 1 < nk) {
            const int k0 = (kt + 1) << 5;
            #pragma unroll
            for (int i = 0; i < 4; i++) {
                a4[i] = *(const float4*)(Ag + k0 + i*4);
                b4[i] = *(const float4*)(Bg + k0 + i*4);
            }
        }
        #pragma unroll
        for (int kk = 0; kk < 4; kk++) {
            const int ks = kk * 8;
            uint32_t af[2][4], bf[8][2];
            #pragma unroll
            for (int mt = 0; mt < 2; mt++) {
                int r0 = wm*32 + mt*16 + g;
                af[mt][0] = __float_as_uint(As[r0 * SPAD + ks + t]);
                af[mt][1] = __float_as_uint(As[(r0+8) * SPAD + ks + t]);
                af[mt][2] = __float_as_uint(As[r0 * SPAD + ks + t + 4]);
                af[mt][3] = __float_as_uint(As[(r0+8) * SPAD + ks + t + 4]);
            }
            #pragma unroll
            for (int nt = 0; nt < 8; nt++) {
                int c0 = wn*64 + nt*8 + g;
                bf[nt][0] = __float_as_uint(Bs[c0 * SPAD + ks + t]);
                bf[nt][1] = __float_as_uint(Bs[c0 * SPAD + ks + t + 4]);
            }
            #pragma unroll
            for (int mt = 0; mt < 2; mt++)
                #pragma unroll
                for (int nt = 0; nt < 8; nt++)
                    mma_tf32(c[mt*8 + nt], af[mt], bf[nt]);
        }
    }
    #pragma unroll
    for (int mt = 0; mt < 2; mt++) {
        int row0 = blockIdx.y*128 + wm*32 + mt*16 + g;
        #pragma unroll
        for (int nt = 0; nt < 8; nt++) {
            int col0 = blockIdx.x*128 + wn*64 + nt*8 + 2*t;
            float* v = c[mt*8 + nt];
            float b0 = bias ? bias[col0] : 0.f, b1 = bias ? bias[col0+1] : 0.f;
            float* C0 = C + (long)row0 * ldc + col0;
            float* C1 = C + (long)(row0+8) * ldc + col0;
            float o0 = v[0]*alpha + b0, o1 = v[1]*alpha + b1;
            float o2 = v[2]*alpha + b0, o3 = v[3]*alpha + b1;
            if (acc) { o0 += C0[0]; o1 += C0[1]; o2 += C1[0]; o3 += C1[1]; }
            C0[0] = o0; C0[1] = o1; C1[0] = o2; C1[1] = o3;
        }
    }
}

// ============================================================================
// tf32 batched sLSTM gate GEMMs: PRE[zz] = src @ W[h]^T, zz=(g*4+h)
// ============================================================================
__global__ void __launch_bounds__(256, 2) tgemm_gates(
    const float* __restrict__ XC, const float* __restrict__ XN,
    const float* __restrict__ iw, const float* __restrict__ fw,
    const float* __restrict__ zw, const float* __restrict__ ow,
    float* __restrict__ PRE)
{
    const int zz = blockIdx.z;
    const int gg = zz >> 2, hh = zz & 3;
    const float* A = ((gg < 2) ? XC : XN) + hh * 256;
    const float* Wsel = (gg == 0) ? iw : (gg == 1) ? fw : (gg == 2) ? zw : ow;
    const float* B = Wsel + (long)hh * 65536;
    float* C = PRE + (long)zz * BS * DHS;

    __shared__ float As[128 * SPAD];
    __shared__ float Bs[128 * SPAD];
    const int tid = threadIdx.x;
    const int lane = tid & 31, warp = tid >> 5;
    const int wm = warp & 3, wn = warp >> 2;
    const int g = lane >> 2, t = lane & 3;
    const int lr = tid >> 1, lc = (tid & 1) * 16;
    const float* Ag = A + (long)(blockIdx.y * 128 + lr) * DD + lc;
    const float* Bg = B + (long)(blockIdx.x * 128 + lr) * 256 + lc;

    float c[16][4];
    #pragma unroll
    for (int i = 0; i < 16; i++)
        #pragma unroll
        for (int j = 0; j < 4; j++) c[i][j] = 0.f;

    float4 a4[4], b4[4];
    #pragma unroll
    for (int i = 0; i < 4; i++) {
        a4[i] = *(const float4*)(Ag + i*4);
        b4[i] = *(const float4*)(Bg + i*4);
    }
    const int nk = 256 >> 5;
    for (int kt = 0; kt < nk; kt++) {
        __syncthreads();
        #pragma unroll
        for (int i = 0; i < 4; i++) {
            uint4 av = make_uint4(f2tf32(a4[i].x), f2tf32(a4[i].y),
                                  f2tf32(a4[i].z), f2tf32(a4[i].w));
            uint4 bv = make_uint4(f2tf32(b4[i].x), f2tf32(b4[i].y),
                                  f2tf32(b4[i].z), f2tf32(b4[i].w));
            *(uint4*)&As[lr * SPAD + lc + i*4] = av;
            *(uint4*)&Bs[lr * SPAD + lc + i*4] = bv;
        }
        __syncthreads();
        if (kt + 1 < nk) {
            const int k0 = (kt + 1) << 5;
            #pragma unroll
            for (int i = 0; i < 4; i++) {
                a4[i] = *(const float4*)(Ag + k0 + i*4);
                b4[i] = *(const float4*)(Bg + k0 + i*4);
            }
        }
        #pragma unroll
        for (int kk = 0; kk < 4; kk++) {
            const int ks = kk * 8;
            uint32_t af[2][4], bf[8][2];
            #pragma unroll
            for (int mt = 0; mt < 2; mt++) {
                int r0 = wm*32 + mt*16 + g;
                af[mt][0] = __float_as_uint(As[r0 * SPAD + ks + t]);
                af[mt][1] = __float_as_uint(As[(r0+8) * SPAD + ks + t]);
                af[mt][2] = __float_as_uint(As[r0 * SPAD + ks + t + 4]);
                af[mt][3] = __float_as_uint(As[(r0+8) * SPAD + ks + t + 4]);
            }
            #pragma unroll
            for (int nt = 0; nt < 8; nt++) {
                int c0 = wn*64 + nt*8 + g;
                bf[nt][0] = __float_as_uint(Bs[c0 * SPAD + ks + t]);
                bf[nt][1] = __float_as_uint(Bs[c0 * SPAD + ks + t + 4]);
            }
            #pragma unroll
            for (int mt = 0; mt < 2; mt++)
                #pragma unroll
                for (int nt = 0; nt < 8; nt++)
                    mma_tf32(c[mt*8 + nt], af[mt], bf[nt]);
        }
    }
    #pragma unroll
    for (int mt = 0; mt < 2; mt++) {
        int row0 = blockIdx.y*128 + wm*32 + mt*16 + g;
        #pragma unroll
        for (int nt = 0; nt < 8; nt++) {
            int col0 = blockIdx.x*128 + wn*64 + nt*8 + 2*t;
            float* v = c[mt*8 + nt];
            float* C0 = C + (long)row0 * 256 + col0;
            float* C1 = C + (long)(row0+8) * 256 + col0;
            C0[0] = v[0]; C0[1] = v[1];
            C1[0] = v[2]; C1[1] = v[3];
        }
    }
}

// ============================================================================
// tf32 attention scores, triangle grid, fused row-sums.
// ============================================================================
__global__ void __launch_bounds__(256, 2) attn_qk(
    const float* __restrict__ Qb, const float* __restrict__ Kb,
    float* __restrict__ SC, const float* __restrict__ a_,
    const float* __restrict__ rm_, float* __restrict__ rns)
{
    const int z = blockIdx.z;
    const int b = z >> 2, h = z & 3;
    int by = 0;
    int bx = blockIdx.x;
    while ((by + 1) * (by + 2) / 2 <= bx) by++;
    bx -= by * (by + 1) / 2;

    float* Cb = SC + (long)z * SS * SS;
    const float* A = Qb + (long)b * SS * II + h * DHM;
    const float* B = Kb + (long)b * SS * II + h * DHM;
    __shared__ float As[128 * SPAD];
    __shared__ float Bs[128 * SPAD];
    const int tid = threadIdx.x;
    const int lane = tid & 31, warp = tid >> 5;
    const int wm = warp & 3, wn = warp >> 2;
    const int g = lane >> 2, t = lane & 3;
    const int lr = tid >> 1, lc = (tid & 1) * 16;
    const float* Ag = A + (long)(by*128 + lr) * II + lc;
    const float* Bg = B + (long)(bx*128 + lr) * II + lc;

    float c[16][4];
    #pragma unroll
    for (int i = 0; i < 16; i++)
        #pragma unroll
        for (int j = 0; j < 4; j++) c[i][j] = 0.f;

    float4 a4[4], b4[4];
    #pragma unroll
    for (int i = 0; i < 4; i++) {
        a4[i] = *(const float4*)(Ag + i*4);
        b4[i] = *(const float4*)(Bg + i*4);
    }
    const int nk = DHM >> 5;
    for (int kt = 0; kt < nk; kt++) {
        __syncthreads();
        #pragma unroll
        for (int i = 0; i < 4; i++) {
            uint4 av = make_uint4(f2tf32(a4[i].x), f2tf32(a4[i].y),
                                  f2tf32(a4[i].z), f2tf32(a4[i].w));
            uint4 bv = make_uint4(f2tf32(b4[i].x), f2tf32(b4[i].y),
                                  f2tf32(b4[i].z), f2tf32(b4[i].w));
            *(uint4*)&As[lr * SPAD + lc + i*4] = av;
            *(uint4*)&Bs[lr * SPAD + lc + i*4] = bv;
        }
        __syncthreads();
        if (kt + 1 < nk) {
            const int k0 = (kt + 1) << 5;
            #pragma unroll
            for (int i = 0; i < 4; i++) {
                a4[i] = *(const float4*)(Ag + k0 + i*4);
                b4[i] = *(const float4*)(Bg + k0 + i*4);
            }
        }
        #pragma unroll
        for (int kk = 0; kk < 4; kk++) {
            const int ks = kk * 8;
            uint32_t af[2][4], bf[8][2];
            #pragma unroll
            for (int mt = 0; mt < 2; mt++) {
                int r0 = wm*32 + mt*16 + g;
                af[mt][0] = __float_as_uint(As[r0 * SPAD + ks + t]);
                af[mt][1] = __float_as_uint(As[(r0+8) * SPAD + ks + t]);
                af[mt][2] = __float_as_uint(As[r0 * SPAD + ks + t + 4]);
                af[mt][3] = __float_as_uint(As[(r0+8) * SPAD + ks + t + 4]);
            }
            #pragma unroll
            for (int nt = 0; nt < 8; nt++) {
                int c0 = wn*64 + nt*8 + g;
                bf[nt][0] = __float_as_uint(Bs[c0 * SPAD + ks + t]);
                bf[nt][1] = __float_as_uint(Bs[c0 * SPAD + ks + t + 4]);
            }
            #pragma unroll
            for (int mt = 0; mt < 2; mt++)
                #pragma unroll
                for (int nt = 0; nt < 8; nt++)
                    mma_tf32(c[mt*8 + nt], af[mt], bf[nt]);
        }
    }
    const float* az = a_ + (long)z * SS;
    const float* rz = rm_ + (long)z * SS;
    const float alpha = 0.04419417382415922f;  // 1/sqrt(512)
    float rsum[2][2] = {{0.f, 0.f}, {0.f, 0.f}};
    #pragma unroll
    for (int mt = 0; mt < 2; mt++) {
        int row0 = by*128 + wm*32 + mt*16 + g;
        int row1 = row0 + 8;
        float rm0 = rz[row0], rm1 = rz[row1];
        #pragma unroll
        for (int nt = 0; nt < 8; nt++) {
            int col0 = bx*128 + wn*64 + nt*8 + 2*t;
            float av0 = az[col0], av1 = az[col0+1];
            float* v = c[mt*8 + nt];
            float o00 = (col0   <= row0) ? v[0]*alpha*__expf(av0 - rm0) : 0.f;
            float o01 = (col0+1 <= row0) ? v[1]*alpha*__expf(av1 - rm0) : 0.f;
            float o10 = (col0   <= row1) ? v[2]*alpha*__expf(av0 - rm1) : 0.f;
            float o11 = (col0+1 <= row1) ? v[3]*alpha*__expf(av1 - rm1) : 0.f;
            float* C0 = Cb + (long)row0 * SS + col0;
            float* C1 = Cb + (long)row1 * SS + col0;
            C0[0] = o00; C0[1] = o01;
            C1[0] = o10; C1[1] = o11;
            rsum[mt][0] += o00 + o01;
            rsum[mt][1] += o10 + o11;
        }
    }
    #pragma unroll
    for (int mt = 0; mt < 2; mt++) {
        #pragma unroll
        for (int rr = 0; rr < 2; rr++) {
            float v = rsum[mt][rr];
            v += __shfl_xor_sync(0xffffffffu, v, 1);
            v += __shfl_xor_sync(0xffffffffu, v, 2);
            if (t == 0) {
                int row = by*128 + wm*32 + mt*16 + g + rr*8;
                atomicAdd(&rns[(long)z * SS + row], v);
            }
        }
    }
}

// ============================================================================
// tf32 attention value GEMM (NN), K capped at diagonal, rn inline,
// heavy tiles (large by) scheduled first.
// ============================================================================
__global__ void __launch_bounds__(256, 2) attn_av(
    const float* __restrict__ SC, const float* __restrict__ Vb,
    const float* __restrict__ rns, const float* __restrict__ en,
    float* __restrict__ H)
{
    const int z = blockIdx.z;
    const int b = z >> 2, h = z & 3;
    const int bx = blockIdx.x;
    const int by = 7 - blockIdx.y;   // heavy-first
    const float* A = SC + (long)z * SS * SS;
    const float* B = Vb + (long)b * SS * II + h * DHM;
    float* Cb = H + (long)z * SS * DHM;
    const int kend = (by + 1) * 128;
    __shared__ float As[128 * SPAD];
    __shared__ float Bs[128 * SPAD];
    const int tid = threadIdx.x;
    const int lane = tid & 31, warp = tid >> 5;
    const int wm = warp & 3, wn = warp >> 2;
    const int g = lane >> 2, t = lane & 3;
    const int lr = tid >> 1, lc = (tid & 1) * 16;
    const float* Ag = A + (long)(by*128 + lr) * SS + lc;
    const int bkr = tid >> 3;
    const int bc4 = tid & 7;
    const float* Bg = B + (long)bkr * II + bx*128;

    float c[16][4];
    #pragma unroll
    for (int i = 0; i < 16; i++)
        #pragma unroll
        for (int j = 0; j < 4; j++) c[i][j] = 0.f;

    float4 a4[4], b4[4];
    #pragma unroll
    for (int i = 0; i < 4; i++) {
        a4[i] = *(const float4*)(Ag + i*4);
        b4[i] = *(const float4*)(Bg + (bc4 + i*8) * 4);
    }
    const int nk = kend >> 5;
    for (int kt = 0; kt < nk; kt++) {
        __syncthreads();
        #pragma unroll
        for (int i = 0; i < 4; i++) {
            uint4 av = make_uint4(f2tf32(a4[i].x), f2tf32(a4[i].y),
                                  f2tf32(a4[i].z), f2tf32(a4[i].w));
            *(uint4*)&As[lr * SPAD + lc + i*4] = av;
            int coln = (bc4 + i*8) * 4;
            Bs[(coln+0) * SPAD + bkr] = __uint_as_float(f2tf32(b4[i].x));
            Bs[(coln+1) * SPAD + bkr] = __uint_as_float(f2tf32(b4[i].y));
            Bs[(coln+2) * SPAD + bkr] = __uint_as_float(f2tf32(b4[i].z));
            Bs[(coln+3) * SPAD + bkr] = __uint_as_float(f2tf32(b4[i].w));
        }
        __syncthreads();
        if (kt + 1 < nk) {
            const int k0 = (kt + 1) << 5;
            #pragma unroll
            for (int i = 0; i < 4; i++) {
                a4[i] = *(const float4*)(Ag + k0 + i*4);
                b4[i] = *(const float4*)(Bg + (long)k0 * II + (bc4 + i*8) * 4);
            }
        }
        #pragma unroll
        for (int kk = 0; kk < 4; kk++) {
            const int ks = kk * 8;
            uint32_t af[2][4], bf[8][2];
            #pragma unroll
            for (int mt = 0; mt < 2; mt++) {
                int r0 = wm*32 + mt*16 + g;
                af[mt][0] = __float_as_uint(As[r0 * SPAD + ks + t]);
                af[mt][1] = __float_as_uint(As[(r0+8) * SPAD + ks + t]);
                af[mt][2] = __float_as_uint(As[r0 * SPAD + ks + t + 4]);
                af[mt][3] = __float_as_uint(As[(r0+8) * SPAD + ks + t + 4]);
            }
            #pragma unroll
            for (int nt = 0; nt < 8; nt++) {
                int c0 = wn*64 + nt*8 + g;
                bf[nt][0] = __float_as_uint(Bs[c0 * SPAD + ks + t]);
                bf[nt][1] = __float_as_uint(Bs[c0 * SPAD + ks + t + 4]);
            }
            #pragma unroll
            for (int mt = 0; mt < 2; mt++)
                #pragma unroll
                for (int nt = 0; nt < 8; nt++)
                    mma_tf32(c[mt*8 + nt], af[mt], bf[nt]);
        }
    }
    const float* rz = rns + (long)z * SS;
    const float* ez = en + (long)z * SS;
    #pragma unroll
    for (int mt = 0; mt < 2; mt++) {
        int row0 = by*128 + wm*32 + mt*16 + g;
        int row1 = row0 + 8;
        float rn0 = 1.f / (fmaxf(fabsf(rz[row0]), ez[row0]) + 1e-6f);
        float rn1 = 1.f / (fmaxf(fabsf(rz[row1]), ez[row1]) + 1e-6f);
        #pragma unroll
        for (int nt = 0; nt < 8; nt++) {
            int col0 = bx*128 + wn*64 + nt*8 + 2*t;
            float* v = c[mt*8 + nt];
            float* C0 = Cb + (long)row0 * DHM + col0;
            float* C1 = Cb + (long)row1 * DHM + col0;
            C0[0] = v[0]*rn0; C0[1] = v[1]*rn0;
            C1[0] = v[2]*rn1; C1[1] = v[3]*rn1;
        }
    }
}

// ---------------- causal depthwise conv (K=4) + SiLU (sLSTM path) ----------------
template<int C, int LDIN>
__global__ void conv_silu_t(const float* __restrict__ in, const float* __restrict__ w,
                            const float* __restrict__ bias, float* __restrict__ out)
{
    long idx = (long)blockIdx.x * 256 + threadIdx.x;
    if (idx >= (long)BS * C) return;
    int c = (int)(idx & (C - 1));
    long bs = idx / C;
    int s = (int)(bs & (SS - 1));
    float acc = bias[c];
    #pragma unroll
    for (int kk = 0; kk < 4; kk++) {
        int sp = s + kk - 3;
        if (sp >= 0) acc += in[(bs + kk - 3) * (long)LDIN + c] * w[c*4 + kk];
    }
    out[bs * (long)C + c] = acc / (1.f + __expf(-acc));
}

// ---------------- fused conv+SiLU+headwise qkv (mLSTM path) ----------------
__global__ void conv_qkv(const float* __restrict__ up, const float* __restrict__ cw,
                         const float* __restrict__ cb,
                         const float* __restrict__ qw, const float* __restrict__ kw,
                         const float* __restrict__ vw,
                         float* __restrict__ xa, float* __restrict__ q,
                         float* __restrict__ k, float* __restrict__ v)
{
    long idx = (long)blockIdx.x * 256 + threadIdx.x;
    if (idx >= (long)BS * 512) return;
    int nb = (int)(idx & 511);
    long bs = idx >> 9;
    int s = (int)(bs & (SS - 1));
    const float* upc = up + bs * (2L*II) + nb*4;
    float rr[4][4];
    *(float4*)rr[3] = *(const float4*)upc;
    if (s >= 1) *(float4*)rr[2] = *(const float4*)(upc - (2L*II));
    else rr[2][0] = rr[2][1] = rr[2][2] = rr[2][3] = 0.f;
    if (s >= 2) *(float4*)rr[1] = *(const float4*)(upc - 2*(2L*II));
    else rr[1][0] = rr[1][1] = rr[1][2] = rr[1][3] = 0.f;
    if (s >= 3) *(float4*)rr[0] = *(const float4*)(upc - 3*(2L*II));
    else rr[0][0] = rr[0][1] = rr[0][2] = rr[0][3] = 0.f;

    float xo[4];
    #pragma unroll
    for (int i = 0; i < 4; i++) {
        int c = nb*4 + i;
        float acc = cb[c];
        #pragma unroll
        for (int kk = 0; kk < 4; kk++)
            acc += rr[kk][i] * cw[c*4 + kk];
        xo[i] = acc / (1.f + __expf(-acc));
    }
    *(float4*)(xa + bs * II + nb*4) = make_float4(xo[0], xo[1], xo[2], xo[3]);

    float qo[4], ko[4], vo[4];
    #pragma unroll
    for (int o = 0; o < 4; o++) {
        float aq = 0.f, ak = 0.f, av = 0.f;
        #pragma unroll
        for (int i = 0; i < 4; i++) {
            aq += xo[i]    * qw[nb*16 + o*4 + i];
            ak += xo[i]    * kw[nb*16 + o*4 + i];
            av += rr[3][i] * vw[nb*16 + o*4 + i];
        }
        qo[o] = aq; ko[o] = ak; vo[o] = av;
    }
    *(float4*)(q + bs * II + nb*4) = make_float4(qo[0], qo[1], qo[2], qo[3]);
    *(float4*)(k + bs * II + nb*4) = make_float4(ko[0], ko[1], ko[2], ko[3]);
    *(float4*)(v + bs * II + nb*4) = make_float4(vo[0], vo[1], vo[2], vo[3]);
}

// ---------------- ig/fg gate projections (float4) ----------------
__global__ void igfg_k(const float* __restrict__ q, const float* __restrict__ k,
                       const float* __restrict__ v,
                       const float* __restrict__ igw, const float* __restrict__ igb,
                       const float* __restrict__ fgw, const float* __restrict__ fgb,
                       float* __restrict__ ig, float* __restrict__ fg)
{
    long bs = blockIdx.x;
    int b = (int)(bs >> 10);
    int s = (int)(bs & (SS - 1));
    __shared__ float sx[3 * II];
    __shared__ float rbuf[2][8];
    int tid = threadIdx.x;
    for (int i = tid; i < II / 4; i += 256) {
        ((float4*)sx)[i]        = ((const float4*)(q + bs * II))[i];
        ((float4*)sx)[II/4 + i] = ((const float4*)(k + bs * II))[i];
        ((float4*)sx)[II/2 + i] = ((const float4*)(v + bs * II))[i];
    }
    __syncthreads();
    const float4* sx4 = (const float4*)sx;
    for (int h = 0; h < 4; h++) {
        const float4* iw4 = (const float4*)(igw + h * (3*II));
        const float4* fw4 = (const float4*)(fgw + h * (3*II));
        float pi = 0.f, pf = 0.f;
        for (int j = tid; j < (3*II)/4; j += 256) {
            float4 xv = sx4[j];
            float4 wi = iw4[j];
            float4 wf = fw4[j];
            pi += xv.x*wi.x + xv.y*wi.y + xv.z*wi.z + xv.w*wi.w;
            pf += xv.x*wf.x + xv.y*wf.y + xv.z*wf.z + xv.w*wf.w;
        }
        pi = warpSum(pi); pf = warpSum(pf);
        if ((tid & 31) == 0) { rbuf[0][tid >> 5] = pi; rbuf[1][tid >> 5] = pf; }
        __syncthreads();
        if (tid == 0) {
            float a = 0.f, bb = 0.f;
            #pragma unroll
            for (int w8 = 0; w8 < 8; w8++) { a += rbuf[0][w8]; bb += rbuf[1][w8]; }
            ig[(long)(b*4 + h) * SS + s] = a + igb[h];
            fg[(long)(b*4 + h) * SS + s] = bb + fgb[h];
        }
        __syncthreads();
    }
}

// ---------------- mLSTM decay prep (+ zero RNS) ----------------
__global__ void mlstm_prep(const float* __restrict__ ig, const float* __restrict__ fg,
                           float* __restrict__ a, float* __restrict__ rm,
                           float* __restrict__ en, float* __restrict__ rns)
{
    int z = blockIdx.x;
    int tid = threadIdx.x;  // 256
    __shared__ float slsig[SS], sig_s[SS];
    for (int i = tid; i < SS; i += 256) {
        float fv = fg[(long)z * SS + i];
        slsig[i] = fminf(fv, 0.f) - log1pf(__expf(-fabsf(fv)));
        sig_s[i] = ig[(long)z * SS + i];
        rns[(long)z * SS + i] = 0.f;
    }
    __syncthreads();
    if (tid == 0) {
        float cs = 0.f, run = -1e30f;
        for (int s = 0; s < SS; s++) {
            cs += slsig[s];
            float av = sig_s[s] - cs;
            run = fmaxf(run, av);
            a[(long)z * SS + s]  = av;
            rm[(long)z * SS + s] = run;
            en[(long)z * SS + s] = __expf(-(cs + run));
        }
    }
}

// ---------------- mh_norm(dh=512) + (h+skip*xa)*silu(z) ----------------
__global__ void mh_mix(const float* __restrict__ H, const float* __restrict__ onw,
                       const float* __restrict__ skip, const float* __restrict__ xa,
                       const float* __restrict__ up, float* __restrict__ hmix)
{
    int bs = blockIdx.x, h = blockIdx.y;
    int b = bs >> 10;
    int s = bs & (SS - 1);
    const float* hp = H + ((long)(b*4 + h) * SS + s) * DHM;
    int tid = threadIdx.x;  // 128
    float4 v = ((const float4*)hp)[tid];
    float sm = v.x + v.y + v.z + v.w;
    float sq = v.x*v.x + v.y*v.y + v.z*v.z + v.w*v.w;
    __shared__ float s1[4], s2[4];
    sm = warpSum(sm); sq = warpSum(sq);
    if ((tid & 31) == 0) { s1[tid >> 5] = sm; s2[tid >> 5] = sq; }
    __syncthreads();
    float tot  = s1[0] + s1[1] + s1[2] + s1[3];
    float tot2 = s2[0] + s2[1] + s2[2] + s2[3];
    float mu = tot * (1.f / DHM);
    float rs = rsqrtf(tot2 * (1.f / DHM) - mu * mu + 1e-5f);
    float4 wv  = ((const float4*)onw)[h*128 + tid];
    float4 sk  = ((const float4*)skip)[h*128 + tid];
    float4 xav = ((const float4*)(xa + (long)bs * II))[h*128 + tid];
    float4 zv  = ((const float4*)(up + (long)bs * (2L*II) + II))[h*128 + tid];
    float4 o;
    o.x = ((v.x - mu)*rs*wv.x + sk.x*xav.x) * (zv.x / (1.f + __expf(-zv.x)));
    o.y = ((v.y - mu)*rs*wv.y + sk.y*xav.y) * (zv.y / (1.f + __expf(-zv.y)));
    o.z = ((v.z - mu)*rs*wv.z + sk.z*xav.z) * (zv.z / (1.f + __expf(-zv.z)));
    o.w = ((v.w - mu)*rs*wv.w + sk.w*xav.w) * (zv.w / (1.f + __expf(-zv.w)));
    ((float4*)(hmix + (long)bs * II))[h*128 + tid] = o;
}

// ============================================================================
// Cluster-split sLSTM scan v3: f32x2 matvec, d-quarter split, single barrier.
// Thread = (eg = tid&31 -> 4 e's, dq = tid>>5 -> 64 d's). dq0 warp reduces,
// adds pre+bias, broadcasts raws (b64 x2) to all 8 CTAs; every CTA computes
// the full activation redundantly into its local sh_h.
// ============================================================================
#define SCAN_SMEM_FLOATS (32768 + 256 + 2048 + 512)

__device__ __forceinline__ uint32_t smem_addr_u32(const void* p) {
    return (uint32_t)__cvta_generic_to_shared(p);
}
__device__ __forceinline__ uint32_t mapa_u32(uint32_t addr, uint32_t rank) {
    uint32_t out;
    asm("mapa.shared::cluster.u32 %0, %1, %2;" : "=r"(out) : "r"(addr), "r"(rank));
    return out;
}
__device__ __forceinline__ void st_cluster_u64(uint32_t addr, ull v) {
    asm volatile("st.shared::cluster.u64 [%0], %1;" :: "r"(addr), "l"(v) : "memory");
}
__device__ __forceinline__ void cluster_barrier() {
    asm volatile("barrier.cluster.arrive.aligned;" ::: "memory");
    asm volatile("barrier.cluster.wait.aligned;" ::: "memory");
}

__global__ void __launch_bounds__(128, 1) __cluster_dims__(8, 1, 1)
slstm_scan_cl(const float* __restrict__ pre, const float* __restrict__ rk,
              const float* __restrict__ rb, float* __restrict__ ys)
{
    extern __shared__ float sm[];
    float* W    = sm;                       // [256 d][128 el]
    float* sh_h = sm + 32768;               // [256]
    float* sraw = sm + 33024;               // [2][1024]
    ull*   spart = (ull*)(sm + 35072);      // [3][64]

    const int z = blockIdx.x >> 3;
    const int b = z >> 2, h = z & 3;
    uint32_t rank;
    asm("mov.u32 %0, %%cluster_ctarank;" : "=r"(rank));
    const int g  = rank >> 1;
    const int hf = rank & 1;
    const int tid = threadIdx.x;
    const int eg = tid & 31;
    const int dq = tid >> 5;
    const int el = eg * 4;

    const float* rks = rk + ((long)h * 256 * 4 + g) * 256 + hf * 128;
    for (int idx = tid; idx < 32768; idx += 128) {
        int d = idx >> 7, e2 = idx & 127;
        W[idx] = rks[(long)d * 1024 + e2];
    }
    for (int i = tid; i < 256; i += 128) sh_h[i] = 0.f;
    __syncthreads();

    const float* pb = pre + ((long)(g*4 + h) * BS + (long)b * SS) * DHS + hf*128 + el;
    float4 rbv4 = make_float4(0.f, 0.f, 0.f, 0.f);
    float4 pv4  = make_float4(0.f, 0.f, 0.f, 0.f);
    if (dq == 0) {
        rbv4 = *(const float4*)(rb + (h*4 + g) * DHS + hf*128 + el);
        pv4  = *(const float4*)pb;
    }

    uint32_t rdst[8];
    #pragma unroll
    for (int r = 0; r < 8; r++)
        rdst[r] = mapa_u32(smem_addr_u32(&sraw[g*256 + hf*128 + el]), (uint32_t)r);

    float* yo = ys + (long)z * SS * DHS;

    // redundant activation state: e0 = tid, e1 = tid + 128
    float c0 = 0.f, n0 = 0.f, m0 = 0.f;
    float c1 = 0.f, n1 = 0.f, m1 = 0.f;

    cluster_barrier();

    const float* Wp = W + el + (dq << 13);   // dq*64 d rows * 128
    for (int s = 0; s < SS; s++) {
        // matvec over this thread's 64-d quarter, f32x2 accumulation
        ull a01 = 0ull, a23 = 0ull;
        const int dbase = dq << 6;
        #pragma unroll
        for (int d4 = 0; d4 < 64; d4 += 4) {
            float4 h4 = *(const float4*)&sh_h[dbase + d4];
            F4U w;
            w.f = *(const float4*)&Wp[(d4+0) << 7];
            { ull hh = pack2(h4.x, h4.x); a01 = fma2(w.u[0], hh, a01); a23 = fma2(w.u[1], hh, a23); }
            w.f = *(const float4*)&Wp[(d4+1) << 7];
            { ull hh = pack2(h4.y, h4.y); a01 = fma2(w.u[0], hh, a01); a23 = fma2(w.u[1], hh, a23); }
            w.f = *(const float4*)&Wp[(d4+2) << 7];
            { ull hh = pack2(h4.z, h4.z); a01 = fma2(w.u[0], hh, a01); a23 = fma2(w.u[1], hh, a23); }
            w.f = *(const float4*)&Wp[(d4+3) << 7];
            { ull hh = pack2(h4.w, h4.w); a01 = fma2(w.u[0], hh, a01); a23 = fma2(w.u[1], hh, a23); }
        }
        if (dq > 0) {
            spart[(dq-1)*64 + eg*2]     = a01;
            spart[(dq-1)*64 + eg*2 + 1] = a23;
        }
        __syncthreads();
        if (dq == 0) {
            a01 = add2(a01, add2(spart[eg*2],     add2(spart[64 + eg*2],     spart[128 + eg*2])));
            a23 = add2(a23, add2(spart[eg*2 + 1], add2(spart[64 + eg*2 + 1], spart[128 + eg*2 + 1])));
            float f0, f1, f2, f3;
            unpack2(a01, f0, f1);
            unpack2(a23, f2, f3);
            f0 += pv4.x + rbv4.x; f1 += pv4.y + rbv4.y;
            f2 += pv4.z + rbv4.z; f3 += pv4.w + rbv4.w;
            if (s + 1 < SS) pv4 = *(const float4*)&pb[(long)(s+1) * DHS];
            ull o01 = pack2(f0, f1), o23 = pack2(f2, f3);
            const uint32_t po = (uint32_t)(s & 1) << 12;
            #pragma unroll
            for (int r = 0; r < 8; r++) {
                st_cluster_u64(rdst[r] + po,     o01);
                st_cluster_u64(rdst[r] + po + 8, o23);
            }
        }
        cluster_barrier();

        const float* rw = sraw + (s & 1) * 1024;
        {
            float iraw = rw[tid],       fraw = rw[256 + tid];
            float zraw = rw[512 + tid], oraw = rw[768 + tid];
            float lf = m0 + fminf(fraw, 0.f) - log1pf(__expf(-fabsf(fraw)));
            float mn = fmaxf(iraw, lf);
            float ig_ = __expf(iraw - mn);
            float fg_ = __expf(lf - mn);
            float th  = 1.f - __fdividef(2.f, __expf(2.f * zraw) + 1.f);
            c0 = fg_ * c0 + ig_ * th;
            n0 = fg_ * n0 + ig_;
            m0 = mn;
            float hv = c0 / (n0 * (1.f + __expf(-oraw)));
            sh_h[tid] = hv;
            if (rank == 0) yo[(long)s * DHS + tid] = hv;
        }
        {
            float iraw = rw[128 + tid], fraw = rw[384 + tid];
            float zraw = rw[640 + tid], oraw = rw[896 + tid];
            float lf = m1 + fminf(fraw, 0.f) - log1pf(__expf(-fabsf(fraw)));
            float mn = fmaxf(iraw, lf);
            float ig_ = __expf(iraw - mn);
            float fg_ = __expf(lf - mn);
            float th  = 1.f - __fdividef(2.f, __expf(2.f * zraw) + 1.f);
            c1 = fg_ * c1 + ig_ * th;
            n1 = fg_ * n1 + ig_;
            m1 = mn;
            float hv = c1 / (n1 * (1.f + __expf(-oraw)));
            sh_h[128 + tid] = hv;
            if (rank == 0) yo[(long)s * DHS + 128 + tid] = hv;
        }
        __syncthreads();
    }
}

// ---------------- sLSTM group norm (256) + residual add ----------------
__global__ void slstm_gnorm(const float* __restrict__ ys, const float* __restrict__ gnw,
                            float* __restrict__ x)
{
    int bs = blockIdx.x, h = blockIdx.y;
    int b = bs >> 10, s = bs & (SS - 1);
    const float* yp = ys + ((long)(b*4 + h) * SS + s) * DHS;
    int tid = threadIdx.x;  // 64
    float4 v = ((const float4*)yp)[tid];
    float sm = v.x + v.y + v.z + v.w;
    float sq = v.x*v.x + v.y*v.y + v.z*v.z + v.w*v.w;
    __shared__ float s1[2], s2[2];
    sm = warpSum(sm); sq = warpSum(sq);
    if ((tid & 31) == 0) { s1[tid >> 5] = sm; s2[tid >> 5] = sq; }
    __syncthreads();
    float tot  = s1[0] + s1[1];
    float tot2 = s2[0] + s2[1];
    float mu = tot * (1.f / DHS);
    float rs = rsqrtf(tot2 * (1.f / DHS) - mu * mu + 1e-5f);
    float4 wv = ((const float4*)gnw)[h*64 + tid];
    float* xp = x + (long)bs * DD + h * DHS + tid * 4;
    float4 xv = *(float4*)xp;
    xv.x += (v.x - mu) * rs * wv.x;
    xv.y += (v.y - mu) * rs * wv.y;
    xv.z += (v.z - mu) * rs * wv.z;
    xv.w += (v.w - mu) * rs * wv.w;
    *(float4*)xp = xv;
}

// ---------------- FFN: act = gelu_exact(gate) * up ----------------
__global__ void gelu_mul(const float* __restrict__ f, float* __restrict__ a)
{
    long idx = (long)blockIdx.x * 256 + threadIdx.x;
    if (idx >= (long)BS * UU) return;
    long bs = idx / UU;
    int u = (int)(idx % UU);
    float g = f[bs * (2L*UU) + u];
    float p = f[bs * (2L*UU) + UU + u];
    a[idx] = 0.5f * g * (1.f + erff(g * 0.70710678118654752f)) * p;
}

// ---------------- host ----------------
static inline void gemm(const float* A, const float* B, float* C,
                        int M, int N, int K, int lda, int ldb, int ldc,
                        float alpha, const float* bias, int acc)
{
    dim3 grid(N / 128, M / 128);
    tgemm_nt<<<grid, 256>>>(A, B, C, M, N, K, lda, ldb, ldc, alpha, bias, acc);
}

extern "C" void kernel_launch(void* const* d_in, const int* in_sizes, int n_in,
                              void* d_out, int out_size)
{
    const int*   ids       = (const int*)  d_in[0];
    const float* emb       = (const float*)d_in[1];
    const float* m_ln_w    = (const float*)d_in[2];
    const float* m_up_w    = (const float*)d_in[3];
    const float* m_conv_w  = (const float*)d_in[4];
    const float* m_conv_b  = (const float*)d_in[5];
    const float* m_q_w     = (const float*)d_in[6];
    const float* m_k_w     = (const float*)d_in[7];
    const float* m_v_w     = (const float*)d_in[8];
    const float* m_ig_w    = (const float*)d_in[9];
    const float* m_ig_b    = (const float*)d_in[10];
    const float* m_fg_w    = (const float*)d_in[11];
    const float* m_fg_b    = (const float*)d_in[12];
    const float* m_skip    = (const float*)d_in[13];
    const float* m_on_w    = (const float*)d_in[14];
    const float* m_down_w  = (const float*)d_in[15];
    const float* s_ln_w    = (const float*)d_in[16];
    const float* s_conv_w  = (const float*)d_in[17];
    const float* s_conv_b  = (const float*)d_in[18];
    const float* s_iw      = (const float*)d_in[19];
    const float* s_fw      = (const float*)d_in[20];
    const float* s_zw      = (const float*)d_in[21];
    const float* s_ow      = (const float*)d_in[22];
    const float* s_rk      = (const float*)d_in[23];
    const float* s_rb      = (const float*)d_in[24];
    const float* s_gn_w    = (const float*)d_in[25];
    const float* s_ln2_w   = (const float*)d_in[26];
    const float* s_ffn_up  = (const float*)d_in[27];
    const float* s_ffn_dn  = (const float*)d_in[28];
    const float* post_ln_w = (const float*)d_in[29];
    const float* head_w    = (const float*)d_in[30];
    const float* head_b    = (const float*)d_in[31];
    float* out = (float*)d_out;

    float* pool = nullptr;
    cudaGetSymbolAddress((void**)&pool, g_pool);
    float* X   = pool + O_X;   float* XN  = pool + O_XN;  float* XC  = pool + O_XC;
    float* UP  = pool + O_UP;  float* XA  = pool + O_XA;
    float* Q_  = pool + O_Q;   float* K_  = pool + O_K;   float* V_  = pool + O_V;
    float* SC  = pool + O_SC;  float* HB  = pool + O_HB;  float* HM  = pool + O_HM;
    float* PRE = pool + O_PRE; float* YS  = pool + O_YS;
    float* FFN = pool + O_FFN; float* ACT = pool + O_ACT;
    float* IG  = pool + O_IG;  float* FG  = pool + O_FG;
    float* Aa  = pool + O_A;   float* RM  = pool + O_RM;
    float* EN  = pool + O_EN;  float* RNS = pool + O_RNS;

    cudaFuncSetAttribute(slstm_scan_cl,
                         cudaFuncAttributeMaxDynamicSharedMemorySize,
                         SCAN_SMEM_FLOATS * 4);

    embed_k<<<BS, 256>>>(ids, emb, X);

    int mi = 0;
    for (int blk = 0; blk < 4; blk++) {
        if (blk == 1) {
            // ---------------- sLSTM block ----------------
            layernorm_k<<<BS, 256>>>(X, s_ln_w, XN);
            conv_silu_t<DD, DD><<<(BS * DD) / 256, 256>>>(XN, s_conv_w, s_conv_b, XC);
            tgemm_gates<<<dim3(2, 32, 16), 256>>>(XC, XN, s_iw, s_fw, s_zw, s_ow, PRE);
            slstm_scan_cl<<<128, 128, SCAN_SMEM_FLOATS * 4>>>(PRE, s_rk, s_rb, YS);
            slstm_gnorm<<<dim3(BS, 4), 64>>>(YS, s_gn_w, X);
            layernorm_k<<<BS, 256>>>(X, s_ln2_w, XN);
            gemm(XN, s_ffn_up, FFN, BS, 2*UU, DD, DD, DD, 2*UU, 1.f, nullptr, 0);
            gelu_mul<<<(int)(((long)BS*UU + 255) / 256), 256>>>(FFN, ACT);
            gemm(ACT, s_ffn_dn, X, BS, DD, UU, UU, UU, DD, 1.f, nullptr, 1);
        } else {
            // ---------------- mLSTM block ----------------
            layernorm_k<<<BS, 256>>>(X, m_ln_w + (long)mi*DD, XN);
            gemm(XN, m_up_w + (long)mi*4096*DD, UP, BS, 4096, DD, DD, DD, 4096,
                 1.f, nullptr, 0);
            conv_qkv<<<(int)(((long)BS*512) / 256), 256>>>(
                UP, m_conv_w + (long)mi*II*4, m_conv_b + (long)mi*II,
                m_q_w + (long)mi*512*16, m_k_w + (long)mi*512*16,
                m_v_w + (long)mi*512*16, XA, Q_, K_, V_);
            igfg_k<<<BS, 256>>>(Q_, K_, V_,
                m_ig_w + (long)mi*4*6144, m_ig_b + (long)mi*4,
                m_fg_w + (long)mi*4*6144, m_fg_b + (long)mi*4, IG, FG);
            mlstm_prep<<<16, 256>>>(IG, FG, Aa, RM, EN, RNS);
            attn_qk<<<dim3(36, 1, 16), 256>>>(Q_, K_, SC, Aa, RM, RNS);
            attn_av<<<dim3(4, 8, 16), 256>>>(SC, V_, RNS, EN, HB);
            mh_mix<<<dim3(BS, 4), 128>>>(HB, m_on_w + (long)mi*II,
                m_skip + (long)mi*II, XA, UP, HM);
            gemm(HM, m_down_w + (long)mi*DD*II, X, BS, DD, II, II, II, DD,
                 1.f, nullptr, 1);
            mi++;
        }
    }

    layernorm_k<<<BS, 256>>>(X, post_ln_w, XN);
    gemm(XN, head_w, out, BS, 256, DD, DD, DD, 256, 1.f, head_b, 0);
}

// round 11
// speedup vs baseline: 6.5973x; 1.0784x over previous
#include <cuda_runtime.h>
#include <cuda_bf16.h>
#include <math.h>
#include <stdint.h>

#define BB 4
#define SS 1024
#define DD 1024
#define II 2048
#define BS 4096
#define DHM 512
#define DHS 256
#define UU 1344

constexpr long SZ_X   = (long)BS * DD;
constexpr long SZ_UP  = (long)BS * 2 * II;
constexpr long SZ_I   = (long)BS * II;
constexpr long SZ_SC  = 16L * SS * SS;
constexpr long SZ_HB  = 16L * SS * DHM;
constexpr long SZ_PRE = 16L * BS * DHS;
constexpr long SZ_YS  = 16L * SS * DHS;
constexpr long SZ_FFN = (long)BS * 2 * UU;
constexpr long SZ_ACT = (long)BS * UU;
constexpr long SZ_V16 = 16L * SS;

constexpr long O_X   = 0;
constexpr long O_XN  = O_X   + SZ_X;
constexpr long O_XC  = O_XN  + SZ_X;
constexpr long O_UP  = O_XC  + SZ_X;
constexpr long O_XA  = O_UP  + SZ_UP;
constexpr long O_Q   = O_XA  + SZ_I;
constexpr long O_K   = O_Q   + SZ_I;
constexpr long O_V   = O_K   + SZ_I;
constexpr long O_SC  = O_V   + SZ_I;
constexpr long O_HB  = O_SC  + SZ_SC;
constexpr long O_HM  = O_HB  + SZ_HB;
constexpr long O_PRE = O_HM  + SZ_I;
constexpr long O_YS  = O_PRE + SZ_PRE;
constexpr long O_FFN = O_YS  + SZ_YS;
constexpr long O_ACT = O_FFN + SZ_FFN;
constexpr long O_IG  = O_ACT + SZ_ACT;
constexpr long O_FG  = O_IG  + SZ_V16;
constexpr long O_A   = O_FG  + SZ_V16;
constexpr long O_RM  = O_A   + SZ_V16;
constexpr long O_EN  = O_RM  + SZ_V16;
constexpr long O_RNS = O_EN  + SZ_V16;
constexpr long POOL_SZ = O_RNS + SZ_V16;

__device__ float g_pool[POOL_SZ];

__device__ __forceinline__ float warpSum(float v) {
    #pragma unroll
    for (int o = 16; o > 0; o >>= 1) v += __shfl_down_sync(0xffffffffu, v, o);
    return v;
}

// ---------------- tf32 mma helpers ----------------
__device__ __forceinline__ uint32_t f2tf32(float f) {
    uint32_t r;
    asm("cvt.rna.tf32.f32 %0, %1;" : "=r"(r) : "f"(f));
    return r;
}
__device__ __forceinline__ void mma_tf32(float* c, const uint32_t* a, const uint32_t* b) {
    asm volatile(
        "mma.sync.aligned.m16n8k8.row.col.f32.tf32.tf32.f32 "
        "{%0,%1,%2,%3}, {%4,%5,%6,%7}, {%8,%9}, {%0,%1,%2,%3};"
        : "+f"(c[0]), "+f"(c[1]), "+f"(c[2]), "+f"(c[3])
        : "r"(a[0]), "r"(a[1]), "r"(a[2]), "r"(a[3]), "r"(b[0]), "r"(b[1]));
}
#define SPAD 36

// ---------------- f32x2 helpers ----------------
typedef unsigned long long ull;
__device__ __forceinline__ ull pack2(float a, float b) {
    ull r; asm("mov.b64 %0, {%1,%2};" : "=l"(r) : "f"(a), "f"(b)); return r;
}
__device__ __forceinline__ ull fma2(ull a, ull b, ull c) {
    ull r; asm("fma.rn.f32x2 %0, %1, %2, %3;" : "=l"(r) : "l"(a), "l"(b), "l"(c)); return r;
}
__device__ __forceinline__ ull add2(ull a, ull b) {
    ull r; asm("add.rn.f32x2 %0, %1, %2;" : "=l"(r) : "l"(a), "l"(b)); return r;
}
__device__ __forceinline__ void unpack2(ull v, float& a, float& b) {
    asm("mov.b64 {%0,%1}, %2;" : "=f"(a), "=f"(b) : "l"(v));
}
union F4U { float4 f; ull u[2]; };

// ---------------- embedding gather ----------------
__global__ void embed_k(const int* __restrict__ ids, const float* __restrict__ emb,
                        float* __restrict__ x)
{
    int bs = blockIdx.x;
    long id = ids[bs];
    ((float4*)(x + (long)bs * DD))[threadIdx.x] =
        ((const float4*)(emb + id * DD))[threadIdx.x];
}

// ---------------- LayerNorm width 1024, 256 thr/row ----------------
__global__ void layernorm_k(const float* __restrict__ x, const float* __restrict__ w,
                            float* __restrict__ y)
{
    long row = blockIdx.x;
    int tid = threadIdx.x;
    float4 v = ((const float4*)(x + row * DD))[tid];
    float s = v.x + v.y + v.z + v.w;
    float ss = v.x*v.x + v.y*v.y + v.z*v.z + v.w*v.w;
    __shared__ float sb[8], sb2[8];
    __shared__ float mu_s, rs_s;
    s = warpSum(s); ss = warpSum(ss);
    if ((tid & 31) == 0) { sb[tid >> 5] = s; sb2[tid >> 5] = ss; }
    __syncthreads();
    if (tid == 0) {
        float t = 0.f, t2 = 0.f;
        #pragma unroll
        for (int i = 0; i < 8; i++) { t += sb[i]; t2 += sb2[i]; }
        float mu = t * (1.f / DD);
        mu_s = mu;
        rs_s = rsqrtf(t2 * (1.f / DD) - mu * mu + 1e-5f);
    }
    __syncthreads();
    float mu = mu_s, rs = rs_s;
    float4 wv = ((const float4*)w)[tid];
    float4 o;
    o.x = (v.x - mu) * rs * wv.x;  o.y = (v.y - mu) * rs * wv.y;
    o.z = (v.z - mu) * rs * wv.z;  o.w = (v.w - mu) * rs * wv.w;
    ((float4*)(y + row * DD))[tid] = o;
}

// ============================================================================
// tf32 GEMM NT (LDG prefetch + cvt.rna + STS). C = alpha*A@B^T [+bias][+=C]
// ============================================================================
__global__ void __launch_bounds__(256, 2) tgemm_nt(
    const float* __restrict__ A, const float* __restrict__ B, float* __restrict__ C,
    int M, int N, int K, int lda, int ldb, int ldc,
    float alpha, const float* __restrict__ bias, int acc)
{
    __shared__ float As[128 * SPAD];
    __shared__ float Bs[128 * SPAD];
    const int tid = threadIdx.x;
    const int lane = tid & 31, warp = tid >> 5;
    const int wm = warp & 3, wn = warp >> 2;
    const int g = lane >> 2, t = lane & 3;
    const int lr = tid >> 1, lc = (tid & 1) * 16;
    const float* Ag = A + (long)(blockIdx.y * 128 + lr) * lda + lc;
    const float* Bg = B + (long)(blockIdx.x * 128 + lr) * ldb + lc;

    float c[16][4];
    #pragma unroll
    for (int i = 0; i < 16; i++)
        #pragma unroll
        for (int j = 0; j < 4; j++) c[i][j] = 0.f;

    float4 a4[4], b4[4];
    #pragma unroll
    for (int i = 0; i < 4; i++) {
        a4[i] = *(const float4*)(Ag + i*4);
        b4[i] = *(const float4*)(Bg + i*4);
    }
    const int nk = K >> 5;
    for (int kt = 0; kt < nk; kt++) {
        __syncthreads();
        #pragma unroll
        for (int i = 0; i < 4; i++) {
            uint4 av = make_uint4(f2tf32(a4[i].x), f2tf32(a4[i].y),
                                  f2tf32(a4[i].z), f2tf32(a4[i].w));
            uint4 bv = make_uint4(f2tf32(b4[i].x), f2tf32(b4[i].y),
                                  f2tf32(b4[i].z), f2tf32(b4[i].w));
            *(uint4*)&As[lr * SPAD + lc + i*4] = av;
            *(uint4*)&Bs[lr * SPAD + lc + i*4] = bv;
        }
        __syncthreads();
        if (kt + 1 < nk) {
            const int k0 = (kt + 1) << 5;
            #pragma unroll
            for (int i = 0; i < 4; i++) {
                a4[i] = *(const float4*)(Ag + k0 + i*4);
                b4[i] = *(const float4*)(Bg + k0 + i*4);
            }
        }
        #pragma unroll
        for (int kk = 0; kk < 4; kk++) {
            const int ks = kk * 8;
            uint32_t af[2][4], bf[8][2];
            #pragma unroll
            for (int mt = 0; mt < 2; mt++) {
                int r0 = wm*32 + mt*16 + g;
                af[mt][0] = __float_as_uint(As[r0 * SPAD + ks + t]);
                af[mt][1] = __float_as_uint(As[(r0+8) * SPAD + ks + t]);
                af[mt][2] = __float_as_uint(As[r0 * SPAD + ks + t + 4]);
                af[mt][3] = __float_as_uint(As[(r0+8) * SPAD + ks + t + 4]);
            }
            #pragma unroll
            for (int nt = 0; nt < 8; nt++) {
                int c0 = wn*64 + nt*8 + g;
                bf[nt][0] = __float_as_uint(Bs[c0 * SPAD + ks + t]);
                bf[nt][1] = __float_as_uint(Bs[c0 * SPAD + ks + t + 4]);
            }
            #pragma unroll
            for (int mt = 0; mt < 2; mt++)
                #pragma unroll
                for (int nt = 0; nt < 8; nt++)
                    mma_tf32(c[mt*8 + nt], af[mt], bf[nt]);
        }
    }
    #pragma unroll
    for (int mt = 0; mt < 2; mt++) {
        int row0 = blockIdx.y*128 + wm*32 + mt*16 + g;
        #pragma unroll
        for (int nt = 0; nt < 8; nt++) {
            int col0 = blockIdx.x*128 + wn*64 + nt*8 + 2*t;
            float* v = c[mt*8 + nt];
            float b0 = bias ? bias[col0] : 0.f, b1 = bias ? bias[col0+1] : 0.f;
            float* C0 = C + (long)row0 * ldc + col0;
            float* C1 = C + (long)(row0+8) * ldc + col0;
            float o0 = v[0]*alpha + b0, o1 = v[1]*alpha + b1;
            float o2 = v[2]*alpha + b0, o3 = v[3]*alpha + b1;
            if (acc) { o0 += C0[0]; o1 += C0[1]; o2 += C1[0]; o3 += C1[1]; }
            C0[0] = o0; C0[1] = o1; C1[0] = o2; C1[1] = o3;
        }
    }
}

// ============================================================================
// tf32 batched sLSTM gate GEMMs: PRE[zz] = src @ W[h]^T, zz=(g*4+h)
// ============================================================================
__global__ void __launch_bounds__(256, 2) tgemm_gates(
    const float* __restrict__ XC, const float* __restrict__ XN,
    const float* __restrict__ iw, const float* __restrict__ fw,
    const float* __restrict__ zw, const float* __restrict__ ow,
    float* __restrict__ PRE)
{
    const int zz = blockIdx.z;
    const int gg = zz >> 2, hh = zz & 3;
    const float* A = ((gg < 2) ? XC : XN) + hh * 256;
    const float* Wsel = (gg == 0) ? iw : (gg == 1) ? fw : (gg == 2) ? zw : ow;
    const float* B = Wsel + (long)hh * 65536;
    float* C = PRE + (long)zz * BS * DHS;

    __shared__ float As[128 * SPAD];
    __shared__ float Bs[128 * SPAD];
    const int tid = threadIdx.x;
    const int lane = tid & 31, warp = tid >> 5;
    const int wm = warp & 3, wn = warp >> 2;
    const int g = lane >> 2, t = lane & 3;
    const int lr = tid >> 1, lc = (tid & 1) * 16;
    const float* Ag = A + (long)(blockIdx.y * 128 + lr) * DD + lc;
    const float* Bg = B + (long)(blockIdx.x * 128 + lr) * 256 + lc;

    float c[16][4];
    #pragma unroll
    for (int i = 0; i < 16; i++)
        #pragma unroll
        for (int j = 0; j < 4; j++) c[i][j] = 0.f;

    float4 a4[4], b4[4];
    #pragma unroll
    for (int i = 0; i < 4; i++) {
        a4[i] = *(const float4*)(Ag + i*4);
        b4[i] = *(const float4*)(Bg + i*4);
    }
    const int nk = 256 >> 5;
    for (int kt = 0; kt < nk; kt++) {
        __syncthreads();
        #pragma unroll
        for (int i = 0; i < 4; i++) {
            uint4 av = make_uint4(f2tf32(a4[i].x), f2tf32(a4[i].y),
                                  f2tf32(a4[i].z), f2tf32(a4[i].w));
            uint4 bv = make_uint4(f2tf32(b4[i].x), f2tf32(b4[i].y),
                                  f2tf32(b4[i].z), f2tf32(b4[i].w));
            *(uint4*)&As[lr * SPAD + lc + i*4] = av;
            *(uint4*)&Bs[lr * SPAD + lc + i*4] = bv;
        }
        __syncthreads();
        if (kt + 1 < nk) {
            const int k0 = (kt + 1) << 5;
            #pragma unroll
            for (int i = 0; i < 4; i++) {
                a4[i] = *(const float4*)(Ag + k0 + i*4);
                b4[i] = *(const float4*)(Bg + k0 + i*4);
            }
        }
        #pragma unroll
        for (int kk = 0; kk < 4; kk++) {
            const int ks = kk * 8;
            uint32_t af[2][4], bf[8][2];
            #pragma unroll
            for (int mt = 0; mt < 2; mt++) {
                int r0 = wm*32 + mt*16 + g;
                af[mt][0] = __float_as_uint(As[r0 * SPAD + ks + t]);
                af[mt][1] = __float_as_uint(As[(r0+8) * SPAD + ks + t]);
                af[mt][2] = __float_as_uint(As[r0 * SPAD + ks + t + 4]);
                af[mt][3] = __float_as_uint(As[(r0+8) * SPAD + ks + t + 4]);
            }
            #pragma unroll
            for (int nt = 0; nt < 8; nt++) {
                int c0 = wn*64 + nt*8 + g;
                bf[nt][0] = __float_as_uint(Bs[c0 * SPAD + ks + t]);
                bf[nt][1] = __float_as_uint(Bs[c0 * SPAD + ks + t + 4]);
            }
            #pragma unroll
            for (int mt = 0; mt < 2; mt++)
                #pragma unroll
                for (int nt = 0; nt < 8; nt++)
                    mma_tf32(c[mt*8 + nt], af[mt], bf[nt]);
        }
    }
    #pragma unroll
    for (int mt = 0; mt < 2; mt++) {
        int row0 = blockIdx.y*128 + wm*32 + mt*16 + g;
        #pragma unroll
        for (int nt = 0; nt < 8; nt++) {
            int col0 = blockIdx.x*128 + wn*64 + nt*8 + 2*t;
            float* v = c[mt*8 + nt];
            float* C0 = C + (long)row0 * 256 + col0;
            float* C1 = C + (long)(row0+8) * 256 + col0;
            C0[0] = v[0]; C0[1] = v[1];
            C1[0] = v[2]; C1[1] = v[3];
        }
    }
}

// ============================================================================
// tf32 attention scores, triangle grid, fused row-sums.
// ============================================================================
__global__ void __launch_bounds__(256, 2) attn_qk(
    const float* __restrict__ Qb, const float* __restrict__ Kb,
    float* __restrict__ SC, const float* __restrict__ a_,
    const float* __restrict__ rm_, float* __restrict__ rns)
{
    const int z = blockIdx.z;
    const int b = z >> 2, h = z & 3;
    int by = 0;
    int bx = blockIdx.x;
    while ((by + 1) * (by + 2) / 2 <= bx) by++;
    bx -= by * (by + 1) / 2;

    float* Cb = SC + (long)z * SS * SS;
    const float* A = Qb + (long)b * SS * II + h * DHM;
    const float* B = Kb + (long)b * SS * II + h * DHM;
    __shared__ float As[128 * SPAD];
    __shared__ float Bs[128 * SPAD];
    const int tid = threadIdx.x;
    const int lane = tid & 31, warp = tid >> 5;
    const int wm = warp & 3, wn = warp >> 2;
    const int g = lane >> 2, t = lane & 3;
    const int lr = tid >> 1, lc = (tid & 1) * 16;
    const float* Ag = A + (long)(by*128 + lr) * II + lc;
    const float* Bg = B + (long)(bx*128 + lr) * II + lc;

    float c[16][4];
    #pragma unroll
    for (int i = 0; i < 16; i++)
        #pragma unroll
        for (int j = 0; j < 4; j++) c[i][j] = 0.f;

    float4 a4[4], b4[4];
    #pragma unroll
    for (int i = 0; i < 4; i++) {
        a4[i] = *(const float4*)(Ag + i*4);
        b4[i] = *(const float4*)(Bg + i*4);
    }
    const int nk = DHM >> 5;
    for (int kt = 0; kt < nk; kt++) {
        __syncthreads();
        #pragma unroll
        for (int i = 0; i < 4; i++) {
            uint4 av = make_uint4(f2tf32(a4[i].x), f2tf32(a4[i].y),
                                  f2tf32(a4[i].z), f2tf32(a4[i].w));
            uint4 bv = make_uint4(f2tf32(b4[i].x), f2tf32(b4[i].y),
                                  f2tf32(b4[i].z), f2tf32(b4[i].w));
            *(uint4*)&As[lr * SPAD + lc + i*4] = av;
            *(uint4*)&Bs[lr * SPAD + lc + i*4] = bv;
        }
        __syncthreads();
        if (kt + 1 < nk) {
            const int k0 = (kt + 1) << 5;
            #pragma unroll
            for (int i = 0; i < 4; i++) {
                a4[i] = *(const float4*)(Ag + k0 + i*4);
                b4[i] = *(const float4*)(Bg + k0 + i*4);
            }
        }
        #pragma unroll
        for (int kk = 0; kk < 4; kk++) {
            const int ks = kk * 8;
            uint32_t af[2][4], bf[8][2];
            #pragma unroll
            for (int mt = 0; mt < 2; mt++) {
                int r0 = wm*32 + mt*16 + g;
                af[mt][0] = __float_as_uint(As[r0 * SPAD + ks + t]);
                af[mt][1] = __float_as_uint(As[(r0+8) * SPAD + ks + t]);
                af[mt][2] = __float_as_uint(As[r0 * SPAD + ks + t + 4]);
                af[mt][3] = __float_as_uint(As[(r0+8) * SPAD + ks + t + 4]);
            }
            #pragma unroll
            for (int nt = 0; nt < 8; nt++) {
                int c0 = wn*64 + nt*8 + g;
                bf[nt][0] = __float_as_uint(Bs[c0 * SPAD + ks + t]);
                bf[nt][1] = __float_as_uint(Bs[c0 * SPAD + ks + t + 4]);
            }
            #pragma unroll
            for (int mt = 0; mt < 2; mt++)
                #pragma unroll
                for (int nt = 0; nt < 8; nt++)
                    mma_tf32(c[mt*8 + nt], af[mt], bf[nt]);
        }
    }
    const float* az = a_ + (long)z * SS;
    const float* rz = rm_ + (long)z * SS;
    const float alpha = 0.04419417382415922f;  // 1/sqrt(512)
    float rsum[2][2] = {{0.f, 0.f}, {0.f, 0.f}};
    #pragma unroll
    for (int mt = 0; mt < 2; mt++) {
        int row0 = by*128 + wm*32 + mt*16 + g;
        int row1 = row0 + 8;
        float rm0 = rz[row0], rm1 = rz[row1];
        #pragma unroll
        for (int nt = 0; nt < 8; nt++) {
            int col0 = bx*128 + wn*64 + nt*8 + 2*t;
            float av0 = az[col0], av1 = az[col0+1];
            float* v = c[mt*8 + nt];
            float o00 = (col0   <= row0) ? v[0]*alpha*__expf(av0 - rm0) : 0.f;
            float o01 = (col0+1 <= row0) ? v[1]*alpha*__expf(av1 - rm0) : 0.f;
            float o10 = (col0   <= row1) ? v[2]*alpha*__expf(av0 - rm1) : 0.f;
            float o11 = (col0+1 <= row1) ? v[3]*alpha*__expf(av1 - rm1) : 0.f;
            float* C0 = Cb + (long)row0 * SS + col0;
            float* C1 = Cb + (long)row1 * SS + col0;
            C0[0] = o00; C0[1] = o01;
            C1[0] = o10; C1[1] = o11;
            rsum[mt][0] += o00 + o01;
            rsum[mt][1] += o10 + o11;
        }
    }
    #pragma unroll
    for (int mt = 0; mt < 2; mt++) {
        #pragma unroll
        for (int rr = 0; rr < 2; rr++) {
            float v = rsum[mt][rr];
            v += __shfl_xor_sync(0xffffffffu, v, 1);
            v += __shfl_xor_sync(0xffffffffu, v, 2);
            if (t == 0) {
                int row = by*128 + wm*32 + mt*16 + g + rr*8;
                atomicAdd(&rns[(long)z * SS + row], v);
            }
        }
    }
}

// ============================================================================
// tf32 attention value GEMM (NN), K capped at diagonal, rn inline,
// heavy tiles (large by) scheduled first.
// ============================================================================
__global__ void __launch_bounds__(256, 2) attn_av(
    const float* __restrict__ SC, const float* __restrict__ Vb,
    const float* __restrict__ rns, const float* __restrict__ en,
    float* __restrict__ H)
{
    const int z = blockIdx.z;
    const int b = z >> 2, h = z & 3;
    const int bx = blockIdx.x;
    const int by = 7 - blockIdx.y;   // heavy-first
    const float* A = SC + (long)z * SS * SS;
    const float* B = Vb + (long)b * SS * II + h * DHM;
    float* Cb = H + (long)z * SS * DHM;
    const int kend = (by + 1) * 128;
    __shared__ float As[128 * SPAD];
    __shared__ float Bs[128 * SPAD];
    const int tid = threadIdx.x;
    const int lane = tid & 31, warp = tid >> 5;
    const int wm = warp & 3, wn = warp >> 2;
    const int g = lane >> 2, t = lane & 3;
    const int lr = tid >> 1, lc = (tid & 1) * 16;
    const float* Ag = A + (long)(by*128 + lr) * SS + lc;
    const int bkr = tid >> 3;
    const int bc4 = tid & 7;
    const float* Bg = B + (long)bkr * II + bx*128;

    float c[16][4];
    #pragma unroll
    for (int i = 0; i < 16; i++)
        #pragma unroll
        for (int j = 0; j < 4; j++) c[i][j] = 0.f;

    float4 a4[4], b4[4];
    #pragma unroll
    for (int i = 0; i < 4; i++) {
        a4[i] = *(const float4*)(Ag + i*4);
        b4[i] = *(const float4*)(Bg + (bc4 + i*8) * 4);
    }
    const int nk = kend >> 5;
    for (int kt = 0; kt < nk; kt++) {
        __syncthreads();
        #pragma unroll
        for (int i = 0; i < 4; i++) {
            uint4 av = make_uint4(f2tf32(a4[i].x), f2tf32(a4[i].y),
                                  f2tf32(a4[i].z), f2tf32(a4[i].w));
            *(uint4*)&As[lr * SPAD + lc + i*4] = av;
            int coln = (bc4 + i*8) * 4;
            Bs[(coln+0) * SPAD + bkr] = __uint_as_float(f2tf32(b4[i].x));
            Bs[(coln+1) * SPAD + bkr] = __uint_as_float(f2tf32(b4[i].y));
            Bs[(coln+2) * SPAD + bkr] = __uint_as_float(f2tf32(b4[i].z));
            Bs[(coln+3) * SPAD + bkr] = __uint_as_float(f2tf32(b4[i].w));
        }
        __syncthreads();
        if (kt + 1 < nk) {
            const int k0 = (kt + 1) << 5;
            #pragma unroll
            for (int i = 0; i < 4; i++) {
                a4[i] = *(const float4*)(Ag + k0 + i*4);
                b4[i] = *(const float4*)(Bg + (long)k0 * II + (bc4 + i*8) * 4);
            }
        }
        #pragma unroll
        for (int kk = 0; kk < 4; kk++) {
            const int ks = kk * 8;
            uint32_t af[2][4], bf[8][2];
            #pragma unroll
            for (int mt = 0; mt < 2; mt++) {
                int r0 = wm*32 + mt*16 + g;
                af[mt][0] = __float_as_uint(As[r0 * SPAD + ks + t]);
                af[mt][1] = __float_as_uint(As[(r0+8) * SPAD + ks + t]);
                af[mt][2] = __float_as_uint(As[r0 * SPAD + ks + t + 4]);
                af[mt][3] = __float_as_uint(As[(r0+8) * SPAD + ks + t + 4]);
            }
            #pragma unroll
            for (int nt = 0; nt < 8; nt++) {
                int c0 = wn*64 + nt*8 + g;
                bf[nt][0] = __float_as_uint(Bs[c0 * SPAD + ks + t]);
                bf[nt][1] = __float_as_uint(Bs[c0 * SPAD + ks + t + 4]);
            }
            #pragma unroll
            for (int mt = 0; mt < 2; mt++)
                #pragma unroll
                for (int nt = 0; nt < 8; nt++)
                    mma_tf32(c[mt*8 + nt], af[mt], bf[nt]);
        }
    }
    const float* rz = rns + (long)z * SS;
    const float* ez = en + (long)z * SS;
    #pragma unroll
    for (int mt = 0; mt < 2; mt++) {
        int row0 = by*128 + wm*32 + mt*16 + g;
        int row1 = row0 + 8;
        float rn0 = 1.f / (fmaxf(fabsf(rz[row0]), ez[row0]) + 1e-6f);
        float rn1 = 1.f / (fmaxf(fabsf(rz[row1]), ez[row1]) + 1e-6f);
        #pragma unroll
        for (int nt = 0; nt < 8; nt++) {
            int col0 = bx*128 + wn*64 + nt*8 + 2*t;
            float* v = c[mt*8 + nt];
            float* C0 = Cb + (long)row0 * DHM + col0;
            float* C1 = Cb + (long)row1 * DHM + col0;
            C0[0] = v[0]*rn0; C0[1] = v[1]*rn0;
            C1[0] = v[2]*rn1; C1[1] = v[3]*rn1;
        }
    }
}

// ---------------- causal depthwise conv (K=4) + SiLU (sLSTM path) ----------------
template<int C, int LDIN>
__global__ void conv_silu_t(const float* __restrict__ in, const float* __restrict__ w,
                            const float* __restrict__ bias, float* __restrict__ out)
{
    long idx = (long)blockIdx.x * 256 + threadIdx.x;
    if (idx >= (long)BS * C) return;
    int c = (int)(idx & (C - 1));
    long bs = idx / C;
    int s = (int)(bs & (SS - 1));
    float acc = bias[c];
    #pragma unroll
    for (int kk = 0; kk < 4; kk++) {
        int sp = s + kk - 3;
        if (sp >= 0) acc += in[(bs + kk - 3) * (long)LDIN + c] * w[c*4 + kk];
    }
    out[bs * (long)C + c] = acc / (1.f + __expf(-acc));
}

// ---------------- fused conv+SiLU+headwise qkv, float4 weight loads ----------------
__global__ void conv_qkv(const float* __restrict__ up, const float* __restrict__ cw,
                         const float* __restrict__ cb,
                         const float* __restrict__ qw, const float* __restrict__ kw,
                         const float* __restrict__ vw,
                         float* __restrict__ xa, float* __restrict__ q,
                         float* __restrict__ k, float* __restrict__ v)
{
    long idx = (long)blockIdx.x * 256 + threadIdx.x;
    if (idx >= (long)BS * 512) return;
    int nb = (int)(idx & 511);
    long bs = idx >> 9;
    int s = (int)(bs & (SS - 1));
    const float* upc = up + bs * (2L*II) + nb*4;
    float rr[4][4];
    *(float4*)rr[3] = *(const float4*)upc;
    if (s >= 1) *(float4*)rr[2] = *(const float4*)(upc - (2L*II));
    else rr[2][0] = rr[2][1] = rr[2][2] = rr[2][3] = 0.f;
    if (s >= 2) *(float4*)rr[1] = *(const float4*)(upc - 2*(2L*II));
    else rr[1][0] = rr[1][1] = rr[1][2] = rr[1][3] = 0.f;
    if (s >= 3) *(float4*)rr[0] = *(const float4*)(upc - 3*(2L*II));
    else rr[0][0] = rr[0][1] = rr[0][2] = rr[0][3] = 0.f;

    // conv weights/bias as float4: cw4[nb*4+i] = {kk0..kk3}, cb4[nb]
    float4 cbv = ((const float4*)cb)[nb];
    float cbs[4] = {cbv.x, cbv.y, cbv.z, cbv.w};
    float xo[4];
    #pragma unroll
    for (int i = 0; i < 4; i++) {
        float4 cwv = ((const float4*)cw)[nb*4 + i];
        float acc = cbs[i] + rr[0][i]*cwv.x + rr[1][i]*cwv.y
                  + rr[2][i]*cwv.z + rr[3][i]*cwv.w;
        xo[i] = acc / (1.f + __expf(-acc));
    }
    *(float4*)(xa + bs * II + nb*4) = make_float4(xo[0], xo[1], xo[2], xo[3]);

    // headwise weights as float4 rows: qw4[nb*4+o] = row o (i=0..3)
    float qo[4], ko[4], vo[4];
    #pragma unroll
    for (int o = 0; o < 4; o++) {
        float4 qv = ((const float4*)qw)[nb*4 + o];
        float4 kv = ((const float4*)kw)[nb*4 + o];
        float4 vv = ((const float4*)vw)[nb*4 + o];
        qo[o] = xo[0]*qv.x + xo[1]*qv.y + xo[2]*qv.z + xo[3]*qv.w;
        ko[o] = xo[0]*kv.x + xo[1]*kv.y + xo[2]*kv.z + xo[3]*kv.w;
        vo[o] = rr[3][0]*vv.x + rr[3][1]*vv.y + rr[3][2]*vv.z + rr[3][3]*vv.w;
    }
    *(float4*)(q + bs * II + nb*4) = make_float4(qo[0], qo[1], qo[2], qo[3]);
    *(float4*)(k + bs * II + nb*4) = make_float4(ko[0], ko[1], ko[2], ko[3]);
    *(float4*)(v + bs * II + nb*4) = make_float4(vo[0], vo[1], vo[2], vo[3]);
}

// ---------------- ig/fg gate projections (float4) ----------------
__global__ void igfg_k(const float* __restrict__ q, const float* __restrict__ k,
                       const float* __restrict__ v,
                       const float* __restrict__ igw, const float* __restrict__ igb,
                       const float* __restrict__ fgw, const float* __restrict__ fgb,
                       float* __restrict__ ig, float* __restrict__ fg)
{
    long bs = blockIdx.x;
    int b = (int)(bs >> 10);
    int s = (int)(bs & (SS - 1));
    __shared__ float sx[3 * II];
    __shared__ float rbuf[2][8];
    int tid = threadIdx.x;
    for (int i = tid; i < II / 4; i += 256) {
        ((float4*)sx)[i]        = ((const float4*)(q + bs * II))[i];
        ((float4*)sx)[II/4 + i] = ((const float4*)(k + bs * II))[i];
        ((float4*)sx)[II/2 + i] = ((const float4*)(v + bs * II))[i];
    }
    __syncthreads();
    const float4* sx4 = (const float4*)sx;
    for (int h = 0; h < 4; h++) {
        const float4* iw4 = (const float4*)(igw + h * (3*II));
        const float4* fw4 = (const float4*)(fgw + h * (3*II));
        float pi = 0.f, pf = 0.f;
        for (int j = tid; j < (3*II)/4; j += 256) {
            float4 xv = sx4[j];
            float4 wi = iw4[j];
            float4 wf = fw4[j];
            pi += xv.x*wi.x + xv.y*wi.y + xv.z*wi.z + xv.w*wi.w;
            pf += xv.x*wf.x + xv.y*wf.y + xv.z*wf.z + xv.w*wf.w;
        }
        pi = warpSum(pi); pf = warpSum(pf);
        if ((tid & 31) == 0) { rbuf[0][tid >> 5] = pi; rbuf[1][tid >> 5] = pf; }
        __syncthreads();
        if (tid == 0) {
            float a = 0.f, bb = 0.f;
            #pragma unroll
            for (int w8 = 0; w8 < 8; w8++) { a += rbuf[0][w8]; bb += rbuf[1][w8]; }
            ig[(long)(b*4 + h) * SS + s] = a + igb[h];
            fg[(long)(b*4 + h) * SS + s] = bb + fgb[h];
        }
        __syncthreads();
    }
}

// ---------------- mLSTM decay prep (+ zero RNS) ----------------
__global__ void mlstm_prep(const float* __restrict__ ig, const float* __restrict__ fg,
                           float* __restrict__ a, float* __restrict__ rm,
                           float* __restrict__ en, float* __restrict__ rns)
{
    int z = blockIdx.x;
    int tid = threadIdx.x;  // 256
    __shared__ float slsig[SS], sig_s[SS];
    for (int i = tid; i < SS; i += 256) {
        float fv = fg[(long)z * SS + i];
        slsig[i] = fminf(fv, 0.f) - log1pf(__expf(-fabsf(fv)));
        sig_s[i] = ig[(long)z * SS + i];
        rns[(long)z * SS + i] = 0.f;
    }
    __syncthreads();
    if (tid == 0) {
        float cs = 0.f, run = -1e30f;
        for (int s = 0; s < SS; s++) {
            cs += slsig[s];
            float av = sig_s[s] - cs;
            run = fmaxf(run, av);
            a[(long)z * SS + s]  = av;
            rm[(long)z * SS + s] = run;
            en[(long)z * SS + s] = __expf(-(cs + run));
        }
    }
}

// ---------------- mh_norm(dh=512) + (h+skip*xa)*silu(z) ----------------
__global__ void mh_mix(const float* __restrict__ H, const float* __restrict__ onw,
                       const float* __restrict__ skip, const float* __restrict__ xa,
                       const float* __restrict__ up, float* __restrict__ hmix)
{
    int bs = blockIdx.x, h = blockIdx.y;
    int b = bs >> 10;
    int s = bs & (SS - 1);
    const float* hp = H + ((long)(b*4 + h) * SS + s) * DHM;
    int tid = threadIdx.x;  // 128
    float4 v = ((const float4*)hp)[tid];
    float sm = v.x + v.y + v.z + v.w;
    float sq = v.x*v.x + v.y*v.y + v.z*v.z + v.w*v.w;
    __shared__ float s1[4], s2[4];
    sm = warpSum(sm); sq = warpSum(sq);
    if ((tid & 31) == 0) { s1[tid >> 5] = sm; s2[tid >> 5] = sq; }
    __syncthreads();
    float tot  = s1[0] + s1[1] + s1[2] + s1[3];
    float tot2 = s2[0] + s2[1] + s2[2] + s2[3];
    float mu = tot * (1.f / DHM);
    float rs = rsqrtf(tot2 * (1.f / DHM) - mu * mu + 1e-5f);
    float4 wv  = ((const float4*)onw)[h*128 + tid];
    float4 sk  = ((const float4*)skip)[h*128 + tid];
    float4 xav = ((const float4*)(xa + (long)bs * II))[h*128 + tid];
    float4 zv  = ((const float4*)(up + (long)bs * (2L*II) + II))[h*128 + tid];
    float4 o;
    o.x = ((v.x - mu)*rs*wv.x + sk.x*xav.x) * (zv.x / (1.f + __expf(-zv.x)));
    o.y = ((v.y - mu)*rs*wv.y + sk.y*xav.y) * (zv.y / (1.f + __expf(-zv.y)));
    o.z = ((v.z - mu)*rs*wv.z + sk.z*xav.z) * (zv.z / (1.f + __expf(-zv.z)));
    o.w = ((v.w - mu)*rs*wv.w + sk.w*xav.w) * (zv.w / (1.f + __expf(-zv.w)));
    ((float4*)(hmix + (long)bs * II))[h*128 + tid] = o;
}

// ============================================================================
// Cluster-split sLSTM scan v3 (R10): f32x2 matvec, d-quarter split, 1 barrier.
// ============================================================================
#define SCAN_SMEM_FLOATS (32768 + 256 + 2048 + 512)

__device__ __forceinline__ uint32_t smem_addr_u32(const void* p) {
    return (uint32_t)__cvta_generic_to_shared(p);
}
__device__ __forceinline__ uint32_t mapa_u32(uint32_t addr, uint32_t rank) {
    uint32_t out;
    asm("mapa.shared::cluster.u32 %0, %1, %2;" : "=r"(out) : "r"(addr), "r"(rank));
    return out;
}
__device__ __forceinline__ void st_cluster_u64(uint32_t addr, ull v) {
    asm volatile("st.shared::cluster.u64 [%0], %1;" :: "r"(addr), "l"(v) : "memory");
}
__device__ __forceinline__ void cluster_barrier() {
    asm volatile("barrier.cluster.arrive.aligned;" ::: "memory");
    asm volatile("barrier.cluster.wait.aligned;" ::: "memory");
}

__global__ void __launch_bounds__(128, 1) __cluster_dims__(8, 1, 1)
slstm_scan_cl(const float* __restrict__ pre, const float* __restrict__ rk,
              const float* __restrict__ rb, float* __restrict__ ys)
{
    extern __shared__ float sm[];
    float* W    = sm;                       // [256 d][128 el]
    float* sh_h = sm + 32768;               // [256]
    float* sraw = sm + 33024;               // [2][1024]
    ull*   spart = (ull*)(sm + 35072);      // [3][64]

    const int z = blockIdx.x >> 3;
    const int b = z >> 2, h = z & 3;
    uint32_t rank;
    asm("mov.u32 %0, %%cluster_ctarank;" : "=r"(rank));
    const int g  = rank >> 1;
    const int hf = rank & 1;
    const int tid = threadIdx.x;
    const int eg = tid & 31;
    const int dq = tid >> 5;
    const int el = eg * 4;

    const float* rks = rk + ((long)h * 256 * 4 + g) * 256 + hf * 128;
    for (int idx = tid; idx < 32768; idx += 128) {
        int d = idx >> 7, e2 = idx & 127;
        W[idx] = rks[(long)d * 1024 + e2];
    }
    for (int i = tid; i < 256; i += 128) sh_h[i] = 0.f;
    __syncthreads();

    const float* pb = pre + ((long)(g*4 + h) * BS + (long)b * SS) * DHS + hf*128 + el;
    float4 rbv4 = make_float4(0.f, 0.f, 0.f, 0.f);
    float4 pv4  = make_float4(0.f, 0.f, 0.f, 0.f);
    if (dq == 0) {
        rbv4 = *(const float4*)(rb + (h*4 + g) * DHS + hf*128 + el);
        pv4  = *(const float4*)pb;
    }

    uint32_t rdst[8];
    #pragma unroll
    for (int r = 0; r < 8; r++)
        rdst[r] = mapa_u32(smem_addr_u32(&sraw[g*256 + hf*128 + el]), (uint32_t)r);

    float* yo = ys + (long)z * SS * DHS;

    float c0 = 0.f, n0 = 0.f, m0 = 0.f;
    float c1 = 0.f, n1 = 0.f, m1 = 0.f;

    cluster_barrier();

    const float* Wp = W + el + (dq << 13);
    for (int s = 0; s < SS; s++) {
        ull a01 = 0ull, a23 = 0ull;
        const int dbase = dq << 6;
        #pragma unroll
        for (int d4 = 0; d4 < 64; d4 += 4) {
            float4 h4 = *(const float4*)&sh_h[dbase + d4];
            F4U w;
            w.f = *(const float4*)&Wp[(d4+0) << 7];
            { ull hh = pack2(h4.x, h4.x); a01 = fma2(w.u[0], hh, a01); a23 = fma2(w.u[1], hh, a23); }
            w.f = *(const float4*)&Wp[(d4+1) << 7];
            { ull hh = pack2(h4.y, h4.y); a01 = fma2(w.u[0], hh, a01); a23 = fma2(w.u[1], hh, a23); }
            w.f = *(const float4*)&Wp[(d4+2) << 7];
            { ull hh = pack2(h4.z, h4.z); a01 = fma2(w.u[0], hh, a01); a23 = fma2(w.u[1], hh, a23); }
            w.f = *(const float4*)&Wp[(d4+3) << 7];
            { ull hh = pack2(h4.w, h4.w); a01 = fma2(w.u[0], hh, a01); a23 = fma2(w.u[1], hh, a23); }
        }
        if (dq > 0) {
            spart[(dq-1)*64 + eg*2]     = a01;
            spart[(dq-1)*64 + eg*2 + 1] = a23;
        }
        __syncthreads();
        if (dq == 0) {
            a01 = add2(a01, add2(spart[eg*2],     add2(spart[64 + eg*2],     spart[128 + eg*2])));
            a23 = add2(a23, add2(spart[eg*2 + 1], add2(spart[64 + eg*2 + 1], spart[128 + eg*2 + 1])));
            float f0, f1, f2, f3;
            unpack2(a01, f0, f1);
            unpack2(a23, f2, f3);
            f0 += pv4.x + rbv4.x; f1 += pv4.y + rbv4.y;
            f2 += pv4.z + rbv4.z; f3 += pv4.w + rbv4.w;
            if (s + 1 < SS) pv4 = *(const float4*)&pb[(long)(s+1) * DHS];
            ull o01 = pack2(f0, f1), o23 = pack2(f2, f3);
            const uint32_t po = (uint32_t)(s & 1) << 12;
            #pragma unroll
            for (int r = 0; r < 8; r++) {
                st_cluster_u64(rdst[r] + po,     o01);
                st_cluster_u64(rdst[r] + po + 8, o23);
            }
        }
        cluster_barrier();

        const float* rw = sraw + (s & 1) * 1024;
        {
            float iraw = rw[tid],       fraw = rw[256 + tid];
            float zraw = rw[512 + tid], oraw = rw[768 + tid];
            float lf = m0 + fminf(fraw, 0.f) - log1pf(__expf(-fabsf(fraw)));
            float mn = fmaxf(iraw, lf);
            float ig_ = __expf(iraw - mn);
            float fg_ = __expf(lf - mn);
            float th  = 1.f - __fdividef(2.f, __expf(2.f * zraw) + 1.f);
            c0 = fg_ * c0 + ig_ * th;
            n0 = fg_ * n0 + ig_;
            m0 = mn;
            float hv = c0 / (n0 * (1.f + __expf(-oraw)));
            sh_h[tid] = hv;
            if (rank == 0) yo[(long)s * DHS + tid] = hv;
        }
        {
            float iraw = rw[128 + tid], fraw = rw[384 + tid];
            float zraw = rw[640 + tid], oraw = rw[896 + tid];
            float lf = m1 + fminf(fraw, 0.f) - log1pf(__expf(-fabsf(fraw)));
            float mn = fmaxf(iraw, lf);
            float ig_ = __expf(iraw - mn);
            float fg_ = __expf(lf - mn);
            float th  = 1.f - __fdividef(2.f, __expf(2.f * zraw) + 1.f);
            c1 = fg_ * c1 + ig_ * th;
            n1 = fg_ * n1 + ig_;
            m1 = mn;
            float hv = c1 / (n1 * (1.f + __expf(-oraw)));
            sh_h[128 + tid] = hv;
            if (rank == 0) yo[(long)s * DHS + 128 + tid] = hv;
        }
        __syncthreads();
    }
}

// ---------------- sLSTM group norm (256) + residual add ----------------
__global__ void slstm_gnorm(const float* __restrict__ ys, const float* __restrict__ gnw,
                            float* __restrict__ x)
{
    int bs = blockIdx.x, h = blockIdx.y;
    int b = bs >> 10, s = bs & (SS - 1);
    const float* yp = ys + ((long)(b*4 + h) * SS + s) * DHS;
    int tid = threadIdx.x;  // 64
    float4 v = ((const float4*)yp)[tid];
    float sm = v.x + v.y + v.z + v.w;
    float sq = v.x*v.x + v.y*v.y + v.z*v.z + v.w*v.w;
    __shared__ float s1[2], s2[2];
    sm = warpSum(sm); sq = warpSum(sq);
    if ((tid & 31) == 0) { s1[tid >> 5] = sm; s2[tid >> 5] = sq; }
    __syncthreads();
    float tot  = s1[0] + s1[1];
    float tot2 = s2[0] + s2[1];
    float mu = tot * (1.f / DHS);
    float rs = rsqrtf(tot2 * (1.f / DHS) - mu * mu + 1e-5f);
    float4 wv = ((const float4*)gnw)[h*64 + tid];
    float* xp = x + (long)bs * DD + h * DHS + tid * 4;
    float4 xv = *(float4*)xp;
    xv.x += (v.x - mu) * rs * wv.x;
    xv.y += (v.y - mu) * rs * wv.y;
    xv.z += (v.z - mu) * rs * wv.z;
    xv.w += (v.w - mu) * rs * wv.w;
    *(float4*)xp = xv;
}

// ---------------- FFN: act = gelu_exact(gate) * up ----------------
__global__ void gelu_mul(const float* __restrict__ f, float* __restrict__ a)
{
    long idx = (long)blockIdx.x * 256 + threadIdx.x;
    if (idx >= (long)BS * UU) return;
    long bs = idx / UU;
    int u = (int)(idx % UU);
    float g = f[bs * (2L*UU) + u];
    float p = f[bs * (2L*UU) + UU + u];
    a[idx] = 0.5f * g * (1.f + erff(g * 0.70710678118654752f)) * p;
}

// ---------------- host ----------------
static inline void gemm(const float* A, const float* B, float* C,
                        int M, int N, int K, int lda, int ldb, int ldc,
                        float alpha, const float* bias, int acc)
{
    dim3 grid(N / 128, M / 128);
    tgemm_nt<<<grid, 256>>>(A, B, C, M, N, K, lda, ldb, ldc, alpha, bias, acc);
}

extern "C" void kernel_launch(void* const* d_in, const int* in_sizes, int n_in,
                              void* d_out, int out_size)
{
    const int*   ids       = (const int*)  d_in[0];
    const float* emb       = (const float*)d_in[1];
    const float* m_ln_w    = (const float*)d_in[2];
    const float* m_up_w    = (const float*)d_in[3];
    const float* m_conv_w  = (const float*)d_in[4];
    const float* m_conv_b  = (const float*)d_in[5];
    const float* m_q_w     = (const float*)d_in[6];
    const float* m_k_w     = (const float*)d_in[7];
    const float* m_v_w     = (const float*)d_in[8];
    const float* m_ig_w    = (const float*)d_in[9];
    const float* m_ig_b    = (const float*)d_in[10];
    const float* m_fg_w    = (const float*)d_in[11];
    const float* m_fg_b    = (const float*)d_in[12];
    const float* m_skip    = (const float*)d_in[13];
    const float* m_on_w    = (const float*)d_in[14];
    const float* m_down_w  = (const float*)d_in[15];
    const float* s_ln_w    = (const float*)d_in[16];
    const float* s_conv_w  = (const float*)d_in[17];
    const float* s_conv_b  = (const float*)d_in[18];
    const float* s_iw      = (const float*)d_in[19];
    const float* s_fw      = (const float*)d_in[20];
    const float* s_zw      = (const float*)d_in[21];
    const float* s_ow      = (const float*)d_in[22];
    const float* s_rk      = (const float*)d_in[23];
    const float* s_rb      = (const float*)d_in[24];
    const float* s_gn_w    = (const float*)d_in[25];
    const float* s_ln2_w   = (const float*)d_in[26];
    const float* s_ffn_up  = (const float*)d_in[27];
    const float* s_ffn_dn  = (const float*)d_in[28];
    const float* post_ln_w = (const float*)d_in[29];
    const float* head_w    = (const float*)d_in[30];
    const float* head_b    = (const float*)d_in[31];
    float* out = (float*)d_out;

    float* pool = nullptr;
    cudaGetSymbolAddress((void**)&pool, g_pool);
    float* X   = pool + O_X;   float* XN  = pool + O_XN;  float* XC  = pool + O_XC;
    float* UP  = pool + O_UP;  float* XA  = pool + O_XA;
    float* Q_  = pool + O_Q;   float* K_  = pool + O_K;   float* V_  = pool + O_V;
    float* SC  = pool + O_SC;  float* HB  = pool + O_HB;  float* HM  = pool + O_HM;
    float* PRE = pool + O_PRE; float* YS  = pool + O_YS;
    float* FFN = pool + O_FFN; float* ACT = pool + O_ACT;
    float* IG  = pool + O_IG;  float* FG  = pool + O_FG;
    float* Aa  = pool + O_A;   float* RM  = pool + O_RM;
    float* EN  = pool + O_EN;  float* RNS = pool + O_RNS;

    cudaFuncSetAttribute(slstm_scan_cl,
                         cudaFuncAttributeMaxDynamicSharedMemorySize,
                         SCAN_SMEM_FLOATS * 4);

    embed_k<<<BS, 256>>>(ids, emb, X);

    int mi = 0;
    for (int blk = 0; blk < 4; blk++) {
        if (blk == 1) {
            // ---------------- sLSTM block ----------------
            layernorm_k<<<BS, 256>>>(X, s_ln_w, XN);
            conv_silu_t<DD, DD><<<(BS * DD) / 256, 256>>>(XN, s_conv_w, s_conv_b, XC);
            tgemm_gates<<<dim3(2, 32, 16), 256>>>(XC, XN, s_iw, s_fw, s_zw, s_ow, PRE);
            slstm_scan_cl<<<128, 128, SCAN_SMEM_FLOATS * 4>>>(PRE, s_rk, s_rb, YS);
            slstm_gnorm<<<dim3(BS, 4), 64>>>(YS, s_gn_w, X);
            layernorm_k<<<BS, 256>>>(X, s_ln2_w, XN);
            gemm(XN, s_ffn_up, FFN, BS, 2*UU, DD, DD, DD, 2*UU, 1.f, nullptr, 0);
            gelu_mul<<<(int)(((long)BS*UU + 255) / 256), 256>>>(FFN, ACT);
            gemm(ACT, s_ffn_dn, X, BS, DD, UU, UU, UU, DD, 1.f, nullptr, 1);
        } else {
            // ---------------- mLSTM block ----------------
            layernorm_k<<<BS, 256>>>(X, m_ln_w + (long)mi*DD, XN);
            gemm(XN, m_up_w + (long)mi*4096*DD, UP, BS, 4096, DD, DD, DD, 4096,
                 1.f, nullptr, 0);
            conv_qkv<<<(int)(((long)BS*512) / 256), 256>>>(
                UP, m_conv_w + (long)mi*II*4, m_conv_b + (long)mi*II,
                m_q_w + (long)mi*512*16, m_k_w + (long)mi*512*16,
                m_v_w + (long)mi*512*16, XA, Q_, K_, V_);
            igfg_k<<<BS, 256>>>(Q_, K_, V_,
                m_ig_w + (long)mi*4*6144, m_ig_b + (long)mi*4,
                m_fg_w + (long)mi*4*6144, m_fg_b + (long)mi*4, IG, FG);
            mlstm_prep<<<16, 256>>>(IG, FG, Aa, RM, EN, RNS);
            attn_qk<<<dim3(36, 1, 16), 256>>>(Q_, K_, SC, Aa, RM, RNS);
            attn_av<<<dim3(4, 8, 16), 256>>>(SC, V_, RNS, EN, HB);
            mh_mix<<<dim3(BS, 4), 128>>>(HB, m_on_w + (long)mi*II,
                m_skip + (long)mi*II, XA, UP, HM);
            gemm(HM, m_down_w + (long)mi*DD*II, X, BS, DD, II, II, II, DD,
                 1.f, nullptr, 1);
            mi++;
        }
    }

    layernorm_k<<<BS, 256>>>(X, post_ln_w, XN);
    gemm(XN, head_w, out, BS, 256, DD, DD, DD, 256, 1.f, head_b, 0);
}

// round 12
// speedup vs baseline: 6.6886x; 1.0138x over previous
#include <cuda_runtime.h>
#include <cuda_bf16.h>
#include <math.h>
#include <stdint.h>

#define BB 4
#define SS 1024
#define DD 1024
#define II 2048
#define BS 4096
#define DHM 512
#define DHS 256
#define UU 1344

constexpr long SZ_X   = (long)BS * DD;
constexpr long SZ_UP  = (long)BS * 2 * II;
constexpr long SZ_I   = (long)BS * II;
constexpr long SZ_SC  = 16L * SS * SS;
constexpr long SZ_HB  = 16L * SS * DHM;
constexpr long SZ_PRE = 16L * BS * DHS;
constexpr long SZ_YS  = 16L * SS * DHS;
constexpr long SZ_FFN = (long)BS * 2 * UU;
constexpr long SZ_ACT = (long)BS * UU;
constexpr long SZ_V16 = 16L * SS;

constexpr long O_X   = 0;
constexpr long O_XN  = O_X   + SZ_X;
constexpr long O_XC  = O_XN  + SZ_X;
constexpr long O_UP  = O_XC  + SZ_X;
constexpr long O_XA  = O_UP  + SZ_UP;
constexpr long O_Q   = O_XA  + SZ_I;
constexpr long O_K   = O_Q   + SZ_I;
constexpr long O_V   = O_K   + SZ_I;
constexpr long O_SC  = O_V   + SZ_I;
constexpr long O_HB  = O_SC  + SZ_SC;
constexpr long O_HM  = O_HB  + SZ_HB;
constexpr long O_PRE = O_HM  + SZ_I;
constexpr long O_YS  = O_PRE + SZ_PRE;
constexpr long O_FFN = O_YS  + SZ_YS;
constexpr long O_ACT = O_FFN + SZ_FFN;
constexpr long O_IG  = O_ACT + SZ_ACT;
constexpr long O_FG  = O_IG  + SZ_V16;
constexpr long O_A   = O_FG  + SZ_V16;
constexpr long O_RM  = O_A   + SZ_V16;
constexpr long O_EN  = O_RM  + SZ_V16;
constexpr long O_RNS = O_EN  + SZ_V16;
constexpr long POOL_SZ = O_RNS + SZ_V16;

__device__ float g_pool[POOL_SZ];

__device__ __forceinline__ float warpSum(float v) {
    #pragma unroll
    for (int o = 16; o > 0; o >>= 1) v += __shfl_down_sync(0xffffffffu, v, o);
    return v;
}

// ---------------- tf32 mma helpers ----------------
__device__ __forceinline__ uint32_t f2tf32(float f) {
    uint32_t r;
    asm("cvt.rna.tf32.f32 %0, %1;" : "=r"(r) : "f"(f));
    return r;
}
__device__ __forceinline__ void mma_tf32(float* c, const uint32_t* a, const uint32_t* b) {
    asm volatile(
        "mma.sync.aligned.m16n8k8.row.col.f32.tf32.tf32.f32 "
        "{%0,%1,%2,%3}, {%4,%5,%6,%7}, {%8,%9}, {%0,%1,%2,%3};"
        : "+f"(c[0]), "+f"(c[1]), "+f"(c[2]), "+f"(c[3])
        : "r"(a[0]), "r"(a[1]), "r"(a[2]), "r"(a[3]), "r"(b[0]), "r"(b[1]));
}
#define SPAD 36

// ---------------- f32x2 helpers ----------------
typedef unsigned long long ull;
__device__ __forceinline__ ull pack2(float a, float b) {
    ull r; asm("mov.b64 %0, {%1,%2};" : "=l"(r) : "f"(a), "f"(b)); return r;
}
__device__ __forceinline__ ull fma2(ull a, ull b, ull c) {
    ull r; asm("fma.rn.f32x2 %0, %1, %2, %3;" : "=l"(r) : "l"(a), "l"(b), "l"(c)); return r;
}
__device__ __forceinline__ ull add2(ull a, ull b) {
    ull r; asm("add.rn.f32x2 %0, %1, %2;" : "=l"(r) : "l"(a), "l"(b)); return r;
}
__device__ __forceinline__ void unpack2(ull v, float& a, float& b) {
    asm("mov.b64 {%0,%1}, %2;" : "=f"(a), "=f"(b) : "l"(v));
}
union F4U { float4 f; ull u[2]; };

// ---------------- embedding gather ----------------
__global__ void embed_k(const int* __restrict__ ids, const float* __restrict__ emb,
                        float* __restrict__ x)
{
    int bs = blockIdx.x;
    long id = ids[bs];
    ((float4*)(x + (long)bs * DD))[threadIdx.x] =
        ((const float4*)(emb + id * DD))[threadIdx.x];
}

// ---------------- LayerNorm width 1024, 256 thr/row ----------------
__global__ void layernorm_k(const float* __restrict__ x, const float* __restrict__ w,
                            float* __restrict__ y)
{
    long row = blockIdx.x;
    int tid = threadIdx.x;
    float4 v = ((const float4*)(x + row * DD))[tid];
    float s = v.x + v.y + v.z + v.w;
    float ss = v.x*v.x + v.y*v.y + v.z*v.z + v.w*v.w;
    __shared__ float sb[8], sb2[8];
    __shared__ float mu_s, rs_s;
    s = warpSum(s); ss = warpSum(ss);
    if ((tid & 31) == 0) { sb[tid >> 5] = s; sb2[tid >> 5] = ss; }
    __syncthreads();
    if (tid == 0) {
        float t = 0.f, t2 = 0.f;
        #pragma unroll
        for (int i = 0; i < 8; i++) { t += sb[i]; t2 += sb2[i]; }
        float mu = t * (1.f / DD);
        mu_s = mu;
        rs_s = rsqrtf(t2 * (1.f / DD) - mu * mu + 1e-5f);
    }
    __syncthreads();
    float mu = mu_s, rs = rs_s;
    float4 wv = ((const float4*)w)[tid];
    float4 o;
    o.x = (v.x - mu) * rs * wv.x;  o.y = (v.y - mu) * rs * wv.y;
    o.z = (v.z - mu) * rs * wv.z;  o.w = (v.w - mu) * rs * wv.w;
    ((float4*)(y + row * DD))[tid] = o;
}

// ============================================================================
// tf32 GEMM NT (LDG prefetch + cvt.rna + STS). C = alpha*A@B^T [+bias][+=C]
// ============================================================================
__global__ void __launch_bounds__(256, 2) tgemm_nt(
    const float* __restrict__ A, const float* __restrict__ B, float* __restrict__ C,
    int M, int N, int K, int lda, int ldb, int ldc,
    float alpha, const float* __restrict__ bias, int acc)
{
    __shared__ float As[128 * SPAD];
    __shared__ float Bs[128 * SPAD];
    const int tid = threadIdx.x;
    const int lane = tid & 31, warp = tid >> 5;
    const int wm = warp & 3, wn = warp >> 2;
    const int g = lane >> 2, t = lane & 3;
    const int lr = tid >> 1, lc = (tid & 1) * 16;
    const float* Ag = A + (long)(blockIdx.y * 128 + lr) * lda + lc;
    const float* Bg = B + (long)(blockIdx.x * 128 + lr) * ldb + lc;

    float c[16][4];
    #pragma unroll
    for (int i = 0; i < 16; i++)
        #pragma unroll
        for (int j = 0; j < 4; j++) c[i][j] = 0.f;

    float4 a4[4], b4[4];
    #pragma unroll
    for (int i = 0; i < 4; i++) {
        a4[i] = *(const float4*)(Ag + i*4);
        b4[i] = *(const float4*)(Bg + i*4);
    }
    const int nk = K >> 5;
    for (int kt = 0; kt < nk; kt++) {
        __syncthreads();
        #pragma unroll
        for (int i = 0; i < 4; i++) {
            uint4 av = make_uint4(f2tf32(a4[i].x), f2tf32(a4[i].y),
                                  f2tf32(a4[i].z), f2tf32(a4[i].w));
            uint4 bv = make_uint4(f2tf32(b4[i].x), f2tf32(b4[i].y),
                                  f2tf32(b4[i].z), f2tf32(b4[i].w));
            *(uint4*)&As[lr * SPAD + lc + i*4] = av;
            *(uint4*)&Bs[lr * SPAD + lc + i*4] = bv;
        }
        __syncthreads();
        if (kt + 1 < nk) {
            const int k0 = (kt + 1) << 5;
            #pragma unroll
            for (int i = 0; i < 4; i++) {
                a4[i] = *(const float4*)(Ag + k0 + i*4);
                b4[i] = *(const float4*)(Bg + k0 + i*4);
            }
        }
        #pragma unroll
        for (int kk = 0; kk < 4; kk++) {
            const int ks = kk * 8;
            uint32_t af[2][4], bf[8][2];
            #pragma unroll
            for (int mt = 0; mt < 2; mt++) {
                int r0 = wm*32 + mt*16 + g;
                af[mt][0] = __float_as_uint(As[r0 * SPAD + ks + t]);
                af[mt][1] = __float_as_uint(As[(r0+8) * SPAD + ks + t]);
                af[mt][2] = __float_as_uint(As[r0 * SPAD + ks + t + 4]);
                af[mt][3] = __float_as_uint(As[(r0+8) * SPAD + ks + t + 4]);
            }
            #pragma unroll
            for (int nt = 0; nt < 8; nt++) {
                int c0 = wn*64 + nt*8 + g;
                bf[nt][0] = __float_as_uint(Bs[c0 * SPAD + ks + t]);
                bf[nt][1] = __float_as_uint(Bs[c0 * SPAD + ks + t + 4]);
            }
            #pragma unroll
            for (int mt = 0; mt < 2; mt++)
                #pragma unroll
                for (int nt = 0; nt < 8; nt++)
                    mma_tf32(c[mt*8 + nt], af[mt], bf[nt]);
        }
    }
    #pragma unroll
    for (int mt = 0; mt < 2; mt++) {
        int row0 = blockIdx.y*128 + wm*32 + mt*16 + g;
        #pragma unroll
        for (int nt = 0; nt < 8; nt++) {
            int col0 = blockIdx.x*128 + wn*64 + nt*8 + 2*t;
            float* v = c[mt*8 + nt];
            float b0 = bias ? bias[col0] : 0.f, b1 = bias ? bias[col0+1] : 0.f;
            float* C0 = C + (long)row0 * ldc + col0;
            float* C1 = C + (long)(row0+8) * ldc + col0;
            float o0 = v[0]*alpha + b0, o1 = v[1]*alpha + b1;
            float o2 = v[2]*alpha + b0, o3 = v[3]*alpha + b1;
            if (acc) { o0 += C0[0]; o1 += C0[1]; o2 += C1[0]; o3 += C1[1]; }
            C0[0] = o0; C0[1] = o1; C1[0] = o2; C1[1] = o3;
        }
    }
}

// ============================================================================
// tf32 batched sLSTM gate GEMMs: PRE[zz] = src @ W[h]^T, zz=(g*4+h)
// ============================================================================
__global__ void __launch_bounds__(256, 2) tgemm_gates(
    const float* __restrict__ XC, const float* __restrict__ XN,
    const float* __restrict__ iw, const float* __restrict__ fw,
    const float* __restrict__ zw, const float* __restrict__ ow,
    float* __restrict__ PRE)
{
    const int zz = blockIdx.z;
    const int gg = zz >> 2, hh = zz & 3;
    const float* A = ((gg < 2) ? XC : XN) + hh * 256;
    const float* Wsel = (gg == 0) ? iw : (gg == 1) ? fw : (gg == 2) ? zw : ow;
    const float* B = Wsel + (long)hh * 65536;
    float* C = PRE + (long)zz * BS * DHS;

    __shared__ float As[128 * SPAD];
    __shared__ float Bs[128 * SPAD];
    const int tid = threadIdx.x;
    const int lane = tid & 31, warp = tid >> 5;
    const int wm = warp & 3, wn = warp >> 2;
    const int g = lane >> 2, t = lane & 3;
    const int lr = tid >> 1, lc = (tid & 1) * 16;
    const float* Ag = A + (long)(blockIdx.y * 128 + lr) * DD + lc;
    const float* Bg = B + (long)(blockIdx.x * 128 + lr) * 256 + lc;

    float c[16][4];
    #pragma unroll
    for (int i = 0; i < 16; i++)
        #pragma unroll
        for (int j = 0; j < 4; j++) c[i][j] = 0.f;

    float4 a4[4], b4[4];
    #pragma unroll
    for (int i = 0; i < 4; i++) {
        a4[i] = *(const float4*)(Ag + i*4);
        b4[i] = *(const float4*)(Bg + i*4);
    }
    const int nk = 256 >> 5;
    for (int kt = 0; kt < nk; kt++) {
        __syncthreads();
        #pragma unroll
        for (int i = 0; i < 4; i++) {
            uint4 av = make_uint4(f2tf32(a4[i].x), f2tf32(a4[i].y),
                                  f2tf32(a4[i].z), f2tf32(a4[i].w));
            uint4 bv = make_uint4(f2tf32(b4[i].x), f2tf32(b4[i].y),
                                  f2tf32(b4[i].z), f2tf32(b4[i].w));
            *(uint4*)&As[lr * SPAD + lc + i*4] = av;
            *(uint4*)&Bs[lr * SPAD + lc + i*4] = bv;
        }
        __syncthreads();
        if (kt + 1 < nk) {
            const int k0 = (kt + 1) << 5;
            #pragma unroll
            for (int i = 0; i < 4; i++) {
                a4[i] = *(const float4*)(Ag + k0 + i*4);
                b4[i] = *(const float4*)(Bg + k0 + i*4);
            }
        }
        #pragma unroll
        for (int kk = 0; kk < 4; kk++) {
            const int ks = kk * 8;
            uint32_t af[2][4], bf[8][2];
            #pragma unroll
            for (int mt = 0; mt < 2; mt++) {
                int r0 = wm*32 + mt*16 + g;
                af[mt][0] = __float_as_uint(As[r0 * SPAD + ks + t]);
                af[mt][1] = __float_as_uint(As[(r0+8) * SPAD + ks + t]);
                af[mt][2] = __float_as_uint(As[r0 * SPAD + ks + t + 4]);
                af[mt][3] = __float_as_uint(As[(r0+8) * SPAD + ks + t + 4]);
            }
            #pragma unroll
            for (int nt = 0; nt < 8; nt++) {
                int c0 = wn*64 + nt*8 + g;
                bf[nt][0] = __float_as_uint(Bs[c0 * SPAD + ks + t]);
                bf[nt][1] = __float_as_uint(Bs[c0 * SPAD + ks + t + 4]);
            }
            #pragma unroll
            for (int mt = 0; mt < 2; mt++)
                #pragma unroll
                for (int nt = 0; nt < 8; nt++)
                    mma_tf32(c[mt*8 + nt], af[mt], bf[nt]);
        }
    }
    #pragma unroll
    for (int mt = 0; mt < 2; mt++) {
        int row0 = blockIdx.y*128 + wm*32 + mt*16 + g;
        #pragma unroll
        for (int nt = 0; nt < 8; nt++) {
            int col0 = blockIdx.x*128 + wn*64 + nt*8 + 2*t;
            float* v = c[mt*8 + nt];
            float* C0 = C + (long)row0 * 256 + col0;
            float* C1 = C + (long)(row0+8) * 256 + col0;
            C0[0] = v[0]; C0[1] = v[1];
            C1[0] = v[2]; C1[1] = v[3];
        }
    }
}

// ============================================================================
// tf32 attention scores, triangle grid, fused row-sums.
// ============================================================================
__global__ void __launch_bounds__(256, 2) attn_qk(
    const float* __restrict__ Qb, const float* __restrict__ Kb,
    float* __restrict__ SC, const float* __restrict__ a_,
    const float* __restrict__ rm_, float* __restrict__ rns)
{
    const int z = blockIdx.z;
    const int b = z >> 2, h = z & 3;
    int by = 0;
    int bx = blockIdx.x;
    while ((by + 1) * (by + 2) / 2 <= bx) by++;
    bx -= by * (by + 1) / 2;

    float* Cb = SC + (long)z * SS * SS;
    const float* A = Qb + (long)b * SS * II + h * DHM;
    const float* B = Kb + (long)b * SS * II + h * DHM;
    __shared__ float As[128 * SPAD];
    __shared__ float Bs[128 * SPAD];
    const int tid = threadIdx.x;
    const int lane = tid & 31, warp = tid >> 5;
    const int wm = warp & 3, wn = warp >> 2;
    const int g = lane >> 2, t = lane & 3;
    const int lr = tid >> 1, lc = (tid & 1) * 16;
    const float* Ag = A + (long)(by*128 + lr) * II + lc;
    const float* Bg = B + (long)(bx*128 + lr) * II + lc;

    float c[16][4];
    #pragma unroll
    for (int i = 0; i < 16; i++)
        #pragma unroll
        for (int j = 0; j < 4; j++) c[i][j] = 0.f;

    float4 a4[4], b4[4];
    #pragma unroll
    for (int i = 0; i < 4; i++) {
        a4[i] = *(const float4*)(Ag + i*4);
        b4[i] = *(const float4*)(Bg + i*4);
    }
    const int nk = DHM >> 5;
    for (int kt = 0; kt < nk; kt++) {
        __syncthreads();
        #pragma unroll
        for (int i = 0; i < 4; i++) {
            uint4 av = make_uint4(f2tf32(a4[i].x), f2tf32(a4[i].y),
                                  f2tf32(a4[i].z), f2tf32(a4[i].w));
            uint4 bv = make_uint4(f2tf32(b4[i].x), f2tf32(b4[i].y),
                                  f2tf32(b4[i].z), f2tf32(b4[i].w));
            *(uint4*)&As[lr * SPAD + lc + i*4] = av;
            *(uint4*)&Bs[lr * SPAD + lc + i*4] = bv;
        }
        __syncthreads();
        if (kt + 1 < nk) {
            const int k0 = (kt + 1) << 5;
            #pragma unroll
            for (int i = 0; i < 4; i++) {
                a4[i] = *(const float4*)(Ag + k0 + i*4);
                b4[i] = *(const float4*)(Bg + k0 + i*4);
            }
        }
        #pragma unroll
        for (int kk = 0; kk < 4; kk++) {
            const int ks = kk * 8;
            uint32_t af[2][4], bf[8][2];
            #pragma unroll
            for (int mt = 0; mt < 2; mt++) {
                int r0 = wm*32 + mt*16 + g;
                af[mt][0] = __float_as_uint(As[r0 * SPAD + ks + t]);
                af[mt][1] = __float_as_uint(As[(r0+8) * SPAD + ks + t]);
                af[mt][2] = __float_as_uint(As[r0 * SPAD + ks + t + 4]);
                af[mt][3] = __float_as_uint(As[(r0+8) * SPAD + ks + t + 4]);
            }
            #pragma unroll
            for (int nt = 0; nt < 8; nt++) {
                int c0 = wn*64 + nt*8 + g;
                bf[nt][0] = __float_as_uint(Bs[c0 * SPAD + ks + t]);
                bf[nt][1] = __float_as_uint(Bs[c0 * SPAD + ks + t + 4]);
            }
            #pragma unroll
            for (int mt = 0; mt < 2; mt++)
                #pragma unroll
                for (int nt = 0; nt < 8; nt++)
                    mma_tf32(c[mt*8 + nt], af[mt], bf[nt]);
        }
    }
    const float* az = a_ + (long)z * SS;
    const float* rz = rm_ + (long)z * SS;
    const float alpha = 0.04419417382415922f;  // 1/sqrt(512)
    float rsum[2][2] = {{0.f, 0.f}, {0.f, 0.f}};
    #pragma unroll
    for (int mt = 0; mt < 2; mt++) {
        int row0 = by*128 + wm*32 + mt*16 + g;
        int row1 = row0 + 8;
        float rm0 = rz[row0], rm1 = rz[row1];
        #pragma unroll
        for (int nt = 0; nt < 8; nt++) {
            int col0 = bx*128 + wn*64 + nt*8 + 2*t;
            float av0 = az[col0], av1 = az[col0+1];
            float* v = c[mt*8 + nt];
            float o00 = (col0   <= row0) ? v[0]*alpha*__expf(av0 - rm0) : 0.f;
            float o01 = (col0+1 <= row0) ? v[1]*alpha*__expf(av1 - rm0) : 0.f;
            float o10 = (col0   <= row1) ? v[2]*alpha*__expf(av0 - rm1) : 0.f;
            float o11 = (col0+1 <= row1) ? v[3]*alpha*__expf(av1 - rm1) : 0.f;
            float* C0 = Cb + (long)row0 * SS + col0;
            float* C1 = Cb + (long)row1 * SS + col0;
            C0[0] = o00; C0[1] = o01;
            C1[0] = o10; C1[1] = o11;
            rsum[mt][0] += o00 + o01;
            rsum[mt][1] += o10 + o11;
        }
    }
    #pragma unroll
    for (int mt = 0; mt < 2; mt++) {
        #pragma unroll
        for (int rr = 0; rr < 2; rr++) {
            float v = rsum[mt][rr];
            v += __shfl_xor_sync(0xffffffffu, v, 1);
            v += __shfl_xor_sync(0xffffffffu, v, 2);
            if (t == 0) {
                int row = by*128 + wm*32 + mt*16 + g + rr*8;
                atomicAdd(&rns[(long)z * SS + row], v);
            }
        }
    }
}

// ============================================================================
// tf32 attention value GEMM (NN), K capped at diagonal, rn inline, heavy-first
// ============================================================================
__global__ void __launch_bounds__(256, 2) attn_av(
    const float* __restrict__ SC, const float* __restrict__ Vb,
    const float* __restrict__ rns, const float* __restrict__ en,
    float* __restrict__ H)
{
    const int z = blockIdx.z;
    const int b = z >> 2, h = z & 3;
    const int bx = blockIdx.x;
    const int by = 7 - blockIdx.y;
    const float* A = SC + (long)z * SS * SS;
    const float* B = Vb + (long)b * SS * II + h * DHM;
    float* Cb = H + (long)z * SS * DHM;
    const int kend = (by + 1) * 128;
    __shared__ float As[128 * SPAD];
    __shared__ float Bs[128 * SPAD];
    const int tid = threadIdx.x;
    const int lane = tid & 31, warp = tid >> 5;
    const int wm = warp & 3, wn = warp >> 2;
    const int g = lane >> 2, t = lane & 3;
    const int lr = tid >> 1, lc = (tid & 1) * 16;
    const float* Ag = A + (long)(by*128 + lr) * SS + lc;
    const int bkr = tid >> 3;
    const int bc4 = tid & 7;
    const float* Bg = B + (long)bkr * II + bx*128;

    float c[16][4];
    #pragma unroll
    for (int i = 0; i < 16; i++)
        #pragma unroll
        for (int j = 0; j < 4; j++) c[i][j] = 0.f;

    float4 a4[4], b4[4];
    #pragma unroll
    for (int i = 0; i < 4; i++) {
        a4[i] = *(const float4*)(Ag + i*4);
        b4[i] = *(const float4*)(Bg + (bc4 + i*8) * 4);
    }
    const int nk = kend >> 5;
    for (int kt = 0; kt < nk; kt++) {
        __syncthreads();
        #pragma unroll
        for (int i = 0; i < 4; i++) {
            uint4 av = make_uint4(f2tf32(a4[i].x), f2tf32(a4[i].y),
                                  f2tf32(a4[i].z), f2tf32(a4[i].w));
            *(uint4*)&As[lr * SPAD + lc + i*4] = av;
            int coln = (bc4 + i*8) * 4;
            Bs[(coln+0) * SPAD + bkr] = __uint_as_float(f2tf32(b4[i].x));
            Bs[(coln+1) * SPAD + bkr] = __uint_as_float(f2tf32(b4[i].y));
            Bs[(coln+2) * SPAD + bkr] = __uint_as_float(f2tf32(b4[i].z));
            Bs[(coln+3) * SPAD + bkr] = __uint_as_float(f2tf32(b4[i].w));
        }
        __syncthreads();
        if (kt + 1 < nk) {
            const int k0 = (kt + 1) << 5;
            #pragma unroll
            for (int i = 0; i < 4; i++) {
                a4[i] = *(const float4*)(Ag + k0 + i*4);
                b4[i] = *(const float4*)(Bg + (long)k0 * II + (bc4 + i*8) * 4);
            }
        }
        #pragma unroll
        for (int kk = 0; kk < 4; kk++) {
            const int ks = kk * 8;
            uint32_t af[2][4], bf[8][2];
            #pragma unroll
            for (int mt = 0; mt < 2; mt++) {
                int r0 = wm*32 + mt*16 + g;
                af[mt][0] = __float_as_uint(As[r0 * SPAD + ks + t]);
                af[mt][1] = __float_as_uint(As[(r0+8) * SPAD + ks + t]);
                af[mt][2] = __float_as_uint(As[r0 * SPAD + ks + t + 4]);
                af[mt][3] = __float_as_uint(As[(r0+8) * SPAD + ks + t + 4]);
            }
            #pragma unroll
            for (int nt = 0; nt < 8; nt++) {
                int c0 = wn*64 + nt*8 + g;
                bf[nt][0] = __float_as_uint(Bs[c0 * SPAD + ks + t]);
                bf[nt][1] = __float_as_uint(Bs[c0 * SPAD + ks + t + 4]);
            }
            #pragma unroll
            for (int mt = 0; mt < 2; mt++)
                #pragma unroll
                for (int nt = 0; nt < 8; nt++)
                    mma_tf32(c[mt*8 + nt], af[mt], bf[nt]);
        }
    }
    const float* rz = rns + (long)z * SS;
    const float* ez = en + (long)z * SS;
    #pragma unroll
    for (int mt = 0; mt < 2; mt++) {
        int row0 = by*128 + wm*32 + mt*16 + g;
        int row1 = row0 + 8;
        float rn0 = 1.f / (fmaxf(fabsf(rz[row0]), ez[row0]) + 1e-6f);
        float rn1 = 1.f / (fmaxf(fabsf(rz[row1]), ez[row1]) + 1e-6f);
        #pragma unroll
        for (int nt = 0; nt < 8; nt++) {
            int col0 = bx*128 + wn*64 + nt*8 + 2*t;
            float* v = c[mt*8 + nt];
            float* C0 = Cb + (long)row0 * DHM + col0;
            float* C1 = Cb + (long)row1 * DHM + col0;
            C0[0] = v[0]*rn0; C0[1] = v[1]*rn0;
            C1[0] = v[2]*rn1; C1[1] = v[3]*rn1;
        }
    }
}

// ---------------- causal depthwise conv (K=4) + SiLU (sLSTM path) ----------------
template<int C, int LDIN>
__global__ void conv_silu_t(const float* __restrict__ in, const float* __restrict__ w,
                            const float* __restrict__ bias, float* __restrict__ out)
{
    long idx = (long)blockIdx.x * 256 + threadIdx.x;
    if (idx >= (long)BS * C) return;
    int c = (int)(idx & (C - 1));
    long bs = idx / C;
    int s = (int)(bs & (SS - 1));
    float acc = bias[c];
    #pragma unroll
    for (int kk = 0; kk < 4; kk++) {
        int sp = s + kk - 3;
        if (sp >= 0) acc += in[(bs + kk - 3) * (long)LDIN + c] * w[c*4 + kk];
    }
    out[bs * (long)C + c] = acc / (1.f + __expf(-acc));
}

// ---------------- fused conv+SiLU+headwise qkv, 4-s rolling window ----------------
__global__ void conv_qkv(const float* __restrict__ up, const float* __restrict__ cw,
                         const float* __restrict__ cb,
                         const float* __restrict__ qw, const float* __restrict__ kw,
                         const float* __restrict__ vw,
                         float* __restrict__ xa, float* __restrict__ q,
                         float* __restrict__ k, float* __restrict__ v)
{
    // thread -> (bs4 block of 4 s positions, nb)
    long idx = (long)blockIdx.x * 256 + threadIdx.x;
    if (idx >= (long)(BS/4) * 512) return;
    int nb = (int)(idx & 511);
    long bs4 = idx >> 9;
    long bs0 = bs4 << 2;              // first of 4 s positions
    int s0 = (int)(bs0 & (SS - 1));   // aligned to 4, never wraps within group

    // rolling window rows s0-3 .. s0+3 (7 rows of 4 floats)
    float w7[7][4];
    const float* upc = up + bs0 * (2L*II) + nb*4;
    #pragma unroll
    for (int r = 0; r < 3; r++) {
        if (s0 + r - 3 >= 0) *(float4*)w7[r] = *(const float4*)(upc + (long)(r-3) * (2L*II));
        else w7[r][0] = w7[r][1] = w7[r][2] = w7[r][3] = 0.f;
    }
    #pragma unroll
    for (int r = 3; r < 7; r++)
        *(float4*)w7[r] = *(const float4*)(upc + (long)(r-3) * (2L*II));

    // weights once per thread
    float4 cbv = ((const float4*)cb)[nb];
    float cbs[4] = {cbv.x, cbv.y, cbv.z, cbv.w};
    float4 cw4[4], qv[4], kv[4], vv[4];
    #pragma unroll
    for (int i = 0; i < 4; i++) cw4[i] = ((const float4*)cw)[nb*4 + i];
    #pragma unroll
    for (int o = 0; o < 4; o++) {
        qv[o] = ((const float4*)qw)[nb*4 + o];
        kv[o] = ((const float4*)kw)[nb*4 + o];
        vv[o] = ((const float4*)vw)[nb*4 + o];
    }

    #pragma unroll
    for (int j = 0; j < 4; j++) {       // output s = s0 + j, rows w7[j..j+3]
        long bs = bs0 + j;
        float xo[4];
        #pragma unroll
        for (int i = 0; i < 4; i++) {
            float acc = cbs[i] + w7[j+0][i]*cw4[i].x + w7[j+1][i]*cw4[i].y
                      + w7[j+2][i]*cw4[i].z + w7[j+3][i]*cw4[i].w;
            xo[i] = acc / (1.f + __expf(-acc));
        }
        *(float4*)(xa + bs * II + nb*4) = make_float4(xo[0], xo[1], xo[2], xo[3]);
        const float* xm = w7[j+3];      // current row (conv tap kk=3 input = row s)
        float qo[4], ko[4], vo[4];
        #pragma unroll
        for (int o = 0; o < 4; o++) {
            qo[o] = xo[0]*qv[o].x + xo[1]*qv[o].y + xo[2]*qv[o].z + xo[3]*qv[o].w;
            ko[o] = xo[0]*kv[o].x + xo[1]*kv[o].y + xo[2]*kv[o].z + xo[3]*kv[o].w;
            vo[o] = xm[0]*vv[o].x + xm[1]*vv[o].y + xm[2]*vv[o].z + xm[3]*vv[o].w;
        }
        *(float4*)(q + bs * II + nb*4) = make_float4(qo[0], qo[1], qo[2], qo[3]);
        *(float4*)(k + bs * II + nb*4) = make_float4(ko[0], ko[1], ko[2], ko[3]);
        *(float4*)(v + bs * II + nb*4) = make_float4(vo[0], vo[1], vo[2], vo[3]);
    }
}

// ---------------- ig/fg gate projections: 2 rows per block (weight reuse) ----------------
__global__ void __launch_bounds__(512) igfg_k(
    const float* __restrict__ q, const float* __restrict__ k,
    const float* __restrict__ v,
    const float* __restrict__ igw, const float* __restrict__ igb,
    const float* __restrict__ fgw, const float* __restrict__ fgb,
    float* __restrict__ ig, float* __restrict__ fg)
{
    const int half = threadIdx.x >> 8;       // 0 or 1
    const int t = threadIdx.x & 255;
    long bs = (long)blockIdx.x * 2 + half;
    int b = (int)(bs >> 10);
    int s = (int)(bs & (SS - 1));
    __shared__ float sx[2][3 * II];
    __shared__ float rbuf[2][2][8];
    for (int i = t; i < II / 4; i += 256) {
        ((float4*)sx[half])[i]        = ((const float4*)(q + bs * II))[i];
        ((float4*)sx[half])[II/4 + i] = ((const float4*)(k + bs * II))[i];
        ((float4*)sx[half])[II/2 + i] = ((const float4*)(v + bs * II))[i];
    }
    __syncthreads();
    const float4* sx4 = (const float4*)sx[half];
    for (int h = 0; h < 4; h++) {
        const float4* iw4 = (const float4*)(igw + h * (3*II));
        const float4* fw4 = (const float4*)(fgw + h * (3*II));
        float pi = 0.f, pf = 0.f;
        for (int j = t; j < (3*II)/4; j += 256) {
            float4 xv = sx4[j];
            float4 wi = iw4[j];
            float4 wf = fw4[j];
            pi += xv.x*wi.x + xv.y*wi.y + xv.z*wi.z + xv.w*wi.w;
            pf += xv.x*wf.x + xv.y*wf.y + xv.z*wf.z + xv.w*wf.w;
        }
        pi = warpSum(pi); pf = warpSum(pf);
        if ((t & 31) == 0) { rbuf[half][0][t >> 5] = pi; rbuf[half][1][t >> 5] = pf; }
        __syncthreads();
        if (t == 0) {
            float a = 0.f, bb = 0.f;
            #pragma unroll
            for (int w8 = 0; w8 < 8; w8++) { a += rbuf[half][0][w8]; bb += rbuf[half][1][w8]; }
            ig[(long)(b*4 + h) * SS + s] = a + igb[h];
            fg[(long)(b*4 + h) * SS + s] = bb + fgb[h];
        }
        __syncthreads();
    }
}

// ---------------- mLSTM decay prep (+ zero RNS) ----------------
__global__ void mlstm_prep(const float* __restrict__ ig, const float* __restrict__ fg,
                           float* __restrict__ a, float* __restrict__ rm,
                           float* __restrict__ en, float* __restrict__ rns)
{
    int z = blockIdx.x;
    int tid = threadIdx.x;  // 256
    __shared__ float slsig[SS], sig_s[SS];
    for (int i = tid; i < SS; i += 256) {
        float fv = fg[(long)z * SS + i];
        slsig[i] = fminf(fv, 0.f) - log1pf(__expf(-fabsf(fv)));
        sig_s[i] = ig[(long)z * SS + i];
        rns[(long)z * SS + i] = 0.f;
    }
    __syncthreads();
    if (tid == 0) {
        float cs = 0.f, run = -1e30f;
        for (int s = 0; s < SS; s++) {
            cs += slsig[s];
            float av = sig_s[s] - cs;
            run = fmaxf(run, av);
            a[(long)z * SS + s]  = av;
            rm[(long)z * SS + s] = run;
            en[(long)z * SS + s] = __expf(-(cs + run));
        }
    }
}

// ---------------- mh_norm(dh=512) + (h+skip*xa)*silu(z) ----------------
__global__ void mh_mix(const float* __restrict__ H, const float* __restrict__ onw,
                       const float* __restrict__ skip, const float* __restrict__ xa,
                       const float* __restrict__ up, float* __restrict__ hmix)
{
    int bs = blockIdx.x, h = blockIdx.y;
    int b = bs >> 10;
    int s = bs & (SS - 1);
    const float* hp = H + ((long)(b*4 + h) * SS + s) * DHM;
    int tid = threadIdx.x;  // 128
    float4 v = ((const float4*)hp)[tid];
    float sm = v.x + v.y + v.z + v.w;
    float sq = v.x*v.x + v.y*v.y + v.z*v.z + v.w*v.w;
    __shared__ float s1[4], s2[4];
    sm = warpSum(sm); sq = warpSum(sq);
    if ((tid & 31) == 0) { s1[tid >> 5] = sm; s2[tid >> 5] = sq; }
    __syncthreads();
    float tot  = s1[0] + s1[1] + s1[2] + s1[3];
    float tot2 = s2[0] + s2[1] + s2[2] + s2[3];
    float mu = tot * (1.f / DHM);
    float rs = rsqrtf(tot2 * (1.f / DHM) - mu * mu + 1e-5f);
    float4 wv  = ((const float4*)onw)[h*128 + tid];
    float4 sk  = ((const float4*)skip)[h*128 + tid];
    float4 xav = ((const float4*)(xa + (long)bs * II))[h*128 + tid];
    float4 zv  = ((const float4*)(up + (long)bs * (2L*II) + II))[h*128 + tid];
    float4 o;
    o.x = ((v.x - mu)*rs*wv.x + sk.x*xav.x) * (zv.x / (1.f + __expf(-zv.x)));
    o.y = ((v.y - mu)*rs*wv.y + sk.y*xav.y) * (zv.y / (1.f + __expf(-zv.y)));
    o.z = ((v.z - mu)*rs*wv.z + sk.z*xav.z) * (zv.z / (1.f + __expf(-zv.z)));
    o.w = ((v.w - mu)*rs*wv.w + sk.w*xav.w) * (zv.w / (1.f + __expf(-zv.w)));
    ((float4*)(hmix + (long)bs * II))[h*128 + tid] = o;
}

// ============================================================================
// Cluster-split sLSTM scan v3 (R10): f32x2 matvec, d-quarter split, 1 barrier.
// ============================================================================
#define SCAN_SMEM_FLOATS (32768 + 256 + 2048 + 512)

__device__ __forceinline__ uint32_t smem_addr_u32(const void* p) {
    return (uint32_t)__cvta_generic_to_shared(p);
}
__device__ __forceinline__ uint32_t mapa_u32(uint32_t addr, uint32_t rank) {
    uint32_t out;
    asm("mapa.shared::cluster.u32 %0, %1, %2;" : "=r"(out) : "r"(addr), "r"(rank));
    return out;
}
__device__ __forceinline__ void st_cluster_u64(uint32_t addr, ull v) {
    asm volatile("st.shared::cluster.u64 [%0], %1;" :: "r"(addr), "l"(v) : "memory");
}
__device__ __forceinline__ void cluster_barrier() {
    asm volatile("barrier.cluster.arrive.aligned;" ::: "memory");
    asm volatile("barrier.cluster.wait.aligned;" ::: "memory");
}

__global__ void __launch_bounds__(128, 1) __cluster_dims__(8, 1, 1)
slstm_scan_cl(const float* __restrict__ pre, const float* __restrict__ rk,
              const float* __restrict__ rb, float* __restrict__ ys)
{
    extern __shared__ float sm[];
    float* W    = sm;
    float* sh_h = sm + 32768;
    float* sraw = sm + 33024;
    ull*   spart = (ull*)(sm + 35072);

    const int z = blockIdx.x >> 3;
    const int b = z >> 2, h = z & 3;
    uint32_t rank;
    asm("mov.u32 %0, %%cluster_ctarank;" : "=r"(rank));
    const int g  = rank >> 1;
    const int hf = rank & 1;
    const int tid = threadIdx.x;
    const int eg = tid & 31;
    const int dq = tid >> 5;
    const int el = eg * 4;

    const float* rks = rk + ((long)h * 256 * 4 + g) * 256 + hf * 128;
    for (int idx = tid; idx < 32768; idx += 128) {
        int d = idx >> 7, e2 = idx & 127;
        W[idx] = rks[(long)d * 1024 + e2];
    }
    for (int i = tid; i < 256; i += 128) sh_h[i] = 0.f;
    __syncthreads();

    const float* pb = pre + ((long)(g*4 + h) * BS + (long)b * SS) * DHS + hf*128 + el;
    float4 rbv4 = make_float4(0.f, 0.f, 0.f, 0.f);
    float4 pv4  = make_float4(0.f, 0.f, 0.f, 0.f);
    if (dq == 0) {
        rbv4 = *(const float4*)(rb + (h*4 + g) * DHS + hf*128 + el);
        pv4  = *(const float4*)pb;
    }

    uint32_t rdst[8];
    #pragma unroll
    for (int r = 0; r < 8; r++)
        rdst[r] = mapa_u32(smem_addr_u32(&sraw[g*256 + hf*128 + el]), (uint32_t)r);

    float* yo = ys + (long)z * SS * DHS;

    float c0 = 0.f, n0 = 0.f, m0 = 0.f;
    float c1 = 0.f, n1 = 0.f, m1 = 0.f;

    cluster_barrier();

    const float* Wp = W + el + (dq << 13);
    for (int s = 0; s < SS; s++) {
        ull a01 = 0ull, a23 = 0ull;
        const int dbase = dq << 6;
        #pragma unroll
        for (int d4 = 0; d4 < 64; d4 += 4) {
            float4 h4 = *(const float4*)&sh_h[dbase + d4];
            F4U w;
            w.f = *(const float4*)&Wp[(d4+0) << 7];
            { ull hh = pack2(h4.x, h4.x); a01 = fma2(w.u[0], hh, a01); a23 = fma2(w.u[1], hh, a23); }
            w.f = *(const float4*)&Wp[(d4+1) << 7];
            { ull hh = pack2(h4.y, h4.y); a01 = fma2(w.u[0], hh, a01); a23 = fma2(w.u[1], hh, a23); }
            w.f = *(const float4*)&Wp[(d4+2) << 7];
            { ull hh = pack2(h4.z, h4.z); a01 = fma2(w.u[0], hh, a01); a23 = fma2(w.u[1], hh, a23); }
            w.f = *(const float4*)&Wp[(d4+3) << 7];
            { ull hh = pack2(h4.w, h4.w); a01 = fma2(w.u[0], hh, a01); a23 = fma2(w.u[1], hh, a23); }
        }
        if (dq > 0) {
            spart[(dq-1)*64 + eg*2]     = a01;
            spart[(dq-1)*64 + eg*2 + 1] = a23;
        }
        __syncthreads();
        if (dq == 0) {
            a01 = add2(a01, add2(spart[eg*2],     add2(spart[64 + eg*2],     spart[128 + eg*2])));
            a23 = add2(a23, add2(spart[eg*2 + 1], add2(spart[64 + eg*2 + 1], spart[128 + eg*2 + 1])));
            float f0, f1, f2, f3;
            unpack2(a01, f0, f1);
            unpack2(a23, f2, f3);
            f0 += pv4.x + rbv4.x; f1 += pv4.y + rbv4.y;
            f2 += pv4.z + rbv4.z; f3 += pv4.w + rbv4.w;
            if (s + 1 < SS) pv4 = *(const float4*)&pb[(long)(s+1) * DHS];
            ull o01 = pack2(f0, f1), o23 = pack2(f2, f3);
            const uint32_t po = (uint32_t)(s & 1) << 12;
            #pragma unroll
            for (int r = 0; r < 8; r++) {
                st_cluster_u64(rdst[r] + po,     o01);
                st_cluster_u64(rdst[r] + po + 8, o23);
            }
        }
        cluster_barrier();

        const float* rw = sraw + (s & 1) * 1024;
        {
            float iraw = rw[tid],       fraw = rw[256 + tid];
            float zraw = rw[512 + tid], oraw = rw[768 + tid];
            float lf = m0 + fminf(fraw, 0.f) - log1pf(__expf(-fabsf(fraw)));
            float mn = fmaxf(iraw, lf);
            float ig_ = __expf(iraw - mn);
            float fg_ = __expf(lf - mn);
            float th  = 1.f - __fdividef(2.f, __expf(2.f * zraw) + 1.f);
            c0 = fg_ * c0 + ig_ * th;
            n0 = fg_ * n0 + ig_;
            m0 = mn;
            float hv = c0 / (n0 * (1.f + __expf(-oraw)));
            sh_h[tid] = hv;
            if (rank == 0) yo[(long)s * DHS + tid] = hv;
        }
        {
            float iraw = rw[128 + tid], fraw = rw[384 + tid];
            float zraw = rw[640 + tid], oraw = rw[896 + tid];
            float lf = m1 + fminf(fraw, 0.f) - log1pf(__expf(-fabsf(fraw)));
            float mn = fmaxf(iraw, lf);
            float ig_ = __expf(iraw - mn);
            float fg_ = __expf(lf - mn);
            float th  = 1.f - __fdividef(2.f, __expf(2.f * zraw) + 1.f);
            c1 = fg_ * c1 + ig_ * th;
            n1 = fg_ * n1 + ig_;
            m1 = mn;
            float hv = c1 / (n1 * (1.f + __expf(-oraw)));
            sh_h[128 + tid] = hv;
            if (rank == 0) yo[(long)s * DHS + 128 + tid] = hv;
        }
        __syncthreads();
    }
}

// ---------------- sLSTM group norm (256) + residual add ----------------
__global__ void slstm_gnorm(const float* __restrict__ ys, const float* __restrict__ gnw,
                            float* __restrict__ x)
{
    int bs = blockIdx.x, h = blockIdx.y;
    int b = bs >> 10, s = bs & (SS - 1);
    const float* yp = ys + ((long)(b*4 + h) * SS + s) * DHS;
    int tid = threadIdx.x;  // 64
    float4 v = ((const float4*)yp)[tid];
    float sm = v.x + v.y + v.z + v.w;
    float sq = v.x*v.x + v.y*v.y + v.z*v.z + v.w*v.w;
    __shared__ float s1[2], s2[2];
    sm = warpSum(sm); sq = warpSum(sq);
    if ((tid & 31) == 0) { s1[tid >> 5] = sm; s2[tid >> 5] = sq; }
    __syncthreads();
    float tot  = s1[0] + s1[1];
    float tot2 = s2[0] + s2[1];
    float mu = tot * (1.f / DHS);
    float rs = rsqrtf(tot2 * (1.f / DHS) - mu * mu + 1e-5f);
    float4 wv = ((const float4*)gnw)[h*64 + tid];
    float* xp = x + (long)bs * DD + h * DHS + tid * 4;
    float4 xv = *(float4*)xp;
    xv.x += (v.x - mu) * rs * wv.x;
    xv.y += (v.y - mu) * rs * wv.y;
    xv.z += (v.z - mu) * rs * wv.z;
    xv.w += (v.w - mu) * rs * wv.w;
    *(float4*)xp = xv;
}

// ---------------- FFN: act = gelu_exact(gate) * up ----------------
__global__ void gelu_mul(const float* __restrict__ f, float* __restrict__ a)
{
    long idx = (long)blockIdx.x * 256 + threadIdx.x;
    if (idx >= (long)BS * UU) return;
    long bs = idx / UU;
    int u = (int)(idx % UU);
    float g = f[bs * (2L*UU) + u];
    float p = f[bs * (2L*UU) + UU + u];
    a[idx] = 0.5f * g * (1.f + erff(g * 0.70710678118654752f)) * p;
}

// ---------------- host ----------------
static inline void gemm(const float* A, const float* B, float* C,
                        int M, int N, int K, int lda, int ldb, int ldc,
                        float alpha, const float* bias, int acc)
{
    dim3 grid(N / 128, M / 128);
    tgemm_nt<<<grid, 256>>>(A, B, C, M, N, K, lda, ldb, ldc, alpha, bias, acc);
}

extern "C" void kernel_launch(void* const* d_in, const int* in_sizes, int n_in,
                              void* d_out, int out_size)
{
    const int*   ids       = (const int*)  d_in[0];
    const float* emb       = (const float*)d_in[1];
    const float* m_ln_w    = (const float*)d_in[2];
    const float* m_up_w    = (const float*)d_in[3];
    const float* m_conv_w  = (const float*)d_in[4];
    const float* m_conv_b  = (const float*)d_in[5];
    const float* m_q_w     = (const float*)d_in[6];
    const float* m_k_w     = (const float*)d_in[7];
    const float* m_v_w     = (const float*)d_in[8];
    const float* m_ig_w    = (const float*)d_in[9];
    const float* m_ig_b    = (const float*)d_in[10];
    const float* m_fg_w    = (const float*)d_in[11];
    const float* m_fg_b    = (const float*)d_in[12];
    const float* m_skip    = (const float*)d_in[13];
    const float* m_on_w    = (const float*)d_in[14];
    const float* m_down_w  = (const float*)d_in[15];
    const float* s_ln_w    = (const float*)d_in[16];
    const float* s_conv_w  = (const float*)d_in[17];
    const float* s_conv_b  = (const float*)d_in[18];
    const float* s_iw      = (const float*)d_in[19];
    const float* s_fw      = (const float*)d_in[20];
    const float* s_zw      = (const float*)d_in[21];
    const float* s_ow      = (const float*)d_in[22];
    const float* s_rk      = (const float*)d_in[23];
    const float* s_rb      = (const float*)d_in[24];
    const float* s_gn_w    = (const float*)d_in[25];
    const float* s_ln2_w   = (const float*)d_in[26];
    const float* s_ffn_up  = (const float*)d_in[27];
    const float* s_ffn_dn  = (const float*)d_in[28];
    const float* post_ln_w = (const float*)d_in[29];
    const float* head_w    = (const float*)d_in[30];
    const float* head_b    = (const float*)d_in[31];
    float* out = (float*)d_out;

    float* pool = nullptr;
    cudaGetSymbolAddress((void**)&pool, g_pool);
    float* X   = pool + O_X;   float* XN  = pool + O_XN;  float* XC  = pool + O_XC;
    float* UP  = pool + O_UP;  float* XA  = pool + O_XA;
    float* Q_  = pool + O_Q;   float* K_  = pool + O_K;   float* V_  = pool + O_V;
    float* SC  = pool + O_SC;  float* HB  = pool + O_HB;  float* HM  = pool + O_HM;
    float* PRE = pool + O_PRE; float* YS  = pool + O_YS;
    float* FFN = pool + O_FFN; float* ACT = pool + O_ACT;
    float* IG  = pool + O_IG;  float* FG  = pool + O_FG;
    float* Aa  = pool + O_A;   float* RM  = pool + O_RM;
    float* EN  = pool + O_EN;  float* RNS = pool + O_RNS;

    cudaFuncSetAttribute(slstm_scan_cl,
                         cudaFuncAttributeMaxDynamicSharedMemorySize,
                         SCAN_SMEM_FLOATS * 4);

    embed_k<<<BS, 256>>>(ids, emb, X);

    int mi = 0;
    for (int blk = 0; blk < 4; blk++) {
        if (blk == 1) {
            // ---------------- sLSTM block ----------------
            layernorm_k<<<BS, 256>>>(X, s_ln_w, XN);
            conv_silu_t<DD, DD><<<(BS * DD) / 256, 256>>>(XN, s_conv_w, s_conv_b, XC);
            tgemm_gates<<<dim3(2, 32, 16), 256>>>(XC, XN, s_iw, s_fw, s_zw, s_ow, PRE);
            slstm_scan_cl<<<128, 128, SCAN_SMEM_FLOATS * 4>>>(PRE, s_rk, s_rb, YS);
            slstm_gnorm<<<dim3(BS, 4), 64>>>(YS, s_gn_w, X);
            layernorm_k<<<BS, 256>>>(X, s_ln2_w, XN);
            gemm(XN, s_ffn_up, FFN, BS, 2*UU, DD, DD, DD, 2*UU, 1.f, nullptr, 0);
            gelu_mul<<<(int)(((long)BS*UU + 255) / 256), 256>>>(FFN, ACT);
            gemm(ACT, s_ffn_dn, X, BS, DD, UU, UU, UU, DD, 1.f, nullptr, 1);
        } else {
            // ---------------- mLSTM block ----------------
            layernorm_k<<<BS, 256>>>(X, m_ln_w + (long)mi*DD, XN);
            gemm(XN, m_up_w + (long)mi*4096*DD, UP, BS, 4096, DD, DD, DD, 4096,
                 1.f, nullptr, 0);
            conv_qkv<<<(int)(((long)(BS/4)*512) / 256), 256>>>(
                UP, m_conv_w + (long)mi*II*4, m_conv_b + (long)mi*II,
                m_q_w + (long)mi*512*16, m_k_w + (long)mi*512*16,
                m_v_w + (long)mi*512*16, XA, Q_, K_, V_);
            igfg_k<<<BS/2, 512>>>(Q_, K_, V_,
                m_ig_w + (long)mi*4*6144, m_ig_b + (long)mi*4,
                m_fg_w + (long)mi*4*6144, m_fg_b + (long)mi*4, IG, FG);
            mlstm_prep<<<16, 256>>>(IG, FG, Aa, RM, EN, RNS);
            attn_qk<<<dim3(36, 1, 16), 256>>>(Q_, K_, SC, Aa, RM, RNS);
            attn_av<<<dim3(4, 8, 16), 256>>>(SC, V_, RNS, EN, HB);
            mh_mix<<<dim3(BS, 4), 128>>>(HB, m_on_w + (long)mi*II,
                m_skip + (long)mi*II, XA, UP, HM);
            gemm(HM, m_down_w + (long)mi*DD*II, X, BS, DD, II, II, II, DD,
                 1.f, nullptr, 1);
            mi++;
        }
    }

    layernorm_k<<<BS, 256>>>(X, post_ln_w, XN);
    gemm(XN, head_w, out, BS, 256, DD, DD, DD, 256, 1.f, head_b, 0);
}